// round 1
// baseline (speedup 1.0000x reference)
#include <cuda_runtime.h>
#include <math.h>
#include <stdint.h>

// Problem constants
constexpr int CB = 2;      // batch
constexpr int CT = 4096;   // seq len
constexpr int CD = 1024;   // d_model
constexpr int CL = 2;      // layers
constexpr int CH = 16;     // heads
constexpr int CF = 4096;   // d_ff
constexpr int CK = 2048;   // top-k tokens
constexpr int CDH = 64;    // head dim
constexpr int BK_ROWS = CB * CK;           // 4096 rows through the blocks
constexpr size_t BTD = (size_t)CB * CT * CD;

// ---------------- scratch (static device globals; no runtime allocation) ----
__device__ float g_logits[CB * CT];
__device__ int   g_sel[CB * CT];
__device__ int   g_idx[CB * CK];
__device__ float g_gate[CB * CK];
__device__ float g_h[BK_ROWS * CD];
__device__ float g_lnbuf[BK_ROWS * CD];
__device__ float g_qkv[(size_t)BK_ROWS * 3 * CD];
__device__ float g_attn[BK_ROWS * CD];
__device__ float g_mid[(size_t)BK_ROWS * CF];

// ---------------- router: logits[b,t] = dot(x[b,t], w) + b ------------------
__global__ void router_kernel(const float* __restrict__ x,
                              const float* __restrict__ wr,
                              const float* __restrict__ br,
                              float* __restrict__ logits) {
    int gw = (blockIdx.x * blockDim.x + threadIdx.x) >> 5;  // global warp = row
    if (gw >= CB * CT) return;
    int lane = threadIdx.x & 31;
    const float4* p = (const float4*)(x + (size_t)gw * CD);
    const float4* w4 = (const float4*)wr;
    float s = 0.f;
#pragma unroll
    for (int i = 0; i < CD / 128; i++) {
        float4 a = p[lane + i * 32];
        float4 w = w4[lane + i * 32];
        s += a.x * w.x + a.y * w.y + a.z * w.z + a.w * w.w;
    }
#pragma unroll
    for (int o = 16; o > 0; o >>= 1) s += __shfl_down_sync(0xffffffffu, s, o);
    if (lane == 0) logits[gw] = s + br[0];
}

// ---------------- top-K selection: rank counting ----------------------------
// grid = CB*64 blocks, 256 threads. Block handles 64 consecutive tokens.
__global__ void rank_kernel(const float* __restrict__ logits, int* __restrict__ sel) {
    int blk = blockIdx.x;
    int b = blk >> 6;
    int base = (blk & 63) * 64;
    __shared__ float lv[CT];
    int tid = threadIdx.x;
    for (int t = tid; t < CT; t += 256) lv[t] = logits[b * CT + t];
    __syncthreads();
    int tt = tid >> 2, part = tid & 3;
    int t = base + tt;
    float v = lv[t];
    int cnt = 0;
    int s0 = part * 1024;
#pragma unroll 8
    for (int s = s0; s < s0 + 1024; s++) {
        float u = lv[s];
        cnt += (u > v) || (u == v && s < t);
    }
    __shared__ int rk[64];
    if (part == 0) rk[tt] = 0;
    __syncthreads();
    atomicAdd(&rk[tt], cnt);
    __syncthreads();
    if (part == 0) sel[b * CT + t] = (rk[tt] < CK) ? 1 : 0;
}

// grid = CB blocks, 1024 threads. Compact selected indices in ascending order.
__global__ void compact_kernel(const float* __restrict__ logits,
                               const int* __restrict__ sel,
                               int* __restrict__ idx_out,
                               float* __restrict__ gate_out) {
    int b = blockIdx.x;
    int tid = threadIdx.x;  // 1024
    int f[4]; int c = 0;
#pragma unroll
    for (int i = 0; i < 4; i++) { f[i] = sel[b * CT + tid * 4 + i]; c += f[i]; }
    int lane = tid & 31, wid = tid >> 5;
    int incl = c;
#pragma unroll
    for (int o = 1; o < 32; o <<= 1) {
        int n = __shfl_up_sync(0xffffffffu, incl, o);
        if (lane >= o) incl += n;
    }
    __shared__ int wsum[32];
    if (lane == 31) wsum[wid] = incl;
    __syncthreads();
    if (wid == 0) {
        int w = wsum[lane];
#pragma unroll
        for (int o = 1; o < 32; o <<= 1) {
            int n = __shfl_up_sync(0xffffffffu, w, o);
            if (lane >= o) w += n;
        }
        wsum[lane] = w;
    }
    __syncthreads();
    int pos = (wid ? wsum[wid - 1] : 0) + incl - c;  // exclusive prefix
#pragma unroll
    for (int i = 0; i < 4; i++) {
        if (f[i]) {
            int t = tid * 4 + i;
            idx_out[b * CK + pos] = t;
            float lg = logits[b * CT + t];
            gate_out[b * CK + pos] = 1.f / (1.f + expf(-lg));
            pos++;
        }
    }
}

// ---------------- gather rows -----------------------------------------------
__global__ void gather_kernel(const float* __restrict__ x, const int* __restrict__ idx,
                              float* __restrict__ h) {
    int bk = blockIdx.x;            // 0..BK_ROWS-1
    int b = bk >> 11;               // /CK
    int t = idx[bk];
    const float4* src = (const float4*)(x + ((size_t)b * CT + t) * CD);
    float4* dst = (float4*)(h + (size_t)bk * CD);
    dst[threadIdx.x] = src[threadIdx.x];   // 256 threads * float4 = 1024
}

// ---------------- layernorm --------------------------------------------------
__global__ void layernorm_kernel(const float* __restrict__ in, float* __restrict__ out,
                                 const float* __restrict__ scale,
                                 const float* __restrict__ bias) {
    int row = blockIdx.x;
    int tid = threadIdx.x;  // 256
    const float4* p = (const float4*)(in + (size_t)row * CD);
    float4 v = p[tid];
    float s = v.x + v.y + v.z + v.w;
    float ss = v.x * v.x + v.y * v.y + v.z * v.z + v.w * v.w;
#pragma unroll
    for (int o = 16; o > 0; o >>= 1) {
        s += __shfl_down_sync(0xffffffffu, s, o);
        ss += __shfl_down_sync(0xffffffffu, ss, o);
    }
    __shared__ float red[64];
    int lane = tid & 31, wid = tid >> 5;
    if (lane == 0) { red[wid] = s; red[32 + wid] = ss; }
    __syncthreads();
    if (tid == 0) {
        float S = 0, SS = 0;
#pragma unroll
        for (int w = 0; w < 8; w++) { S += red[w]; SS += red[32 + w]; }
        red[0] = S; red[32] = SS;
    }
    __syncthreads();
    float mean = red[0] * (1.f / CD);
    float var = red[32] * (1.f / CD) - mean * mean;
    float inv = rsqrtf(var + 1e-5f);
    int n = tid * 4;
    float4 sc = ((const float4*)scale)[tid];
    float4 bi = ((const float4*)bias)[tid];
    float4 o4;
    o4.x = (v.x - mean) * inv * sc.x + bi.x;
    o4.y = (v.y - mean) * inv * sc.y + bi.y;
    o4.z = (v.z - mean) * inv * sc.z + bi.z;
    o4.w = (v.w - mean) * inv * sc.w + bi.w;
    ((float4*)(out + (size_t)row * CD))[tid] = o4;
    (void)n;
}

// ---------------- SGEMM: C = act(A @ W + bias) [+ residual] -----------------
__device__ __forceinline__ float gelu_tanh(float x) {
    float x3 = x * x * x;
    float t = tanhf(0.7978845608028654f * (x + 0.044715f * x3));
    return 0.5f * x * (1.f + t);
}

template <bool GELU, bool RESID>
__global__ __launch_bounds__(256) void sgemm_kernel(
    const float* __restrict__ A, const float* __restrict__ W,
    const float* __restrict__ bias, const float* __restrict__ R,
    float* __restrict__ C, int M, int N, int Kd) {
    constexpr int BM = 128, BN = 128, BKT = 16;
    __shared__ float As[BKT][BM];
    __shared__ float Bs[BKT][BN];
    int tid = threadIdx.x;
    int bx = blockIdx.x, by = blockIdx.y;
    int tx = tid & 15, ty = tid >> 4;
    float acc[8][8];
#pragma unroll
    for (int i = 0; i < 8; i++)
#pragma unroll
        for (int j = 0; j < 8; j++) acc[i][j] = 0.f;

    for (int k0 = 0; k0 < Kd; k0 += BKT) {
        __syncthreads();
#pragma unroll
        for (int L2 = 0; L2 < 2; L2++) {
            int idx4 = tid + L2 * 256;
            int ar = idx4 >> 2, ac = (idx4 & 3) * 4;
            float4 av = *(const float4*)(A + (size_t)(by * BM + ar) * Kd + k0 + ac);
            As[ac + 0][ar] = av.x; As[ac + 1][ar] = av.y;
            As[ac + 2][ar] = av.z; As[ac + 3][ar] = av.w;
            int br = idx4 >> 5, bc = (idx4 & 31) * 4;
            *(float4*)(&Bs[br][bc]) = *(const float4*)(W + (size_t)(k0 + br) * N + bx * BN + bc);
        }
        __syncthreads();
#pragma unroll
        for (int kk = 0; kk < BKT; kk++) {
            float a[8], b[8];
            *(float4*)(a)     = *(const float4*)(&As[kk][ty * 8]);
            *(float4*)(a + 4) = *(const float4*)(&As[kk][ty * 8 + 4]);
            *(float4*)(b)     = *(const float4*)(&Bs[kk][tx * 8]);
            *(float4*)(b + 4) = *(const float4*)(&Bs[kk][tx * 8 + 4]);
#pragma unroll
            for (int i = 0; i < 8; i++)
#pragma unroll
                for (int j = 0; j < 8; j++) acc[i][j] += a[i] * b[j];
        }
    }
#pragma unroll
    for (int i = 0; i < 8; i++) {
        int m = by * BM + ty * 8 + i;
#pragma unroll
        for (int j = 0; j < 8; j++) {
            int n = bx * BN + tx * 8 + j;
            float v = acc[i][j] + bias[n];
            if (GELU) v = gelu_tanh(v);
            if (RESID) v += R[(size_t)m * N + n];
            C[(size_t)m * N + n] = v;
        }
    }
}

// ---------------- causal flash attention (fp32) ------------------------------
__global__ __launch_bounds__(64) void attn_kernel(const float* __restrict__ qkv,
                                                  float* __restrict__ o) {
    const int qt = blockIdx.x;   // q tile
    const int h = blockIdx.y;
    const int b = blockIdx.z;
    const int r = threadIdx.x;   // 0..63
    const int m = qt * 64 + r;
    __shared__ float Ks[64][68];
    __shared__ float Vs[64][68];
    float q[64], acc[64];
    const float* qptr = qkv + ((size_t)(b * CK + m)) * (3 * CD) + h * CDH;
#pragma unroll
    for (int d = 0; d < 64; d += 4) {
        float4 t4 = *(const float4*)(qptr + d);
        q[d] = t4.x; q[d + 1] = t4.y; q[d + 2] = t4.z; q[d + 3] = t4.w;
    }
#pragma unroll
    for (int d = 0; d < 64; d++) acc[d] = 0.f;
    float mi = -1e30f, l = 0.f;

    for (int kt = 0; kt <= qt; kt++) {
        __syncthreads();
        const float* kbase = qkv + ((size_t)(b * CK + kt * 64 + r)) * (3 * CD) + CD + h * CDH;
        const float* vbase = kbase + CD;
#pragma unroll
        for (int d = 0; d < 64; d += 4) {
            *(float4*)(&Ks[r][d]) = *(const float4*)(kbase + d);
            *(float4*)(&Vs[r][d]) = *(const float4*)(vbase + d);
        }
        __syncthreads();
        int jmax = (kt == qt) ? r : 63;
        for (int j = 0; j <= jmax; j++) {
            float s = 0.f;
#pragma unroll
            for (int d = 0; d < 64; d++) s += q[d] * Ks[j][d];
            s *= 0.125f;
            float nm = fmaxf(mi, s);
            float co = __expf(mi - nm);
            float p = __expf(s - nm);
            l = l * co + p;
#pragma unroll
            for (int d = 0; d < 64; d++) acc[d] = acc[d] * co + p * Vs[j][d];
            mi = nm;
        }
    }
    float invl = 1.f / l;
    float* optr = o + ((size_t)(b * CK + m)) * CD + h * CDH;
#pragma unroll
    for (int d = 0; d < 64; d += 4) {
        float4 t4;
        t4.x = acc[d] * invl; t4.y = acc[d + 1] * invl;
        t4.z = acc[d + 2] * invl; t4.w = acc[d + 3] * invl;
        *(float4*)(optr + d) = t4;
    }
}

// ---------------- output assembly -------------------------------------------
__global__ void copyx_kernel(const float* __restrict__ x, float* __restrict__ out) {
    size_t i = (size_t)blockIdx.x * blockDim.x + threadIdx.x;  // float4 index
    ((float4*)out)[i] = ((const float4*)x)[i];
}

__global__ void scatter_kernel(const float* __restrict__ h, const int* __restrict__ idx,
                               const float* __restrict__ gate, float* __restrict__ out) {
    int bk = blockIdx.x;
    int b = bk >> 11;
    int t = idx[bk];
    float g = gate[bk];
    float4* dst = (float4*)(out + ((size_t)b * CT + t) * CD);
    const float4* src = (const float4*)(h + (size_t)bk * CD);
    float4 s = src[threadIdx.x];
    float4 d0 = dst[threadIdx.x];
    d0.x += s.x * g; d0.y += s.y * g; d0.z += s.z * g; d0.w += s.w * g;
    dst[threadIdx.x] = d0;
}

__global__ void tail_kernel(const int* __restrict__ idx, const float* __restrict__ logits,
                            float* __restrict__ out) {
    int i = blockIdx.x * blockDim.x + threadIdx.x;
    if (i < CB * CK) {
        out[BTD + i] = (float)idx[i];
    } else if (i < CB * CK + CB * CT) {
        int j = i - CB * CK;
        out[BTD + CB * CK + j] = logits[j];
    }
}

// ---------------- launch -----------------------------------------------------
extern "C" void kernel_launch(void* const* d_in, const int* in_sizes, int n_in,
                              void* d_out, int out_size) {
    const float* x         = (const float*)d_in[0];
    const float* w_router  = (const float*)d_in[1];
    const float* b_router  = (const float*)d_in[2];
    const float* ln1_scale = (const float*)d_in[3];
    const float* ln1_bias  = (const float*)d_in[4];
    const float* w_qkv     = (const float*)d_in[5];
    const float* b_qkv     = (const float*)d_in[6];
    const float* w_o       = (const float*)d_in[7];
    const float* b_o       = (const float*)d_in[8];
    const float* ln2_scale = (const float*)d_in[9];
    const float* ln2_bias  = (const float*)d_in[10];
    const float* w1        = (const float*)d_in[11];
    const float* b1        = (const float*)d_in[12];
    const float* w2        = (const float*)d_in[13];
    const float* b2        = (const float*)d_in[14];
    float* out = (float*)d_out;

    float *logits, *gate, *h, *lnb, *qkvb, *attnb, *midb;
    int *sel, *idxp;
    cudaGetSymbolAddress((void**)&logits, g_logits);
    cudaGetSymbolAddress((void**)&sel, g_sel);
    cudaGetSymbolAddress((void**)&idxp, g_idx);
    cudaGetSymbolAddress((void**)&gate, g_gate);
    cudaGetSymbolAddress((void**)&h, g_h);
    cudaGetSymbolAddress((void**)&lnb, g_lnbuf);
    cudaGetSymbolAddress((void**)&qkvb, g_qkv);
    cudaGetSymbolAddress((void**)&attnb, g_attn);
    cudaGetSymbolAddress((void**)&midb, g_mid);

    // 1. router
    router_kernel<<<(CB * CT) / 8, 256>>>(x, w_router, b_router, logits);
    // 2. expert-choice top-K
    rank_kernel<<<CB * 64, 256>>>(logits, sel);
    compact_kernel<<<CB, 1024>>>(logits, sel, idxp, gate);
    // 3. gather
    gather_kernel<<<BK_ROWS, 256>>>(x, idxp, h);

    // 4. transformer blocks
    for (int l = 0; l < CL; l++) {
        layernorm_kernel<<<BK_ROWS, 256>>>(h, lnb, ln1_scale + l * CD, ln1_bias + l * CD);
        sgemm_kernel<false, false><<<dim3(3 * CD / 128, BK_ROWS / 128), 256>>>(
            lnb, w_qkv + (size_t)l * CD * 3 * CD, b_qkv + l * 3 * CD, nullptr, qkvb,
            BK_ROWS, 3 * CD, CD);
        attn_kernel<<<dim3(CK / 64, CH, CB), 64>>>(qkvb, attnb);
        sgemm_kernel<false, true><<<dim3(CD / 128, BK_ROWS / 128), 256>>>(
            attnb, w_o + (size_t)l * CD * CD, b_o + l * CD, h, h, BK_ROWS, CD, CD);
        layernorm_kernel<<<BK_ROWS, 256>>>(h, lnb, ln2_scale + l * CD, ln2_bias + l * CD);
        sgemm_kernel<true, false><<<dim3(CF / 128, BK_ROWS / 128), 256>>>(
            lnb, w1 + (size_t)l * CD * CF, b1 + l * CF, nullptr, midb,
            BK_ROWS, CF, CD);
        sgemm_kernel<false, true><<<dim3(CD / 128, BK_ROWS / 128), 256>>>(
            midb, w2 + (size_t)l * CF * CD, b2 + l * CD, h, h, BK_ROWS, CD, CF);
    }

    // 5. assemble output: total, idx, logits
    copyx_kernel<<<(int)(BTD / 4 / 256), 256>>>(x, out);
    scatter_kernel<<<BK_ROWS, 256>>>(h, idxp, gate, out);
    if ((size_t)out_size >= BTD + CB * CK + CB * CT) {
        int ntail = CB * CK + CB * CT;
        tail_kernel<<<(ntail + 255) / 256, 256>>>(idxp, logits, out);
    }
}

// round 2
// speedup vs baseline: 1.0042x; 1.0042x over previous
#include <cuda_runtime.h>
#include <math.h>
#include <stdint.h>

// Problem constants
constexpr int CB = 2;      // batch
constexpr int CT = 4096;   // seq len
constexpr int CD = 1024;   // d_model
constexpr int CL = 2;      // layers
constexpr int CH = 16;     // heads
constexpr int CF = 4096;   // d_ff
constexpr int CK = 2048;   // top-k tokens
constexpr int CDH = 64;    // head dim
constexpr int BK_ROWS = CB * CK;           // 4096 rows through the blocks
constexpr size_t BTD = (size_t)CB * CT * CD;

// ---------------- scratch (static device globals; no runtime allocation) ----
__device__ float g_logits[CB * CT];
__device__ int   g_sel[CB * CT];
__device__ int   g_idx[CB * CK];
__device__ float g_gate[CB * CK];
__device__ float g_h[BK_ROWS * CD];
__device__ float g_lnbuf[BK_ROWS * CD];
__device__ float g_qkv[(size_t)BK_ROWS * 3 * CD];
__device__ float g_attn[BK_ROWS * CD];
__device__ float g_mid[(size_t)BK_ROWS * CF];

// ---------------- router: logits[b,t] = dot(x[b,t], w) + b ------------------
__global__ void router_kernel(const float* __restrict__ x,
                              const float* __restrict__ wr,
                              const float* __restrict__ br,
                              float* __restrict__ logits) {
    int gw = (blockIdx.x * blockDim.x + threadIdx.x) >> 5;  // global warp = row
    if (gw >= CB * CT) return;
    int lane = threadIdx.x & 31;
    const float4* p = (const float4*)(x + (size_t)gw * CD);
    const float4* w4 = (const float4*)wr;
    float s = 0.f;
#pragma unroll
    for (int i = 0; i < CD / 128; i++) {
        float4 a = p[lane + i * 32];
        float4 w = w4[lane + i * 32];
        s += a.x * w.x + a.y * w.y + a.z * w.z + a.w * w.w;
    }
#pragma unroll
    for (int o = 16; o > 0; o >>= 1) s += __shfl_down_sync(0xffffffffu, s, o);
    if (lane == 0) logits[gw] = s + br[0];
}

// ---------------- top-K selection: rank counting ----------------------------
// grid = CB*64 blocks, 256 threads. Block handles 64 consecutive tokens.
__global__ void rank_kernel(const float* __restrict__ logits, int* __restrict__ sel) {
    int blk = blockIdx.x;
    int b = blk >> 6;
    int base = (blk & 63) * 64;
    __shared__ float lv[CT];
    int tid = threadIdx.x;
    for (int t = tid; t < CT; t += 256) lv[t] = logits[b * CT + t];
    __syncthreads();
    int tt = tid >> 2, part = tid & 3;
    int t = base + tt;
    float v = lv[t];
    int cnt = 0;
    int s0 = part * 1024;
#pragma unroll 8
    for (int s = s0; s < s0 + 1024; s++) {
        float u = lv[s];
        cnt += (u > v) || (u == v && s < t);
    }
    __shared__ int rk[64];
    if (part == 0) rk[tt] = 0;
    __syncthreads();
    atomicAdd(&rk[tt], cnt);
    __syncthreads();
    if (part == 0) sel[b * CT + t] = (rk[tt] < CK) ? 1 : 0;
}

// grid = CB blocks, 1024 threads. Compact selected indices in ascending order.
__global__ void compact_kernel(const float* __restrict__ logits,
                               const int* __restrict__ sel,
                               int* __restrict__ idx_out,
                               float* __restrict__ gate_out) {
    int b = blockIdx.x;
    int tid = threadIdx.x;  // 1024
    int f[4]; int c = 0;
#pragma unroll
    for (int i = 0; i < 4; i++) { f[i] = sel[b * CT + tid * 4 + i]; c += f[i]; }
    int lane = tid & 31, wid = tid >> 5;
    int incl = c;
#pragma unroll
    for (int o = 1; o < 32; o <<= 1) {
        int n = __shfl_up_sync(0xffffffffu, incl, o);
        if (lane >= o) incl += n;
    }
    __shared__ int wsum[32];
    if (lane == 31) wsum[wid] = incl;
    __syncthreads();
    if (wid == 0) {
        int w = wsum[lane];
#pragma unroll
        for (int o = 1; o < 32; o <<= 1) {
            int n = __shfl_up_sync(0xffffffffu, w, o);
            if (lane >= o) w += n;
        }
        wsum[lane] = w;
    }
    __syncthreads();
    int pos = (wid ? wsum[wid - 1] : 0) + incl - c;  // exclusive prefix
#pragma unroll
    for (int i = 0; i < 4; i++) {
        if (f[i]) {
            int t = tid * 4 + i;
            idx_out[b * CK + pos] = t;
            float lg = logits[b * CT + t];
            gate_out[b * CK + pos] = 1.f / (1.f + expf(-lg));
            pos++;
        }
    }
}

// ---------------- gather rows -----------------------------------------------
__global__ void gather_kernel(const float* __restrict__ x, const int* __restrict__ idx,
                              float* __restrict__ h) {
    int bk = blockIdx.x;            // 0..BK_ROWS-1
    int b = bk >> 11;               // /CK
    int t = idx[bk];
    const float4* src = (const float4*)(x + ((size_t)b * CT + t) * CD);
    float4* dst = (float4*)(h + (size_t)bk * CD);
    dst[threadIdx.x] = src[threadIdx.x];   // 256 threads * float4 = 1024
}

// ---------------- layernorm --------------------------------------------------
__global__ void layernorm_kernel(const float* __restrict__ in, float* __restrict__ out,
                                 const float* __restrict__ scale,
                                 const float* __restrict__ bias) {
    int row = blockIdx.x;
    int tid = threadIdx.x;  // 256
    const float4* p = (const float4*)(in + (size_t)row * CD);
    float4 v = p[tid];
    float s = v.x + v.y + v.z + v.w;
    float ss = v.x * v.x + v.y * v.y + v.z * v.z + v.w * v.w;
#pragma unroll
    for (int o = 16; o > 0; o >>= 1) {
        s += __shfl_down_sync(0xffffffffu, s, o);
        ss += __shfl_down_sync(0xffffffffu, ss, o);
    }
    __shared__ float red[64];
    int lane = tid & 31, wid = tid >> 5;
    if (lane == 0) { red[wid] = s; red[32 + wid] = ss; }
    __syncthreads();
    if (tid == 0) {
        float S = 0, SS = 0;
#pragma unroll
        for (int w = 0; w < 8; w++) { S += red[w]; SS += red[32 + w]; }
        red[0] = S; red[32] = SS;
    }
    __syncthreads();
    float mean = red[0] * (1.f / CD);
    float var = red[32] * (1.f / CD) - mean * mean;
    float inv = rsqrtf(var + 1e-5f);
    int n = tid * 4;
    float4 sc = ((const float4*)scale)[tid];
    float4 bi = ((const float4*)bias)[tid];
    float4 o4;
    o4.x = (v.x - mean) * inv * sc.x + bi.x;
    o4.y = (v.y - mean) * inv * sc.y + bi.y;
    o4.z = (v.z - mean) * inv * sc.z + bi.z;
    o4.w = (v.w - mean) * inv * sc.w + bi.w;
    ((float4*)(out + (size_t)row * CD))[tid] = o4;
    (void)n;
}

// ---------------- SGEMM: C = act(A @ W + bias) [+ residual] -----------------
__device__ __forceinline__ float gelu_tanh(float x) {
    float x3 = x * x * x;
    float t = tanhf(0.7978845608028654f * (x + 0.044715f * x3));
    return 0.5f * x * (1.f + t);
}

template <bool GELU, bool RESID>
__global__ __launch_bounds__(256) void sgemm_kernel(
    const float* __restrict__ A, const float* __restrict__ W,
    const float* __restrict__ bias, const float* __restrict__ R,
    float* __restrict__ C, int M, int N, int Kd) {
    constexpr int BM = 128, BN = 128, BKT = 16;
    __shared__ float As[BKT][BM];
    __shared__ float Bs[BKT][BN];
    int tid = threadIdx.x;
    int bx = blockIdx.x, by = blockIdx.y;
    int tx = tid & 15, ty = tid >> 4;
    float acc[8][8];
#pragma unroll
    for (int i = 0; i < 8; i++)
#pragma unroll
        for (int j = 0; j < 8; j++) acc[i][j] = 0.f;

    for (int k0 = 0; k0 < Kd; k0 += BKT) {
        __syncthreads();
#pragma unroll
        for (int L2 = 0; L2 < 2; L2++) {
            int idx4 = tid + L2 * 256;
            int ar = idx4 >> 2, ac = (idx4 & 3) * 4;
            float4 av = *(const float4*)(A + (size_t)(by * BM + ar) * Kd + k0 + ac);
            As[ac + 0][ar] = av.x; As[ac + 1][ar] = av.y;
            As[ac + 2][ar] = av.z; As[ac + 3][ar] = av.w;
            int br = idx4 >> 5, bc = (idx4 & 31) * 4;
            *(float4*)(&Bs[br][bc]) = *(const float4*)(W + (size_t)(k0 + br) * N + bx * BN + bc);
        }
        __syncthreads();
#pragma unroll
        for (int kk = 0; kk < BKT; kk++) {
            float a[8], b[8];
            *(float4*)(a)     = *(const float4*)(&As[kk][ty * 8]);
            *(float4*)(a + 4) = *(const float4*)(&As[kk][ty * 8 + 4]);
            *(float4*)(b)     = *(const float4*)(&Bs[kk][tx * 8]);
            *(float4*)(b + 4) = *(const float4*)(&Bs[kk][tx * 8 + 4]);
#pragma unroll
            for (int i = 0; i < 8; i++)
#pragma unroll
                for (int j = 0; j < 8; j++) acc[i][j] += a[i] * b[j];
        }
    }
#pragma unroll
    for (int i = 0; i < 8; i++) {
        int m = by * BM + ty * 8 + i;
#pragma unroll
        for (int j = 0; j < 8; j++) {
            int n = bx * BN + tx * 8 + j;
            float v = acc[i][j] + bias[n];
            if (GELU) v = gelu_tanh(v);
            if (RESID) v += R[(size_t)m * N + n];
            C[(size_t)m * N + n] = v;
        }
    }
}

// ---------------- causal flash attention (fp32) ------------------------------
__global__ __launch_bounds__(64) void attn_kernel(const float* __restrict__ qkv,
                                                  float* __restrict__ o) {
    const int qt = blockIdx.x;   // q tile
    const int h = blockIdx.y;
    const int b = blockIdx.z;
    const int r = threadIdx.x;   // 0..63
    const int m = qt * 64 + r;
    __shared__ float Ks[64][68];
    __shared__ float Vs[64][68];
    float q[64], acc[64];
    const float* qptr = qkv + ((size_t)(b * CK + m)) * (3 * CD) + h * CDH;
#pragma unroll
    for (int d = 0; d < 64; d += 4) {
        float4 t4 = *(const float4*)(qptr + d);
        q[d] = t4.x; q[d + 1] = t4.y; q[d + 2] = t4.z; q[d + 3] = t4.w;
    }
#pragma unroll
    for (int d = 0; d < 64; d++) acc[d] = 0.f;
    float mi = -1e30f, l = 0.f;

    for (int kt = 0; kt <= qt; kt++) {
        __syncthreads();
        const float* kbase = qkv + ((size_t)(b * CK + kt * 64 + r)) * (3 * CD) + CD + h * CDH;
        const float* vbase = kbase + CD;
#pragma unroll
        for (int d = 0; d < 64; d += 4) {
            *(float4*)(&Ks[r][d]) = *(const float4*)(kbase + d);
            *(float4*)(&Vs[r][d]) = *(const float4*)(vbase + d);
        }
        __syncthreads();
        int jmax = (kt == qt) ? r : 63;
        for (int j = 0; j <= jmax; j++) {
            float s = 0.f;
#pragma unroll
            for (int d = 0; d < 64; d++) s += q[d] * Ks[j][d];
            s *= 0.125f;
            float nm = fmaxf(mi, s);
            float co = __expf(mi - nm);
            float p = __expf(s - nm);
            l = l * co + p;
#pragma unroll
            for (int d = 0; d < 64; d++) acc[d] = acc[d] * co + p * Vs[j][d];
            mi = nm;
        }
    }
    float invl = 1.f / l;
    float* optr = o + ((size_t)(b * CK + m)) * CD + h * CDH;
#pragma unroll
    for (int d = 0; d < 64; d += 4) {
        float4 t4;
        t4.x = acc[d] * invl; t4.y = acc[d + 1] * invl;
        t4.z = acc[d + 2] * invl; t4.w = acc[d + 3] * invl;
        *(float4*)(optr + d) = t4;
    }
}

// ---------------- output assembly -------------------------------------------
__global__ void copyx_kernel(const float* __restrict__ x, float* __restrict__ out) {
    size_t i = (size_t)blockIdx.x * blockDim.x + threadIdx.x;  // float4 index
    ((float4*)out)[i] = ((const float4*)x)[i];
}

__global__ void scatter_kernel(const float* __restrict__ h, const int* __restrict__ idx,
                               const float* __restrict__ gate, float* __restrict__ out) {
    int bk = blockIdx.x;
    int b = bk >> 11;
    int t = idx[bk];
    float g = gate[bk];
    float4* dst = (float4*)(out + ((size_t)b * CT + t) * CD);
    const float4* src = (const float4*)(h + (size_t)bk * CD);
    float4 s = src[threadIdx.x];
    float4 d0 = dst[threadIdx.x];
    d0.x += s.x * g; d0.y += s.y * g; d0.z += s.z * g; d0.w += s.w * g;
    dst[threadIdx.x] = d0;
}

__global__ void tail_kernel(const int* __restrict__ idx, const float* __restrict__ logits,
                            float* __restrict__ out) {
    int i = blockIdx.x * blockDim.x + threadIdx.x;
    if (i < CB * CK) {
        out[BTD + i] = (float)idx[i];
    } else if (i < CB * CK + CB * CT) {
        int j = i - CB * CK;
        out[BTD + CB * CK + j] = logits[j];
    }
}

// ---------------- launch -----------------------------------------------------
extern "C" void kernel_launch(void* const* d_in, const int* in_sizes, int n_in,
                              void* d_out, int out_size) {
    const float* x         = (const float*)d_in[0];
    const float* w_router  = (const float*)d_in[1];
    const float* b_router  = (const float*)d_in[2];
    const float* ln1_scale = (const float*)d_in[3];
    const float* ln1_bias  = (const float*)d_in[4];
    const float* w_qkv     = (const float*)d_in[5];
    const float* b_qkv     = (const float*)d_in[6];
    const float* w_o       = (const float*)d_in[7];
    const float* b_o       = (const float*)d_in[8];
    const float* ln2_scale = (const float*)d_in[9];
    const float* ln2_bias  = (const float*)d_in[10];
    const float* w1        = (const float*)d_in[11];
    const float* b1        = (const float*)d_in[12];
    const float* w2        = (const float*)d_in[13];
    const float* b2        = (const float*)d_in[14];
    float* out = (float*)d_out;

    float *logits, *gate, *h, *lnb, *qkvb, *attnb, *midb;
    int *sel, *idxp;
    cudaGetSymbolAddress((void**)&logits, g_logits);
    cudaGetSymbolAddress((void**)&sel, g_sel);
    cudaGetSymbolAddress((void**)&idxp, g_idx);
    cudaGetSymbolAddress((void**)&gate, g_gate);
    cudaGetSymbolAddress((void**)&h, g_h);
    cudaGetSymbolAddress((void**)&lnb, g_lnbuf);
    cudaGetSymbolAddress((void**)&qkvb, g_qkv);
    cudaGetSymbolAddress((void**)&attnb, g_attn);
    cudaGetSymbolAddress((void**)&midb, g_mid);

    // 1. router
    router_kernel<<<(CB * CT) / 8, 256>>>(x, w_router, b_router, logits);
    // 2. expert-choice top-K
    rank_kernel<<<CB * 64, 256>>>(logits, sel);
    compact_kernel<<<CB, 1024>>>(logits, sel, idxp, gate);
    // 3. gather
    gather_kernel<<<BK_ROWS, 256>>>(x, idxp, h);

    // 4. transformer blocks
    for (int l = 0; l < CL; l++) {
        layernorm_kernel<<<BK_ROWS, 256>>>(h, lnb, ln1_scale + l * CD, ln1_bias + l * CD);
        sgemm_kernel<false, false><<<dim3(3 * CD / 128, BK_ROWS / 128), 256>>>(
            lnb, w_qkv + (size_t)l * CD * 3 * CD, b_qkv + l * 3 * CD, nullptr, qkvb,
            BK_ROWS, 3 * CD, CD);
        attn_kernel<<<dim3(CK / 64, CH, CB), 64>>>(qkvb, attnb);
        sgemm_kernel<false, true><<<dim3(CD / 128, BK_ROWS / 128), 256>>>(
            attnb, w_o + (size_t)l * CD * CD, b_o + l * CD, h, h, BK_ROWS, CD, CD);
        layernorm_kernel<<<BK_ROWS, 256>>>(h, lnb, ln2_scale + l * CD, ln2_bias + l * CD);
        sgemm_kernel<true, false><<<dim3(CF / 128, BK_ROWS / 128), 256>>>(
            lnb, w1 + (size_t)l * CD * CF, b1 + l * CF, nullptr, midb,
            BK_ROWS, CF, CD);
        sgemm_kernel<false, true><<<dim3(CD / 128, BK_ROWS / 128), 256>>>(
            midb, w2 + (size_t)l * CF * CD, b2 + l * CD, h, h, BK_ROWS, CD, CF);
    }

    // 5. assemble output: total, idx, logits
    copyx_kernel<<<(int)(BTD / 4 / 256), 256>>>(x, out);
    scatter_kernel<<<BK_ROWS, 256>>>(h, idxp, gate, out);
    if ((size_t)out_size >= BTD + CB * CK + CB * CT) {
        int ntail = CB * CK + CB * CT;
        tail_kernel<<<(ntail + 255) / 256, 256>>>(idxp, logits, out);
    }
}

// round 3
// speedup vs baseline: 1.5600x; 1.5535x over previous
#include <cuda_runtime.h>
#include <math.h>
#include <stdint.h>

// Problem constants
constexpr int CB = 2;      // batch
constexpr int CT = 4096;   // seq len
constexpr int CD = 1024;   // d_model
constexpr int CL = 2;      // layers
constexpr int CH = 16;     // heads
constexpr int CF = 4096;   // d_ff
constexpr int CK = 2048;   // top-k tokens
constexpr int CDH = 64;    // head dim
constexpr int BK_ROWS = CB * CK;           // 4096 rows through the blocks
constexpr size_t BTD = (size_t)CB * CT * CD;

// ---------------- scratch (static device globals; no runtime allocation) ----
__device__ float g_logits[CB * CT];
__device__ int   g_sel[CB * CT];
__device__ int   g_idx[CB * CK];
__device__ float g_gate[CB * CK];
__device__ float g_h[BK_ROWS * CD];
__device__ float g_lnbuf[BK_ROWS * CD];
__device__ float g_qkv[(size_t)BK_ROWS * 3 * CD];
__device__ float g_attn[BK_ROWS * CD];
__device__ float g_mid[(size_t)BK_ROWS * CF];

// ---------------- router: logits[b,t] = dot(x[b,t], w) + b ------------------
__global__ void router_kernel(const float* __restrict__ x,
                              const float* __restrict__ wr,
                              const float* __restrict__ br,
                              float* __restrict__ logits) {
    int gw = (blockIdx.x * blockDim.x + threadIdx.x) >> 5;  // global warp = row
    if (gw >= CB * CT) return;
    int lane = threadIdx.x & 31;
    const float4* p = (const float4*)(x + (size_t)gw * CD);
    const float4* w4 = (const float4*)wr;
    float s = 0.f;
#pragma unroll
    for (int i = 0; i < CD / 128; i++) {
        float4 a = p[lane + i * 32];
        float4 w = w4[lane + i * 32];
        s += a.x * w.x + a.y * w.y + a.z * w.z + a.w * w.w;
    }
#pragma unroll
    for (int o = 16; o > 0; o >>= 1) s += __shfl_down_sync(0xffffffffu, s, o);
    if (lane == 0) logits[gw] = s + br[0];
}

// ---------------- top-K selection: rank counting ----------------------------
__global__ void rank_kernel(const float* __restrict__ logits, int* __restrict__ sel) {
    int blk = blockIdx.x;
    int b = blk >> 6;
    int base = (blk & 63) * 64;
    __shared__ float lv[CT];
    int tid = threadIdx.x;
    for (int t = tid; t < CT; t += 256) lv[t] = logits[b * CT + t];
    __syncthreads();
    int tt = tid >> 2, part = tid & 3;
    int t = base + tt;
    float v = lv[t];
    int cnt = 0;
    int s0 = part * 1024;
#pragma unroll 8
    for (int s = s0; s < s0 + 1024; s++) {
        float u = lv[s];
        cnt += (u > v) || (u == v && s < t);
    }
    __shared__ int rk[64];
    if (part == 0) rk[tt] = 0;
    __syncthreads();
    atomicAdd(&rk[tt], cnt);
    __syncthreads();
    if (part == 0) sel[b * CT + t] = (rk[tt] < CK) ? 1 : 0;
}

__global__ void compact_kernel(const float* __restrict__ logits,
                               const int* __restrict__ sel,
                               int* __restrict__ idx_out,
                               float* __restrict__ gate_out) {
    int b = blockIdx.x;
    int tid = threadIdx.x;  // 1024
    int f[4]; int c = 0;
#pragma unroll
    for (int i = 0; i < 4; i++) { f[i] = sel[b * CT + tid * 4 + i]; c += f[i]; }
    int lane = tid & 31, wid = tid >> 5;
    int incl = c;
#pragma unroll
    for (int o = 1; o < 32; o <<= 1) {
        int n = __shfl_up_sync(0xffffffffu, incl, o);
        if (lane >= o) incl += n;
    }
    __shared__ int wsum[32];
    if (lane == 31) wsum[wid] = incl;
    __syncthreads();
    if (wid == 0) {
        int w = wsum[lane];
#pragma unroll
        for (int o = 1; o < 32; o <<= 1) {
            int n = __shfl_up_sync(0xffffffffu, w, o);
            if (lane >= o) w += n;
        }
        wsum[lane] = w;
    }
    __syncthreads();
    int pos = (wid ? wsum[wid - 1] : 0) + incl - c;  // exclusive prefix
#pragma unroll
    for (int i = 0; i < 4; i++) {
        if (f[i]) {
            int t = tid * 4 + i;
            idx_out[b * CK + pos] = t;
            float lg = logits[b * CT + t];
            gate_out[b * CK + pos] = 1.f / (1.f + expf(-lg));
            pos++;
        }
    }
}

// ---------------- gather rows -----------------------------------------------
__global__ void gather_kernel(const float* __restrict__ x, const int* __restrict__ idx,
                              float* __restrict__ h) {
    int bk = blockIdx.x;            // 0..BK_ROWS-1
    int b = bk >> 11;               // /CK
    int t = idx[bk];
    const float4* src = (const float4*)(x + ((size_t)b * CT + t) * CD);
    float4* dst = (float4*)(h + (size_t)bk * CD);
    dst[threadIdx.x] = src[threadIdx.x];   // 256 threads * float4 = 1024
}

// ---------------- layernorm --------------------------------------------------
__global__ void layernorm_kernel(const float* __restrict__ in, float* __restrict__ out,
                                 const float* __restrict__ scale,
                                 const float* __restrict__ bias) {
    int row = blockIdx.x;
    int tid = threadIdx.x;  // 256
    const float4* p = (const float4*)(in + (size_t)row * CD);
    float4 v = p[tid];
    float s = v.x + v.y + v.z + v.w;
    float ss = v.x * v.x + v.y * v.y + v.z * v.z + v.w * v.w;
#pragma unroll
    for (int o = 16; o > 0; o >>= 1) {
        s += __shfl_down_sync(0xffffffffu, s, o);
        ss += __shfl_down_sync(0xffffffffu, ss, o);
    }
    __shared__ float red[64];
    int lane = tid & 31, wid = tid >> 5;
    if (lane == 0) { red[wid] = s; red[32 + wid] = ss; }
    __syncthreads();
    if (tid == 0) {
        float S = 0, SS = 0;
#pragma unroll
        for (int w = 0; w < 8; w++) { S += red[w]; SS += red[32 + w]; }
        red[0] = S; red[32] = SS;
    }
    __syncthreads();
    float mean = red[0] * (1.f / CD);
    float var = red[32] * (1.f / CD) - mean * mean;
    float inv = rsqrtf(var + 1e-5f);
    float4 sc = ((const float4*)scale)[tid];
    float4 bi = ((const float4*)bias)[tid];
    float4 o4;
    o4.x = (v.x - mean) * inv * sc.x + bi.x;
    o4.y = (v.y - mean) * inv * sc.y + bi.y;
    o4.z = (v.z - mean) * inv * sc.z + bi.z;
    o4.w = (v.w - mean) * inv * sc.w + bi.w;
    ((float4*)(out + (size_t)row * CD))[tid] = o4;
}

// ---------------- TF32 tensor-core GEMM -------------------------------------
__device__ __forceinline__ float gelu_tanh(float x) {
    float x3 = x * x * x;
    float t = tanhf(0.7978845608028654f * (x + 0.044715f * x3));
    return 0.5f * x * (1.f + t);
}

__device__ __forceinline__ uint32_t f2tf32(float x) {
    uint32_t u;
    asm("cvt.rna.tf32.f32 %0, %1;" : "=r"(u) : "f"(x));
    return u;
}

// C[M,N] = act(A[M,K] @ W[K,N] + bias) [+ R]
// Block tile 128x128, BK=32, 8 warps: warp tile 64x32 (4x4 m16n8k8 per k-step).
template <bool GELU, bool RESID>
__global__ __launch_bounds__(256) void tgemm_kernel(
    const float* __restrict__ A, const float* __restrict__ W,
    const float* __restrict__ bias, const float* __restrict__ R,
    float* __restrict__ C, int M, int N, int Kd) {
    constexpr int BM = 128, BN = 128, BKT = 32;
    constexpr int ASTR = BKT + 4;   // 36: stride%32==4 -> conflict-free frag loads
    constexpr int BSTR = BN + 8;    // 136: stride%32==8 -> conflict-free frag loads
    __shared__ uint32_t As[BM * ASTR];   // m-major [m][k]
    __shared__ uint32_t Bs[BKT * BSTR];  // k-major [k][n]

    const int tid = threadIdx.x;
    const int bx = blockIdx.x, by = blockIdx.y;
    const int wid = tid >> 5, lane = tid & 31;
    const int warp_m = wid & 1;          // 2
    const int warp_n = wid >> 1;         // 4
    const int g = lane >> 2;             // groupID
    const int tg = lane & 3;             // thread-in-group

    float c[4][4][4];                    // [mi][ni][frag]
#pragma unroll
    for (int mi = 0; mi < 4; mi++)
#pragma unroll
        for (int ni = 0; ni < 4; ni++)
#pragma unroll
            for (int r = 0; r < 4; r++) c[mi][ni][r] = 0.f;

    for (int k0 = 0; k0 < Kd; k0 += BKT) {
        __syncthreads();
        // A tile: 128 rows x 32 k = 1024 float4; 4 per thread
#pragma unroll
        for (int i = 0; i < 4; i++) {
            int q = tid + i * 256;
            int row = q >> 3, k4 = (q & 7) * 4;
            float4 v = *(const float4*)(A + (size_t)(by * BM + row) * Kd + k0 + k4);
            uint4 u;
            u.x = f2tf32(v.x); u.y = f2tf32(v.y); u.z = f2tf32(v.z); u.w = f2tf32(v.w);
            *(uint4*)(&As[row * ASTR + k4]) = u;
        }
        // B tile: 32 k-rows x 128 n = 1024 float4; 4 per thread
#pragma unroll
        for (int i = 0; i < 4; i++) {
            int q = tid + i * 256;
            int row = q >> 5, n4 = (q & 31) * 4;
            float4 v = *(const float4*)(W + (size_t)(k0 + row) * N + bx * BN + n4);
            uint4 u;
            u.x = f2tf32(v.x); u.y = f2tf32(v.y); u.z = f2tf32(v.z); u.w = f2tf32(v.w);
            *(uint4*)(&Bs[row * BSTR + n4]) = u;
        }
        __syncthreads();

#pragma unroll
        for (int ks = 0; ks < BKT; ks += 8) {
            uint32_t a[4][4], b[4][2];
#pragma unroll
            for (int mi = 0; mi < 4; mi++) {
                int r0 = warp_m * 64 + mi * 16 + g;
                a[mi][0] = As[r0 * ASTR + ks + tg];
                a[mi][1] = As[(r0 + 8) * ASTR + ks + tg];
                a[mi][2] = As[r0 * ASTR + ks + 4 + tg];
                a[mi][3] = As[(r0 + 8) * ASTR + ks + 4 + tg];
            }
#pragma unroll
            for (int ni = 0; ni < 4; ni++) {
                int n0 = warp_n * 32 + ni * 8 + g;
                b[ni][0] = Bs[(ks + tg) * BSTR + n0];
                b[ni][1] = Bs[(ks + 4 + tg) * BSTR + n0];
            }
#pragma unroll
            for (int mi = 0; mi < 4; mi++)
#pragma unroll
                for (int ni = 0; ni < 4; ni++) {
                    asm volatile(
                        "mma.sync.aligned.m16n8k8.row.col.f32.tf32.tf32.f32 "
                        "{%0,%1,%2,%3}, {%4,%5,%6,%7}, {%8,%9}, {%0,%1,%2,%3};\n"
                        : "+f"(c[mi][ni][0]), "+f"(c[mi][ni][1]),
                          "+f"(c[mi][ni][2]), "+f"(c[mi][ni][3])
                        : "r"(a[mi][0]), "r"(a[mi][1]), "r"(a[mi][2]), "r"(a[mi][3]),
                          "r"(b[ni][0]), "r"(b[ni][1]));
                }
        }
    }

    // epilogue
#pragma unroll
    for (int mi = 0; mi < 4; mi++) {
        int m0 = by * BM + warp_m * 64 + mi * 16 + g;
#pragma unroll
        for (int ni = 0; ni < 4; ni++) {
            int n0 = bx * BN + warp_n * 32 + ni * 8 + 2 * tg;
            float b0 = bias[n0], b1 = bias[n0 + 1];
#pragma unroll
            for (int half = 0; half < 2; half++) {
                int m = m0 + half * 8;
                float v0 = c[mi][ni][half * 2 + 0] + b0;
                float v1 = c[mi][ni][half * 2 + 1] + b1;
                if (GELU) { v0 = gelu_tanh(v0); v1 = gelu_tanh(v1); }
                if (RESID) {
                    const float2 r2 = *(const float2*)(R + (size_t)m * N + n0);
                    v0 += r2.x; v1 += r2.y;
                }
                float2 o2 = make_float2(v0, v1);
                *(float2*)(C + (size_t)m * N + n0) = o2;
            }
        }
    }
}

// ---------------- causal flash attention (fp32) ------------------------------
__global__ __launch_bounds__(64) void attn_kernel(const float* __restrict__ qkv,
                                                  float* __restrict__ o) {
    const int qt = blockIdx.x;   // q tile
    const int h = blockIdx.y;
    const int b = blockIdx.z;
    const int r = threadIdx.x;   // 0..63
    const int m = qt * 64 + r;
    __shared__ float Ks[64][68];
    __shared__ float Vs[64][68];
    float q[64], acc[64];
    const float* qptr = qkv + ((size_t)(b * CK + m)) * (3 * CD) + h * CDH;
#pragma unroll
    for (int d = 0; d < 64; d += 4) {
        float4 t4 = *(const float4*)(qptr + d);
        q[d] = t4.x; q[d + 1] = t4.y; q[d + 2] = t4.z; q[d + 3] = t4.w;
    }
#pragma unroll
    for (int d = 0; d < 64; d++) acc[d] = 0.f;
    float mi = -1e30f, l = 0.f;

    for (int kt = 0; kt <= qt; kt++) {
        __syncthreads();
        const float* kbase = qkv + ((size_t)(b * CK + kt * 64 + r)) * (3 * CD) + CD + h * CDH;
        const float* vbase = kbase + CD;
#pragma unroll
        for (int d = 0; d < 64; d += 4) {
            *(float4*)(&Ks[r][d]) = *(const float4*)(kbase + d);
            *(float4*)(&Vs[r][d]) = *(const float4*)(vbase + d);
        }
        __syncthreads();
        int jmax = (kt == qt) ? r : 63;
        for (int j = 0; j <= jmax; j++) {
            float s = 0.f;
#pragma unroll
            for (int d = 0; d < 64; d++) s += q[d] * Ks[j][d];
            s *= 0.125f;
            float nm = fmaxf(mi, s);
            float co = __expf(mi - nm);
            float p = __expf(s - nm);
            l = l * co + p;
#pragma unroll
            for (int d = 0; d < 64; d++) acc[d] = acc[d] * co + p * Vs[j][d];
            mi = nm;
        }
    }
    float invl = 1.f / l;
    float* optr = o + ((size_t)(b * CK + m)) * CD + h * CDH;
#pragma unroll
    for (int d = 0; d < 64; d += 4) {
        float4 t4;
        t4.x = acc[d] * invl; t4.y = acc[d + 1] * invl;
        t4.z = acc[d + 2] * invl; t4.w = acc[d + 3] * invl;
        *(float4*)(optr + d) = t4;
    }
}

// ---------------- output assembly -------------------------------------------
__global__ void copyx_kernel(const float* __restrict__ x, float* __restrict__ out) {
    size_t i = (size_t)blockIdx.x * blockDim.x + threadIdx.x;  // float4 index
    ((float4*)out)[i] = ((const float4*)x)[i];
}

__global__ void scatter_kernel(const float* __restrict__ h, const int* __restrict__ idx,
                               const float* __restrict__ gate, float* __restrict__ out) {
    int bk = blockIdx.x;
    int b = bk >> 11;
    int t = idx[bk];
    float g = gate[bk];
    float4* dst = (float4*)(out + ((size_t)b * CT + t) * CD);
    const float4* src = (const float4*)(h + (size_t)bk * CD);
    float4 s = src[threadIdx.x];
    float4 d0 = dst[threadIdx.x];
    d0.x += s.x * g; d0.y += s.y * g; d0.z += s.z * g; d0.w += s.w * g;
    dst[threadIdx.x] = d0;
}

__global__ void tail_kernel(const int* __restrict__ idx, const float* __restrict__ logits,
                            float* __restrict__ out) {
    int i = blockIdx.x * blockDim.x + threadIdx.x;
    if (i < CB * CK) {
        out[BTD + i] = (float)idx[i];
    } else if (i < CB * CK + CB * CT) {
        int j = i - CB * CK;
        out[BTD + CB * CK + j] = logits[j];
    }
}

// ---------------- launch -----------------------------------------------------
extern "C" void kernel_launch(void* const* d_in, const int* in_sizes, int n_in,
                              void* d_out, int out_size) {
    const float* x         = (const float*)d_in[0];
    const float* w_router  = (const float*)d_in[1];
    const float* b_router  = (const float*)d_in[2];
    const float* ln1_scale = (const float*)d_in[3];
    const float* ln1_bias  = (const float*)d_in[4];
    const float* w_qkv     = (const float*)d_in[5];
    const float* b_qkv     = (const float*)d_in[6];
    const float* w_o       = (const float*)d_in[7];
    const float* b_o       = (const float*)d_in[8];
    const float* ln2_scale = (const float*)d_in[9];
    const float* ln2_bias  = (const float*)d_in[10];
    const float* w1        = (const float*)d_in[11];
    const float* b1        = (const float*)d_in[12];
    const float* w2        = (const float*)d_in[13];
    const float* b2        = (const float*)d_in[14];
    float* out = (float*)d_out;

    float *logits, *gate, *h, *lnb, *qkvb, *attnb, *midb;
    int *sel, *idxp;
    cudaGetSymbolAddress((void**)&logits, g_logits);
    cudaGetSymbolAddress((void**)&sel, g_sel);
    cudaGetSymbolAddress((void**)&idxp, g_idx);
    cudaGetSymbolAddress((void**)&gate, g_gate);
    cudaGetSymbolAddress((void**)&h, g_h);
    cudaGetSymbolAddress((void**)&lnb, g_lnbuf);
    cudaGetSymbolAddress((void**)&qkvb, g_qkv);
    cudaGetSymbolAddress((void**)&attnb, g_attn);
    cudaGetSymbolAddress((void**)&midb, g_mid);

    // 1. router
    router_kernel<<<(CB * CT) / 8, 256>>>(x, w_router, b_router, logits);
    // 2. expert-choice top-K
    rank_kernel<<<CB * 64, 256>>>(logits, sel);
    compact_kernel<<<CB, 1024>>>(logits, sel, idxp, gate);
    // 3. gather
    gather_kernel<<<BK_ROWS, 256>>>(x, idxp, h);

    // 4. transformer blocks
    for (int l = 0; l < CL; l++) {
        layernorm_kernel<<<BK_ROWS, 256>>>(h, lnb, ln1_scale + l * CD, ln1_bias + l * CD);
        tgemm_kernel<false, false><<<dim3(3 * CD / 128, BK_ROWS / 128), 256>>>(
            lnb, w_qkv + (size_t)l * CD * 3 * CD, b_qkv + l * 3 * CD, nullptr, qkvb,
            BK_ROWS, 3 * CD, CD);
        attn_kernel<<<dim3(CK / 64, CH, CB), 64>>>(qkvb, attnb);
        tgemm_kernel<false, true><<<dim3(CD / 128, BK_ROWS / 128), 256>>>(
            attnb, w_o + (size_t)l * CD * CD, b_o + l * CD, h, h, BK_ROWS, CD, CD);
        layernorm_kernel<<<BK_ROWS, 256>>>(h, lnb, ln2_scale + l * CD, ln2_bias + l * CD);
        tgemm_kernel<true, false><<<dim3(CF / 128, BK_ROWS / 128), 256>>>(
            lnb, w1 + (size_t)l * CD * CF, b1 + l * CF, nullptr, midb,
            BK_ROWS, CF, CD);
        tgemm_kernel<false, true><<<dim3(CD / 128, BK_ROWS / 128), 256>>>(
            midb, w2 + (size_t)l * CF * CD, b2 + l * CD, h, h, BK_ROWS, CD, CF);
    }

    // 5. assemble output: total, idx, logits
    copyx_kernel<<<(int)(BTD / 4 / 256), 256>>>(x, out);
    scatter_kernel<<<BK_ROWS, 256>>>(h, idxp, gate, out);
    if ((size_t)out_size >= BTD + CB * CK + CB * CT) {
        int ntail = CB * CK + CB * CT;
        tail_kernel<<<(ntail + 255) / 256, 256>>>(idxp, logits, out);
    }
}

// round 4
// speedup vs baseline: 3.3879x; 2.1717x over previous
#include <cuda_runtime.h>
#include <math.h>
#include <stdint.h>

// Problem constants
constexpr int CB = 2;      // batch
constexpr int CT = 4096;   // seq len
constexpr int CD = 1024;   // d_model
constexpr int CL = 2;      // layers
constexpr int CH = 16;     // heads
constexpr int CF = 4096;   // d_ff
constexpr int CK = 2048;   // top-k tokens
constexpr int BK_ROWS = CB * CK;           // 4096 rows through the blocks
constexpr size_t BTD = (size_t)CB * CT * CD;

// Weight tf32 scratch offsets (floats)
constexpr size_t WQKV_OFF = 0;
constexpr size_t WQKV_SZ  = (size_t)CL * CD * 3 * CD;   // 6291456
constexpr size_t WO_OFF   = WQKV_OFF + WQKV_SZ;
constexpr size_t WO_SZ    = (size_t)CL * CD * CD;       // 2097152
constexpr size_t W1_OFF   = WO_OFF + WO_SZ;
constexpr size_t W1_SZ    = (size_t)CL * CD * CF;       // 8388608
constexpr size_t W2_OFF   = W1_OFF + W1_SZ;
constexpr size_t W2_SZ    = (size_t)CL * CF * CD;       // 8388608
constexpr size_t WTF_TOTAL = W2_OFF + W2_SZ;            // 25165824

// ---------------- scratch (static device globals; no runtime allocation) ----
__device__ float g_logits[CB * CT];
__device__ int   g_sel[CB * CT];
__device__ int   g_idx[CB * CK];
__device__ float g_gate[CB * CK];
__device__ float g_h[BK_ROWS * CD];
__device__ float g_lnbuf[BK_ROWS * CD];
__device__ float g_qkv[(size_t)BK_ROWS * 3 * CD];
__device__ float g_attn[BK_ROWS * CD];
__device__ float g_mid[(size_t)BK_ROWS * CF];
__device__ float g_wtf[WTF_TOTAL];

__device__ __forceinline__ uint32_t f2tf32(float x) {
    uint32_t u;
    asm("cvt.rna.tf32.f32 %0, %1;" : "=r"(u) : "f"(x));
    return u;
}
__device__ __forceinline__ float roundtf(float x) {
    return __uint_as_float(f2tf32(x));
}

__device__ __forceinline__ void mma_tf32(float c[4], const uint32_t a[4],
                                         uint32_t b0, uint32_t b1) {
    asm volatile(
        "mma.sync.aligned.m16n8k8.row.col.f32.tf32.tf32.f32 "
        "{%0,%1,%2,%3}, {%4,%5,%6,%7}, {%8,%9}, {%0,%1,%2,%3};\n"
        : "+f"(c[0]), "+f"(c[1]), "+f"(c[2]), "+f"(c[3])
        : "r"(a[0]), "r"(a[1]), "r"(a[2]), "r"(a[3]), "r"(b0), "r"(b1));
}

// ---------------- router ----------------------------------------------------
__global__ void router_kernel(const float* __restrict__ x,
                              const float* __restrict__ wr,
                              const float* __restrict__ br,
                              float* __restrict__ logits) {
    int gw = (blockIdx.x * blockDim.x + threadIdx.x) >> 5;
    if (gw >= CB * CT) return;
    int lane = threadIdx.x & 31;
    const float4* p = (const float4*)(x + (size_t)gw * CD);
    const float4* w4 = (const float4*)wr;
    float s = 0.f;
#pragma unroll
    for (int i = 0; i < CD / 128; i++) {
        float4 a = p[lane + i * 32];
        float4 w = w4[lane + i * 32];
        s += a.x * w.x + a.y * w.y + a.z * w.z + a.w * w.w;
    }
#pragma unroll
    for (int o = 16; o > 0; o >>= 1) s += __shfl_down_sync(0xffffffffu, s, o);
    if (lane == 0) logits[gw] = s + br[0];
}

// ---------------- top-K -----------------------------------------------------
__global__ void rank_kernel(const float* __restrict__ logits, int* __restrict__ sel) {
    int blk = blockIdx.x;
    int b = blk >> 6;
    int base = (blk & 63) * 64;
    __shared__ float lv[CT];
    int tid = threadIdx.x;
    for (int t = tid; t < CT; t += 256) lv[t] = logits[b * CT + t];
    __syncthreads();
    int tt = tid >> 2, part = tid & 3;
    int t = base + tt;
    float v = lv[t];
    int cnt = 0;
    int s0 = part * 1024;
#pragma unroll 8
    for (int s = s0; s < s0 + 1024; s++) {
        float u = lv[s];
        cnt += (u > v) || (u == v && s < t);
    }
    __shared__ int rk[64];
    if (part == 0) rk[tt] = 0;
    __syncthreads();
    atomicAdd(&rk[tt], cnt);
    __syncthreads();
    if (part == 0) sel[b * CT + t] = (rk[tt] < CK) ? 1 : 0;
}

__global__ void compact_kernel(const float* __restrict__ logits,
                               const int* __restrict__ sel,
                               int* __restrict__ idx_out,
                               float* __restrict__ gate_out) {
    int b = blockIdx.x;
    int tid = threadIdx.x;
    int f[4]; int c = 0;
#pragma unroll
    for (int i = 0; i < 4; i++) { f[i] = sel[b * CT + tid * 4 + i]; c += f[i]; }
    int lane = tid & 31, wid = tid >> 5;
    int incl = c;
#pragma unroll
    for (int o = 1; o < 32; o <<= 1) {
        int n = __shfl_up_sync(0xffffffffu, incl, o);
        if (lane >= o) incl += n;
    }
    __shared__ int wsum[32];
    if (lane == 31) wsum[wid] = incl;
    __syncthreads();
    if (wid == 0) {
        int w = wsum[lane];
#pragma unroll
        for (int o = 1; o < 32; o <<= 1) {
            int n = __shfl_up_sync(0xffffffffu, w, o);
            if (lane >= o) w += n;
        }
        wsum[lane] = w;
    }
    __syncthreads();
    int pos = (wid ? wsum[wid - 1] : 0) + incl - c;
#pragma unroll
    for (int i = 0; i < 4; i++) {
        if (f[i]) {
            int t = tid * 4 + i;
            idx_out[b * CK + pos] = t;
            float lg = logits[b * CT + t];
            gate_out[b * CK + pos] = 1.f / (1.f + expf(-lg));
            pos++;
        }
    }
}

// ---------------- gather ----------------------------------------------------
__global__ void gather_kernel(const float* __restrict__ x, const int* __restrict__ idx,
                              float* __restrict__ h) {
    int bk = blockIdx.x;
    int b = bk >> 11;
    int t = idx[bk];
    const float4* src = (const float4*)(x + ((size_t)b * CT + t) * CD);
    float4* dst = (float4*)(h + (size_t)bk * CD);
    dst[threadIdx.x] = src[threadIdx.x];
}

// ---------------- layernorm (writes tf32-rounded output) ---------------------
__global__ void layernorm_kernel(const float* __restrict__ in, float* __restrict__ out,
                                 const float* __restrict__ scale,
                                 const float* __restrict__ bias) {
    int row = blockIdx.x;
    int tid = threadIdx.x;
    const float4* p = (const float4*)(in + (size_t)row * CD);
    float4 v = p[tid];
    float s = v.x + v.y + v.z + v.w;
    float ss = v.x * v.x + v.y * v.y + v.z * v.z + v.w * v.w;
#pragma unroll
    for (int o = 16; o > 0; o >>= 1) {
        s += __shfl_down_sync(0xffffffffu, s, o);
        ss += __shfl_down_sync(0xffffffffu, ss, o);
    }
    __shared__ float red[64];
    int lane = tid & 31, wid = tid >> 5;
    if (lane == 0) { red[wid] = s; red[32 + wid] = ss; }
    __syncthreads();
    if (tid == 0) {
        float S = 0, SS = 0;
#pragma unroll
        for (int w = 0; w < 8; w++) { S += red[w]; SS += red[32 + w]; }
        red[0] = S; red[32] = SS;
    }
    __syncthreads();
    float mean = red[0] * (1.f / CD);
    float var = red[32] * (1.f / CD) - mean * mean;
    float inv = rsqrtf(var + 1e-5f);
    float4 sc = ((const float4*)scale)[tid];
    float4 bi = ((const float4*)bias)[tid];
    float4 o4;
    o4.x = roundtf((v.x - mean) * inv * sc.x + bi.x);
    o4.y = roundtf((v.y - mean) * inv * sc.y + bi.y);
    o4.z = roundtf((v.z - mean) * inv * sc.z + bi.z);
    o4.w = roundtf((v.w - mean) * inv * sc.w + bi.w);
    ((float4*)(out + (size_t)row * CD))[tid] = o4;
}

// ---------------- weight tf32 pre-round -------------------------------------
__global__ void cvtw_kernel(const float* __restrict__ src, float* __restrict__ dst,
                            int n4) {
    int i = blockIdx.x * blockDim.x + threadIdx.x;
    if (i >= n4) return;
    float4 v = ((const float4*)src)[i];
    v.x = roundtf(v.x); v.y = roundtf(v.y); v.z = roundtf(v.z); v.w = roundtf(v.w);
    ((float4*)dst)[i] = v;
}

// ---------------- TF32 tensor-core GEMM, cp.async double-buffered -----------
__device__ __forceinline__ float gelu_tanh(float x) {
    float x3 = x * x * x;
    float t = tanhf(0.7978845608028654f * (x + 0.044715f * x3));
    return 0.5f * x * (1.f + t);
}

constexpr int GBM = 128, GBN = 128, GBK = 32;
constexpr int ASTR = GBK + 4;    // 36 words
constexpr int BSTR = GBN + 8;    // 136 words
constexpr int ABUF = GBM * ASTR; // 4608 words
constexpr int BBUF = GBK * BSTR; // 4352 words
constexpr size_t TGEMM_SMEM = (size_t)(ABUF + BBUF) * 2 * 4;  // 71680 B

// Inputs A and W must be pre-rounded to tf32 values.
template <bool GELU, bool RESID>
__global__ __launch_bounds__(256) void tgemm_kernel(
    const float* __restrict__ A, const float* __restrict__ W,
    const float* __restrict__ bias, const float* __restrict__ R,
    float* __restrict__ C, int M, int N, int Kd) {
    extern __shared__ uint32_t dsm[];
    uint32_t* As = dsm;                 // [2][ABUF]
    uint32_t* Bs = dsm + 2 * ABUF;      // [2][BBUF]

    const int tid = threadIdx.x;
    const int bx = blockIdx.x, by = blockIdx.y;
    const int wid = tid >> 5, lane = tid & 31;
    const int warp_m = wid & 1;
    const int warp_n = wid >> 1;
    const int g = lane >> 2;
    const int tg = lane & 3;

    float c[4][4][4];
#pragma unroll
    for (int mi = 0; mi < 4; mi++)
#pragma unroll
        for (int ni = 0; ni < 4; ni++)
#pragma unroll
            for (int r = 0; r < 4; r++) c[mi][ni][r] = 0.f;

    const int ntiles = Kd / GBK;

    auto issue_tile = [&](int t, int buf) {
        int k0 = t * GBK;
        uint32_t abase = (uint32_t)__cvta_generic_to_shared(As + buf * ABUF);
        uint32_t bbase = (uint32_t)__cvta_generic_to_shared(Bs + buf * BBUF);
#pragma unroll
        for (int i = 0; i < 4; i++) {
            int q = tid + i * 256;
            int row = q >> 3, k4 = (q & 7) * 4;
            const float* src = A + (size_t)(by * GBM + row) * Kd + k0 + k4;
            uint32_t dst = abase + (row * ASTR + k4) * 4;
            asm volatile("cp.async.cg.shared.global [%0], [%1], 16;\n"
                         :: "r"(dst), "l"(src));
        }
#pragma unroll
        for (int i = 0; i < 4; i++) {
            int q = tid + i * 256;
            int row = q >> 5, n4 = (q & 31) * 4;
            const float* src = W + (size_t)(k0 + row) * N + bx * GBN + n4;
            uint32_t dst = bbase + (row * BSTR + n4) * 4;
            asm volatile("cp.async.cg.shared.global [%0], [%1], 16;\n"
                         :: "r"(dst), "l"(src));
        }
        asm volatile("cp.async.commit_group;\n");
    };

    issue_tile(0, 0);
    for (int t = 0; t < ntiles; t++) {
        if (t + 1 < ntiles) issue_tile(t + 1, (t + 1) & 1);
        if (t + 1 < ntiles) asm volatile("cp.async.wait_group 1;\n");
        else                asm volatile("cp.async.wait_group 0;\n");
        __syncthreads();
        const uint32_t* Ab = As + (t & 1) * ABUF;
        const uint32_t* Bb = Bs + (t & 1) * BBUF;
#pragma unroll
        for (int ks = 0; ks < GBK; ks += 8) {
            uint32_t a[4][4], b[4][2];
#pragma unroll
            for (int mi = 0; mi < 4; mi++) {
                int r0 = warp_m * 64 + mi * 16 + g;
                a[mi][0] = Ab[r0 * ASTR + ks + tg];
                a[mi][1] = Ab[(r0 + 8) * ASTR + ks + tg];
                a[mi][2] = Ab[r0 * ASTR + ks + 4 + tg];
                a[mi][3] = Ab[(r0 + 8) * ASTR + ks + 4 + tg];
            }
#pragma unroll
            for (int ni = 0; ni < 4; ni++) {
                int n0 = warp_n * 32 + ni * 8 + g;
                b[ni][0] = Bb[(ks + tg) * BSTR + n0];
                b[ni][1] = Bb[(ks + 4 + tg) * BSTR + n0];
            }
#pragma unroll
            for (int mi = 0; mi < 4; mi++)
#pragma unroll
                for (int ni = 0; ni < 4; ni++)
                    mma_tf32(c[mi][ni], a[mi], b[ni][0], b[ni][1]);
        }
        __syncthreads();
    }

#pragma unroll
    for (int mi = 0; mi < 4; mi++) {
        int m0 = by * GBM + warp_m * 64 + mi * 16 + g;
#pragma unroll
        for (int ni = 0; ni < 4; ni++) {
            int n0 = bx * GBN + warp_n * 32 + ni * 8 + 2 * tg;
            float b0 = bias[n0], b1 = bias[n0 + 1];
#pragma unroll
            for (int half = 0; half < 2; half++) {
                int m = m0 + half * 8;
                float v0 = c[mi][ni][half * 2 + 0] + b0;
                float v1 = c[mi][ni][half * 2 + 1] + b1;
                if (GELU) { v0 = roundtf(gelu_tanh(v0)); v1 = roundtf(gelu_tanh(v1)); }
                if (RESID) {
                    const float2 r2 = *(const float2*)(R + (size_t)m * N + n0);
                    v0 += r2.x; v1 += r2.y;
                }
                *(float2*)(C + (size_t)m * N + n0) = make_float2(v0, v1);
            }
        }
    }
}

// ---------------- MMA flash attention (tf32) ---------------------------------
// Block: 128 threads (4 warps). Q tile = 64 rows. Warp w owns rows w*16..+16.
__global__ __launch_bounds__(128) void attn_kernel(const float* __restrict__ qkv,
                                                   float* __restrict__ o) {
    const int qt = blockIdx.x, h = blockIdx.y, b = blockIdx.z;
    const int tid = threadIdx.x;
    const int w = tid >> 5, lane = tid & 31;
    const int g = lane >> 2, tg = lane & 3;

    __shared__ uint32_t Ks[64 * 68];   // K tile; reused for P tiles
    __shared__ uint32_t Vs[64 * 68];

    // stage Q tile (scaled by 1/8, tf32) into Ks, build A-frags
#pragma unroll
    for (int i = 0; i < 8; i++) {
        int q4 = tid + i * 128;
        int r = q4 >> 4, c4 = (q4 & 15) * 4;
        float4 v = *(const float4*)(qkv + ((size_t)(b * CK + qt * 64 + r)) * (3 * CD) + h * 64 + c4);
        uint4 u;
        u.x = f2tf32(v.x * 0.125f); u.y = f2tf32(v.y * 0.125f);
        u.z = f2tf32(v.z * 0.125f); u.w = f2tf32(v.w * 0.125f);
        *(uint4*)&Ks[r * 68 + c4] = u;
    }
    __syncthreads();
    uint32_t qf[8][4];
    {
        int r0 = w * 16 + g;
#pragma unroll
        for (int ks = 0; ks < 8; ks++) {
            qf[ks][0] = Ks[r0 * 68 + ks * 8 + tg];
            qf[ks][1] = Ks[(r0 + 8) * 68 + ks * 8 + tg];
            qf[ks][2] = Ks[r0 * 68 + ks * 8 + 4 + tg];
            qf[ks][3] = Ks[(r0 + 8) * 68 + ks * 8 + 4 + tg];
        }
    }

    float of[8][4];
#pragma unroll
    for (int ni = 0; ni < 8; ni++)
#pragma unroll
        for (int r = 0; r < 4; r++) of[ni][r] = 0.f;
    float mi0 = -1e30f, mi1 = -1e30f, li0 = 0.f, li1 = 0.f;

    for (int kt = 0; kt <= qt; kt++) {
        __syncthreads();   // previous iteration's P/V reads complete
        // load K,V tiles (tf32)
#pragma unroll
        for (int i = 0; i < 8; i++) {
            int q4 = tid + i * 128;
            int r = q4 >> 4, c4 = (q4 & 15) * 4;
            const float* kb = qkv + ((size_t)(b * CK + kt * 64 + r)) * (3 * CD) + CD + h * 64 + c4;
            float4 kv = *(const float4*)kb;
            float4 vv = *(const float4*)(kb + CD);
            uint4 ku, vu;
            ku.x = f2tf32(kv.x); ku.y = f2tf32(kv.y); ku.z = f2tf32(kv.z); ku.w = f2tf32(kv.w);
            vu.x = f2tf32(vv.x); vu.y = f2tf32(vv.y); vu.z = f2tf32(vv.z); vu.w = f2tf32(vv.w);
            *(uint4*)&Ks[r * 68 + c4] = ku;
            *(uint4*)&Vs[r * 68 + c4] = vu;
        }
        __syncthreads();

        // S = Q K^T  (16x64 per warp)
        float sf[8][4];
#pragma unroll
        for (int ni = 0; ni < 8; ni++)
#pragma unroll
            for (int r = 0; r < 4; r++) sf[ni][r] = 0.f;
#pragma unroll
        for (int ks = 0; ks < 8; ks++) {
#pragma unroll
            for (int ni = 0; ni < 8; ni++) {
                uint32_t b0 = Ks[(ni * 8 + g) * 68 + ks * 8 + tg];
                uint32_t b1 = Ks[(ni * 8 + g) * 68 + ks * 8 + 4 + tg];
                mma_tf32(sf[ni], qf[ks], b0, b1);
            }
        }

        // causal mask within diagonal tile
        if (kt == qt) {
            int row0 = w * 16 + g, row1 = row0 + 8;
#pragma unroll
            for (int ni = 0; ni < 8; ni++) {
                int c0 = ni * 8 + 2 * tg, c1 = c0 + 1;
                if (c0 > row0) sf[ni][0] = -1e30f;
                if (c1 > row0) sf[ni][1] = -1e30f;
                if (c0 > row1) sf[ni][2] = -1e30f;
                if (c1 > row1) sf[ni][3] = -1e30f;
            }
        }

        // online softmax
        float m0 = -1e30f, m1 = -1e30f;
#pragma unroll
        for (int ni = 0; ni < 8; ni++) {
            m0 = fmaxf(m0, fmaxf(sf[ni][0], sf[ni][1]));
            m1 = fmaxf(m1, fmaxf(sf[ni][2], sf[ni][3]));
        }
        m0 = fmaxf(m0, __shfl_xor_sync(0xffffffffu, m0, 1));
        m0 = fmaxf(m0, __shfl_xor_sync(0xffffffffu, m0, 2));
        m1 = fmaxf(m1, __shfl_xor_sync(0xffffffffu, m1, 1));
        m1 = fmaxf(m1, __shfl_xor_sync(0xffffffffu, m1, 2));
        float nm0 = fmaxf(mi0, m0), nm1 = fmaxf(mi1, m1);
        float co0 = __expf(mi0 - nm0), co1 = __expf(mi1 - nm1);
        float rs0 = 0.f, rs1 = 0.f;
#pragma unroll
        for (int ni = 0; ni < 8; ni++) {
            sf[ni][0] = __expf(sf[ni][0] - nm0);
            sf[ni][1] = __expf(sf[ni][1] - nm0);
            sf[ni][2] = __expf(sf[ni][2] - nm1);
            sf[ni][3] = __expf(sf[ni][3] - nm1);
            rs0 += sf[ni][0] + sf[ni][1];
            rs1 += sf[ni][2] + sf[ni][3];
        }
        rs0 += __shfl_xor_sync(0xffffffffu, rs0, 1);
        rs0 += __shfl_xor_sync(0xffffffffu, rs0, 2);
        rs1 += __shfl_xor_sync(0xffffffffu, rs1, 1);
        rs1 += __shfl_xor_sync(0xffffffffu, rs1, 2);
        li0 = li0 * co0 + rs0;
        li1 = li1 * co1 + rs1;
        mi0 = nm0; mi1 = nm1;
#pragma unroll
        for (int ni = 0; ni < 8; ni++) {
            of[ni][0] *= co0; of[ni][1] *= co0;
            of[ni][2] *= co1; of[ni][3] *= co1;
        }

        __syncthreads();   // all warps finished reading Ks as K
        // write P (tf32) into this warp's 16-row slice of Ks
        {
            int pr0 = w * 16 + g;
#pragma unroll
            for (int ni = 0; ni < 8; ni++) {
                Ks[pr0 * 68 + ni * 8 + 2 * tg]           = f2tf32(sf[ni][0]);
                Ks[pr0 * 68 + ni * 8 + 2 * tg + 1]       = f2tf32(sf[ni][1]);
                Ks[(pr0 + 8) * 68 + ni * 8 + 2 * tg]     = f2tf32(sf[ni][2]);
                Ks[(pr0 + 8) * 68 + ni * 8 + 2 * tg + 1] = f2tf32(sf[ni][3]);
            }
        }
        __syncwarp();

        // O += P V
#pragma unroll
        for (int js = 0; js < 8; js++) {
            uint32_t a[4];
            int pr0 = w * 16 + g;
            a[0] = Ks[pr0 * 68 + js * 8 + tg];
            a[1] = Ks[(pr0 + 8) * 68 + js * 8 + tg];
            a[2] = Ks[pr0 * 68 + js * 8 + 4 + tg];
            a[3] = Ks[(pr0 + 8) * 68 + js * 8 + 4 + tg];
#pragma unroll
            for (int ni = 0; ni < 8; ni++) {
                uint32_t b0 = Vs[(js * 8 + tg) * 68 + ni * 8 + g];
                uint32_t b1 = Vs[(js * 8 + 4 + tg) * 68 + ni * 8 + g];
                mma_tf32(of[ni], a, b0, b1);
            }
        }
    }

    // epilogue: normalize, round to tf32 (feeds w_o GEMM), store
    float il0 = 1.f / li0, il1 = 1.f / li1;
    int m0g = qt * 64 + w * 16 + g, m1g = m0g + 8;
#pragma unroll
    for (int ni = 0; ni < 8; ni++) {
        int col = h * 64 + ni * 8 + 2 * tg;
        float2 p0 = make_float2(roundtf(of[ni][0] * il0), roundtf(of[ni][1] * il0));
        float2 p1 = make_float2(roundtf(of[ni][2] * il1), roundtf(of[ni][3] * il1));
        *(float2*)(o + ((size_t)(b * CK + m0g)) * CD + col) = p0;
        *(float2*)(o + ((size_t)(b * CK + m1g)) * CD + col) = p1;
    }
}

// ---------------- output assembly -------------------------------------------
__global__ void copyx_kernel(const float* __restrict__ x, float* __restrict__ out) {
    size_t i = (size_t)blockIdx.x * blockDim.x + threadIdx.x;
    ((float4*)out)[i] = ((const float4*)x)[i];
}

__global__ void scatter_kernel(const float* __restrict__ h, const int* __restrict__ idx,
                               const float* __restrict__ gate, float* __restrict__ out) {
    int bk = blockIdx.x;
    int b = bk >> 11;
    int t = idx[bk];
    float g = gate[bk];
    float4* dst = (float4*)(out + ((size_t)b * CT + t) * CD);
    const float4* src = (const float4*)(h + (size_t)bk * CD);
    float4 s = src[threadIdx.x];
    float4 d0 = dst[threadIdx.x];
    d0.x += s.x * g; d0.y += s.y * g; d0.z += s.z * g; d0.w += s.w * g;
    dst[threadIdx.x] = d0;
}

__global__ void tail_kernel(const int* __restrict__ idx, const float* __restrict__ logits,
                            float* __restrict__ out) {
    int i = blockIdx.x * blockDim.x + threadIdx.x;
    if (i < CB * CK) {
        out[BTD + i] = (float)idx[i];
    } else if (i < CB * CK + CB * CT) {
        int j = i - CB * CK;
        out[BTD + CB * CK + j] = logits[j];
    }
}

// ---------------- launch -----------------------------------------------------
extern "C" void kernel_launch(void* const* d_in, const int* in_sizes, int n_in,
                              void* d_out, int out_size) {
    const float* x         = (const float*)d_in[0];
    const float* w_router  = (const float*)d_in[1];
    const float* b_router  = (const float*)d_in[2];
    const float* ln1_scale = (const float*)d_in[3];
    const float* ln1_bias  = (const float*)d_in[4];
    const float* w_qkv     = (const float*)d_in[5];
    const float* b_qkv     = (const float*)d_in[6];
    const float* w_o       = (const float*)d_in[7];
    const float* b_o       = (const float*)d_in[8];
    const float* ln2_scale = (const float*)d_in[9];
    const float* ln2_bias  = (const float*)d_in[10];
    const float* w1        = (const float*)d_in[11];
    const float* b1        = (const float*)d_in[12];
    const float* w2        = (const float*)d_in[13];
    const float* b2        = (const float*)d_in[14];
    float* out = (float*)d_out;

    float *logits, *gate, *h, *lnb, *qkvb, *attnb, *midb, *wtf;
    int *sel, *idxp;
    cudaGetSymbolAddress((void**)&logits, g_logits);
    cudaGetSymbolAddress((void**)&sel, g_sel);
    cudaGetSymbolAddress((void**)&idxp, g_idx);
    cudaGetSymbolAddress((void**)&gate, g_gate);
    cudaGetSymbolAddress((void**)&h, g_h);
    cudaGetSymbolAddress((void**)&lnb, g_lnbuf);
    cudaGetSymbolAddress((void**)&qkvb, g_qkv);
    cudaGetSymbolAddress((void**)&attnb, g_attn);
    cudaGetSymbolAddress((void**)&midb, g_mid);
    cudaGetSymbolAddress((void**)&wtf, g_wtf);

    // allow >48KB dynamic smem on the tgemm instances (idempotent host call)
    cudaFuncSetAttribute(tgemm_kernel<false, false>,
                         cudaFuncAttributeMaxDynamicSharedMemorySize, (int)TGEMM_SMEM);
    cudaFuncSetAttribute(tgemm_kernel<false, true>,
                         cudaFuncAttributeMaxDynamicSharedMemorySize, (int)TGEMM_SMEM);
    cudaFuncSetAttribute(tgemm_kernel<true, false>,
                         cudaFuncAttributeMaxDynamicSharedMemorySize, (int)TGEMM_SMEM);

    // 0. pre-round weights to tf32
    cvtw_kernel<<<(int)(WQKV_SZ / 4 / 256), 256>>>(w_qkv, wtf + WQKV_OFF, (int)(WQKV_SZ / 4));
    cvtw_kernel<<<(int)(WO_SZ / 4 / 256), 256>>>(w_o,   wtf + WO_OFF,   (int)(WO_SZ / 4));
    cvtw_kernel<<<(int)(W1_SZ / 4 / 256), 256>>>(w1,    wtf + W1_OFF,   (int)(W1_SZ / 4));
    cvtw_kernel<<<(int)(W2_SZ / 4 / 256), 256>>>(w2,    wtf + W2_OFF,   (int)(W2_SZ / 4));

    // 1. router
    router_kernel<<<(CB * CT) / 8, 256>>>(x, w_router, b_router, logits);
    // 2. expert-choice top-K
    rank_kernel<<<CB * 64, 256>>>(logits, sel);
    compact_kernel<<<CB, 1024>>>(logits, sel, idxp, gate);
    // 3. gather
    gather_kernel<<<BK_ROWS, 256>>>(x, idxp, h);

    // 4. transformer blocks
    for (int l = 0; l < CL; l++) {
        layernorm_kernel<<<BK_ROWS, 256>>>(h, lnb, ln1_scale + l * CD, ln1_bias + l * CD);
        tgemm_kernel<false, false><<<dim3(3 * CD / GBN, BK_ROWS / GBM), 256, TGEMM_SMEM>>>(
            lnb, wtf + WQKV_OFF + (size_t)l * CD * 3 * CD, b_qkv + l * 3 * CD, nullptr,
            qkvb, BK_ROWS, 3 * CD, CD);
        attn_kernel<<<dim3(CK / 64, CH, CB), 128>>>(qkvb, attnb);
        tgemm_kernel<false, true><<<dim3(CD / GBN, BK_ROWS / GBM), 256, TGEMM_SMEM>>>(
            attnb, wtf + WO_OFF + (size_t)l * CD * CD, b_o + l * CD, h, h,
            BK_ROWS, CD, CD);
        layernorm_kernel<<<BK_ROWS, 256>>>(h, lnb, ln2_scale + l * CD, ln2_bias + l * CD);
        tgemm_kernel<true, false><<<dim3(CF / GBN, BK_ROWS / GBM), 256, TGEMM_SMEM>>>(
            lnb, wtf + W1_OFF + (size_t)l * CD * CF, b1 + l * CF, nullptr, midb,
            BK_ROWS, CF, CD);
        tgemm_kernel<false, true><<<dim3(CD / GBN, BK_ROWS / GBM), 256, TGEMM_SMEM>>>(
            midb, wtf + W2_OFF + (size_t)l * CF * CD, b2 + l * CD, h, h,
            BK_ROWS, CD, CF);
    }

    // 5. assemble output: total, idx, logits
    copyx_kernel<<<(int)(BTD / 4 / 256), 256>>>(x, out);
    scatter_kernel<<<BK_ROWS, 256>>>(h, idxp, gate, out);
    if ((size_t)out_size >= BTD + CB * CK + CB * CT) {
        int ntail = CB * CK + CB * CT;
        tail_kernel<<<(ntail + 255) / 256, 256>>>(idxp, logits, out);
    }
}

// round 5
// speedup vs baseline: 6.4374x; 1.9001x over previous
#include <cuda_runtime.h>
#include <cuda_fp16.h>
#include <math.h>
#include <stdint.h>

// Problem constants
constexpr int CB = 2;      // batch
constexpr int CT = 4096;   // seq len
constexpr int CD = 1024;   // d_model
constexpr int CL = 2;      // layers
constexpr int CH = 16;     // heads
constexpr int CF = 4096;   // d_ff
constexpr int CK = 2048;   // top-k tokens
constexpr int BK_ROWS = CB * CK;           // 4096 rows through the blocks
constexpr size_t BTD = (size_t)CB * CT * CD;

// Weight fp16 scratch offsets (elements)
constexpr size_t WQKV_OFF = 0;
constexpr size_t WQKV_SZ  = (size_t)CL * CD * 3 * CD;
constexpr size_t WO_OFF   = WQKV_OFF + WQKV_SZ;
constexpr size_t WO_SZ    = (size_t)CL * CD * CD;
constexpr size_t W1_OFF   = WO_OFF + WO_SZ;
constexpr size_t W1_SZ    = (size_t)CL * CD * CF;
constexpr size_t W2_OFF   = W1_OFF + W1_SZ;
constexpr size_t W2_SZ    = (size_t)CL * CF * CD;
constexpr size_t WTF_TOTAL = W2_OFF + W2_SZ;

// ---------------- scratch (static device globals) ---------------------------
__device__ float  g_logits[CB * CT];
__device__ int    g_sel[CB * CT];
__device__ int    g_idx[CB * CK];
__device__ float  g_gate[CB * CK];
__device__ float  g_h[BK_ROWS * CD];
__device__ __half g_lnh[BK_ROWS * CD];
__device__ __half g_qkvh[(size_t)BK_ROWS * 3 * CD];
__device__ __half g_attnh[BK_ROWS * CD];
__device__ __half g_midh[(size_t)BK_ROWS * CF];
__device__ __half g_wth[WTF_TOTAL];

__device__ __forceinline__ void mma_f16(float c[4], const uint32_t a[4],
                                        uint32_t b0, uint32_t b1) {
    asm volatile(
        "mma.sync.aligned.m16n8k16.row.col.f32.f16.f16.f32 "
        "{%0,%1,%2,%3}, {%4,%5,%6,%7}, {%8,%9}, {%0,%1,%2,%3};\n"
        : "+f"(c[0]), "+f"(c[1]), "+f"(c[2]), "+f"(c[3])
        : "r"(a[0]), "r"(a[1]), "r"(a[2]), "r"(a[3]), "r"(b0), "r"(b1));
}
__device__ __forceinline__ void ldsm_x4(uint32_t r[4], uint32_t saddr) {
    asm volatile("ldmatrix.sync.aligned.m8n8.x4.shared.b16 {%0,%1,%2,%3}, [%4];"
                 : "=r"(r[0]), "=r"(r[1]), "=r"(r[2]), "=r"(r[3]) : "r"(saddr));
}
__device__ __forceinline__ void ldsm_x2(uint32_t& r0, uint32_t& r1, uint32_t saddr) {
    asm volatile("ldmatrix.sync.aligned.m8n8.x2.shared.b16 {%0,%1}, [%2];"
                 : "=r"(r0), "=r"(r1) : "r"(saddr));
}
__device__ __forceinline__ void ldsm_x2t(uint32_t& r0, uint32_t& r1, uint32_t saddr) {
    asm volatile("ldmatrix.sync.aligned.m8n8.x2.trans.shared.b16 {%0,%1}, [%2];"
                 : "=r"(r0), "=r"(r1) : "r"(saddr));
}

// ---------------- router ----------------------------------------------------
__global__ void router_kernel(const float* __restrict__ x,
                              const float* __restrict__ wr,
                              const float* __restrict__ br,
                              float* __restrict__ logits) {
    int gw = (blockIdx.x * blockDim.x + threadIdx.x) >> 5;
    if (gw >= CB * CT) return;
    int lane = threadIdx.x & 31;
    const float4* p = (const float4*)(x + (size_t)gw * CD);
    const float4* w4 = (const float4*)wr;
    float s = 0.f;
#pragma unroll
    for (int i = 0; i < CD / 128; i++) {
        float4 a = p[lane + i * 32];
        float4 w = w4[lane + i * 32];
        s += a.x * w.x + a.y * w.y + a.z * w.z + a.w * w.w;
    }
#pragma unroll
    for (int o = 16; o > 0; o >>= 1) s += __shfl_down_sync(0xffffffffu, s, o);
    if (lane == 0) logits[gw] = s + br[0];
}

// ---------------- top-K -----------------------------------------------------
__global__ void rank_kernel(const float* __restrict__ logits, int* __restrict__ sel) {
    int blk = blockIdx.x;
    int b = blk >> 6;
    int base = (blk & 63) * 64;
    __shared__ float lv[CT];
    int tid = threadIdx.x;
    for (int t = tid; t < CT; t += 256) lv[t] = logits[b * CT + t];
    __syncthreads();
    int tt = tid >> 2, part = tid & 3;
    int t = base + tt;
    float v = lv[t];
    int cnt = 0;
    int s0 = part * 1024;
#pragma unroll 8
    for (int s = s0; s < s0 + 1024; s++) {
        float u = lv[s];
        cnt += (u > v) || (u == v && s < t);
    }
    __shared__ int rk[64];
    if (part == 0) rk[tt] = 0;
    __syncthreads();
    atomicAdd(&rk[tt], cnt);
    __syncthreads();
    if (part == 0) sel[b * CT + t] = (rk[tt] < CK) ? 1 : 0;
}

__global__ void compact_kernel(const float* __restrict__ logits,
                               const int* __restrict__ sel,
                               int* __restrict__ idx_out,
                               float* __restrict__ gate_out) {
    int b = blockIdx.x;
    int tid = threadIdx.x;
    int f[4]; int c = 0;
#pragma unroll
    for (int i = 0; i < 4; i++) { f[i] = sel[b * CT + tid * 4 + i]; c += f[i]; }
    int lane = tid & 31, wid = tid >> 5;
    int incl = c;
#pragma unroll
    for (int o = 1; o < 32; o <<= 1) {
        int n = __shfl_up_sync(0xffffffffu, incl, o);
        if (lane >= o) incl += n;
    }
    __shared__ int wsum[32];
    if (lane == 31) wsum[wid] = incl;
    __syncthreads();
    if (wid == 0) {
        int w = wsum[lane];
#pragma unroll
        for (int o = 1; o < 32; o <<= 1) {
            int n = __shfl_up_sync(0xffffffffu, w, o);
            if (lane >= o) w += n;
        }
        wsum[lane] = w;
    }
    __syncthreads();
    int pos = (wid ? wsum[wid - 1] : 0) + incl - c;
#pragma unroll
    for (int i = 0; i < 4; i++) {
        if (f[i]) {
            int t = tid * 4 + i;
            idx_out[b * CK + pos] = t;
            float lg = logits[b * CT + t];
            gate_out[b * CK + pos] = 1.f / (1.f + expf(-lg));
            pos++;
        }
    }
}

// ---------------- gather ----------------------------------------------------
__global__ void gather_kernel(const float* __restrict__ x, const int* __restrict__ idx,
                              float* __restrict__ h) {
    int bk = blockIdx.x;
    int b = bk >> 11;
    int t = idx[bk];
    const float4* src = (const float4*)(x + ((size_t)b * CT + t) * CD);
    float4* dst = (float4*)(h + (size_t)bk * CD);
    dst[threadIdx.x] = src[threadIdx.x];
}

// ---------------- layernorm (fp32 in -> fp16 out) ---------------------------
__global__ void layernorm_kernel(const float* __restrict__ in, __half* __restrict__ out,
                                 const float* __restrict__ scale,
                                 const float* __restrict__ bias) {
    int row = blockIdx.x;
    int tid = threadIdx.x;
    const float4* p = (const float4*)(in + (size_t)row * CD);
    float4 v = p[tid];
    float s = v.x + v.y + v.z + v.w;
    float ss = v.x * v.x + v.y * v.y + v.z * v.z + v.w * v.w;
#pragma unroll
    for (int o = 16; o > 0; o >>= 1) {
        s += __shfl_down_sync(0xffffffffu, s, o);
        ss += __shfl_down_sync(0xffffffffu, ss, o);
    }
    __shared__ float red[64];
    int lane = tid & 31, wid = tid >> 5;
    if (lane == 0) { red[wid] = s; red[32 + wid] = ss; }
    __syncthreads();
    if (tid == 0) {
        float S = 0, SS = 0;
#pragma unroll
        for (int w = 0; w < 8; w++) { S += red[w]; SS += red[32 + w]; }
        red[0] = S; red[32] = SS;
    }
    __syncthreads();
    float mean = red[0] * (1.f / CD);
    float var = red[32] * (1.f / CD) - mean * mean;
    float inv = rsqrtf(var + 1e-5f);
    float4 sc = ((const float4*)scale)[tid];
    float4 bi = ((const float4*)bias)[tid];
    __half2 h0 = __floats2half2_rn((v.x - mean) * inv * sc.x + bi.x,
                                   (v.y - mean) * inv * sc.y + bi.y);
    __half2 h1 = __floats2half2_rn((v.z - mean) * inv * sc.z + bi.z,
                                   (v.w - mean) * inv * sc.w + bi.w);
    __half2* o2 = (__half2*)(out + (size_t)row * CD);
    o2[2 * tid] = h0;
    o2[2 * tid + 1] = h1;
}

// ---------------- weight fp16 convert ---------------------------------------
__global__ void cvtw_kernel(const float* __restrict__ src, __half* __restrict__ dst,
                            int n4) {
    int i = blockIdx.x * blockDim.x + threadIdx.x;
    if (i >= n4) return;
    float4 v = ((const float4*)src)[i];
    __half2* d2 = (__half2*)dst;
    d2[2 * i]     = __floats2half2_rn(v.x, v.y);
    d2[2 * i + 1] = __floats2half2_rn(v.z, v.w);
}

// ---------------- FP16 tensor-core GEMM, cp.async double-buffered -----------
__device__ __forceinline__ float gelu_tanh(float x) {
    float x3 = x * x * x;
    float t = tanhf(0.7978845608028654f * (x + 0.044715f * x3));
    return 0.5f * x * (1.f + t);
}

constexpr int GBM = 128, GBN = 128, GBK = 64;
constexpr int AST = GBK + 8;     // 72 halfs/row
constexpr int BST = GBN + 8;     // 136 halfs/row
constexpr int ABUFH = GBM * AST; // 9216 halfs
constexpr int BBUFH = GBK * BST; // 8704 halfs
constexpr size_t TGEMM_SMEM = (size_t)(ABUFH + BBUFH) * 2 * sizeof(__half); // 71680 B

template <bool GELU, bool RESID, bool OUTH>
__global__ __launch_bounds__(256) void tgemm_kernel(
    const __half* __restrict__ A, const __half* __restrict__ W,
    const float* __restrict__ bias, const float* __restrict__ R,
    void* __restrict__ Cv, int M, int N, int Kd) {
    extern __shared__ __half dsm[];
    __half* As = dsm;
    __half* Bs = dsm + 2 * ABUFH;

    const int tid = threadIdx.x;
    const int bx = blockIdx.x, by = blockIdx.y;
    const int wid = tid >> 5, lane = tid & 31;
    const int warp_m = wid & 1;
    const int warp_n = wid >> 1;
    const int g = lane >> 2;
    const int tg = lane & 3;
    const int lm = (lane & 7) + ((lane >> 3) & 1) * 8;   // A-frag row
    const int lk = ((lane >> 4) & 1) * 8;                // A-frag k
    const int lkb = (lane & 7) + ((lane >> 3) & 1) * 8;  // B-frag k row

    float c[4][4][4];
#pragma unroll
    for (int mi = 0; mi < 4; mi++)
#pragma unroll
        for (int ni = 0; ni < 4; ni++)
#pragma unroll
            for (int r = 0; r < 4; r++) c[mi][ni][r] = 0.f;

    const int ntiles = Kd / GBK;

    auto issue_tile = [&](int t, int buf) {
        int k0 = t * GBK;
        uint32_t abase = (uint32_t)__cvta_generic_to_shared(As + buf * ABUFH);
        uint32_t bbase = (uint32_t)__cvta_generic_to_shared(Bs + buf * BBUFH);
#pragma unroll
        for (int i = 0; i < 4; i++) {
            int q = tid + i * 256;
            int row = q >> 3, c8 = (q & 7) * 8;
            const __half* src = A + (size_t)(by * GBM + row) * Kd + k0 + c8;
            uint32_t dst = abase + (row * AST + c8) * 2;
            asm volatile("cp.async.cg.shared.global [%0], [%1], 16;\n"
                         :: "r"(dst), "l"(src));
        }
#pragma unroll
        for (int i = 0; i < 4; i++) {
            int q = tid + i * 256;
            int row = q >> 4, n8 = (q & 15) * 8;
            const __half* src = W + (size_t)(k0 + row) * N + bx * GBN + n8;
            uint32_t dst = bbase + (row * BST + n8) * 2;
            asm volatile("cp.async.cg.shared.global [%0], [%1], 16;\n"
                         :: "r"(dst), "l"(src));
        }
        asm volatile("cp.async.commit_group;\n");
    };

    issue_tile(0, 0);
    for (int t = 0; t < ntiles; t++) {
        if (t + 1 < ntiles) {
            issue_tile(t + 1, (t + 1) & 1);
            asm volatile("cp.async.wait_group 1;\n");
        } else {
            asm volatile("cp.async.wait_group 0;\n");
        }
        __syncthreads();
        uint32_t Ab = (uint32_t)__cvta_generic_to_shared(As + (t & 1) * ABUFH);
        uint32_t Bb = (uint32_t)__cvta_generic_to_shared(Bs + (t & 1) * BBUFH);
        uint32_t a_off = Ab + ((warp_m * 64 + lm) * AST + lk) * 2;
        uint32_t b_off = Bb + (lkb * BST + warp_n * 32) * 2;
#pragma unroll
        for (int ks = 0; ks < GBK / 16; ks++) {
            uint32_t a[4][4], b[4][2];
#pragma unroll
            for (int mi = 0; mi < 4; mi++)
                ldsm_x4(a[mi], a_off + (mi * 16 * AST + ks * 16) * 2);
#pragma unroll
            for (int ni = 0; ni < 4; ni++)
                ldsm_x2t(b[ni][0], b[ni][1], b_off + (ks * 16 * BST + ni * 8) * 2);
#pragma unroll
            for (int mi = 0; mi < 4; mi++)
#pragma unroll
                for (int ni = 0; ni < 4; ni++)
                    mma_f16(c[mi][ni], a[mi], b[ni][0], b[ni][1]);
        }
        __syncthreads();
    }

#pragma unroll
    for (int mi = 0; mi < 4; mi++) {
        int m0 = by * GBM + warp_m * 64 + mi * 16 + g;
#pragma unroll
        for (int ni = 0; ni < 4; ni++) {
            int n0 = bx * GBN + warp_n * 32 + ni * 8 + 2 * tg;
            float b0 = bias[n0], b1 = bias[n0 + 1];
#pragma unroll
            for (int half = 0; half < 2; half++) {
                int m = m0 + half * 8;
                float v0 = c[mi][ni][half * 2 + 0] + b0;
                float v1 = c[mi][ni][half * 2 + 1] + b1;
                if (GELU) { v0 = gelu_tanh(v0); v1 = gelu_tanh(v1); }
                if (RESID) {
                    const float2 r2 = *(const float2*)(R + (size_t)m * N + n0);
                    v0 += r2.x; v1 += r2.y;
                }
                if (OUTH) {
                    *(__half2*)((__half*)Cv + (size_t)m * N + n0) =
                        __floats2half2_rn(v0, v1);
                } else {
                    *(float2*)((float*)Cv + (size_t)m * N + n0) = make_float2(v0, v1);
                }
            }
        }
    }
}

// ---------------- FP16 MMA flash attention -----------------------------------
// 128 threads (4 warps), Q tile 64 rows, warp w owns rows w*16..w*16+15.
constexpr int SATT = 72;  // smem row stride (halfs)
__global__ __launch_bounds__(128) void attn_kernel(const __half* __restrict__ qkv,
                                                   __half* __restrict__ o) {
    const int qt = blockIdx.x, h = blockIdx.y, b = blockIdx.z;
    const int tid = threadIdx.x;
    const int w = tid >> 5, lane = tid & 31;
    const int g = lane >> 2, tg = lane & 3;
    const int lm = (lane & 7) + ((lane >> 3) & 1) * 8;
    const int lk = ((lane >> 4) & 1) * 8;
    const int lkb = (lane & 7) + ((lane >> 3) & 1) * 8;

    __shared__ __half Qs[64 * SATT];   // reused as P after Q frags loaded
    __shared__ __half Ks[64 * SATT];
    __shared__ __half Vs[64 * SATT];
    uint32_t qsb = (uint32_t)__cvta_generic_to_shared(Qs);
    uint32_t ksb = (uint32_t)__cvta_generic_to_shared(Ks);
    uint32_t vsb = (uint32_t)__cvta_generic_to_shared(Vs);

    // stage Q (scaled by 1/8)
    const __half2 sc8 = __float2half2_rn(0.125f);
#pragma unroll
    for (int i = 0; i < 4; i++) {
        int q = tid + i * 128;
        int r = q >> 3, c8 = (q & 7) * 8;
        const __half* src = qkv + ((size_t)(b * CK + qt * 64 + r)) * (3 * CD) + h * 64 + c8;
        uint4 u = *(const uint4*)src;
        __half2* hp = (__half2*)&u;
#pragma unroll
        for (int j = 0; j < 4; j++) hp[j] = __hmul2(hp[j], sc8);
        *(uint4*)&Qs[r * SATT + c8] = u;
    }
    __syncthreads();
    uint32_t qf[4][4];
#pragma unroll
    for (int ks = 0; ks < 4; ks++)
        ldsm_x4(qf[ks], qsb + ((w * 16 + lm) * SATT + ks * 16 + lk) * 2);

    float of[8][4];
#pragma unroll
    for (int ni = 0; ni < 8; ni++)
#pragma unroll
        for (int r = 0; r < 4; r++) of[ni][r] = 0.f;
    float mi0 = -1e30f, mi1 = -1e30f, li0 = 0.f, li1 = 0.f;

    for (int kt = 0; kt <= qt; kt++) {
        __syncthreads();
#pragma unroll
        for (int i = 0; i < 4; i++) {
            int q = tid + i * 128;
            int r = q >> 3, c8 = (q & 7) * 8;
            const __half* kb = qkv + ((size_t)(b * CK + kt * 64 + r)) * (3 * CD) + CD + h * 64 + c8;
            *(uint4*)&Ks[r * SATT + c8] = *(const uint4*)kb;
            *(uint4*)&Vs[r * SATT + c8] = *(const uint4*)(kb + CD);
        }
        __syncthreads();

        // S = Q K^T  (16x64 per warp); K tile is [n][d] -> non-trans ldmatrix
        float sf[8][4];
#pragma unroll
        for (int ni = 0; ni < 8; ni++)
#pragma unroll
            for (int r = 0; r < 4; r++) sf[ni][r] = 0.f;
#pragma unroll
        for (int ks = 0; ks < 4; ks++) {
#pragma unroll
            for (int ni = 0; ni < 8; ni++) {
                uint32_t b0, b1;
                ldsm_x2(b0, b1,
                        ksb + ((ni * 8 + (lane & 7)) * SATT + ks * 16 + ((lane >> 3) & 1) * 8) * 2);
                mma_f16(sf[ni], qf[ks], b0, b1);
            }
        }

        if (kt == qt) {
            int row0 = w * 16 + g, row1 = row0 + 8;
#pragma unroll
            for (int ni = 0; ni < 8; ni++) {
                int c0 = ni * 8 + 2 * tg, c1 = c0 + 1;
                if (c0 > row0) sf[ni][0] = -1e30f;
                if (c1 > row0) sf[ni][1] = -1e30f;
                if (c0 > row1) sf[ni][2] = -1e30f;
                if (c1 > row1) sf[ni][3] = -1e30f;
            }
        }

        // online softmax
        float m0 = -1e30f, m1 = -1e30f;
#pragma unroll
        for (int ni = 0; ni < 8; ni++) {
            m0 = fmaxf(m0, fmaxf(sf[ni][0], sf[ni][1]));
            m1 = fmaxf(m1, fmaxf(sf[ni][2], sf[ni][3]));
        }
        m0 = fmaxf(m0, __shfl_xor_sync(0xffffffffu, m0, 1));
        m0 = fmaxf(m0, __shfl_xor_sync(0xffffffffu, m0, 2));
        m1 = fmaxf(m1, __shfl_xor_sync(0xffffffffu, m1, 1));
        m1 = fmaxf(m1, __shfl_xor_sync(0xffffffffu, m1, 2));
        float nm0 = fmaxf(mi0, m0), nm1 = fmaxf(mi1, m1);
        float co0 = __expf(mi0 - nm0), co1 = __expf(mi1 - nm1);
        float rs0 = 0.f, rs1 = 0.f;
#pragma unroll
        for (int ni = 0; ni < 8; ni++) {
            sf[ni][0] = __expf(sf[ni][0] - nm0);
            sf[ni][1] = __expf(sf[ni][1] - nm0);
            sf[ni][2] = __expf(sf[ni][2] - nm1);
            sf[ni][3] = __expf(sf[ni][3] - nm1);
            rs0 += sf[ni][0] + sf[ni][1];
            rs1 += sf[ni][2] + sf[ni][3];
        }
        rs0 += __shfl_xor_sync(0xffffffffu, rs0, 1);
        rs0 += __shfl_xor_sync(0xffffffffu, rs0, 2);
        rs1 += __shfl_xor_sync(0xffffffffu, rs1, 1);
        rs1 += __shfl_xor_sync(0xffffffffu, rs1, 2);
        li0 = li0 * co0 + rs0;
        li1 = li1 * co1 + rs1;
        mi0 = nm0; mi1 = nm1;
#pragma unroll
        for (int ni = 0; ni < 8; ni++) {
            of[ni][0] *= co0; of[ni][1] *= co0;
            of[ni][2] *= co1; of[ni][3] *= co1;
        }

        // write P (half) into this warp's own 16 rows of Qs
        {
            int pr = w * 16 + g;
#pragma unroll
            for (int ni = 0; ni < 8; ni++) {
                *(__half2*)&Qs[pr * SATT + ni * 8 + 2 * tg] =
                    __floats2half2_rn(sf[ni][0], sf[ni][1]);
                *(__half2*)&Qs[(pr + 8) * SATT + ni * 8 + 2 * tg] =
                    __floats2half2_rn(sf[ni][2], sf[ni][3]);
            }
        }
        __syncwarp();

        // O += P V ; V tile [j][d] -> trans ldmatrix for B
#pragma unroll
        for (int js = 0; js < 4; js++) {
            uint32_t a[4];
            ldsm_x4(a, qsb + ((w * 16 + lm) * SATT + js * 16 + lk) * 2);
#pragma unroll
            for (int ni = 0; ni < 8; ni++) {
                uint32_t b0, b1;
                ldsm_x2t(b0, b1, vsb + ((js * 16 + lkb) * SATT + ni * 8) * 2);
                mma_f16(of[ni], a, b0, b1);
            }
        }
    }

    float il0 = 1.f / li0, il1 = 1.f / li1;
    int m0g = qt * 64 + w * 16 + g, m1g = m0g + 8;
#pragma unroll
    for (int ni = 0; ni < 8; ni++) {
        int col = h * 64 + ni * 8 + 2 * tg;
        *(__half2*)(o + ((size_t)(b * CK + m0g)) * CD + col) =
            __floats2half2_rn(of[ni][0] * il0, of[ni][1] * il0);
        *(__half2*)(o + ((size_t)(b * CK + m1g)) * CD + col) =
            __floats2half2_rn(of[ni][2] * il1, of[ni][3] * il1);
    }
}

// ---------------- output assembly -------------------------------------------
__global__ void copyx_kernel(const float* __restrict__ x, float* __restrict__ out) {
    size_t i = (size_t)blockIdx.x * blockDim.x + threadIdx.x;
    ((float4*)out)[i] = ((const float4*)x)[i];
}

__global__ void scatter_kernel(const float* __restrict__ h, const int* __restrict__ idx,
                               const float* __restrict__ gate, float* __restrict__ out) {
    int bk = blockIdx.x;
    int b = bk >> 11;
    int t = idx[bk];
    float g = gate[bk];
    float4* dst = (float4*)(out + ((size_t)b * CT + t) * CD);
    const float4* src = (const float4*)(h + (size_t)bk * CD);
    float4 s = src[threadIdx.x];
    float4 d0 = dst[threadIdx.x];
    d0.x += s.x * g; d0.y += s.y * g; d0.z += s.z * g; d0.w += s.w * g;
    dst[threadIdx.x] = d0;
}

__global__ void tail_kernel(const int* __restrict__ idx, const float* __restrict__ logits,
                            float* __restrict__ out) {
    int i = blockIdx.x * blockDim.x + threadIdx.x;
    if (i < CB * CK) {
        out[BTD + i] = (float)idx[i];
    } else if (i < CB * CK + CB * CT) {
        int j = i - CB * CK;
        out[BTD + CB * CK + j] = logits[j];
    }
}

// ---------------- launch -----------------------------------------------------
extern "C" void kernel_launch(void* const* d_in, const int* in_sizes, int n_in,
                              void* d_out, int out_size) {
    const float* x         = (const float*)d_in[0];
    const float* w_router  = (const float*)d_in[1];
    const float* b_router  = (const float*)d_in[2];
    const float* ln1_scale = (const float*)d_in[3];
    const float* ln1_bias  = (const float*)d_in[4];
    const float* w_qkv     = (const float*)d_in[5];
    const float* b_qkv     = (const float*)d_in[6];
    const float* w_o       = (const float*)d_in[7];
    const float* b_o       = (const float*)d_in[8];
    const float* ln2_scale = (const float*)d_in[9];
    const float* ln2_bias  = (const float*)d_in[10];
    const float* w1        = (const float*)d_in[11];
    const float* b1        = (const float*)d_in[12];
    const float* w2        = (const float*)d_in[13];
    const float* b2        = (const float*)d_in[14];
    float* out = (float*)d_out;

    float *logits, *gate, *h;
    int *sel, *idxp;
    __half *lnh, *qkvh, *attnh, *midh, *wth;
    cudaGetSymbolAddress((void**)&logits, g_logits);
    cudaGetSymbolAddress((void**)&sel, g_sel);
    cudaGetSymbolAddress((void**)&idxp, g_idx);
    cudaGetSymbolAddress((void**)&gate, g_gate);
    cudaGetSymbolAddress((void**)&h, g_h);
    cudaGetSymbolAddress((void**)&lnh, g_lnh);
    cudaGetSymbolAddress((void**)&qkvh, g_qkvh);
    cudaGetSymbolAddress((void**)&attnh, g_attnh);
    cudaGetSymbolAddress((void**)&midh, g_midh);
    cudaGetSymbolAddress((void**)&wth, g_wth);

    cudaFuncSetAttribute(tgemm_kernel<false, false, true>,
                         cudaFuncAttributeMaxDynamicSharedMemorySize, (int)TGEMM_SMEM);
    cudaFuncSetAttribute(tgemm_kernel<false, true, false>,
                         cudaFuncAttributeMaxDynamicSharedMemorySize, (int)TGEMM_SMEM);
    cudaFuncSetAttribute(tgemm_kernel<true, false, true>,
                         cudaFuncAttributeMaxDynamicSharedMemorySize, (int)TGEMM_SMEM);

    // 0. pre-convert weights to fp16
    cvtw_kernel<<<(int)(WQKV_SZ / 4 / 256), 256>>>(w_qkv, wth + WQKV_OFF, (int)(WQKV_SZ / 4));
    cvtw_kernel<<<(int)(WO_SZ / 4 / 256), 256>>>(w_o,   wth + WO_OFF,   (int)(WO_SZ / 4));
    cvtw_kernel<<<(int)(W1_SZ / 4 / 256), 256>>>(w1,    wth + W1_OFF,   (int)(W1_SZ / 4));
    cvtw_kernel<<<(int)(W2_SZ / 4 / 256), 256>>>(w2,    wth + W2_OFF,   (int)(W2_SZ / 4));

    // 1. router
    router_kernel<<<(CB * CT) / 8, 256>>>(x, w_router, b_router, logits);
    // 2. expert-choice top-K
    rank_kernel<<<CB * 64, 256>>>(logits, sel);
    compact_kernel<<<CB, 1024>>>(logits, sel, idxp, gate);
    // 3. gather
    gather_kernel<<<BK_ROWS, 256>>>(x, idxp, h);

    // 4. transformer blocks
    for (int l = 0; l < CL; l++) {
        layernorm_kernel<<<BK_ROWS, 256>>>(h, lnh, ln1_scale + l * CD, ln1_bias + l * CD);
        tgemm_kernel<false, false, true><<<dim3(3 * CD / GBN, BK_ROWS / GBM), 256, TGEMM_SMEM>>>(
            lnh, wth + WQKV_OFF + (size_t)l * CD * 3 * CD, b_qkv + l * 3 * CD, nullptr,
            qkvh, BK_ROWS, 3 * CD, CD);
        attn_kernel<<<dim3(CK / 64, CH, CB), 128>>>(qkvh, attnh);
        tgemm_kernel<false, true, false><<<dim3(CD / GBN, BK_ROWS / GBM), 256, TGEMM_SMEM>>>(
            attnh, wth + WO_OFF + (size_t)l * CD * CD, b_o + l * CD, h, h,
            BK_ROWS, CD, CD);
        layernorm_kernel<<<BK_ROWS, 256>>>(h, lnh, ln2_scale + l * CD, ln2_bias + l * CD);
        tgemm_kernel<true, false, true><<<dim3(CF / GBN, BK_ROWS / GBM), 256, TGEMM_SMEM>>>(
            lnh, wth + W1_OFF + (size_t)l * CD * CF, b1 + l * CF, nullptr, midh,
            BK_ROWS, CF, CD);
        tgemm_kernel<false, true, false><<<dim3(CD / GBN, BK_ROWS / GBM), 256, TGEMM_SMEM>>>(
            midh, wth + W2_OFF + (size_t)l * CF * CD, b2 + l * CD, h, h,
            BK_ROWS, CD, CF);
    }

    // 5. assemble output: total, idx, logits
    copyx_kernel<<<(int)(BTD / 4 / 256), 256>>>(x, out);
    scatter_kernel<<<BK_ROWS, 256>>>(h, idxp, gate, out);
    if ((size_t)out_size >= BTD + CB * CK + CB * CT) {
        int ntail = CB * CK + CB * CT;
        tail_kernel<<<(ntail + 255) / 256, 256>>>(idxp, logits, out);
    }
}

// round 7
// speedup vs baseline: 6.5736x; 1.0212x over previous
#include <cuda_runtime.h>
#include <cuda_fp16.h>
#include <math.h>
#include <stdint.h>

// Problem constants
constexpr int CB = 2;      // batch
constexpr int CT = 4096;   // seq len
constexpr int CD = 1024;   // d_model
constexpr int CL = 2;      // layers
constexpr int CH = 16;     // heads
constexpr int CF = 4096;   // d_ff
constexpr int CK = 2048;   // top-k tokens
constexpr int BK_ROWS = CB * CK;
constexpr size_t BTD = (size_t)CB * CT * CD;

// Weight fp16 scratch offsets (elements)
constexpr size_t WQKV_OFF = 0;
constexpr size_t WQKV_SZ  = (size_t)CL * CD * 3 * CD;
constexpr size_t WO_OFF   = WQKV_OFF + WQKV_SZ;
constexpr size_t WO_SZ    = (size_t)CL * CD * CD;
constexpr size_t W1_OFF   = WO_OFF + WO_SZ;
constexpr size_t W1_SZ    = (size_t)CL * CD * CF;
constexpr size_t W2_OFF   = W1_OFF + W1_SZ;
constexpr size_t W2_SZ    = (size_t)CL * CF * CD;
constexpr size_t WTF_TOTAL = W2_OFF + W2_SZ;

// ---------------- scratch (static device globals) ---------------------------
__device__ float  g_logits[CB * CT];
__device__ int    g_sel[CB * CT];
__device__ int    g_idx[CB * CK];
__device__ float  g_gate[CB * CK];
__device__ float  g_h[BK_ROWS * CD];
__device__ __half g_lnh[BK_ROWS * CD];
__device__ __half g_qkvh[(size_t)BK_ROWS * 3 * CD];
__device__ __half g_attnh[BK_ROWS * CD];
__device__ __half g_midh[(size_t)BK_ROWS * CF];
__device__ __half g_wth[WTF_TOTAL];

__device__ __forceinline__ void mma_f16(float c[4], const uint32_t a[4],
                                        uint32_t b0, uint32_t b1) {
    asm volatile(
        "mma.sync.aligned.m16n8k16.row.col.f32.f16.f16.f32 "
        "{%0,%1,%2,%3}, {%4,%5,%6,%7}, {%8,%9}, {%0,%1,%2,%3};\n"
        : "+f"(c[0]), "+f"(c[1]), "+f"(c[2]), "+f"(c[3])
        : "r"(a[0]), "r"(a[1]), "r"(a[2]), "r"(a[3]), "r"(b0), "r"(b1));
}
__device__ __forceinline__ void ldsm_x4(uint32_t r[4], uint32_t saddr) {
    asm volatile("ldmatrix.sync.aligned.m8n8.x4.shared.b16 {%0,%1,%2,%3}, [%4];"
                 : "=r"(r[0]), "=r"(r[1]), "=r"(r[2]), "=r"(r[3]) : "r"(saddr));
}
__device__ __forceinline__ void ldsm_x2(uint32_t& r0, uint32_t& r1, uint32_t saddr) {
    asm volatile("ldmatrix.sync.aligned.m8n8.x2.shared.b16 {%0,%1}, [%2];"
                 : "=r"(r0), "=r"(r1) : "r"(saddr));
}
__device__ __forceinline__ void ldsm_x2t(uint32_t& r0, uint32_t& r1, uint32_t saddr) {
    asm volatile("ldmatrix.sync.aligned.m8n8.x2.trans.shared.b16 {%0,%1}, [%2];"
                 : "=r"(r0), "=r"(r1) : "r"(saddr));
}
__device__ __forceinline__ void cp16(uint32_t dst, const void* src) {
    asm volatile("cp.async.cg.shared.global [%0], [%1], 16;\n" :: "r"(dst), "l"(src));
}

// ---------------- router ----------------------------------------------------
__global__ void router_kernel(const float* __restrict__ x,
                              const float* __restrict__ wr,
                              const float* __restrict__ br,
                              float* __restrict__ logits) {
    int gw = (blockIdx.x * blockDim.x + threadIdx.x) >> 5;
    if (gw >= CB * CT) return;
    int lane = threadIdx.x & 31;
    const float4* p = (const float4*)(x + (size_t)gw * CD);
    const float4* w4 = (const float4*)wr;
    float s = 0.f;
#pragma unroll
    for (int i = 0; i < CD / 128; i++) {
        float4 a = p[lane + i * 32];
        float4 w = w4[lane + i * 32];
        s += a.x * w.x + a.y * w.y + a.z * w.z + a.w * w.w;
    }
#pragma unroll
    for (int o = 16; o > 0; o >>= 1) s += __shfl_down_sync(0xffffffffu, s, o);
    if (lane == 0) logits[gw] = s + br[0];
}

// ---------------- top-K -----------------------------------------------------
__global__ void rank_kernel(const float* __restrict__ logits, int* __restrict__ sel) {
    int blk = blockIdx.x;
    int b = blk >> 6;
    int base = (blk & 63) * 64;
    __shared__ float lv[CT];
    int tid = threadIdx.x;
    for (int t = tid; t < CT; t += 256) lv[t] = logits[b * CT + t];
    __syncthreads();
    int tt = tid >> 2, part = tid & 3;
    int t = base + tt;
    float v = lv[t];
    int cnt = 0;
    int s0 = part * 1024;
#pragma unroll 8
    for (int s = s0; s < s0 + 1024; s++) {
        float u = lv[s];
        cnt += (u > v) || (u == v && s < t);
    }
    __shared__ int rk[64];
    if (part == 0) rk[tt] = 0;
    __syncthreads();
    atomicAdd(&rk[tt], cnt);
    __syncthreads();
    if (part == 0) sel[b * CT + t] = (rk[tt] < CK) ? 1 : 0;
}

__global__ void compact_kernel(const float* __restrict__ logits,
                               const int* __restrict__ sel,
                               int* __restrict__ idx_out,
                               float* __restrict__ gate_out) {
    int b = blockIdx.x;
    int tid = threadIdx.x;
    int f[4]; int c = 0;
#pragma unroll
    for (int i = 0; i < 4; i++) { f[i] = sel[b * CT + tid * 4 + i]; c += f[i]; }
    int lane = tid & 31, wid = tid >> 5;
    int incl = c;
#pragma unroll
    for (int o = 1; o < 32; o <<= 1) {
        int n = __shfl_up_sync(0xffffffffu, incl, o);
        if (lane >= o) incl += n;
    }
    __shared__ int wsum[32];
    if (lane == 31) wsum[wid] = incl;
    __syncthreads();
    if (wid == 0) {
        int w = wsum[lane];
#pragma unroll
        for (int o = 1; o < 32; o <<= 1) {
            int n = __shfl_up_sync(0xffffffffu, w, o);
            if (lane >= o) w += n;
        }
        wsum[lane] = w;
    }
    __syncthreads();
    int pos = (wid ? wsum[wid - 1] : 0) + incl - c;
#pragma unroll
    for (int i = 0; i < 4; i++) {
        if (f[i]) {
            int t = tid * 4 + i;
            idx_out[b * CK + pos] = t;
            float lg = logits[b * CT + t];
            gate_out[b * CK + pos] = 1.f / (1.f + expf(-lg));
            pos++;
        }
    }
}

// ---------------- gather ----------------------------------------------------
__global__ void gather_kernel(const float* __restrict__ x, const int* __restrict__ idx,
                              float* __restrict__ h) {
    int bk = blockIdx.x;
    int b = bk >> 11;
    int t = idx[bk];
    const float4* src = (const float4*)(x + ((size_t)b * CT + t) * CD);
    float4* dst = (float4*)(h + (size_t)bk * CD);
    dst[threadIdx.x] = src[threadIdx.x];
}

// ---------------- layernorm (fp32 in -> fp16 out) ---------------------------
__global__ void layernorm_kernel(const float* __restrict__ in, __half* __restrict__ out,
                                 const float* __restrict__ scale,
                                 const float* __restrict__ bias) {
    int row = blockIdx.x;
    int tid = threadIdx.x;
    const float4* p = (const float4*)(in + (size_t)row * CD);
    float4 v = p[tid];
    float s = v.x + v.y + v.z + v.w;
    float ss = v.x * v.x + v.y * v.y + v.z * v.z + v.w * v.w;
#pragma unroll
    for (int o = 16; o > 0; o >>= 1) {
        s += __shfl_down_sync(0xffffffffu, s, o);
        ss += __shfl_down_sync(0xffffffffu, ss, o);
    }
    __shared__ float red[64];
    int lane = tid & 31, wid = tid >> 5;
    if (lane == 0) { red[wid] = s; red[32 + wid] = ss; }
    __syncthreads();
    if (tid == 0) {
        float S = 0, SS = 0;
#pragma unroll
        for (int w = 0; w < 8; w++) { S += red[w]; SS += red[32 + w]; }
        red[0] = S; red[32] = SS;
    }
    __syncthreads();
    float mean = red[0] * (1.f / CD);
    float var = red[32] * (1.f / CD) - mean * mean;
    float inv = rsqrtf(var + 1e-5f);
    float4 sc = ((const float4*)scale)[tid];
    float4 bi = ((const float4*)bias)[tid];
    __half2 h0 = __floats2half2_rn((v.x - mean) * inv * sc.x + bi.x,
                                   (v.y - mean) * inv * sc.y + bi.y);
    __half2 h1 = __floats2half2_rn((v.z - mean) * inv * sc.z + bi.z,
                                   (v.w - mean) * inv * sc.w + bi.w);
    __half2* o2 = (__half2*)(out + (size_t)row * CD);
    o2[2 * tid] = h0;
    o2[2 * tid + 1] = h1;
}

// ---------------- weight fp16 convert ---------------------------------------
__global__ void cvtw_kernel(const float* __restrict__ src, __half* __restrict__ dst,
                            int n4) {
    int i = blockIdx.x * blockDim.x + threadIdx.x;
    if (i >= n4) return;
    float4 v = ((const float4*)src)[i];
    __half2* d2 = (__half2*)dst;
    d2[2 * i]     = __floats2half2_rn(v.x, v.y);
    d2[2 * i + 1] = __floats2half2_rn(v.z, v.w);
}

// ---------------- common GEMM bits -------------------------------------------
__device__ __forceinline__ float gelu_tanh(float x) {
    float x3 = x * x * x;
    float t = tanhf(0.7978845608028654f * (x + 0.044715f * x3));
    return 0.5f * x * (1.f + t);
}

// ============ narrow GEMM: 128x128x64, fp32 out + residual (Wo, FFN2) =======
constexpr int GBM = 128, GBN = 128, GBK = 64;
constexpr int AST = GBK + 8;     // 72 halfs/row
constexpr int BST = GBN + 8;     // 136 halfs/row
constexpr int ABUFH = GBM * AST; // 9216 halfs
constexpr int BBUFH = GBK * BST; // 8704 halfs
constexpr size_t TGEMM_SMEM = (size_t)(ABUFH + BBUFH) * 2 * sizeof(__half); // 71680 B

__global__ __launch_bounds__(256) void tgemm_kernel(
    const __half* __restrict__ A, const __half* __restrict__ W,
    const float* __restrict__ bias, const float* __restrict__ R,
    float* __restrict__ C, int M, int N, int Kd) {
    extern __shared__ __half dsm[];
    __half* As = dsm;
    __half* Bs = dsm + 2 * ABUFH;

    const int tid = threadIdx.x;
    const int bx = blockIdx.x, by = blockIdx.y;
    const int wid = tid >> 5, lane = tid & 31;
    const int warp_m = wid & 1;
    const int warp_n = wid >> 1;
    const int g = lane >> 2;
    const int tg = lane & 3;
    const int lm = (lane & 7) + ((lane >> 3) & 1) * 8;
    const int lk = ((lane >> 4) & 1) * 8;
    const int lkb = (lane & 7) + ((lane >> 3) & 1) * 8;

    float c[4][4][4];
#pragma unroll
    for (int mi = 0; mi < 4; mi++)
#pragma unroll
        for (int ni = 0; ni < 4; ni++)
#pragma unroll
            for (int r = 0; r < 4; r++) c[mi][ni][r] = 0.f;

    const int ntiles = Kd / GBK;

    auto issue_tile = [&](int t, int buf) {
        int k0 = t * GBK;
        uint32_t abase = (uint32_t)__cvta_generic_to_shared(As + buf * ABUFH);
        uint32_t bbase = (uint32_t)__cvta_generic_to_shared(Bs + buf * BBUFH);
#pragma unroll
        for (int i = 0; i < 4; i++) {
            int q = tid + i * 256;
            int row = q >> 3, c8 = (q & 7) * 8;
            cp16(abase + (row * AST + c8) * 2, A + (size_t)(by * GBM + row) * Kd + k0 + c8);
        }
#pragma unroll
        for (int i = 0; i < 4; i++) {
            int q = tid + i * 256;
            int row = q >> 4, n8 = (q & 15) * 8;
            cp16(bbase + (row * BST + n8) * 2, W + (size_t)(k0 + row) * N + bx * GBN + n8);
        }
        asm volatile("cp.async.commit_group;\n");
    };

    issue_tile(0, 0);
    for (int t = 0; t < ntiles; t++) {
        if (t + 1 < ntiles) {
            issue_tile(t + 1, (t + 1) & 1);
            asm volatile("cp.async.wait_group 1;\n");
        } else {
            asm volatile("cp.async.wait_group 0;\n");
        }
        __syncthreads();
        uint32_t Ab = (uint32_t)__cvta_generic_to_shared(As + (t & 1) * ABUFH);
        uint32_t Bb = (uint32_t)__cvta_generic_to_shared(Bs + (t & 1) * BBUFH);
        uint32_t a_off = Ab + ((warp_m * 64 + lm) * AST + lk) * 2;
        uint32_t b_off = Bb + (lkb * BST + warp_n * 32) * 2;
#pragma unroll
        for (int ks = 0; ks < GBK / 16; ks++) {
            uint32_t a[4][4], b[4][2];
#pragma unroll
            for (int mi = 0; mi < 4; mi++)
                ldsm_x4(a[mi], a_off + (mi * 16 * AST + ks * 16) * 2);
#pragma unroll
            for (int ni = 0; ni < 4; ni++)
                ldsm_x2t(b[ni][0], b[ni][1], b_off + (ks * 16 * BST + ni * 8) * 2);
#pragma unroll
            for (int mi = 0; mi < 4; mi++)
#pragma unroll
                for (int ni = 0; ni < 4; ni++)
                    mma_f16(c[mi][ni], a[mi], b[ni][0], b[ni][1]);
        }
        __syncthreads();
    }

#pragma unroll
    for (int mi = 0; mi < 4; mi++) {
        int m0 = by * GBM + warp_m * 64 + mi * 16 + g;
#pragma unroll
        for (int ni = 0; ni < 4; ni++) {
            int n0 = bx * GBN + warp_n * 32 + ni * 8 + 2 * tg;
            float b0 = bias[n0], b1 = bias[n0 + 1];
#pragma unroll
            for (int half = 0; half < 2; half++) {
                int m = m0 + half * 8;
                float v0 = c[mi][ni][half * 2 + 0] + b0;
                float v1 = c[mi][ni][half * 2 + 1] + b1;
                const float2 r2 = *(const float2*)(R + (size_t)m * N + n0);
                v0 += r2.x; v1 += r2.y;
                *(float2*)(C + (size_t)m * N + n0) = make_float2(v0, v1);
            }
        }
    }
}

// ============ wide GEMM: 128x256x64, fp16 out, opt GELU (QKV, FFN1) =========
constexpr int WBN = 256;
constexpr int BSTW = WBN + 8;      // 264 halfs/row
constexpr int BBUFW = GBK * BSTW;  // 16896 halfs
constexpr size_t TGEMW_SMEM = (size_t)(ABUFH + BBUFW) * 2 * sizeof(__half); // 104448 B

template <bool GELU>
__global__ __launch_bounds__(256) void tgemm_wide(
    const __half* __restrict__ A, const __half* __restrict__ W,
    const float* __restrict__ bias, __half* __restrict__ C,
    int M, int N, int Kd) {
    extern __shared__ __half dsm[];
    __half* As = dsm;
    __half* Bs = dsm + 2 * ABUFH;

    const int tid = threadIdx.x;
    const int bx = blockIdx.x, by = blockIdx.y;
    const int wid = tid >> 5, lane = tid & 31;
    const int warp_m = wid & 1;        // 2 in M
    const int warp_n = wid >> 1;       // 4 in N (64 cols each)
    const int g = lane >> 2;
    const int tg = lane & 3;
    const int lm = (lane & 7) + ((lane >> 3) & 1) * 8;
    const int lk = ((lane >> 4) & 1) * 8;
    const int lkb = (lane & 7) + ((lane >> 3) & 1) * 8;

    float c[4][8][4];
#pragma unroll
    for (int mi = 0; mi < 4; mi++)
#pragma unroll
        for (int ni = 0; ni < 8; ni++)
#pragma unroll
            for (int r = 0; r < 4; r++) c[mi][ni][r] = 0.f;

    const int ntiles = Kd / GBK;

    auto issue_tile = [&](int t, int buf) {
        int k0 = t * GBK;
        uint32_t abase = (uint32_t)__cvta_generic_to_shared(As + buf * ABUFH);
        uint32_t bbase = (uint32_t)__cvta_generic_to_shared(Bs + buf * BBUFW);
#pragma unroll
        for (int i = 0; i < 4; i++) {
            int q = tid + i * 256;
            int row = q >> 3, c8 = (q & 7) * 8;
            cp16(abase + (row * AST + c8) * 2, A + (size_t)(by * GBM + row) * Kd + k0 + c8);
        }
#pragma unroll
        for (int i = 0; i < 8; i++) {
            int q = tid + i * 256;
            int row = q >> 5, n8 = (q & 31) * 8;
            cp16(bbase + (row * BSTW + n8) * 2, W + (size_t)(k0 + row) * N + bx * WBN + n8);
        }
        asm volatile("cp.async.commit_group;\n");
    };

    issue_tile(0, 0);
    for (int t = 0; t < ntiles; t++) {
        if (t + 1 < ntiles) {
            issue_tile(t + 1, (t + 1) & 1);
            asm volatile("cp.async.wait_group 1;\n");
        } else {
            asm volatile("cp.async.wait_group 0;\n");
        }
        __syncthreads();
        uint32_t Ab = (uint32_t)__cvta_generic_to_shared(As + (t & 1) * ABUFH);
        uint32_t Bb = (uint32_t)__cvta_generic_to_shared(Bs + (t & 1) * BBUFW);
        uint32_t a_off = Ab + ((warp_m * 64 + lm) * AST + lk) * 2;
        uint32_t b_off = Bb + (lkb * BSTW + warp_n * 64) * 2;
#pragma unroll
        for (int ks = 0; ks < GBK / 16; ks++) {
            uint32_t a[4][4], b[8][2];
#pragma unroll
            for (int mi = 0; mi < 4; mi++)
                ldsm_x4(a[mi], a_off + (mi * 16 * AST + ks * 16) * 2);
#pragma unroll
            for (int ni = 0; ni < 8; ni++)
                ldsm_x2t(b[ni][0], b[ni][1], b_off + (ks * 16 * BSTW + ni * 8) * 2);
#pragma unroll
            for (int mi = 0; mi < 4; mi++)
#pragma unroll
                for (int ni = 0; ni < 8; ni++)
                    mma_f16(c[mi][ni], a[mi], b[ni][0], b[ni][1]);
        }
        __syncthreads();
    }

#pragma unroll
    for (int mi = 0; mi < 4; mi++) {
        int m0 = by * GBM + warp_m * 64 + mi * 16 + g;
#pragma unroll
        for (int ni = 0; ni < 8; ni++) {
            int n0 = bx * WBN + warp_n * 64 + ni * 8 + 2 * tg;
            float b0 = bias[n0], b1 = bias[n0 + 1];
#pragma unroll
            for (int half = 0; half < 2; half++) {
                int m = m0 + half * 8;
                float v0 = c[mi][ni][half * 2 + 0] + b0;
                float v1 = c[mi][ni][half * 2 + 1] + b1;
                if (GELU) { v0 = gelu_tanh(v0); v1 = gelu_tanh(v1); }
                *(__half2*)(C + (size_t)m * N + n0) = __floats2half2_rn(v0, v1);
            }
        }
    }
}

// ---------------- FP16 MMA flash attention -----------------------------------
constexpr int SATT = 72;
__global__ __launch_bounds__(128) void attn_kernel(const __half* __restrict__ qkv,
                                                   __half* __restrict__ o) {
    const int qt = blockIdx.x, h = blockIdx.y, b = blockIdx.z;
    const int tid = threadIdx.x;
    const int w = tid >> 5, lane = tid & 31;
    const int g = lane >> 2, tg = lane & 3;
    const int lm = (lane & 7) + ((lane >> 3) & 1) * 8;
    const int lk = ((lane >> 4) & 1) * 8;
    const int lkb = (lane & 7) + ((lane >> 3) & 1) * 8;

    __shared__ __half Qs[64 * SATT];
    __shared__ __half Ks[64 * SATT];
    __shared__ __half Vs[64 * SATT];
    uint32_t qsb = (uint32_t)__cvta_generic_to_shared(Qs);
    uint32_t ksb = (uint32_t)__cvta_generic_to_shared(Ks);
    uint32_t vsb = (uint32_t)__cvta_generic_to_shared(Vs);

    const __half2 sc8 = __float2half2_rn(0.125f);
#pragma unroll
    for (int i = 0; i < 4; i++) {
        int q = tid + i * 128;
        int r = q >> 3, c8 = (q & 7) * 8;
        const __half* src = qkv + ((size_t)(b * CK + qt * 64 + r)) * (3 * CD) + h * 64 + c8;
        uint4 u = *(const uint4*)src;
        __half2* hp = (__half2*)&u;
#pragma unroll
        for (int j = 0; j < 4; j++) hp[j] = __hmul2(hp[j], sc8);
        *(uint4*)&Qs[r * SATT + c8] = u;
    }
    __syncthreads();
    uint32_t qf[4][4];
#pragma unroll
    for (int ks = 0; ks < 4; ks++)
        ldsm_x4(qf[ks], qsb + ((w * 16 + lm) * SATT + ks * 16 + lk) * 2);

    float of[8][4];
#pragma unroll
    for (int ni = 0; ni < 8; ni++)
#pragma unroll
        for (int r = 0; r < 4; r++) of[ni][r] = 0.f;
    float mi0 = -1e30f, mi1 = -1e30f, li0 = 0.f, li1 = 0.f;

    for (int kt = 0; kt <= qt; kt++) {
        __syncthreads();
#pragma unroll
        for (int i = 0; i < 4; i++) {
            int q = tid + i * 128;
            int r = q >> 3, c8 = (q & 7) * 8;
            const __half* kb = qkv + ((size_t)(b * CK + kt * 64 + r)) * (3 * CD) + CD + h * 64 + c8;
            *(uint4*)&Ks[r * SATT + c8] = *(const uint4*)kb;
            *(uint4*)&Vs[r * SATT + c8] = *(const uint4*)(kb + CD);
        }
        __syncthreads();

        float sf[8][4];
#pragma unroll
        for (int ni = 0; ni < 8; ni++)
#pragma unroll
            for (int r = 0; r < 4; r++) sf[ni][r] = 0.f;
#pragma unroll
        for (int ks = 0; ks < 4; ks++) {
#pragma unroll
            for (int ni = 0; ni < 8; ni++) {
                uint32_t b0, b1;
                ldsm_x2(b0, b1,
                        ksb + ((ni * 8 + (lane & 7)) * SATT + ks * 16 + ((lane >> 3) & 1) * 8) * 2);
                mma_f16(sf[ni], qf[ks], b0, b1);
            }
        }

        if (kt == qt) {
            int row0 = w * 16 + g, row1 = row0 + 8;
#pragma unroll
            for (int ni = 0; ni < 8; ni++) {
                int c0 = ni * 8 + 2 * tg, c1 = c0 + 1;
                if (c0 > row0) sf[ni][0] = -1e30f;
                if (c1 > row0) sf[ni][1] = -1e30f;
                if (c0 > row1) sf[ni][2] = -1e30f;
                if (c1 > row1) sf[ni][3] = -1e30f;
            }
        }

        float m0 = -1e30f, m1 = -1e30f;
#pragma unroll
        for (int ni = 0; ni < 8; ni++) {
            m0 = fmaxf(m0, fmaxf(sf[ni][0], sf[ni][1]));
            m1 = fmaxf(m1, fmaxf(sf[ni][2], sf[ni][3]));
        }
        m0 = fmaxf(m0, __shfl_xor_sync(0xffffffffu, m0, 1));
        m0 = fmaxf(m0, __shfl_xor_sync(0xffffffffu, m0, 2));
        m1 = fmaxf(m1, __shfl_xor_sync(0xffffffffu, m1, 1));
        m1 = fmaxf(m1, __shfl_xor_sync(0xffffffffu, m1, 2));
        float nm0 = fmaxf(mi0, m0), nm1 = fmaxf(mi1, m1);
        float co0 = __expf(mi0 - nm0), co1 = __expf(mi1 - nm1);
        float rs0 = 0.f, rs1 = 0.f;
#pragma unroll
        for (int ni = 0; ni < 8; ni++) {
            sf[ni][0] = __expf(sf[ni][0] - nm0);
            sf[ni][1] = __expf(sf[ni][1] - nm0);
            sf[ni][2] = __expf(sf[ni][2] - nm1);
            sf[ni][3] = __expf(sf[ni][3] - nm1);
            rs0 += sf[ni][0] + sf[ni][1];
            rs1 += sf[ni][2] + sf[ni][3];
        }
        rs0 += __shfl_xor_sync(0xffffffffu, rs0, 1);
        rs0 += __shfl_xor_sync(0xffffffffu, rs0, 2);
        rs1 += __shfl_xor_sync(0xffffffffu, rs1, 1);
        rs1 += __shfl_xor_sync(0xffffffffu, rs1, 2);
        li0 = li0 * co0 + rs0;
        li1 = li1 * co1 + rs1;
        mi0 = nm0; mi1 = nm1;
#pragma unroll
        for (int ni = 0; ni < 8; ni++) {
            of[ni][0] *= co0; of[ni][1] *= co0;
            of[ni][2] *= co1; of[ni][3] *= co1;
        }

        {
            int pr = w * 16 + g;
#pragma unroll
            for (int ni = 0; ni < 8; ni++) {
                *(__half2*)&Qs[pr * SATT + ni * 8 + 2 * tg] =
                    __floats2half2_rn(sf[ni][0], sf[ni][1]);
                *(__half2*)&Qs[(pr + 8) * SATT + ni * 8 + 2 * tg] =
                    __floats2half2_rn(sf[ni][2], sf[ni][3]);
            }
        }
        __syncwarp();

#pragma unroll
        for (int js = 0; js < 4; js++) {
            uint32_t a[4];
            ldsm_x4(a, qsb + ((w * 16 + lm) * SATT + js * 16 + lk) * 2);
#pragma unroll
            for (int ni = 0; ni < 8; ni++) {
                uint32_t b0, b1;
                ldsm_x2t(b0, b1, vsb + ((js * 16 + lkb) * SATT + ni * 8) * 2);
                mma_f16(of[ni], a, b0, b1);
            }
        }
    }

    float il0 = 1.f / li0, il1 = 1.f / li1;
    int m0g = qt * 64 + w * 16 + g, m1g = m0g + 8;
#pragma unroll
    for (int ni = 0; ni < 8; ni++) {
        int col = h * 64 + ni * 8 + 2 * tg;
        *(__half2*)(o + ((size_t)(b * CK + m0g)) * CD + col) =
            __floats2half2_rn(of[ni][0] * il0, of[ni][1] * il0);
        *(__half2*)(o + ((size_t)(b * CK + m1g)) * CD + col) =
            __floats2half2_rn(of[ni][2] * il1, of[ni][3] * il1);
    }
}

// ---------------- output assembly -------------------------------------------
__global__ void copyx_kernel(const float* __restrict__ x, float* __restrict__ out) {
    size_t i = (size_t)blockIdx.x * blockDim.x + threadIdx.x;
    ((float4*)out)[i] = ((const float4*)x)[i];
}

__global__ void scatter_kernel(const float* __restrict__ h, const int* __restrict__ idx,
                               const float* __restrict__ gate, float* __restrict__ out) {
    int bk = blockIdx.x;
    int b = bk >> 11;
    int t = idx[bk];
    float g = gate[bk];
    float4* dst = (float4*)(out + ((size_t)b * CT + t) * CD);
    const float4* src = (const float4*)(h + (size_t)bk * CD);
    float4 s = src[threadIdx.x];
    float4 d0 = dst[threadIdx.x];
    d0.x += s.x * g; d0.y += s.y * g; d0.z += s.z * g; d0.w += s.w * g;
    dst[threadIdx.x] = d0;
}

__global__ void tail_kernel(const int* __restrict__ idx, const float* __restrict__ logits,
                            float* __restrict__ out) {
    int i = blockIdx.x * blockDim.x + threadIdx.x;
    if (i < CB * CK) {
        out[BTD + i] = (float)idx[i];
    } else if (i < CB * CK + CB * CT) {
        int j = i - CB * CK;
        out[BTD + CB * CK + j] = logits[j];
    }
}

// ---------------- launch -----------------------------------------------------
extern "C" void kernel_launch(void* const* d_in, const int* in_sizes, int n_in,
                              void* d_out, int out_size) {
    const float* x         = (const float*)d_in[0];
    const float* w_router  = (const float*)d_in[1];
    const float* b_router  = (const float*)d_in[2];
    const float* ln1_scale = (const float*)d_in[3];
    const float* ln1_bias  = (const float*)d_in[4];
    const float* w_qkv     = (const float*)d_in[5];
    const float* b_qkv     = (const float*)d_in[6];
    const float* w_o       = (const float*)d_in[7];
    const float* b_o       = (const float*)d_in[8];
    const float* ln2_scale = (const float*)d_in[9];
    const float* ln2_bias  = (const float*)d_in[10];
    const float* w1        = (const float*)d_in[11];
    const float* b1        = (const float*)d_in[12];
    const float* w2        = (const float*)d_in[13];
    const float* b2        = (const float*)d_in[14];
    float* out = (float*)d_out;

    float *logits, *gate, *h;
    int *sel, *idxp;
    __half *lnh, *qkvh, *attnh, *midh, *wth;
    cudaGetSymbolAddress((void**)&logits, g_logits);
    cudaGetSymbolAddress((void**)&sel, g_sel);
    cudaGetSymbolAddress((void**)&idxp, g_idx);
    cudaGetSymbolAddress((void**)&gate, g_gate);
    cudaGetSymbolAddress((void**)&h, g_h);
    cudaGetSymbolAddress((void**)&lnh, g_lnh);
    cudaGetSymbolAddress((void**)&qkvh, g_qkvh);
    cudaGetSymbolAddress((void**)&attnh, g_attnh);
    cudaGetSymbolAddress((void**)&midh, g_midh);
    cudaGetSymbolAddress((void**)&wth, g_wth);

    cudaFuncSetAttribute(tgemm_kernel,
                         cudaFuncAttributeMaxDynamicSharedMemorySize, (int)TGEMM_SMEM);
    cudaFuncSetAttribute(tgemm_wide<false>,
                         cudaFuncAttributeMaxDynamicSharedMemorySize, (int)TGEMW_SMEM);
    cudaFuncSetAttribute(tgemm_wide<true>,
                         cudaFuncAttributeMaxDynamicSharedMemorySize, (int)TGEMW_SMEM);

    // 0. pre-convert weights to fp16
    cvtw_kernel<<<(int)(WQKV_SZ / 4 / 256), 256>>>(w_qkv, wth + WQKV_OFF, (int)(WQKV_SZ / 4));
    cvtw_kernel<<<(int)(WO_SZ / 4 / 256), 256>>>(w_o,   wth + WO_OFF,   (int)(WO_SZ / 4));
    cvtw_kernel<<<(int)(W1_SZ / 4 / 256), 256>>>(w1,    wth + W1_OFF,   (int)(W1_SZ / 4));
    cvtw_kernel<<<(int)(W2_SZ / 4 / 256), 256>>>(w2,    wth + W2_OFF,   (int)(W2_SZ / 4));

    // 1. router
    router_kernel<<<(CB * CT) / 8, 256>>>(x, w_router, b_router, logits);
    // 2. expert-choice top-K
    rank_kernel<<<CB * 64, 256>>>(logits, sel);
    compact_kernel<<<CB, 1024>>>(logits, sel, idxp, gate);
    // 3. gather
    gather_kernel<<<BK_ROWS, 256>>>(x, idxp, h);

    // 4. transformer blocks
    for (int l = 0; l < CL; l++) {
        layernorm_kernel<<<BK_ROWS, 256>>>(h, lnh, ln1_scale + l * CD, ln1_bias + l * CD);
        tgemm_wide<false><<<dim3(3 * CD / WBN, BK_ROWS / GBM), 256, TGEMW_SMEM>>>(
            lnh, wth + WQKV_OFF + (size_t)l * CD * 3 * CD, b_qkv + l * 3 * CD,
            qkvh, BK_ROWS, 3 * CD, CD);
        attn_kernel<<<dim3(CK / 64, CH, CB), 128>>>(qkvh, attnh);
        tgemm_kernel<<<dim3(CD / GBN, BK_ROWS / GBM), 256, TGEMM_SMEM>>>(
            attnh, wth + WO_OFF + (size_t)l * CD * CD, b_o + l * CD, h, h,
            BK_ROWS, CD, CD);
        layernorm_kernel<<<BK_ROWS, 256>>>(h, lnh, ln2_scale + l * CD, ln2_bias + l * CD);
        tgemm_wide<true><<<dim3(CF / WBN, BK_ROWS / GBM), 256, TGEMW_SMEM>>>(
            lnh, wth + W1_OFF + (size_t)l * CD * CF, b1 + l * CF,
            midh, BK_ROWS, CF, CD);
        tgemm_kernel<<<dim3(CD / GBN, BK_ROWS / GBM), 256, TGEMM_SMEM>>>(
            midh, wth + W2_OFF + (size_t)l * CF * CD, b2 + l * CD, h, h,
            BK_ROWS, CD, CF);
    }

    // 5. assemble output: total, idx, logits
    copyx_kernel<<<(int)(BTD / 4 / 256), 256>>>(x, out);
    scatter_kernel<<<BK_ROWS, 256>>>(h, idxp, gate, out);
    if ((size_t)out_size >= BTD + CB * CK + CB * CT) {
        int ntail = CB * CK + CB * CT;
        tail_kernel<<<(ntail + 255) / 256, 256>>>(idxp, logits, out);
    }
}

// round 8
// speedup vs baseline: 6.6369x; 1.0096x over previous
#include <cuda_runtime.h>
#include <cuda_fp16.h>
#include <math.h>
#include <stdint.h>

// Problem constants
constexpr int CB = 2;      // batch
constexpr int CT = 4096;   // seq len
constexpr int CD = 1024;   // d_model
constexpr int CL = 2;      // layers
constexpr int CH = 16;     // heads
constexpr int CF = 4096;   // d_ff
constexpr int CK = 2048;   // top-k tokens
constexpr int BK_ROWS = CB * CK;
constexpr size_t BTD = (size_t)CB * CT * CD;

// Weight fp16 scratch offsets (elements)
constexpr size_t WQKV_OFF = 0;
constexpr size_t WQKV_SZ  = (size_t)CL * CD * 3 * CD;
constexpr size_t WO_OFF   = WQKV_OFF + WQKV_SZ;
constexpr size_t WO_SZ    = (size_t)CL * CD * CD;
constexpr size_t W1_OFF   = WO_OFF + WO_SZ;
constexpr size_t W1_SZ    = (size_t)CL * CD * CF;
constexpr size_t W2_OFF   = W1_OFF + W1_SZ;
constexpr size_t W2_SZ    = (size_t)CL * CF * CD;
constexpr size_t WTF_TOTAL = W2_OFF + W2_SZ;

// ---------------- scratch (static device globals) ---------------------------
__device__ float  g_logits[CB * CT];
__device__ int    g_sel[CB * CT];
__device__ int    g_idx[CB * CK];
__device__ int    g_inv[CB * CT];
__device__ float  g_gate[CB * CK];
__device__ float  g_h[BK_ROWS * CD];
__device__ __half g_lnh[BK_ROWS * CD];
__device__ __half g_qkvh[(size_t)BK_ROWS * 3 * CD];
__device__ __half g_attnh[BK_ROWS * CD];
__device__ __half g_midh[(size_t)BK_ROWS * CF];
__device__ __half g_wth[WTF_TOTAL];

__device__ __forceinline__ void mma_f16(float c[4], const uint32_t a[4],
                                        uint32_t b0, uint32_t b1) {
    asm volatile(
        "mma.sync.aligned.m16n8k16.row.col.f32.f16.f16.f32 "
        "{%0,%1,%2,%3}, {%4,%5,%6,%7}, {%8,%9}, {%0,%1,%2,%3};\n"
        : "+f"(c[0]), "+f"(c[1]), "+f"(c[2]), "+f"(c[3])
        : "r"(a[0]), "r"(a[1]), "r"(a[2]), "r"(a[3]), "r"(b0), "r"(b1));
}
__device__ __forceinline__ void ldsm_x4(uint32_t r[4], uint32_t saddr) {
    asm volatile("ldmatrix.sync.aligned.m8n8.x4.shared.b16 {%0,%1,%2,%3}, [%4];"
                 : "=r"(r[0]), "=r"(r[1]), "=r"(r[2]), "=r"(r[3]) : "r"(saddr));
}
__device__ __forceinline__ void ldsm_x2(uint32_t& r0, uint32_t& r1, uint32_t saddr) {
    asm volatile("ldmatrix.sync.aligned.m8n8.x2.shared.b16 {%0,%1}, [%2];"
                 : "=r"(r0), "=r"(r1) : "r"(saddr));
}
__device__ __forceinline__ void ldsm_x2t(uint32_t& r0, uint32_t& r1, uint32_t saddr) {
    asm volatile("ldmatrix.sync.aligned.m8n8.x2.trans.shared.b16 {%0,%1}, [%2];"
                 : "=r"(r0), "=r"(r1) : "r"(saddr));
}
__device__ __forceinline__ void cp16(uint32_t dst, const void* src) {
    asm volatile("cp.async.cg.shared.global [%0], [%1], 16;\n" :: "r"(dst), "l"(src));
}
__device__ __forceinline__ uint32_t pack_h2(float a, float b) {
    __half2 h = __floats2half2_rn(a, b);
    return *(uint32_t*)&h;
}

// ---------------- router ----------------------------------------------------
__global__ void router_kernel(const float* __restrict__ x,
                              const float* __restrict__ wr,
                              const float* __restrict__ br,
                              float* __restrict__ logits) {
    int gw = (blockIdx.x * blockDim.x + threadIdx.x) >> 5;
    if (gw >= CB * CT) return;
    int lane = threadIdx.x & 31;
    const float4* p = (const float4*)(x + (size_t)gw * CD);
    const float4* w4 = (const float4*)wr;
    float s = 0.f;
#pragma unroll
    for (int i = 0; i < CD / 128; i++) {
        float4 a = p[lane + i * 32];
        float4 w = w4[lane + i * 32];
        s += a.x * w.x + a.y * w.y + a.z * w.z + a.w * w.w;
    }
#pragma unroll
    for (int o = 16; o > 0; o >>= 1) s += __shfl_down_sync(0xffffffffu, s, o);
    if (lane == 0) logits[gw] = s + br[0];
}

// ---------------- top-K -----------------------------------------------------
__global__ void rank_kernel(const float* __restrict__ logits, int* __restrict__ sel) {
    int blk = blockIdx.x;
    int b = blk >> 6;
    int base = (blk & 63) * 64;
    __shared__ float lv[CT];
    int tid = threadIdx.x;
    for (int t = tid; t < CT; t += 256) lv[t] = logits[b * CT + t];
    __syncthreads();
    int tt = tid >> 2, part = tid & 3;
    int t = base + tt;
    float v = lv[t];
    int cnt = 0;
    int s0 = part * 1024;
#pragma unroll 8
    for (int s = s0; s < s0 + 1024; s++) {
        float u = lv[s];
        cnt += (u > v) || (u == v && s < t);
    }
    __shared__ int rk[64];
    if (part == 0) rk[tt] = 0;
    __syncthreads();
    atomicAdd(&rk[tt], cnt);
    __syncthreads();
    if (part == 0) sel[b * CT + t] = (rk[tt] < CK) ? 1 : 0;
}

__global__ void compact_kernel(const float* __restrict__ logits,
                               const int* __restrict__ sel,
                               int* __restrict__ idx_out,
                               int* __restrict__ inv_out,
                               float* __restrict__ gate_out) {
    int b = blockIdx.x;
    int tid = threadIdx.x;
    int f[4]; int c = 0;
#pragma unroll
    for (int i = 0; i < 4; i++) { f[i] = sel[b * CT + tid * 4 + i]; c += f[i]; }
    int lane = tid & 31, wid = tid >> 5;
    int incl = c;
#pragma unroll
    for (int o = 1; o < 32; o <<= 1) {
        int n = __shfl_up_sync(0xffffffffu, incl, o);
        if (lane >= o) incl += n;
    }
    __shared__ int wsum[32];
    if (lane == 31) wsum[wid] = incl;
    __syncthreads();
    if (wid == 0) {
        int w = wsum[lane];
#pragma unroll
        for (int o = 1; o < 32; o <<= 1) {
            int n = __shfl_up_sync(0xffffffffu, w, o);
            if (lane >= o) w += n;
        }
        wsum[lane] = w;
    }
    __syncthreads();
    int pos = (wid ? wsum[wid - 1] : 0) + incl - c;
#pragma unroll
    for (int i = 0; i < 4; i++) {
        int t = tid * 4 + i;
        if (f[i]) {
            idx_out[b * CK + pos] = t;
            inv_out[b * CT + t] = pos;
            float lg = logits[b * CT + t];
            gate_out[b * CK + pos] = 1.f / (1.f + expf(-lg));
            pos++;
        } else {
            inv_out[b * CT + t] = -1;
        }
    }
}

// ---------------- gather ----------------------------------------------------
__global__ void gather_kernel(const float* __restrict__ x, const int* __restrict__ idx,
                              float* __restrict__ h) {
    int bk = blockIdx.x;
    int b = bk >> 11;
    int t = idx[bk];
    const float4* src = (const float4*)(x + ((size_t)b * CT + t) * CD);
    float4* dst = (float4*)(h + (size_t)bk * CD);
    dst[threadIdx.x] = src[threadIdx.x];
}

// ---------------- layernorm (fp32 in -> fp16 out) ---------------------------
__global__ void layernorm_kernel(const float* __restrict__ in, __half* __restrict__ out,
                                 const float* __restrict__ scale,
                                 const float* __restrict__ bias) {
    int row = blockIdx.x;
    int tid = threadIdx.x;
    const float4* p = (const float4*)(in + (size_t)row * CD);
    float4 v = p[tid];
    float s = v.x + v.y + v.z + v.w;
    float ss = v.x * v.x + v.y * v.y + v.z * v.z + v.w * v.w;
#pragma unroll
    for (int o = 16; o > 0; o >>= 1) {
        s += __shfl_down_sync(0xffffffffu, s, o);
        ss += __shfl_down_sync(0xffffffffu, ss, o);
    }
    __shared__ float red[64];
    int lane = tid & 31, wid = tid >> 5;
    if (lane == 0) { red[wid] = s; red[32 + wid] = ss; }
    __syncthreads();
    if (tid == 0) {
        float S = 0, SS = 0;
#pragma unroll
        for (int w = 0; w < 8; w++) { S += red[w]; SS += red[32 + w]; }
        red[0] = S; red[32] = SS;
    }
    __syncthreads();
    float mean = red[0] * (1.f / CD);
    float var = red[32] * (1.f / CD) - mean * mean;
    float inv = rsqrtf(var + 1e-5f);
    float4 sc = ((const float4*)scale)[tid];
    float4 bi = ((const float4*)bias)[tid];
    __half2 h0 = __floats2half2_rn((v.x - mean) * inv * sc.x + bi.x,
                                   (v.y - mean) * inv * sc.y + bi.y);
    __half2 h1 = __floats2half2_rn((v.z - mean) * inv * sc.z + bi.z,
                                   (v.w - mean) * inv * sc.w + bi.w);
    __half2* o2 = (__half2*)(out + (size_t)row * CD);
    o2[2 * tid] = h0;
    o2[2 * tid + 1] = h1;
}

// ---------------- weight fp16 convert ---------------------------------------
__global__ void cvtw_kernel(const float* __restrict__ src, __half* __restrict__ dst,
                            int n4) {
    int i = blockIdx.x * blockDim.x + threadIdx.x;
    if (i >= n4) return;
    float4 v = ((const float4*)src)[i];
    __half2* d2 = (__half2*)dst;
    d2[2 * i]     = __floats2half2_rn(v.x, v.y);
    d2[2 * i + 1] = __floats2half2_rn(v.z, v.w);
}

// ---------------- common GEMM bits -------------------------------------------
__device__ __forceinline__ float gelu_tanh(float x) {
    float x3 = x * x * x;
    float t = tanhf(0.7978845608028654f * (x + 0.044715f * x3));
    return 0.5f * x * (1.f + t);
}

// ============ narrow GEMM: 128x128x64, fp32 out + residual (Wo, FFN2) =======
constexpr int GBM = 128, GBN = 128, GBK = 64;
constexpr int AST = GBK + 8;     // 72 halfs/row
constexpr int BST = GBN + 8;     // 136 halfs/row
constexpr int ABUFH = GBM * AST; // 9216 halfs
constexpr int BBUFH = GBK * BST; // 8704 halfs
constexpr size_t TGEMM_SMEM = (size_t)(ABUFH + BBUFH) * 2 * sizeof(__half); // 71680 B

__global__ __launch_bounds__(256) void tgemm_kernel(
    const __half* __restrict__ A, const __half* __restrict__ W,
    const float* __restrict__ bias, const float* __restrict__ R,
    float* __restrict__ C, int M, int N, int Kd) {
    extern __shared__ __half dsm[];
    __half* As = dsm;
    __half* Bs = dsm + 2 * ABUFH;

    const int tid = threadIdx.x;
    const int bx = blockIdx.x, by = blockIdx.y;
    const int wid = tid >> 5, lane = tid & 31;
    const int warp_m = wid & 1;
    const int warp_n = wid >> 1;
    const int g = lane >> 2;
    const int tg = lane & 3;
    const int lm = (lane & 7) + ((lane >> 3) & 1) * 8;
    const int lk = ((lane >> 4) & 1) * 8;
    const int lkb = (lane & 7) + ((lane >> 3) & 1) * 8;

    float c[4][4][4];
#pragma unroll
    for (int mi = 0; mi < 4; mi++)
#pragma unroll
        for (int ni = 0; ni < 4; ni++)
#pragma unroll
            for (int r = 0; r < 4; r++) c[mi][ni][r] = 0.f;

    const int ntiles = Kd / GBK;

    auto issue_tile = [&](int t, int buf) {
        int k0 = t * GBK;
        uint32_t abase = (uint32_t)__cvta_generic_to_shared(As + buf * ABUFH);
        uint32_t bbase = (uint32_t)__cvta_generic_to_shared(Bs + buf * BBUFH);
#pragma unroll
        for (int i = 0; i < 4; i++) {
            int q = tid + i * 256;
            int row = q >> 3, c8 = (q & 7) * 8;
            cp16(abase + (row * AST + c8) * 2, A + (size_t)(by * GBM + row) * Kd + k0 + c8);
        }
#pragma unroll
        for (int i = 0; i < 4; i++) {
            int q = tid + i * 256;
            int row = q >> 4, n8 = (q & 15) * 8;
            cp16(bbase + (row * BST + n8) * 2, W + (size_t)(k0 + row) * N + bx * GBN + n8);
        }
        asm volatile("cp.async.commit_group;\n");
    };

    issue_tile(0, 0);
    for (int t = 0; t < ntiles; t++) {
        if (t + 1 < ntiles) {
            issue_tile(t + 1, (t + 1) & 1);
            asm volatile("cp.async.wait_group 1;\n");
        } else {
            asm volatile("cp.async.wait_group 0;\n");
        }
        __syncthreads();
        uint32_t Ab = (uint32_t)__cvta_generic_to_shared(As + (t & 1) * ABUFH);
        uint32_t Bb = (uint32_t)__cvta_generic_to_shared(Bs + (t & 1) * BBUFH);
        uint32_t a_off = Ab + ((warp_m * 64 + lm) * AST + lk) * 2;
        uint32_t b_off = Bb + (lkb * BST + warp_n * 32) * 2;
#pragma unroll
        for (int ks = 0; ks < GBK / 16; ks++) {
            uint32_t a[4][4], b[4][2];
#pragma unroll
            for (int mi = 0; mi < 4; mi++)
                ldsm_x4(a[mi], a_off + (mi * 16 * AST + ks * 16) * 2);
#pragma unroll
            for (int ni = 0; ni < 4; ni++)
                ldsm_x2t(b[ni][0], b[ni][1], b_off + (ks * 16 * BST + ni * 8) * 2);
#pragma unroll
            for (int mi = 0; mi < 4; mi++)
#pragma unroll
                for (int ni = 0; ni < 4; ni++)
                    mma_f16(c[mi][ni], a[mi], b[ni][0], b[ni][1]);
        }
        __syncthreads();
    }

#pragma unroll
    for (int mi = 0; mi < 4; mi++) {
        int m0 = by * GBM + warp_m * 64 + mi * 16 + g;
#pragma unroll
        for (int ni = 0; ni < 4; ni++) {
            int n0 = bx * GBN + warp_n * 32 + ni * 8 + 2 * tg;
            float b0 = bias[n0], b1 = bias[n0 + 1];
#pragma unroll
            for (int half = 0; half < 2; half++) {
                int m = m0 + half * 8;
                float v0 = c[mi][ni][half * 2 + 0] + b0;
                float v1 = c[mi][ni][half * 2 + 1] + b1;
                const float2 r2 = *(const float2*)(R + (size_t)m * N + n0);
                v0 += r2.x; v1 += r2.y;
                *(float2*)(C + (size_t)m * N + n0) = make_float2(v0, v1);
            }
        }
    }
}

// ============ wide GEMM: 128x256x64, fp16 out, opt GELU (QKV, FFN1) =========
constexpr int WBN = 256;
constexpr int BSTW = WBN + 8;      // 264 halfs/row
constexpr int BBUFW = GBK * BSTW;  // 16896 halfs
constexpr size_t TGEMW_SMEM = (size_t)(ABUFH + BBUFW) * 2 * sizeof(__half); // 104448 B

template <bool GELU>
__global__ __launch_bounds__(256) void tgemm_wide(
    const __half* __restrict__ A, const __half* __restrict__ W,
    const float* __restrict__ bias, __half* __restrict__ C,
    int M, int N, int Kd) {
    extern __shared__ __half dsm[];
    __half* As = dsm;
    __half* Bs = dsm + 2 * ABUFH;

    const int tid = threadIdx.x;
    const int bx = blockIdx.x, by = blockIdx.y;
    const int wid = tid >> 5, lane = tid & 31;
    const int warp_m = wid & 1;
    const int warp_n = wid >> 1;
    const int g = lane >> 2;
    const int tg = lane & 3;
    const int lm = (lane & 7) + ((lane >> 3) & 1) * 8;
    const int lk = ((lane >> 4) & 1) * 8;
    const int lkb = (lane & 7) + ((lane >> 3) & 1) * 8;

    float c[4][8][4];
#pragma unroll
    for (int mi = 0; mi < 4; mi++)
#pragma unroll
        for (int ni = 0; ni < 8; ni++)
#pragma unroll
            for (int r = 0; r < 4; r++) c[mi][ni][r] = 0.f;

    const int ntiles = Kd / GBK;

    auto issue_tile = [&](int t, int buf) {
        int k0 = t * GBK;
        uint32_t abase = (uint32_t)__cvta_generic_to_shared(As + buf * ABUFH);
        uint32_t bbase = (uint32_t)__cvta_generic_to_shared(Bs + buf * BBUFW);
#pragma unroll
        for (int i = 0; i < 4; i++) {
            int q = tid + i * 256;
            int row = q >> 3, c8 = (q & 7) * 8;
            cp16(abase + (row * AST + c8) * 2, A + (size_t)(by * GBM + row) * Kd + k0 + c8);
        }
#pragma unroll
        for (int i = 0; i < 8; i++) {
            int q = tid + i * 256;
            int row = q >> 5, n8 = (q & 31) * 8;
            cp16(bbase + (row * BSTW + n8) * 2, W + (size_t)(k0 + row) * N + bx * WBN + n8);
        }
        asm volatile("cp.async.commit_group;\n");
    };

    issue_tile(0, 0);
    for (int t = 0; t < ntiles; t++) {
        if (t + 1 < ntiles) {
            issue_tile(t + 1, (t + 1) & 1);
            asm volatile("cp.async.wait_group 1;\n");
        } else {
            asm volatile("cp.async.wait_group 0;\n");
        }
        __syncthreads();
        uint32_t Ab = (uint32_t)__cvta_generic_to_shared(As + (t & 1) * ABUFH);
        uint32_t Bb = (uint32_t)__cvta_generic_to_shared(Bs + (t & 1) * BBUFW);
        uint32_t a_off = Ab + ((warp_m * 64 + lm) * AST + lk) * 2;
        uint32_t b_off = Bb + (lkb * BSTW + warp_n * 64) * 2;
#pragma unroll
        for (int ks = 0; ks < GBK / 16; ks++) {
            uint32_t a[4][4], b[8][2];
#pragma unroll
            for (int mi = 0; mi < 4; mi++)
                ldsm_x4(a[mi], a_off + (mi * 16 * AST + ks * 16) * 2);
#pragma unroll
            for (int ni = 0; ni < 8; ni++)
                ldsm_x2t(b[ni][0], b[ni][1], b_off + (ks * 16 * BSTW + ni * 8) * 2);
#pragma unroll
            for (int mi = 0; mi < 4; mi++)
#pragma unroll
                for (int ni = 0; ni < 8; ni++)
                    mma_f16(c[mi][ni], a[mi], b[ni][0], b[ni][1]);
        }
        __syncthreads();
    }

#pragma unroll
    for (int mi = 0; mi < 4; mi++) {
        int m0 = by * GBM + warp_m * 64 + mi * 16 + g;
#pragma unroll
        for (int ni = 0; ni < 8; ni++) {
            int n0 = bx * WBN + warp_n * 64 + ni * 8 + 2 * tg;
            float b0 = bias[n0], b1 = bias[n0 + 1];
#pragma unroll
            for (int half = 0; half < 2; half++) {
                int m = m0 + half * 8;
                float v0 = c[mi][ni][half * 2 + 0] + b0;
                float v1 = c[mi][ni][half * 2 + 1] + b1;
                if (GELU) { v0 = gelu_tanh(v0); v1 = gelu_tanh(v1); }
                *(__half2*)(C + (size_t)m * N + n0) = __floats2half2_rn(v0, v1);
            }
        }
    }
}

// ---------------- FP16 MMA flash attention v2 --------------------------------
// 256 threads (8 warps), Q tile 128 rows. K/V tiles 64 rows, cp.async
// double-buffered. P stays in registers (accumulator->A-fragment identity).
constexpr int SATT = 72;
__global__ __launch_bounds__(256) void attn_kernel(const __half* __restrict__ qkv,
                                                   __half* __restrict__ o) {
    const int qb = blockIdx.x, h = blockIdx.y, b = blockIdx.z;
    const int tid = threadIdx.x;
    const int w = tid >> 5, lane = tid & 31;
    const int g = lane >> 2, tg = lane & 3;
    const int lm = (lane & 7) + ((lane >> 3) & 1) * 8;
    const int lk = ((lane >> 4) & 1) * 8;
    const int lkb = (lane & 7) + ((lane >> 3) & 1) * 8;

    __shared__ __half KV[4][64 * SATT];   // K0, K1, V0, V1; Q staged over K0+K1
    uint32_t base[4];
#pragma unroll
    for (int i = 0; i < 4; i++) base[i] = (uint32_t)__cvta_generic_to_shared(KV[i]);

    // ---- stage Q (128 rows x 64, scaled by 1/8) over KV[0..1], extract frags
    const __half2 sc8 = __float2half2_rn(0.125f);
#pragma unroll
    for (int i = 0; i < 4; i++) {
        int q = tid + i * 256;
        int r = q >> 3, c8 = (q & 7) * 8;
        const __half* src = qkv + ((size_t)(b * CK + qb * 128 + r)) * (3 * CD) + h * 64 + c8;
        uint4 u = *(const uint4*)src;
        __half2* hp = (__half2*)&u;
#pragma unroll
        for (int j = 0; j < 4; j++) hp[j] = __hmul2(hp[j], sc8);
        *(uint4*)&KV[0][r * SATT + c8] = u;
    }
    __syncthreads();
    uint32_t qf[4][4];
#pragma unroll
    for (int ks = 0; ks < 4; ks++)
        ldsm_x4(qf[ks], base[0] + ((w * 16 + lm) * SATT + ks * 16 + lk) * 2);
    __syncthreads();   // Q frags extracted; smem reusable for K/V

    float of[8][4];
#pragma unroll
    for (int ni = 0; ni < 8; ni++)
#pragma unroll
        for (int r = 0; r < 4; r++) of[ni][r] = 0.f;
    float mi0 = -1e30f, mi1 = -1e30f, li0 = 0.f, li1 = 0.f;

    const int nt = 2 * qb + 2;
    const int rowg0 = qb * 128 + w * 16 + g;   // this thread's first global row
    const int rowg1 = rowg0 + 8;

    auto issue = [&](int kt, int buf) {
        uint32_t kb = base[buf];
        uint32_t vb = base[2 + buf];
#pragma unroll
        for (int i = 0; i < 2; i++) {
            int q = tid + i * 256;        // 0..511
            int r = q >> 3, c8 = (q & 7) * 8;
            const __half* kbp = qkv + ((size_t)(b * CK + kt * 64 + r)) * (3 * CD) + CD + h * 64 + c8;
            cp16(kb + (r * SATT + c8) * 2, kbp);
            cp16(vb + (r * SATT + c8) * 2, kbp + CD);
        }
        asm volatile("cp.async.commit_group;\n");
    };

    issue(0, 0);
    for (int kt = 0; kt < nt; kt++) {
        if (kt + 1 < nt) {
            issue(kt + 1, (kt + 1) & 1);
            asm volatile("cp.async.wait_group 1;\n");
        } else {
            asm volatile("cp.async.wait_group 0;\n");
        }
        __syncthreads();
        uint32_t ksb = base[kt & 1];
        uint32_t vsb = base[2 + (kt & 1)];

        // S = Q K^T : 16 (warp rows) x 64
        float sf[8][4];
#pragma unroll
        for (int ni = 0; ni < 8; ni++)
#pragma unroll
            for (int r = 0; r < 4; r++) sf[ni][r] = 0.f;
#pragma unroll
        for (int ks = 0; ks < 4; ks++) {
#pragma unroll
            for (int ni = 0; ni < 8; ni++) {
                uint32_t b0, b1;
                ldsm_x2(b0, b1,
                        ksb + ((ni * 8 + (lane & 7)) * SATT + ks * 16 + ((lane >> 3) & 1) * 8) * 2);
                mma_f16(sf[ni], qf[ks], b0, b1);
            }
        }

        // causal mask (only possible on the last two tiles)
        if (kt >= 2 * qb) {
            int cbase = kt * 64;
#pragma unroll
            for (int ni = 0; ni < 8; ni++) {
                int c0 = cbase + ni * 8 + 2 * tg, c1 = c0 + 1;
                if (c0 > rowg0) sf[ni][0] = -1e30f;
                if (c1 > rowg0) sf[ni][1] = -1e30f;
                if (c0 > rowg1) sf[ni][2] = -1e30f;
                if (c1 > rowg1) sf[ni][3] = -1e30f;
            }
        }

        // online softmax (rows g and g+8)
        float m0 = -1e30f, m1 = -1e30f;
#pragma unroll
        for (int ni = 0; ni < 8; ni++) {
            m0 = fmaxf(m0, fmaxf(sf[ni][0], sf[ni][1]));
            m1 = fmaxf(m1, fmaxf(sf[ni][2], sf[ni][3]));
        }
        m0 = fmaxf(m0, __shfl_xor_sync(0xffffffffu, m0, 1));
        m0 = fmaxf(m0, __shfl_xor_sync(0xffffffffu, m0, 2));
        m1 = fmaxf(m1, __shfl_xor_sync(0xffffffffu, m1, 1));
        m1 = fmaxf(m1, __shfl_xor_sync(0xffffffffu, m1, 2));
        float nm0 = fmaxf(mi0, m0), nm1 = fmaxf(mi1, m1);
        float co0 = __expf(mi0 - nm0), co1 = __expf(mi1 - nm1);
        float rs0 = 0.f, rs1 = 0.f;
#pragma unroll
        for (int ni = 0; ni < 8; ni++) {
            sf[ni][0] = __expf(sf[ni][0] - nm0);
            sf[ni][1] = __expf(sf[ni][1] - nm0);
            sf[ni][2] = __expf(sf[ni][2] - nm1);
            sf[ni][3] = __expf(sf[ni][3] - nm1);
            rs0 += sf[ni][0] + sf[ni][1];
            rs1 += sf[ni][2] + sf[ni][3];
        }
        rs0 += __shfl_xor_sync(0xffffffffu, rs0, 1);
        rs0 += __shfl_xor_sync(0xffffffffu, rs0, 2);
        rs1 += __shfl_xor_sync(0xffffffffu, rs1, 1);
        rs1 += __shfl_xor_sync(0xffffffffu, rs1, 2);
        li0 = li0 * co0 + rs0;
        li1 = li1 * co1 + rs1;
        mi0 = nm0; mi1 = nm1;
#pragma unroll
        for (int ni = 0; ni < 8; ni++) {
            of[ni][0] *= co0; of[ni][1] *= co0;
            of[ni][2] *= co1; of[ni][3] *= co1;
        }

        // O += P V : P stays in registers (accumulator -> A-fragment identity)
#pragma unroll
        for (int js = 0; js < 4; js++) {
            uint32_t a[4];
            a[0] = pack_h2(sf[2 * js][0], sf[2 * js][1]);
            a[1] = pack_h2(sf[2 * js][2], sf[2 * js][3]);
            a[2] = pack_h2(sf[2 * js + 1][0], sf[2 * js + 1][1]);
            a[3] = pack_h2(sf[2 * js + 1][2], sf[2 * js + 1][3]);
#pragma unroll
            for (int ni = 0; ni < 8; ni++) {
                uint32_t b0, b1;
                ldsm_x2t(b0, b1, vsb + ((js * 16 + lkb) * SATT + ni * 8) * 2);
                mma_f16(of[ni], a, b0, b1);
            }
        }
        __syncthreads();   // all warps done with this buffer before it reloads
    }

    float il0 = 1.f / li0, il1 = 1.f / li1;
#pragma unroll
    for (int ni = 0; ni < 8; ni++) {
        int col = h * 64 + ni * 8 + 2 * tg;
        *(__half2*)(o + ((size_t)(b * CK + rowg0)) * CD + col) =
            __floats2half2_rn(of[ni][0] * il0, of[ni][1] * il0);
        *(__half2*)(o + ((size_t)(b * CK + rowg1)) * CD + col) =
            __floats2half2_rn(of[ni][2] * il1, of[ni][3] * il1);
    }
}

// ---------------- output assembly (fused copy + gated scatter) ---------------
__global__ void outfuse_kernel(const float* __restrict__ x,
                               const float* __restrict__ h,
                               const int* __restrict__ inv,
                               const float* __restrict__ gate,
                               float* __restrict__ out) {
    int row = blockIdx.x;                 // 0 .. CB*CT-1
    int b = row >> 12;                    // /CT
    int pos = inv[row];
    const float4* src = (const float4*)(x + (size_t)row * CD);
    float4* dst = (float4*)(out + (size_t)row * CD);
    float4 v = src[threadIdx.x];
    if (pos >= 0) {
        float gval = gate[b * CK + pos];
        const float4* hp = (const float4*)(h + (size_t)(b * CK + pos) * CD);
        float4 hv = hp[threadIdx.x];
        v.x += hv.x * gval; v.y += hv.y * gval;
        v.z += hv.z * gval; v.w += hv.w * gval;
    }
    dst[threadIdx.x] = v;
}

__global__ void tail_kernel(const int* __restrict__ idx, const float* __restrict__ logits,
                            float* __restrict__ out) {
    int i = blockIdx.x * blockDim.x + threadIdx.x;
    if (i < CB * CK) {
        out[BTD + i] = (float)idx[i];
    } else if (i < CB * CK + CB * CT) {
        int j = i - CB * CK;
        out[BTD + CB * CK + j] = logits[j];
    }
}

// ---------------- launch -----------------------------------------------------
extern "C" void kernel_launch(void* const* d_in, const int* in_sizes, int n_in,
                              void* d_out, int out_size) {
    const float* x         = (const float*)d_in[0];
    const float* w_router  = (const float*)d_in[1];
    const float* b_router  = (const float*)d_in[2];
    const float* ln1_scale = (const float*)d_in[3];
    const float* ln1_bias  = (const float*)d_in[4];
    const float* w_qkv     = (const float*)d_in[5];
    const float* b_qkv     = (const float*)d_in[6];
    const float* w_o       = (const float*)d_in[7];
    const float* b_o       = (const float*)d_in[8];
    const float* ln2_scale = (const float*)d_in[9];
    const float* ln2_bias  = (const float*)d_in[10];
    const float* w1        = (const float*)d_in[11];
    const float* b1        = (const float*)d_in[12];
    const float* w2        = (const float*)d_in[13];
    const float* b2        = (const float*)d_in[14];
    float* out = (float*)d_out;

    float *logits, *gate, *h;
    int *sel, *idxp, *invp;
    __half *lnh, *qkvh, *attnh, *midh, *wth;
    cudaGetSymbolAddress((void**)&logits, g_logits);
    cudaGetSymbolAddress((void**)&sel, g_sel);
    cudaGetSymbolAddress((void**)&idxp, g_idx);
    cudaGetSymbolAddress((void**)&invp, g_inv);
    cudaGetSymbolAddress((void**)&gate, g_gate);
    cudaGetSymbolAddress((void**)&h, g_h);
    cudaGetSymbolAddress((void**)&lnh, g_lnh);
    cudaGetSymbolAddress((void**)&qkvh, g_qkvh);
    cudaGetSymbolAddress((void**)&attnh, g_attnh);
    cudaGetSymbolAddress((void**)&midh, g_midh);
    cudaGetSymbolAddress((void**)&wth, g_wth);

    cudaFuncSetAttribute(tgemm_kernel,
                         cudaFuncAttributeMaxDynamicSharedMemorySize, (int)TGEMM_SMEM);
    cudaFuncSetAttribute(tgemm_wide<false>,
                         cudaFuncAttributeMaxDynamicSharedMemorySize, (int)TGEMW_SMEM);
    cudaFuncSetAttribute(tgemm_wide<true>,
                         cudaFuncAttributeMaxDynamicSharedMemorySize, (int)TGEMW_SMEM);

    // 0. pre-convert weights to fp16
    cvtw_kernel<<<(int)(WQKV_SZ / 4 / 256), 256>>>(w_qkv, wth + WQKV_OFF, (int)(WQKV_SZ / 4));
    cvtw_kernel<<<(int)(WO_SZ / 4 / 256), 256>>>(w_o,   wth + WO_OFF,   (int)(WO_SZ / 4));
    cvtw_kernel<<<(int)(W1_SZ / 4 / 256), 256>>>(w1,    wth + W1_OFF,   (int)(W1_SZ / 4));
    cvtw_kernel<<<(int)(W2_SZ / 4 / 256), 256>>>(w2,    wth + W2_OFF,   (int)(W2_SZ / 4));

    // 1. router
    router_kernel<<<(CB * CT) / 8, 256>>>(x, w_router, b_router, logits);
    // 2. expert-choice top-K
    rank_kernel<<<CB * 64, 256>>>(logits, sel);
    compact_kernel<<<CB, 1024>>>(logits, sel, idxp, invp, gate);
    // 3. gather
    gather_kernel<<<BK_ROWS, 256>>>(x, idxp, h);

    // 4. transformer blocks
    for (int l = 0; l < CL; l++) {
        layernorm_kernel<<<BK_ROWS, 256>>>(h, lnh, ln1_scale + l * CD, ln1_bias + l * CD);
        tgemm_wide<false><<<dim3(3 * CD / WBN, BK_ROWS / GBM), 256, TGEMW_SMEM>>>(
            lnh, wth + WQKV_OFF + (size_t)l * CD * 3 * CD, b_qkv + l * 3 * CD,
            qkvh, BK_ROWS, 3 * CD, CD);
        attn_kernel<<<dim3(CK / 128, CH, CB), 256>>>(qkvh, attnh);
        tgemm_kernel<<<dim3(CD / GBN, BK_ROWS / GBM), 256, TGEMM_SMEM>>>(
            attnh, wth + WO_OFF + (size_t)l * CD * CD, b_o + l * CD, h, h,
            BK_ROWS, CD, CD);
        layernorm_kernel<<<BK_ROWS, 256>>>(h, lnh, ln2_scale + l * CD, ln2_bias + l * CD);
        tgemm_wide<true><<<dim3(CF / WBN, BK_ROWS / GBM), 256, TGEMW_SMEM>>>(
            lnh, wth + W1_OFF + (size_t)l * CD * CF, b1 + l * CF,
            midh, BK_ROWS, CF, CD);
        tgemm_kernel<<<dim3(CD / GBN, BK_ROWS / GBM), 256, TGEMM_SMEM>>>(
            midh, wth + W2_OFF + (size_t)l * CF * CD, b2 + l * CD, h, h,
            BK_ROWS, CD, CF);
    }

    // 5. assemble output: total (fused copy+scatter), idx, logits
    outfuse_kernel<<<CB * CT, 256>>>(x, h, invp, gate, out);
    if ((size_t)out_size >= BTD + CB * CK + CB * CT) {
        int ntail = CB * CK + CB * CT;
        tail_kernel<<<(ntail + 255) / 256, 256>>>(idxp, logits, out);
    }
}

// round 9
// speedup vs baseline: 6.8696x; 1.0351x over previous
#include <cuda_runtime.h>
#include <cuda_fp16.h>
#include <math.h>
#include <stdint.h>

// Problem constants
constexpr int CB = 2;      // batch
constexpr int CT = 4096;   // seq len
constexpr int CD = 1024;   // d_model
constexpr int CL = 2;      // layers
constexpr int CH = 16;     // heads
constexpr int CF = 4096;   // d_ff
constexpr int CK = 2048;   // top-k tokens
constexpr int BK_ROWS = CB * CK;
constexpr size_t BTD = (size_t)CB * CT * CD;

// Weight fp16 scratch offsets (elements)
constexpr size_t WQKV_OFF = 0;
constexpr size_t WQKV_SZ  = (size_t)CL * CD * 3 * CD;
constexpr size_t WO_OFF   = WQKV_OFF + WQKV_SZ;
constexpr size_t WO_SZ    = (size_t)CL * CD * CD;
constexpr size_t W1_OFF   = WO_OFF + WO_SZ;
constexpr size_t W1_SZ    = (size_t)CL * CD * CF;
constexpr size_t W2_OFF   = W1_OFF + W1_SZ;
constexpr size_t W2_SZ    = (size_t)CL * CF * CD;
constexpr size_t WTF_TOTAL = W2_OFF + W2_SZ;

// ---------------- scratch (static device globals) ---------------------------
__device__ float  g_logits[CB * CT];
__device__ int    g_sel[CB * CT];
__device__ int    g_idx[CB * CK];
__device__ int    g_inv[CB * CT];
__device__ float  g_gate[CB * CK];
__device__ float  g_h[BK_ROWS * CD];
__device__ __half g_lnh[BK_ROWS * CD];
__device__ __half g_qkvh[(size_t)BK_ROWS * 3 * CD];
__device__ __half g_attnh[BK_ROWS * CD];
__device__ __half g_midh[(size_t)BK_ROWS * CF];
__device__ __half g_wth[WTF_TOTAL];

__device__ __forceinline__ void mma_f16(float c[4], const uint32_t a[4],
                                        uint32_t b0, uint32_t b1) {
    asm volatile(
        "mma.sync.aligned.m16n8k16.row.col.f32.f16.f16.f32 "
        "{%0,%1,%2,%3}, {%4,%5,%6,%7}, {%8,%9}, {%0,%1,%2,%3};\n"
        : "+f"(c[0]), "+f"(c[1]), "+f"(c[2]), "+f"(c[3])
        : "r"(a[0]), "r"(a[1]), "r"(a[2]), "r"(a[3]), "r"(b0), "r"(b1));
}
__device__ __forceinline__ void ldsm_x4(uint32_t r[4], uint32_t saddr) {
    asm volatile("ldmatrix.sync.aligned.m8n8.x4.shared.b16 {%0,%1,%2,%3}, [%4];"
                 : "=r"(r[0]), "=r"(r[1]), "=r"(r[2]), "=r"(r[3]) : "r"(saddr));
}
__device__ __forceinline__ void ldsm_x4t(uint32_t r[4], uint32_t saddr) {
    asm volatile("ldmatrix.sync.aligned.m8n8.x4.trans.shared.b16 {%0,%1,%2,%3}, [%4];"
                 : "=r"(r[0]), "=r"(r[1]), "=r"(r[2]), "=r"(r[3]) : "r"(saddr));
}
__device__ __forceinline__ void ldsm_x2t(uint32_t& r0, uint32_t& r1, uint32_t saddr) {
    asm volatile("ldmatrix.sync.aligned.m8n8.x2.trans.shared.b16 {%0,%1}, [%2];"
                 : "=r"(r0), "=r"(r1) : "r"(saddr));
}
__device__ __forceinline__ void cp16(uint32_t dst, const void* src) {
    asm volatile("cp.async.cg.shared.global [%0], [%1], 16;\n" :: "r"(dst), "l"(src));
}
__device__ __forceinline__ uint32_t pack_h2(float a, float b) {
    __half2 h = __floats2half2_rn(a, b);
    return *(uint32_t*)&h;
}

// ---------------- router ----------------------------------------------------
__global__ void router_kernel(const float* __restrict__ x,
                              const float* __restrict__ wr,
                              const float* __restrict__ br,
                              float* __restrict__ logits) {
    int gw = (blockIdx.x * blockDim.x + threadIdx.x) >> 5;
    if (gw >= CB * CT) return;
    int lane = threadIdx.x & 31;
    const float4* p = (const float4*)(x + (size_t)gw * CD);
    const float4* w4 = (const float4*)wr;
    float s = 0.f;
#pragma unroll
    for (int i = 0; i < CD / 128; i++) {
        float4 a = p[lane + i * 32];
        float4 w = w4[lane + i * 32];
        s += a.x * w.x + a.y * w.y + a.z * w.z + a.w * w.w;
    }
#pragma unroll
    for (int o = 16; o > 0; o >>= 1) s += __shfl_down_sync(0xffffffffu, s, o);
    if (lane == 0) logits[gw] = s + br[0];
}

// ---------------- top-K -----------------------------------------------------
__global__ void rank_kernel(const float* __restrict__ logits, int* __restrict__ sel) {
    int blk = blockIdx.x;
    int b = blk >> 6;
    int base = (blk & 63) * 64;
    __shared__ float lv[CT];
    int tid = threadIdx.x;
    for (int t = tid; t < CT; t += 256) lv[t] = logits[b * CT + t];
    __syncthreads();
    int tt = tid >> 2, part = tid & 3;
    int t = base + tt;
    float v = lv[t];
    int cnt = 0;
    int s0 = part * 1024;
#pragma unroll 8
    for (int s = s0; s < s0 + 1024; s++) {
        float u = lv[s];
        cnt += (u > v) || (u == v && s < t);
    }
    __shared__ int rk[64];
    if (part == 0) rk[tt] = 0;
    __syncthreads();
    atomicAdd(&rk[tt], cnt);
    __syncthreads();
    if (part == 0) sel[b * CT + t] = (rk[tt] < CK) ? 1 : 0;
}

__global__ void compact_kernel(const float* __restrict__ logits,
                               const int* __restrict__ sel,
                               int* __restrict__ idx_out,
                               int* __restrict__ inv_out,
                               float* __restrict__ gate_out) {
    int b = blockIdx.x;
    int tid = threadIdx.x;
    int f[4]; int c = 0;
#pragma unroll
    for (int i = 0; i < 4; i++) { f[i] = sel[b * CT + tid * 4 + i]; c += f[i]; }
    int lane = tid & 31, wid = tid >> 5;
    int incl = c;
#pragma unroll
    for (int o = 1; o < 32; o <<= 1) {
        int n = __shfl_up_sync(0xffffffffu, incl, o);
        if (lane >= o) incl += n;
    }
    __shared__ int wsum[32];
    if (lane == 31) wsum[wid] = incl;
    __syncthreads();
    if (wid == 0) {
        int w = wsum[lane];
#pragma unroll
        for (int o = 1; o < 32; o <<= 1) {
            int n = __shfl_up_sync(0xffffffffu, w, o);
            if (lane >= o) w += n;
        }
        wsum[lane] = w;
    }
    __syncthreads();
    int pos = (wid ? wsum[wid - 1] : 0) + incl - c;
#pragma unroll
    for (int i = 0; i < 4; i++) {
        int t = tid * 4 + i;
        if (f[i]) {
            idx_out[b * CK + pos] = t;
            inv_out[b * CT + t] = pos;
            float lg = logits[b * CT + t];
            gate_out[b * CK + pos] = 1.f / (1.f + expf(-lg));
            pos++;
        } else {
            inv_out[b * CT + t] = -1;
        }
    }
}

// ---------------- fused gather + first layernorm ------------------------------
__global__ void gather_ln_kernel(const float* __restrict__ x, const int* __restrict__ idx,
                                 const float* __restrict__ scale,
                                 const float* __restrict__ bias,
                                 float* __restrict__ h, __half* __restrict__ lnh) {
    int bk = blockIdx.x;
    int b = bk >> 11;
    int t = idx[bk];
    int tid = threadIdx.x;
    const float4* src = (const float4*)(x + ((size_t)b * CT + t) * CD);
    float4 v = src[tid];
    ((float4*)(h + (size_t)bk * CD))[tid] = v;
    float s = v.x + v.y + v.z + v.w;
    float ss = v.x * v.x + v.y * v.y + v.z * v.z + v.w * v.w;
#pragma unroll
    for (int o = 16; o > 0; o >>= 1) {
        s += __shfl_down_sync(0xffffffffu, s, o);
        ss += __shfl_down_sync(0xffffffffu, ss, o);
    }
    __shared__ float red[64];
    int lane = tid & 31, wid = tid >> 5;
    if (lane == 0) { red[wid] = s; red[32 + wid] = ss; }
    __syncthreads();
    if (tid == 0) {
        float S = 0, SS = 0;
#pragma unroll
        for (int w = 0; w < 8; w++) { S += red[w]; SS += red[32 + w]; }
        red[0] = S; red[32] = SS;
    }
    __syncthreads();
    float mean = red[0] * (1.f / CD);
    float var = red[32] * (1.f / CD) - mean * mean;
    float inv = rsqrtf(var + 1e-5f);
    float4 sc = ((const float4*)scale)[tid];
    float4 bi = ((const float4*)bias)[tid];
    __half2* o2 = (__half2*)(lnh + (size_t)bk * CD);
    o2[2 * tid] = __floats2half2_rn((v.x - mean) * inv * sc.x + bi.x,
                                    (v.y - mean) * inv * sc.y + bi.y);
    o2[2 * tid + 1] = __floats2half2_rn((v.z - mean) * inv * sc.z + bi.z,
                                        (v.w - mean) * inv * sc.w + bi.w);
}

// ---------------- layernorm (fp32 in -> fp16 out) ---------------------------
__global__ void layernorm_kernel(const float* __restrict__ in, __half* __restrict__ out,
                                 const float* __restrict__ scale,
                                 const float* __restrict__ bias) {
    int row = blockIdx.x;
    int tid = threadIdx.x;
    const float4* p = (const float4*)(in + (size_t)row * CD);
    float4 v = p[tid];
    float s = v.x + v.y + v.z + v.w;
    float ss = v.x * v.x + v.y * v.y + v.z * v.z + v.w * v.w;
#pragma unroll
    for (int o = 16; o > 0; o >>= 1) {
        s += __shfl_down_sync(0xffffffffu, s, o);
        ss += __shfl_down_sync(0xffffffffu, ss, o);
    }
    __shared__ float red[64];
    int lane = tid & 31, wid = tid >> 5;
    if (lane == 0) { red[wid] = s; red[32 + wid] = ss; }
    __syncthreads();
    if (tid == 0) {
        float S = 0, SS = 0;
#pragma unroll
        for (int w = 0; w < 8; w++) { S += red[w]; SS += red[32 + w]; }
        red[0] = S; red[32] = SS;
    }
    __syncthreads();
    float mean = red[0] * (1.f / CD);
    float var = red[32] * (1.f / CD) - mean * mean;
    float inv = rsqrtf(var + 1e-5f);
    float4 sc = ((const float4*)scale)[tid];
    float4 bi = ((const float4*)bias)[tid];
    __half2* o2 = (__half2*)(out + (size_t)row * CD);
    o2[2 * tid] = __floats2half2_rn((v.x - mean) * inv * sc.x + bi.x,
                                    (v.y - mean) * inv * sc.y + bi.y);
    o2[2 * tid + 1] = __floats2half2_rn((v.z - mean) * inv * sc.z + bi.z,
                                        (v.w - mean) * inv * sc.w + bi.w);
}

// ---------------- merged weight fp16 convert ---------------------------------
__global__ void cvtw_all_kernel(const float* __restrict__ wqkv,
                                const float* __restrict__ wo,
                                const float* __restrict__ w1,
                                const float* __restrict__ w2,
                                __half* __restrict__ dst) {
    constexpr size_t Q4 = WQKV_SZ / 4, O4 = WO_SZ / 4, A4 = W1_SZ / 4;
    size_t i = (size_t)blockIdx.x * blockDim.x + threadIdx.x;
    float4 v;
    if (i < Q4)                 v = ((const float4*)wqkv)[i];
    else if (i < Q4 + O4)       v = ((const float4*)wo)[i - Q4];
    else if (i < Q4 + O4 + A4)  v = ((const float4*)w1)[i - Q4 - O4];
    else                        v = ((const float4*)w2)[i - Q4 - O4 - A4];
    __half2* d2 = (__half2*)dst;
    d2[2 * i]     = __floats2half2_rn(v.x, v.y);
    d2[2 * i + 1] = __floats2half2_rn(v.z, v.w);
}

// ---------------- common GEMM bits -------------------------------------------
__device__ __forceinline__ float gelu_tanh(float x) {
    float x3 = x * x * x;
    float t = tanhf(0.7978845608028654f * (x + 0.044715f * x3));
    return 0.5f * x * (1.f + t);
}

// ============ narrow GEMM: 128x128x64, fp32 out + residual (Wo, FFN2) =======
constexpr int GBM = 128, GBN = 128, GBK = 64;
constexpr int AST = GBK + 8;
constexpr int BST = GBN + 8;
constexpr int ABUFH = GBM * AST;
constexpr int BBUFH = GBK * BST;
constexpr size_t TGEMM_SMEM = (size_t)(ABUFH + BBUFH) * 2 * sizeof(__half);

__global__ __launch_bounds__(256) void tgemm_kernel(
    const __half* __restrict__ A, const __half* __restrict__ W,
    const float* __restrict__ bias, const float* __restrict__ R,
    float* __restrict__ C, int M, int N, int Kd) {
    extern __shared__ __half dsm[];
    __half* As = dsm;
    __half* Bs = dsm + 2 * ABUFH;

    const int tid = threadIdx.x;
    const int bx = blockIdx.x, by = blockIdx.y;
    const int wid = tid >> 5, lane = tid & 31;
    const int warp_m = wid & 1;
    const int warp_n = wid >> 1;
    const int g = lane >> 2;
    const int tg = lane & 3;
    const int lm = (lane & 7) + ((lane >> 3) & 1) * 8;
    const int lk = ((lane >> 4) & 1) * 8;
    const int lkb = (lane & 7) + ((lane >> 3) & 1) * 8;

    float c[4][4][4];
#pragma unroll
    for (int mi = 0; mi < 4; mi++)
#pragma unroll
        for (int ni = 0; ni < 4; ni++)
#pragma unroll
            for (int r = 0; r < 4; r++) c[mi][ni][r] = 0.f;

    const int ntiles = Kd / GBK;

    auto issue_tile = [&](int t, int buf) {
        int k0 = t * GBK;
        uint32_t abase = (uint32_t)__cvta_generic_to_shared(As + buf * ABUFH);
        uint32_t bbase = (uint32_t)__cvta_generic_to_shared(Bs + buf * BBUFH);
#pragma unroll
        for (int i = 0; i < 4; i++) {
            int q = tid + i * 256;
            int row = q >> 3, c8 = (q & 7) * 8;
            cp16(abase + (row * AST + c8) * 2, A + (size_t)(by * GBM + row) * Kd + k0 + c8);
        }
#pragma unroll
        for (int i = 0; i < 4; i++) {
            int q = tid + i * 256;
            int row = q >> 4, n8 = (q & 15) * 8;
            cp16(bbase + (row * BST + n8) * 2, W + (size_t)(k0 + row) * N + bx * GBN + n8);
        }
        asm volatile("cp.async.commit_group;\n");
    };

    issue_tile(0, 0);
    for (int t = 0; t < ntiles; t++) {
        if (t + 1 < ntiles) {
            issue_tile(t + 1, (t + 1) & 1);
            asm volatile("cp.async.wait_group 1;\n");
        } else {
            asm volatile("cp.async.wait_group 0;\n");
        }
        __syncthreads();
        uint32_t Ab = (uint32_t)__cvta_generic_to_shared(As + (t & 1) * ABUFH);
        uint32_t Bb = (uint32_t)__cvta_generic_to_shared(Bs + (t & 1) * BBUFH);
        uint32_t a_off = Ab + ((warp_m * 64 + lm) * AST + lk) * 2;
        uint32_t b_off = Bb + (lkb * BST + warp_n * 32) * 2;
#pragma unroll
        for (int ks = 0; ks < GBK / 16; ks++) {
            uint32_t a[4][4], b[4][2];
#pragma unroll
            for (int mi = 0; mi < 4; mi++)
                ldsm_x4(a[mi], a_off + (mi * 16 * AST + ks * 16) * 2);
#pragma unroll
            for (int ni = 0; ni < 4; ni++)
                ldsm_x2t(b[ni][0], b[ni][1], b_off + (ks * 16 * BST + ni * 8) * 2);
#pragma unroll
            for (int mi = 0; mi < 4; mi++)
#pragma unroll
                for (int ni = 0; ni < 4; ni++)
                    mma_f16(c[mi][ni], a[mi], b[ni][0], b[ni][1]);
        }
        __syncthreads();
    }

#pragma unroll
    for (int mi = 0; mi < 4; mi++) {
        int m0 = by * GBM + warp_m * 64 + mi * 16 + g;
#pragma unroll
        for (int ni = 0; ni < 4; ni++) {
            int n0 = bx * GBN + warp_n * 32 + ni * 8 + 2 * tg;
            float b0 = bias[n0], b1 = bias[n0 + 1];
#pragma unroll
            for (int half = 0; half < 2; half++) {
                int m = m0 + half * 8;
                float v0 = c[mi][ni][half * 2 + 0] + b0;
                float v1 = c[mi][ni][half * 2 + 1] + b1;
                const float2 r2 = *(const float2*)(R + (size_t)m * N + n0);
                v0 += r2.x; v1 += r2.y;
                *(float2*)(C + (size_t)m * N + n0) = make_float2(v0, v1);
            }
        }
    }
}

// ============ wide GEMM: 128x256x64, fp16 out, opt GELU (QKV, FFN1) =========
constexpr int WBN = 256;
constexpr int BSTW = WBN + 8;
constexpr int BBUFW = GBK * BSTW;
constexpr size_t TGEMW_SMEM = (size_t)(ABUFH + BBUFW) * 2 * sizeof(__half);

template <bool GELU>
__global__ __launch_bounds__(256) void tgemm_wide(
    const __half* __restrict__ A, const __half* __restrict__ W,
    const float* __restrict__ bias, __half* __restrict__ C,
    int M, int N, int Kd) {
    extern __shared__ __half dsm[];
    __half* As = dsm;
    __half* Bs = dsm + 2 * ABUFH;

    const int tid = threadIdx.x;
    const int bx = blockIdx.x, by = blockIdx.y;
    const int wid = tid >> 5, lane = tid & 31;
    const int warp_m = wid & 1;
    const int warp_n = wid >> 1;
    const int g = lane >> 2;
    const int tg = lane & 3;
    const int lm = (lane & 7) + ((lane >> 3) & 1) * 8;
    const int lk = ((lane >> 4) & 1) * 8;
    const int lkb = (lane & 7) + ((lane >> 3) & 1) * 8;

    float c[4][8][4];
#pragma unroll
    for (int mi = 0; mi < 4; mi++)
#pragma unroll
        for (int ni = 0; ni < 8; ni++)
#pragma unroll
            for (int r = 0; r < 4; r++) c[mi][ni][r] = 0.f;

    const int ntiles = Kd / GBK;

    auto issue_tile = [&](int t, int buf) {
        int k0 = t * GBK;
        uint32_t abase = (uint32_t)__cvta_generic_to_shared(As + buf * ABUFH);
        uint32_t bbase = (uint32_t)__cvta_generic_to_shared(Bs + buf * BBUFW);
#pragma unroll
        for (int i = 0; i < 4; i++) {
            int q = tid + i * 256;
            int row = q >> 3, c8 = (q & 7) * 8;
            cp16(abase + (row * AST + c8) * 2, A + (size_t)(by * GBM + row) * Kd + k0 + c8);
        }
#pragma unroll
        for (int i = 0; i < 8; i++) {
            int q = tid + i * 256;
            int row = q >> 5, n8 = (q & 31) * 8;
            cp16(bbase + (row * BSTW + n8) * 2, W + (size_t)(k0 + row) * N + bx * WBN + n8);
        }
        asm volatile("cp.async.commit_group;\n");
    };

    issue_tile(0, 0);
    for (int t = 0; t < ntiles; t++) {
        if (t + 1 < ntiles) {
            issue_tile(t + 1, (t + 1) & 1);
            asm volatile("cp.async.wait_group 1;\n");
        } else {
            asm volatile("cp.async.wait_group 0;\n");
        }
        __syncthreads();
        uint32_t Ab = (uint32_t)__cvta_generic_to_shared(As + (t & 1) * ABUFH);
        uint32_t Bb = (uint32_t)__cvta_generic_to_shared(Bs + (t & 1) * BBUFW);
        uint32_t a_off = Ab + ((warp_m * 64 + lm) * AST + lk) * 2;
        uint32_t b_off = Bb + (lkb * BSTW + warp_n * 64) * 2;
#pragma unroll
        for (int ks = 0; ks < GBK / 16; ks++) {
            uint32_t a[4][4], b[8][2];
#pragma unroll
            for (int mi = 0; mi < 4; mi++)
                ldsm_x4(a[mi], a_off + (mi * 16 * AST + ks * 16) * 2);
#pragma unroll
            for (int ni = 0; ni < 8; ni++)
                ldsm_x2t(b[ni][0], b[ni][1], b_off + (ks * 16 * BSTW + ni * 8) * 2);
#pragma unroll
            for (int mi = 0; mi < 4; mi++)
#pragma unroll
                for (int ni = 0; ni < 8; ni++)
                    mma_f16(c[mi][ni], a[mi], b[ni][0], b[ni][1]);
        }
        __syncthreads();
    }

#pragma unroll
    for (int mi = 0; mi < 4; mi++) {
        int m0 = by * GBM + warp_m * 64 + mi * 16 + g;
#pragma unroll
        for (int ni = 0; ni < 8; ni++) {
            int n0 = bx * WBN + warp_n * 64 + ni * 8 + 2 * tg;
            float b0 = bias[n0], b1 = bias[n0 + 1];
#pragma unroll
            for (int half = 0; half < 2; half++) {
                int m = m0 + half * 8;
                float v0 = c[mi][ni][half * 2 + 0] + b0;
                float v1 = c[mi][ni][half * 2 + 1] + b1;
                if (GELU) { v0 = gelu_tanh(v0); v1 = gelu_tanh(v1); }
                *(__half2*)(C + (size_t)m * N + n0) = __floats2half2_rn(v0, v1);
            }
        }
    }
}

// ---------------- FP16 MMA flash attention v3 --------------------------------
// 256 threads (8 warps). Diagonal-paired Q tiles: CTA does qb=p then qb=15-p
// (constant 34 tile-iters per CTA). K/V cp.async double-buffered; P in regs;
// ldsm x4 for B operands (2 MMAs per load).
constexpr int SATT = 72;
constexpr int NQB = CK / 128;   // 16
__global__ __launch_bounds__(256) void attn_kernel(const __half* __restrict__ qkv,
                                                   __half* __restrict__ o) {
    const int pairi = blockIdx.x, h = blockIdx.y, b = blockIdx.z;
    const int tid = threadIdx.x;
    const int w = tid >> 5, lane = tid & 31;
    const int g = lane >> 2, tg = lane & 3;
    const int lm = (lane & 7) + ((lane >> 3) & 1) * 8;
    const int lk = ((lane >> 4) & 1) * 8;

    __shared__ __half KV[4][64 * SATT];
    uint32_t base[4];
#pragma unroll
    for (int i = 0; i < 4; i++) base[i] = (uint32_t)__cvta_generic_to_shared(KV[i]);

    // B-operand x4 ldsm lane addressing (covers two adjacent 8-col groups)
    const int srow = (lane & 7) + ((lane >> 4) & 1) * 8;   // S-phase: n-row within 16
    const int scol = ((lane >> 3) & 1) * 8;                // S-phase: k-col half
    const int vrow = (lane & 7) + ((lane >> 3) & 1) * 8;   // PV: k-row within 16
    const int vcol = ((lane >> 4) & 1) * 8;                // PV: n-col half

    const __half2 sc8 = __float2half2_rn(0.125f);

    for (int s = 0; s < 2; s++) {
        const int qb = (s == 0) ? pairi : (NQB - 1 - pairi);

        // ---- stage Q (128 x 64, scaled) over KV[0..1], extract frags
#pragma unroll
        for (int i = 0; i < 4; i++) {
            int q = tid + i * 256;
            int r = q >> 3, c8 = (q & 7) * 8;
            const __half* src = qkv + ((size_t)(b * CK + qb * 128 + r)) * (3 * CD) + h * 64 + c8;
            uint4 u = *(const uint4*)src;
            __half2* hp = (__half2*)&u;
#pragma unroll
            for (int j = 0; j < 4; j++) hp[j] = __hmul2(hp[j], sc8);
            *(uint4*)&KV[0][r * SATT + c8] = u;
        }
        __syncthreads();
        uint32_t qf[4][4];
#pragma unroll
        for (int ks = 0; ks < 4; ks++)
            ldsm_x4(qf[ks], base[0] + ((w * 16 + lm) * SATT + ks * 16 + lk) * 2);
        __syncthreads();

        float of[8][4];
#pragma unroll
        for (int ni = 0; ni < 8; ni++)
#pragma unroll
            for (int r = 0; r < 4; r++) of[ni][r] = 0.f;
        float mi0 = -1e30f, mi1 = -1e30f, li0 = 0.f, li1 = 0.f;

        const int nt = 2 * qb + 2;
        const int rowg0 = qb * 128 + w * 16 + g;
        const int rowg1 = rowg0 + 8;

        auto issue = [&](int kt, int buf) {
            uint32_t kb = base[buf];
            uint32_t vb = base[2 + buf];
#pragma unroll
            for (int i = 0; i < 2; i++) {
                int q = tid + i * 256;
                int r = q >> 3, c8 = (q & 7) * 8;
                const __half* kbp = qkv + ((size_t)(b * CK + kt * 64 + r)) * (3 * CD) + CD + h * 64 + c8;
                cp16(kb + (r * SATT + c8) * 2, kbp);
                cp16(vb + (r * SATT + c8) * 2, kbp + CD);
            }
            asm volatile("cp.async.commit_group;\n");
        };

        issue(0, 0);
        for (int kt = 0; kt < nt; kt++) {
            if (kt + 1 < nt) {
                issue(kt + 1, (kt + 1) & 1);
                asm volatile("cp.async.wait_group 1;\n");
            } else {
                asm volatile("cp.async.wait_group 0;\n");
            }
            __syncthreads();
            uint32_t ksb = base[kt & 1];
            uint32_t vsb = base[2 + (kt & 1)];

            // S = Q K^T
            float sf[8][4];
#pragma unroll
            for (int ni = 0; ni < 8; ni++)
#pragma unroll
                for (int r = 0; r < 4; r++) sf[ni][r] = 0.f;
#pragma unroll
            for (int ks = 0; ks < 4; ks++) {
#pragma unroll
                for (int ni = 0; ni < 8; ni += 2) {
                    uint32_t b4[4];
                    ldsm_x4(b4, ksb + ((ni * 8 + srow) * SATT + ks * 16 + scol) * 2);
                    mma_f16(sf[ni],     qf[ks], b4[0], b4[1]);
                    mma_f16(sf[ni + 1], qf[ks], b4[2], b4[3]);
                }
            }

            // causal mask (last two tiles only)
            if (kt >= 2 * qb) {
                int cbase = kt * 64;
#pragma unroll
                for (int ni = 0; ni < 8; ni++) {
                    int c0 = cbase + ni * 8 + 2 * tg, c1 = c0 + 1;
                    if (c0 > rowg0) sf[ni][0] = -1e30f;
                    if (c1 > rowg0) sf[ni][1] = -1e30f;
                    if (c0 > rowg1) sf[ni][2] = -1e30f;
                    if (c1 > rowg1) sf[ni][3] = -1e30f;
                }
            }

            // online softmax
            float m0 = -1e30f, m1 = -1e30f;
#pragma unroll
            for (int ni = 0; ni < 8; ni++) {
                m0 = fmaxf(m0, fmaxf(sf[ni][0], sf[ni][1]));
                m1 = fmaxf(m1, fmaxf(sf[ni][2], sf[ni][3]));
            }
            m0 = fmaxf(m0, __shfl_xor_sync(0xffffffffu, m0, 1));
            m0 = fmaxf(m0, __shfl_xor_sync(0xffffffffu, m0, 2));
            m1 = fmaxf(m1, __shfl_xor_sync(0xffffffffu, m1, 1));
            m1 = fmaxf(m1, __shfl_xor_sync(0xffffffffu, m1, 2));
            float nm0 = fmaxf(mi0, m0), nm1 = fmaxf(mi1, m1);
            float co0 = __expf(mi0 - nm0), co1 = __expf(mi1 - nm1);
            float rs0 = 0.f, rs1 = 0.f;
#pragma unroll
            for (int ni = 0; ni < 8; ni++) {
                sf[ni][0] = __expf(sf[ni][0] - nm0);
                sf[ni][1] = __expf(sf[ni][1] - nm0);
                sf[ni][2] = __expf(sf[ni][2] - nm1);
                sf[ni][3] = __expf(sf[ni][3] - nm1);
                rs0 += sf[ni][0] + sf[ni][1];
                rs1 += sf[ni][2] + sf[ni][3];
            }
            rs0 += __shfl_xor_sync(0xffffffffu, rs0, 1);
            rs0 += __shfl_xor_sync(0xffffffffu, rs0, 2);
            rs1 += __shfl_xor_sync(0xffffffffu, rs1, 1);
            rs1 += __shfl_xor_sync(0xffffffffu, rs1, 2);
            li0 = li0 * co0 + rs0;
            li1 = li1 * co1 + rs1;
            mi0 = nm0; mi1 = nm1;
#pragma unroll
            for (int ni = 0; ni < 8; ni++) {
                of[ni][0] *= co0; of[ni][1] *= co0;
                of[ni][2] *= co1; of[ni][3] *= co1;
            }

            // O += P V  (P in registers)
#pragma unroll
            for (int js = 0; js < 4; js++) {
                uint32_t a[4];
                a[0] = pack_h2(sf[2 * js][0], sf[2 * js][1]);
                a[1] = pack_h2(sf[2 * js][2], sf[2 * js][3]);
                a[2] = pack_h2(sf[2 * js + 1][0], sf[2 * js + 1][1]);
                a[3] = pack_h2(sf[2 * js + 1][2], sf[2 * js + 1][3]);
#pragma unroll
                for (int ni = 0; ni < 8; ni += 2) {
                    uint32_t b4[4];
                    ldsm_x4t(b4, vsb + ((js * 16 + vrow) * SATT + (ni + (vcol >> 3)) * 8) * 2);
                    mma_f16(of[ni],     a, b4[0], b4[1]);
                    mma_f16(of[ni + 1], a, b4[2], b4[3]);
                }
            }
            __syncthreads();
        }

        float il0 = 1.f / li0, il1 = 1.f / li1;
#pragma unroll
        for (int ni = 0; ni < 8; ni++) {
            int col = h * 64 + ni * 8 + 2 * tg;
            *(__half2*)(o + ((size_t)(b * CK + rowg0)) * CD + col) =
                __floats2half2_rn(of[ni][0] * il0, of[ni][1] * il0);
            *(__half2*)(o + ((size_t)(b * CK + rowg1)) * CD + col) =
                __floats2half2_rn(of[ni][2] * il1, of[ni][3] * il1);
        }
    }
}

// ---------------- output assembly (fused copy + gated scatter) ---------------
__global__ void outfuse_kernel(const float* __restrict__ x,
                               const float* __restrict__ h,
                               const int* __restrict__ inv,
                               const float* __restrict__ gate,
                               float* __restrict__ out) {
    int row = blockIdx.x;
    int b = row >> 12;
    int pos = inv[row];
    const float4* src = (const float4*)(x + (size_t)row * CD);
    float4* dst = (float4*)(out + (size_t)row * CD);
    float4 v = src[threadIdx.x];
    if (pos >= 0) {
        float gval = gate[b * CK + pos];
        const float4* hp = (const float4*)(h + (size_t)(b * CK + pos) * CD);
        float4 hv = hp[threadIdx.x];
        v.x += hv.x * gval; v.y += hv.y * gval;
        v.z += hv.z * gval; v.w += hv.w * gval;
    }
    dst[threadIdx.x] = v;
}

__global__ void tail_kernel(const int* __restrict__ idx, const float* __restrict__ logits,
                            float* __restrict__ out) {
    int i = blockIdx.x * blockDim.x + threadIdx.x;
    if (i < CB * CK) {
        out[BTD + i] = (float)idx[i];
    } else if (i < CB * CK + CB * CT) {
        int j = i - CB * CK;
        out[BTD + CB * CK + j] = logits[j];
    }
}

// ---------------- launch -----------------------------------------------------
extern "C" void kernel_launch(void* const* d_in, const int* in_sizes, int n_in,
                              void* d_out, int out_size) {
    const float* x         = (const float*)d_in[0];
    const float* w_router  = (const float*)d_in[1];
    const float* b_router  = (const float*)d_in[2];
    const float* ln1_scale = (const float*)d_in[3];
    const float* ln1_bias  = (const float*)d_in[4];
    const float* w_qkv     = (const float*)d_in[5];
    const float* b_qkv     = (const float*)d_in[6];
    const float* w_o       = (const float*)d_in[7];
    const float* b_o       = (const float*)d_in[8];
    const float* ln2_scale = (const float*)d_in[9];
    const float* ln2_bias  = (const float*)d_in[10];
    const float* w1        = (const float*)d_in[11];
    const float* b1        = (const float*)d_in[12];
    const float* w2        = (const float*)d_in[13];
    const float* b2        = (const float*)d_in[14];
    float* out = (float*)d_out;

    float *logits, *gate, *h;
    int *sel, *idxp, *invp;
    __half *lnh, *qkvh, *attnh, *midh, *wth;
    cudaGetSymbolAddress((void**)&logits, g_logits);
    cudaGetSymbolAddress((void**)&sel, g_sel);
    cudaGetSymbolAddress((void**)&idxp, g_idx);
    cudaGetSymbolAddress((void**)&invp, g_inv);
    cudaGetSymbolAddress((void**)&gate, g_gate);
    cudaGetSymbolAddress((void**)&h, g_h);
    cudaGetSymbolAddress((void**)&lnh, g_lnh);
    cudaGetSymbolAddress((void**)&qkvh, g_qkvh);
    cudaGetSymbolAddress((void**)&attnh, g_attnh);
    cudaGetSymbolAddress((void**)&midh, g_midh);
    cudaGetSymbolAddress((void**)&wth, g_wth);

    cudaFuncSetAttribute(tgemm_kernel,
                         cudaFuncAttributeMaxDynamicSharedMemorySize, (int)TGEMM_SMEM);
    cudaFuncSetAttribute(tgemm_wide<false>,
                         cudaFuncAttributeMaxDynamicSharedMemorySize, (int)TGEMW_SMEM);
    cudaFuncSetAttribute(tgemm_wide<true>,
                         cudaFuncAttributeMaxDynamicSharedMemorySize, (int)TGEMW_SMEM);

    // 0. pre-convert all weights to fp16 (single kernel)
    cvtw_all_kernel<<<(int)(WTF_TOTAL / 4 / 256), 256>>>(w_qkv, w_o, w1, w2, wth);

    // 1-3. router, top-K, fused gather+LN1(layer0)
    router_kernel<<<(CB * CT) / 8, 256>>>(x, w_router, b_router, logits);
    rank_kernel<<<CB * 64, 256>>>(logits, sel);
    compact_kernel<<<CB, 1024>>>(logits, sel, idxp, invp, gate);
    gather_ln_kernel<<<BK_ROWS, 256>>>(x, idxp, ln1_scale, ln1_bias, h, lnh);

    // 4. transformer blocks
    for (int l = 0; l < CL; l++) {
        if (l > 0)
            layernorm_kernel<<<BK_ROWS, 256>>>(h, lnh, ln1_scale + l * CD, ln1_bias + l * CD);
        tgemm_wide<false><<<dim3(3 * CD / WBN, BK_ROWS / GBM), 256, TGEMW_SMEM>>>(
            lnh, wth + WQKV_OFF + (size_t)l * CD * 3 * CD, b_qkv + l * 3 * CD,
            qkvh, BK_ROWS, 3 * CD, CD);
        attn_kernel<<<dim3(NQB / 2, CH, CB), 256>>>(qkvh, attnh);
        tgemm_kernel<<<dim3(CD / GBN, BK_ROWS / GBM), 256, TGEMM_SMEM>>>(
            attnh, wth + WO_OFF + (size_t)l * CD * CD, b_o + l * CD, h, h,
            BK_ROWS, CD, CD);
        layernorm_kernel<<<BK_ROWS, 256>>>(h, lnh, ln2_scale + l * CD, ln2_bias + l * CD);
        tgemm_wide<true><<<dim3(CF / WBN, BK_ROWS / GBM), 256, TGEMW_SMEM>>>(
            lnh, wth + W1_OFF + (size_t)l * CD * CF, b1 + l * CF,
            midh, BK_ROWS, CF, CD);
        tgemm_kernel<<<dim3(CD / GBN, BK_ROWS / GBM), 256, TGEMM_SMEM>>>(
            midh, wth + W2_OFF + (size_t)l * CF * CD, b2 + l * CD, h, h,
            BK_ROWS, CD, CF);
    }

    // 5. assemble output: total (fused copy+scatter), idx, logits
    outfuse_kernel<<<CB * CT, 256>>>(x, h, invp, gate, out);
    if ((size_t)out_size >= BTD + CB * CK + CB * CT) {
        int ntail = CB * CK + CB * CT;
        tail_kernel<<<(ntail + 255) / 256, 256>>>(idxp, logits, out);
    }
}

// round 10
// speedup vs baseline: 7.1576x; 1.0419x over previous
#include <cuda_runtime.h>
#include <cuda_fp16.h>
#include <math.h>
#include <stdint.h>

// Problem constants
constexpr int CB = 2;      // batch
constexpr int CT = 4096;   // seq len
constexpr int CD = 1024;   // d_model
constexpr int CL = 2;      // layers
constexpr int CH = 16;     // heads
constexpr int CF = 4096;   // d_ff
constexpr int CK = 2048;   // top-k tokens
constexpr int BK_ROWS = CB * CK;
constexpr size_t BTD = (size_t)CB * CT * CD;

// Weight fp16 scratch offsets (elements)
constexpr size_t WQKV_OFF = 0;
constexpr size_t WQKV_SZ  = (size_t)CL * CD * 3 * CD;
constexpr size_t WO_OFF   = WQKV_OFF + WQKV_SZ;
constexpr size_t WO_SZ    = (size_t)CL * CD * CD;
constexpr size_t W1_OFF   = WO_OFF + WO_SZ;
constexpr size_t W1_SZ    = (size_t)CL * CD * CF;
constexpr size_t W2_OFF   = W1_OFF + W1_SZ;
constexpr size_t W2_SZ    = (size_t)CL * CF * CD;
constexpr size_t WTF_TOTAL = W2_OFF + W2_SZ;

// ---------------- scratch (static device globals) ---------------------------
__device__ float  g_logits[CB * CT];
__device__ int    g_sel[CB * CT];
__device__ int    g_idx[CB * CK];
__device__ int    g_inv[CB * CT];
__device__ float  g_gate[CB * CK];
__device__ float  g_h[BK_ROWS * CD];
__device__ __half g_lnh[BK_ROWS * CD];
__device__ __half g_qkvh[(size_t)BK_ROWS * 3 * CD];
__device__ __half g_attnh[BK_ROWS * CD];
__device__ __half g_midh[(size_t)BK_ROWS * CF];
__device__ __half g_wth[WTF_TOTAL];

__device__ __forceinline__ void mma_f16(float c[4], const uint32_t a[4],
                                        uint32_t b0, uint32_t b1) {
    asm volatile(
        "mma.sync.aligned.m16n8k16.row.col.f32.f16.f16.f32 "
        "{%0,%1,%2,%3}, {%4,%5,%6,%7}, {%8,%9}, {%0,%1,%2,%3};\n"
        : "+f"(c[0]), "+f"(c[1]), "+f"(c[2]), "+f"(c[3])
        : "r"(a[0]), "r"(a[1]), "r"(a[2]), "r"(a[3]), "r"(b0), "r"(b1));
}
__device__ __forceinline__ void ldsm_x4(uint32_t r[4], uint32_t saddr) {
    asm volatile("ldmatrix.sync.aligned.m8n8.x4.shared.b16 {%0,%1,%2,%3}, [%4];"
                 : "=r"(r[0]), "=r"(r[1]), "=r"(r[2]), "=r"(r[3]) : "r"(saddr));
}
__device__ __forceinline__ void ldsm_x4t(uint32_t r[4], uint32_t saddr) {
    asm volatile("ldmatrix.sync.aligned.m8n8.x4.trans.shared.b16 {%0,%1,%2,%3}, [%4];"
                 : "=r"(r[0]), "=r"(r[1]), "=r"(r[2]), "=r"(r[3]) : "r"(saddr));
}
__device__ __forceinline__ void cp16(uint32_t dst, const void* src) {
    asm volatile("cp.async.cg.shared.global [%0], [%1], 16;\n" :: "r"(dst), "l"(src));
}
__device__ __forceinline__ uint32_t pack_h2(float a, float b) {
    __half2 h = __floats2half2_rn(a, b);
    return *(uint32_t*)&h;
}

// ---------------- router ----------------------------------------------------
__global__ void router_kernel(const float* __restrict__ x,
                              const float* __restrict__ wr,
                              const float* __restrict__ br,
                              float* __restrict__ logits) {
    int gw = (blockIdx.x * blockDim.x + threadIdx.x) >> 5;
    if (gw >= CB * CT) return;
    int lane = threadIdx.x & 31;
    const float4* p = (const float4*)(x + (size_t)gw * CD);
    const float4* w4 = (const float4*)wr;
    float s = 0.f;
#pragma unroll
    for (int i = 0; i < CD / 128; i++) {
        float4 a = p[lane + i * 32];
        float4 w = w4[lane + i * 32];
        s += a.x * w.x + a.y * w.y + a.z * w.z + a.w * w.w;
    }
#pragma unroll
    for (int o = 16; o > 0; o >>= 1) s += __shfl_down_sync(0xffffffffu, s, o);
    if (lane == 0) logits[gw] = s + br[0];
}

// ---------------- top-K -----------------------------------------------------
__global__ void rank_kernel(const float* __restrict__ logits, int* __restrict__ sel) {
    int blk = blockIdx.x;
    int b = blk >> 6;
    int base = (blk & 63) * 64;
    __shared__ float lv[CT];
    int tid = threadIdx.x;
    for (int t = tid; t < CT; t += 256) lv[t] = logits[b * CT + t];
    __syncthreads();
    int tt = tid >> 2, part = tid & 3;
    int t = base + tt;
    float v = lv[t];
    int cnt = 0;
    int s0 = part * 1024;
#pragma unroll 8
    for (int s = s0; s < s0 + 1024; s++) {
        float u = lv[s];
        cnt += (u > v) || (u == v && s < t);
    }
    __shared__ int rk[64];
    if (part == 0) rk[tt] = 0;
    __syncthreads();
    atomicAdd(&rk[tt], cnt);
    __syncthreads();
    if (part == 0) sel[b * CT + t] = (rk[tt] < CK) ? 1 : 0;
}

__global__ void compact_kernel(const float* __restrict__ logits,
                               const int* __restrict__ sel,
                               int* __restrict__ idx_out,
                               int* __restrict__ inv_out,
                               float* __restrict__ gate_out) {
    int b = blockIdx.x;
    int tid = threadIdx.x;
    int f[4]; int c = 0;
#pragma unroll
    for (int i = 0; i < 4; i++) { f[i] = sel[b * CT + tid * 4 + i]; c += f[i]; }
    int lane = tid & 31, wid = tid >> 5;
    int incl = c;
#pragma unroll
    for (int o = 1; o < 32; o <<= 1) {
        int n = __shfl_up_sync(0xffffffffu, incl, o);
        if (lane >= o) incl += n;
    }
    __shared__ int wsum[32];
    if (lane == 31) wsum[wid] = incl;
    __syncthreads();
    if (wid == 0) {
        int w = wsum[lane];
#pragma unroll
        for (int o = 1; o < 32; o <<= 1) {
            int n = __shfl_up_sync(0xffffffffu, w, o);
            if (lane >= o) w += n;
        }
        wsum[lane] = w;
    }
    __syncthreads();
    int pos = (wid ? wsum[wid - 1] : 0) + incl - c;
#pragma unroll
    for (int i = 0; i < 4; i++) {
        int t = tid * 4 + i;
        if (f[i]) {
            idx_out[b * CK + pos] = t;
            inv_out[b * CT + t] = pos;
            float lg = logits[b * CT + t];
            gate_out[b * CK + pos] = 1.f / (1.f + expf(-lg));
            pos++;
        } else {
            inv_out[b * CT + t] = -1;
        }
    }
}

// ---------------- fused gather + first layernorm ------------------------------
__global__ void gather_ln_kernel(const float* __restrict__ x, const int* __restrict__ idx,
                                 const float* __restrict__ scale,
                                 const float* __restrict__ bias,
                                 float* __restrict__ h, __half* __restrict__ lnh) {
    int bk = blockIdx.x;
    int b = bk >> 11;
    int t = idx[bk];
    int tid = threadIdx.x;
    const float4* src = (const float4*)(x + ((size_t)b * CT + t) * CD);
    float4 v = src[tid];
    ((float4*)(h + (size_t)bk * CD))[tid] = v;
    float s = v.x + v.y + v.z + v.w;
    float ss = v.x * v.x + v.y * v.y + v.z * v.z + v.w * v.w;
#pragma unroll
    for (int o = 16; o > 0; o >>= 1) {
        s += __shfl_down_sync(0xffffffffu, s, o);
        ss += __shfl_down_sync(0xffffffffu, ss, o);
    }
    __shared__ float red[64];
    int lane = tid & 31, wid = tid >> 5;
    if (lane == 0) { red[wid] = s; red[32 + wid] = ss; }
    __syncthreads();
    if (tid == 0) {
        float S = 0, SS = 0;
#pragma unroll
        for (int w = 0; w < 8; w++) { S += red[w]; SS += red[32 + w]; }
        red[0] = S; red[32] = SS;
    }
    __syncthreads();
    float mean = red[0] * (1.f / CD);
    float var = red[32] * (1.f / CD) - mean * mean;
    float inv = rsqrtf(var + 1e-5f);
    float4 sc = ((const float4*)scale)[tid];
    float4 bi = ((const float4*)bias)[tid];
    __half2* o2 = (__half2*)(lnh + (size_t)bk * CD);
    o2[2 * tid] = __floats2half2_rn((v.x - mean) * inv * sc.x + bi.x,
                                    (v.y - mean) * inv * sc.y + bi.y);
    o2[2 * tid + 1] = __floats2half2_rn((v.z - mean) * inv * sc.z + bi.z,
                                        (v.w - mean) * inv * sc.w + bi.w);
}

// ---------------- layernorm (fp32 in -> fp16 out) ---------------------------
__global__ void layernorm_kernel(const float* __restrict__ in, __half* __restrict__ out,
                                 const float* __restrict__ scale,
                                 const float* __restrict__ bias) {
    int row = blockIdx.x;
    int tid = threadIdx.x;
    const float4* p = (const float4*)(in + (size_t)row * CD);
    float4 v = p[tid];
    float s = v.x + v.y + v.z + v.w;
    float ss = v.x * v.x + v.y * v.y + v.z * v.z + v.w * v.w;
#pragma unroll
    for (int o = 16; o > 0; o >>= 1) {
        s += __shfl_down_sync(0xffffffffu, s, o);
        ss += __shfl_down_sync(0xffffffffu, ss, o);
    }
    __shared__ float red[64];
    int lane = tid & 31, wid = tid >> 5;
    if (lane == 0) { red[wid] = s; red[32 + wid] = ss; }
    __syncthreads();
    if (tid == 0) {
        float S = 0, SS = 0;
#pragma unroll
        for (int w = 0; w < 8; w++) { S += red[w]; SS += red[32 + w]; }
        red[0] = S; red[32] = SS;
    }
    __syncthreads();
    float mean = red[0] * (1.f / CD);
    float var = red[32] * (1.f / CD) - mean * mean;
    float inv = rsqrtf(var + 1e-5f);
    float4 sc = ((const float4*)scale)[tid];
    float4 bi = ((const float4*)bias)[tid];
    __half2* o2 = (__half2*)(out + (size_t)row * CD);
    o2[2 * tid] = __floats2half2_rn((v.x - mean) * inv * sc.x + bi.x,
                                    (v.y - mean) * inv * sc.y + bi.y);
    o2[2 * tid + 1] = __floats2half2_rn((v.z - mean) * inv * sc.z + bi.z,
                                        (v.w - mean) * inv * sc.w + bi.w);
}

// ---------------- merged weight fp16 convert ---------------------------------
__global__ void cvtw_all_kernel(const float* __restrict__ wqkv,
                                const float* __restrict__ wo,
                                const float* __restrict__ w1,
                                const float* __restrict__ w2,
                                __half* __restrict__ dst) {
    constexpr size_t Q4 = WQKV_SZ / 4, O4 = WO_SZ / 4, A4 = W1_SZ / 4;
    size_t i = (size_t)blockIdx.x * blockDim.x + threadIdx.x;
    float4 v;
    if (i < Q4)                 v = ((const float4*)wqkv)[i];
    else if (i < Q4 + O4)       v = ((const float4*)wo)[i - Q4];
    else if (i < Q4 + O4 + A4)  v = ((const float4*)w1)[i - Q4 - O4];
    else                        v = ((const float4*)w2)[i - Q4 - O4 - A4];
    __half2* d2 = (__half2*)dst;
    d2[2 * i]     = __floats2half2_rn(v.x, v.y);
    d2[2 * i + 1] = __floats2half2_rn(v.z, v.w);
}

// ---------------- common GEMM bits -------------------------------------------
__device__ __forceinline__ float gelu_tanh(float x) {
    float x3 = x * x * x;
    float t = tanhf(0.7978845608028654f * (x + 0.044715f * x3));
    return 0.5f * x * (1.f + t);
}

// ============ narrow GEMM: 128x128x64, 3-stage cp.async, fp32 out + residual
constexpr int GBM = 128, GBN = 128, GBK = 64;
constexpr int AST = GBK + 8;
constexpr int BST = GBN + 8;
constexpr int ABUFH = GBM * AST;
constexpr int BBUFH = GBK * BST;
constexpr size_t TGEMM_SMEM = (size_t)(ABUFH + BBUFH) * 3 * sizeof(__half); // 107520

__global__ __launch_bounds__(256) void tgemm_kernel(
    const __half* __restrict__ A, const __half* __restrict__ W,
    const float* __restrict__ bias, const float* __restrict__ R,
    float* __restrict__ C, int M, int N, int Kd) {
    extern __shared__ __half dsm[];
    __half* As = dsm;
    __half* Bs = dsm + 3 * ABUFH;

    const int tid = threadIdx.x;
    const int bx = blockIdx.x, by = blockIdx.y;
    const int wid = tid >> 5, lane = tid & 31;
    const int warp_m = wid & 1;
    const int warp_n = wid >> 1;
    const int g = lane >> 2;
    const int tg = lane & 3;
    const int lm = (lane & 7) + ((lane >> 3) & 1) * 8;
    const int lk = ((lane >> 4) & 1) * 8;
    // x4t B addressing (validated in attention PV path)
    const int vrow = (lane & 7) + ((lane >> 3) & 1) * 8;
    const int vcol = ((lane >> 4) & 1) * 8;

    float c[4][4][4];
#pragma unroll
    for (int mi = 0; mi < 4; mi++)
#pragma unroll
        for (int ni = 0; ni < 4; ni++)
#pragma unroll
            for (int r = 0; r < 4; r++) c[mi][ni][r] = 0.f;

    const int ntiles = Kd / GBK;

    auto issue_tile = [&](int t, int buf) {
        int k0 = t * GBK;
        uint32_t abase = (uint32_t)__cvta_generic_to_shared(As + buf * ABUFH);
        uint32_t bbase = (uint32_t)__cvta_generic_to_shared(Bs + buf * BBUFH);
#pragma unroll
        for (int i = 0; i < 4; i++) {
            int q = tid + i * 256;
            int row = q >> 3, c8 = (q & 7) * 8;
            cp16(abase + (row * AST + c8) * 2, A + (size_t)(by * GBM + row) * Kd + k0 + c8);
        }
#pragma unroll
        for (int i = 0; i < 4; i++) {
            int q = tid + i * 256;
            int row = q >> 4, n8 = (q & 15) * 8;
            cp16(bbase + (row * BST + n8) * 2, W + (size_t)(k0 + row) * N + bx * GBN + n8);
        }
        asm volatile("cp.async.commit_group;\n");
    };

    issue_tile(0, 0);
    if (ntiles > 1) issue_tile(1, 1);
    for (int t = 0; t < ntiles; t++) {
        if (t + 2 < ntiles) {
            issue_tile(t + 2, (t + 2) % 3);
            asm volatile("cp.async.wait_group 2;\n");
        } else if (t + 1 < ntiles) {
            asm volatile("cp.async.wait_group 1;\n");
        } else {
            asm volatile("cp.async.wait_group 0;\n");
        }
        __syncthreads();
        int buf = t % 3;
        uint32_t Ab = (uint32_t)__cvta_generic_to_shared(As + buf * ABUFH);
        uint32_t Bb = (uint32_t)__cvta_generic_to_shared(Bs + buf * BBUFH);
        uint32_t a_off = Ab + ((warp_m * 64 + lm) * AST + lk) * 2;
#pragma unroll
        for (int ks = 0; ks < GBK / 16; ks++) {
            uint32_t a[4][4], b[4][2];
#pragma unroll
            for (int mi = 0; mi < 4; mi++)
                ldsm_x4(a[mi], a_off + (mi * 16 * AST + ks * 16) * 2);
#pragma unroll
            for (int ni = 0; ni < 4; ni += 2) {
                uint32_t b4[4];
                ldsm_x4t(b4, Bb + ((ks * 16 + vrow) * BST + warp_n * 32 + ni * 8 + vcol) * 2);
                b[ni][0] = b4[0]; b[ni][1] = b4[1];
                b[ni + 1][0] = b4[2]; b[ni + 1][1] = b4[3];
            }
#pragma unroll
            for (int mi = 0; mi < 4; mi++)
#pragma unroll
                for (int ni = 0; ni < 4; ni++)
                    mma_f16(c[mi][ni], a[mi], b[ni][0], b[ni][1]);
        }
        __syncthreads();
    }

#pragma unroll
    for (int mi = 0; mi < 4; mi++) {
        int m0 = by * GBM + warp_m * 64 + mi * 16 + g;
#pragma unroll
        for (int ni = 0; ni < 4; ni++) {
            int n0 = bx * GBN + warp_n * 32 + ni * 8 + 2 * tg;
            float b0 = bias[n0], b1 = bias[n0 + 1];
#pragma unroll
            for (int half = 0; half < 2; half++) {
                int m = m0 + half * 8;
                float v0 = c[mi][ni][half * 2 + 0] + b0;
                float v1 = c[mi][ni][half * 2 + 1] + b1;
                const float2 r2 = *(const float2*)(R + (size_t)m * N + n0);
                v0 += r2.x; v1 += r2.y;
                *(float2*)(C + (size_t)m * N + n0) = make_float2(v0, v1);
            }
        }
    }
}

// ============ wide GEMM: 128x256x64, 2-stage, fp16 out, opt GELU ============
constexpr int WBN = 256;
constexpr int BSTW = WBN + 8;
constexpr int BBUFW = GBK * BSTW;
constexpr size_t TGEMW_SMEM = (size_t)(ABUFH + BBUFW) * 2 * sizeof(__half);

template <bool GELU>
__global__ __launch_bounds__(256) void tgemm_wide(
    const __half* __restrict__ A, const __half* __restrict__ W,
    const float* __restrict__ bias, __half* __restrict__ C,
    int M, int N, int Kd) {
    extern __shared__ __half dsm[];
    __half* As = dsm;
    __half* Bs = dsm + 2 * ABUFH;

    const int tid = threadIdx.x;
    const int bx = blockIdx.x, by = blockIdx.y;
    const int wid = tid >> 5, lane = tid & 31;
    const int warp_m = wid & 1;
    const int warp_n = wid >> 1;
    const int g = lane >> 2;
    const int tg = lane & 3;
    const int lm = (lane & 7) + ((lane >> 3) & 1) * 8;
    const int lk = ((lane >> 4) & 1) * 8;
    const int vrow = (lane & 7) + ((lane >> 3) & 1) * 8;
    const int vcol = ((lane >> 4) & 1) * 8;

    float c[4][8][4];
#pragma unroll
    for (int mi = 0; mi < 4; mi++)
#pragma unroll
        for (int ni = 0; ni < 8; ni++)
#pragma unroll
            for (int r = 0; r < 4; r++) c[mi][ni][r] = 0.f;

    const int ntiles = Kd / GBK;

    auto issue_tile = [&](int t, int buf) {
        int k0 = t * GBK;
        uint32_t abase = (uint32_t)__cvta_generic_to_shared(As + buf * ABUFH);
        uint32_t bbase = (uint32_t)__cvta_generic_to_shared(Bs + buf * BBUFW);
#pragma unroll
        for (int i = 0; i < 4; i++) {
            int q = tid + i * 256;
            int row = q >> 3, c8 = (q & 7) * 8;
            cp16(abase + (row * AST + c8) * 2, A + (size_t)(by * GBM + row) * Kd + k0 + c8);
        }
#pragma unroll
        for (int i = 0; i < 8; i++) {
            int q = tid + i * 256;
            int row = q >> 5, n8 = (q & 31) * 8;
            cp16(bbase + (row * BSTW + n8) * 2, W + (size_t)(k0 + row) * N + bx * WBN + n8);
        }
        asm volatile("cp.async.commit_group;\n");
    };

    issue_tile(0, 0);
    for (int t = 0; t < ntiles; t++) {
        if (t + 1 < ntiles) {
            issue_tile(t + 1, (t + 1) & 1);
            asm volatile("cp.async.wait_group 1;\n");
        } else {
            asm volatile("cp.async.wait_group 0;\n");
        }
        __syncthreads();
        uint32_t Ab = (uint32_t)__cvta_generic_to_shared(As + (t & 1) * ABUFH);
        uint32_t Bb = (uint32_t)__cvta_generic_to_shared(Bs + (t & 1) * BBUFW);
        uint32_t a_off = Ab + ((warp_m * 64 + lm) * AST + lk) * 2;
#pragma unroll
        for (int ks = 0; ks < GBK / 16; ks++) {
            uint32_t a[4][4], b[8][2];
#pragma unroll
            for (int mi = 0; mi < 4; mi++)
                ldsm_x4(a[mi], a_off + (mi * 16 * AST + ks * 16) * 2);
#pragma unroll
            for (int ni = 0; ni < 8; ni += 2) {
                uint32_t b4[4];
                ldsm_x4t(b4, Bb + ((ks * 16 + vrow) * BSTW + warp_n * 64 + ni * 8 + vcol) * 2);
                b[ni][0] = b4[0]; b[ni][1] = b4[1];
                b[ni + 1][0] = b4[2]; b[ni + 1][1] = b4[3];
            }
#pragma unroll
            for (int mi = 0; mi < 4; mi++)
#pragma unroll
                for (int ni = 0; ni < 8; ni++)
                    mma_f16(c[mi][ni], a[mi], b[ni][0], b[ni][1]);
        }
        __syncthreads();
    }

#pragma unroll
    for (int mi = 0; mi < 4; mi++) {
        int m0 = by * GBM + warp_m * 64 + mi * 16 + g;
#pragma unroll
        for (int ni = 0; ni < 8; ni++) {
            int n0 = bx * WBN + warp_n * 64 + ni * 8 + 2 * tg;
            float b0 = bias[n0], b1 = bias[n0 + 1];
#pragma unroll
            for (int half = 0; half < 2; half++) {
                int m = m0 + half * 8;
                float v0 = c[mi][ni][half * 2 + 0] + b0;
                float v1 = c[mi][ni][half * 2 + 1] + b1;
                if (GELU) { v0 = gelu_tanh(v0); v1 = gelu_tanh(v1); }
                *(__half2*)(C + (size_t)m * N + n0) = __floats2half2_rn(v0, v1);
            }
        }
    }
}

// ---------------- FP16 MMA flash attention v3 (unchanged from R8) ------------
constexpr int SATT = 72;
constexpr int NQB = CK / 128;   // 16
__global__ __launch_bounds__(256) void attn_kernel(const __half* __restrict__ qkv,
                                                   __half* __restrict__ o) {
    const int pairi = blockIdx.x, h = blockIdx.y, b = blockIdx.z;
    const int tid = threadIdx.x;
    const int w = tid >> 5, lane = tid & 31;
    const int g = lane >> 2, tg = lane & 3;
    const int lm = (lane & 7) + ((lane >> 3) & 1) * 8;
    const int lk = ((lane >> 4) & 1) * 8;

    __shared__ __half KV[4][64 * SATT];
    uint32_t base[4];
#pragma unroll
    for (int i = 0; i < 4; i++) base[i] = (uint32_t)__cvta_generic_to_shared(KV[i]);

    const int srow = (lane & 7) + ((lane >> 4) & 1) * 8;
    const int scol = ((lane >> 3) & 1) * 8;
    const int vrow = (lane & 7) + ((lane >> 3) & 1) * 8;
    const int vcol = ((lane >> 4) & 1) * 8;

    const __half2 sc8 = __float2half2_rn(0.125f);

    for (int s = 0; s < 2; s++) {
        const int qb = (s == 0) ? pairi : (NQB - 1 - pairi);

#pragma unroll
        for (int i = 0; i < 4; i++) {
            int q = tid + i * 256;
            int r = q >> 3, c8 = (q & 7) * 8;
            const __half* src = qkv + ((size_t)(b * CK + qb * 128 + r)) * (3 * CD) + h * 64 + c8;
            uint4 u = *(const uint4*)src;
            __half2* hp = (__half2*)&u;
#pragma unroll
            for (int j = 0; j < 4; j++) hp[j] = __hmul2(hp[j], sc8);
            *(uint4*)&KV[0][r * SATT + c8] = u;
        }
        __syncthreads();
        uint32_t qf[4][4];
#pragma unroll
        for (int ks = 0; ks < 4; ks++)
            ldsm_x4(qf[ks], base[0] + ((w * 16 + lm) * SATT + ks * 16 + lk) * 2);
        __syncthreads();

        float of[8][4];
#pragma unroll
        for (int ni = 0; ni < 8; ni++)
#pragma unroll
            for (int r = 0; r < 4; r++) of[ni][r] = 0.f;
        float mi0 = -1e30f, mi1 = -1e30f, li0 = 0.f, li1 = 0.f;

        const int nt = 2 * qb + 2;
        const int rowg0 = qb * 128 + w * 16 + g;
        const int rowg1 = rowg0 + 8;

        auto issue = [&](int kt, int buf) {
            uint32_t kb = base[buf];
            uint32_t vb = base[2 + buf];
#pragma unroll
            for (int i = 0; i < 2; i++) {
                int q = tid + i * 256;
                int r = q >> 3, c8 = (q & 7) * 8;
                const __half* kbp = qkv + ((size_t)(b * CK + kt * 64 + r)) * (3 * CD) + CD + h * 64 + c8;
                cp16(kb + (r * SATT + c8) * 2, kbp);
                cp16(vb + (r * SATT + c8) * 2, kbp + CD);
            }
            asm volatile("cp.async.commit_group;\n");
        };

        issue(0, 0);
        for (int kt = 0; kt < nt; kt++) {
            if (kt + 1 < nt) {
                issue(kt + 1, (kt + 1) & 1);
                asm volatile("cp.async.wait_group 1;\n");
            } else {
                asm volatile("cp.async.wait_group 0;\n");
            }
            __syncthreads();
            uint32_t ksb = base[kt & 1];
            uint32_t vsb = base[2 + (kt & 1)];

            float sf[8][4];
#pragma unroll
            for (int ni = 0; ni < 8; ni++)
#pragma unroll
                for (int r = 0; r < 4; r++) sf[ni][r] = 0.f;
#pragma unroll
            for (int ks = 0; ks < 4; ks++) {
#pragma unroll
                for (int ni = 0; ni < 8; ni += 2) {
                    uint32_t b4[4];
                    ldsm_x4(b4, ksb + ((ni * 8 + srow) * SATT + ks * 16 + scol) * 2);
                    mma_f16(sf[ni],     qf[ks], b4[0], b4[1]);
                    mma_f16(sf[ni + 1], qf[ks], b4[2], b4[3]);
                }
            }

            if (kt >= 2 * qb) {
                int cbase = kt * 64;
#pragma unroll
                for (int ni = 0; ni < 8; ni++) {
                    int c0 = cbase + ni * 8 + 2 * tg, c1 = c0 + 1;
                    if (c0 > rowg0) sf[ni][0] = -1e30f;
                    if (c1 > rowg0) sf[ni][1] = -1e30f;
                    if (c0 > rowg1) sf[ni][2] = -1e30f;
                    if (c1 > rowg1) sf[ni][3] = -1e30f;
                }
            }

            float m0 = -1e30f, m1 = -1e30f;
#pragma unroll
            for (int ni = 0; ni < 8; ni++) {
                m0 = fmaxf(m0, fmaxf(sf[ni][0], sf[ni][1]));
                m1 = fmaxf(m1, fmaxf(sf[ni][2], sf[ni][3]));
            }
            m0 = fmaxf(m0, __shfl_xor_sync(0xffffffffu, m0, 1));
            m0 = fmaxf(m0, __shfl_xor_sync(0xffffffffu, m0, 2));
            m1 = fmaxf(m1, __shfl_xor_sync(0xffffffffu, m1, 1));
            m1 = fmaxf(m1, __shfl_xor_sync(0xffffffffu, m1, 2));
            float nm0 = fmaxf(mi0, m0), nm1 = fmaxf(mi1, m1);
            float co0 = __expf(mi0 - nm0), co1 = __expf(mi1 - nm1);
            float rs0 = 0.f, rs1 = 0.f;
#pragma unroll
            for (int ni = 0; ni < 8; ni++) {
                sf[ni][0] = __expf(sf[ni][0] - nm0);
                sf[ni][1] = __expf(sf[ni][1] - nm0);
                sf[ni][2] = __expf(sf[ni][2] - nm1);
                sf[ni][3] = __expf(sf[ni][3] - nm1);
                rs0 += sf[ni][0] + sf[ni][1];
                rs1 += sf[ni][2] + sf[ni][3];
            }
            rs0 += __shfl_xor_sync(0xffffffffu, rs0, 1);
            rs0 += __shfl_xor_sync(0xffffffffu, rs0, 2);
            rs1 += __shfl_xor_sync(0xffffffffu, rs1, 1);
            rs1 += __shfl_xor_sync(0xffffffffu, rs1, 2);
            li0 = li0 * co0 + rs0;
            li1 = li1 * co1 + rs1;
            mi0 = nm0; mi1 = nm1;
#pragma unroll
            for (int ni = 0; ni < 8; ni++) {
                of[ni][0] *= co0; of[ni][1] *= co0;
                of[ni][2] *= co1; of[ni][3] *= co1;
            }

#pragma unroll
            for (int js = 0; js < 4; js++) {
                uint32_t a[4];
                a[0] = pack_h2(sf[2 * js][0], sf[2 * js][1]);
                a[1] = pack_h2(sf[2 * js][2], sf[2 * js][3]);
                a[2] = pack_h2(sf[2 * js + 1][0], sf[2 * js + 1][1]);
                a[3] = pack_h2(sf[2 * js + 1][2], sf[2 * js + 1][3]);
#pragma unroll
                for (int ni = 0; ni < 8; ni += 2) {
                    uint32_t b4[4];
                    ldsm_x4t(b4, vsb + ((js * 16 + vrow) * SATT + (ni + (vcol >> 3)) * 8) * 2);
                    mma_f16(of[ni],     a, b4[0], b4[1]);
                    mma_f16(of[ni + 1], a, b4[2], b4[3]);
                }
            }
            __syncthreads();
        }

        float il0 = 1.f / li0, il1 = 1.f / li1;
#pragma unroll
        for (int ni = 0; ni < 8; ni++) {
            int col = h * 64 + ni * 8 + 2 * tg;
            *(__half2*)(o + ((size_t)(b * CK + rowg0)) * CD + col) =
                __floats2half2_rn(of[ni][0] * il0, of[ni][1] * il0);
            *(__half2*)(o + ((size_t)(b * CK + rowg1)) * CD + col) =
                __floats2half2_rn(of[ni][2] * il1, of[ni][3] * il1);
        }
    }
}

// ---------------- output assembly (fused copy + gated scatter) ---------------
__global__ void outfuse_kernel(const float* __restrict__ x,
                               const float* __restrict__ h,
                               const int* __restrict__ inv,
                               const float* __restrict__ gate,
                               float* __restrict__ out) {
    int row = blockIdx.x;
    int b = row >> 12;
    int pos = inv[row];
    const float4* src = (const float4*)(x + (size_t)row * CD);
    float4* dst = (float4*)(out + (size_t)row * CD);
    float4 v = src[threadIdx.x];
    if (pos >= 0) {
        float gval = gate[b * CK + pos];
        const float4* hp = (const float4*)(h + (size_t)(b * CK + pos) * CD);
        float4 hv = hp[threadIdx.x];
        v.x += hv.x * gval; v.y += hv.y * gval;
        v.z += hv.z * gval; v.w += hv.w * gval;
    }
    dst[threadIdx.x] = v;
}

__global__ void tail_kernel(const int* __restrict__ idx, const float* __restrict__ logits,
                            float* __restrict__ out) {
    int i = blockIdx.x * blockDim.x + threadIdx.x;
    if (i < CB * CK) {
        out[BTD + i] = (float)idx[i];
    } else if (i < CB * CK + CB * CT) {
        int j = i - CB * CK;
        out[BTD + CB * CK + j] = logits[j];
    }
}

// ---------------- launch -----------------------------------------------------
extern "C" void kernel_launch(void* const* d_in, const int* in_sizes, int n_in,
                              void* d_out, int out_size) {
    const float* x         = (const float*)d_in[0];
    const float* w_router  = (const float*)d_in[1];
    const float* b_router  = (const float*)d_in[2];
    const float* ln1_scale = (const float*)d_in[3];
    const float* ln1_bias  = (const float*)d_in[4];
    const float* w_qkv     = (const float*)d_in[5];
    const float* b_qkv     = (const float*)d_in[6];
    const float* w_o       = (const float*)d_in[7];
    const float* b_o       = (const float*)d_in[8];
    const float* ln2_scale = (const float*)d_in[9];
    const float* ln2_bias  = (const float*)d_in[10];
    const float* w1        = (const float*)d_in[11];
    const float* b1        = (const float*)d_in[12];
    const float* w2        = (const float*)d_in[13];
    const float* b2        = (const float*)d_in[14];
    float* out = (float*)d_out;

    float *logits, *gate, *h;
    int *sel, *idxp, *invp;
    __half *lnh, *qkvh, *attnh, *midh, *wth;
    cudaGetSymbolAddress((void**)&logits, g_logits);
    cudaGetSymbolAddress((void**)&sel, g_sel);
    cudaGetSymbolAddress((void**)&idxp, g_idx);
    cudaGetSymbolAddress((void**)&invp, g_inv);
    cudaGetSymbolAddress((void**)&gate, g_gate);
    cudaGetSymbolAddress((void**)&h, g_h);
    cudaGetSymbolAddress((void**)&lnh, g_lnh);
    cudaGetSymbolAddress((void**)&qkvh, g_qkvh);
    cudaGetSymbolAddress((void**)&attnh, g_attnh);
    cudaGetSymbolAddress((void**)&midh, g_midh);
    cudaGetSymbolAddress((void**)&wth, g_wth);

    cudaFuncSetAttribute(tgemm_kernel,
                         cudaFuncAttributeMaxDynamicSharedMemorySize, (int)TGEMM_SMEM);
    cudaFuncSetAttribute(tgemm_wide<false>,
                         cudaFuncAttributeMaxDynamicSharedMemorySize, (int)TGEMW_SMEM);
    cudaFuncSetAttribute(tgemm_wide<true>,
                         cudaFuncAttributeMaxDynamicSharedMemorySize, (int)TGEMW_SMEM);

    // 0. pre-convert all weights to fp16 (single kernel)
    cvtw_all_kernel<<<(int)(WTF_TOTAL / 4 / 256), 256>>>(w_qkv, w_o, w1, w2, wth);

    // 1-3. router, top-K, fused gather+LN1(layer0)
    router_kernel<<<(CB * CT) / 8, 256>>>(x, w_router, b_router, logits);
    rank_kernel<<<CB * 64, 256>>>(logits, sel);
    compact_kernel<<<CB, 1024>>>(logits, sel, idxp, invp, gate);
    gather_ln_kernel<<<BK_ROWS, 256>>>(x, idxp, ln1_scale, ln1_bias, h, lnh);

    // 4. transformer blocks
    for (int l = 0; l < CL; l++) {
        if (l > 0)
            layernorm_kernel<<<BK_ROWS, 256>>>(h, lnh, ln1_scale + l * CD, ln1_bias + l * CD);
        tgemm_wide<false><<<dim3(3 * CD / WBN, BK_ROWS / GBM), 256, TGEMW_SMEM>>>(
            lnh, wth + WQKV_OFF + (size_t)l * CD * 3 * CD, b_qkv + l * 3 * CD,
            qkvh, BK_ROWS, 3 * CD, CD);
        attn_kernel<<<dim3(NQB / 2, CH, CB), 256>>>(qkvh, attnh);
        tgemm_kernel<<<dim3(CD / GBN, BK_ROWS / GBM), 256, TGEMM_SMEM>>>(
            attnh, wth + WO_OFF + (size_t)l * CD * CD, b_o + l * CD, h, h,
            BK_ROWS, CD, CD);
        layernorm_kernel<<<BK_ROWS, 256>>>(h, lnh, ln2_scale + l * CD, ln2_bias + l * CD);
        tgemm_wide<true><<<dim3(CF / WBN, BK_ROWS / GBM), 256, TGEMW_SMEM>>>(
            lnh, wth + W1_OFF + (size_t)l * CD * CF, b1 + l * CF,
            midh, BK_ROWS, CF, CD);
        tgemm_kernel<<<dim3(CD / GBN, BK_ROWS / GBM), 256, TGEMM_SMEM>>>(
            midh, wth + W2_OFF + (size_t)l * CF * CD, b2 + l * CD, h, h,
            BK_ROWS, CD, CF);
    }

    // 5. assemble output: total (fused copy+scatter), idx, logits
    outfuse_kernel<<<CB * CT, 256>>>(x, h, invp, gate, out);
    if ((size_t)out_size >= BTD + CB * CK + CB * CT) {
        int ntail = CB * CK + CB * CT;
        tail_kernel<<<(ntail + 255) / 256, 256>>>(idxp, logits, out);
    }
}

// round 11
// speedup vs baseline: 7.1780x; 1.0029x over previous
#include <cuda_runtime.h>
#include <cuda_fp16.h>
#include <math.h>
#include <stdint.h>

// Problem constants
constexpr int CB = 2;      // batch
constexpr int CT = 4096;   // seq len
constexpr int CD = 1024;   // d_model
constexpr int CL = 2;      // layers
constexpr int CH = 16;     // heads
constexpr int CF = 4096;   // d_ff
constexpr int CK = 2048;   // top-k tokens
constexpr int BK_ROWS = CB * CK;
constexpr size_t BTD = (size_t)CB * CT * CD;

// Weight fp16 scratch offsets (elements)
constexpr size_t WQKV_OFF = 0;
constexpr size_t WQKV_SZ  = (size_t)CL * CD * 3 * CD;
constexpr size_t WO_OFF   = WQKV_OFF + WQKV_SZ;
constexpr size_t WO_SZ    = (size_t)CL * CD * CD;
constexpr size_t W1_OFF   = WO_OFF + WO_SZ;
constexpr size_t W1_SZ    = (size_t)CL * CD * CF;
constexpr size_t W2_OFF   = W1_OFF + W1_SZ;
constexpr size_t W2_SZ    = (size_t)CL * CF * CD;
constexpr size_t WTF_TOTAL = W2_OFF + W2_SZ;

// ---------------- scratch (static device globals) ---------------------------
__device__ float  g_logits[CB * CT];
__device__ int    g_sel[CB * CT];
__device__ int    g_idx[CB * CK];
__device__ int    g_inv[CB * CT];
__device__ float  g_gate[CB * CK];
__device__ float  g_h[BK_ROWS * CD];
__device__ __half g_lnh[BK_ROWS * CD];
__device__ __half g_qkvh[(size_t)BK_ROWS * 3 * CD];
__device__ __half g_attnh[BK_ROWS * CD];
__device__ __half g_midh[(size_t)BK_ROWS * CF];
__device__ __half g_wth[WTF_TOTAL];

__device__ __forceinline__ void mma_f16(float c[4], const uint32_t a[4],
                                        uint32_t b0, uint32_t b1) {
    asm volatile(
        "mma.sync.aligned.m16n8k16.row.col.f32.f16.f16.f32 "
        "{%0,%1,%2,%3}, {%4,%5,%6,%7}, {%8,%9}, {%0,%1,%2,%3};\n"
        : "+f"(c[0]), "+f"(c[1]), "+f"(c[2]), "+f"(c[3])
        : "r"(a[0]), "r"(a[1]), "r"(a[2]), "r"(a[3]), "r"(b0), "r"(b1));
}
__device__ __forceinline__ void ldsm_x4(uint32_t r[4], uint32_t saddr) {
    asm volatile("ldmatrix.sync.aligned.m8n8.x4.shared.b16 {%0,%1,%2,%3}, [%4];"
                 : "=r"(r[0]), "=r"(r[1]), "=r"(r[2]), "=r"(r[3]) : "r"(saddr));
}
__device__ __forceinline__ void ldsm_x4t(uint32_t r[4], uint32_t saddr) {
    asm volatile("ldmatrix.sync.aligned.m8n8.x4.trans.shared.b16 {%0,%1,%2,%3}, [%4];"
                 : "=r"(r[0]), "=r"(r[1]), "=r"(r[2]), "=r"(r[3]) : "r"(saddr));
}
__device__ __forceinline__ void cp16(uint32_t dst, const void* src) {
    asm volatile("cp.async.cg.shared.global [%0], [%1], 16;\n" :: "r"(dst), "l"(src));
}
__device__ __forceinline__ uint32_t pack_h2(float a, float b) {
    __half2 h = __floats2half2_rn(a, b);
    return *(uint32_t*)&h;
}

// ---------------- router ----------------------------------------------------
__global__ void router_kernel(const float* __restrict__ x,
                              const float* __restrict__ wr,
                              const float* __restrict__ br,
                              float* __restrict__ logits) {
    int gw = (blockIdx.x * blockDim.x + threadIdx.x) >> 5;
    if (gw >= CB * CT) return;
    int lane = threadIdx.x & 31;
    const float4* p = (const float4*)(x + (size_t)gw * CD);
    const float4* w4 = (const float4*)wr;
    float s = 0.f;
#pragma unroll
    for (int i = 0; i < CD / 128; i++) {
        float4 a = p[lane + i * 32];
        float4 w = w4[lane + i * 32];
        s += a.x * w.x + a.y * w.y + a.z * w.z + a.w * w.w;
    }
#pragma unroll
    for (int o = 16; o > 0; o >>= 1) s += __shfl_down_sync(0xffffffffu, s, o);
    if (lane == 0) logits[gw] = s + br[0];
}

// ---------------- top-K -----------------------------------------------------
__global__ void rank_kernel(const float* __restrict__ logits, int* __restrict__ sel) {
    int blk = blockIdx.x;
    int b = blk >> 6;
    int base = (blk & 63) * 64;
    __shared__ float lv[CT];
    int tid = threadIdx.x;
    for (int t = tid; t < CT; t += 256) lv[t] = logits[b * CT + t];
    __syncthreads();
    int tt = tid >> 2, part = tid & 3;
    int t = base + tt;
    float v = lv[t];
    int cnt = 0;
    int s0 = part * 1024;
#pragma unroll 8
    for (int s = s0; s < s0 + 1024; s++) {
        float u = lv[s];
        cnt += (u > v) || (u == v && s < t);
    }
    __shared__ int rk[64];
    if (part == 0) rk[tt] = 0;
    __syncthreads();
    atomicAdd(&rk[tt], cnt);
    __syncthreads();
    if (part == 0) sel[b * CT + t] = (rk[tt] < CK) ? 1 : 0;
}

__global__ void compact_kernel(const float* __restrict__ logits,
                               const int* __restrict__ sel,
                               int* __restrict__ idx_out,
                               int* __restrict__ inv_out,
                               float* __restrict__ gate_out) {
    int b = blockIdx.x;
    int tid = threadIdx.x;
    int f[4]; int c = 0;
#pragma unroll
    for (int i = 0; i < 4; i++) { f[i] = sel[b * CT + tid * 4 + i]; c += f[i]; }
    int lane = tid & 31, wid = tid >> 5;
    int incl = c;
#pragma unroll
    for (int o = 1; o < 32; o <<= 1) {
        int n = __shfl_up_sync(0xffffffffu, incl, o);
        if (lane >= o) incl += n;
    }
    __shared__ int wsum[32];
    if (lane == 31) wsum[wid] = incl;
    __syncthreads();
    if (wid == 0) {
        int w = wsum[lane];
#pragma unroll
        for (int o = 1; o < 32; o <<= 1) {
            int n = __shfl_up_sync(0xffffffffu, w, o);
            if (lane >= o) w += n;
        }
        wsum[lane] = w;
    }
    __syncthreads();
    int pos = (wid ? wsum[wid - 1] : 0) + incl - c;
#pragma unroll
    for (int i = 0; i < 4; i++) {
        int t = tid * 4 + i;
        if (f[i]) {
            idx_out[b * CK + pos] = t;
            inv_out[b * CT + t] = pos;
            float lg = logits[b * CT + t];
            gate_out[b * CK + pos] = 1.f / (1.f + expf(-lg));
            pos++;
        } else {
            inv_out[b * CT + t] = -1;
        }
    }
}

// ---------------- fused gather + first layernorm ------------------------------
__global__ void gather_ln_kernel(const float* __restrict__ x, const int* __restrict__ idx,
                                 const float* __restrict__ scale,
                                 const float* __restrict__ bias,
                                 float* __restrict__ h, __half* __restrict__ lnh) {
    int bk = blockIdx.x;
    int b = bk >> 11;
    int t = idx[bk];
    int tid = threadIdx.x;
    const float4* src = (const float4*)(x + ((size_t)b * CT + t) * CD);
    float4 v = src[tid];
    ((float4*)(h + (size_t)bk * CD))[tid] = v;
    float s = v.x + v.y + v.z + v.w;
    float ss = v.x * v.x + v.y * v.y + v.z * v.z + v.w * v.w;
#pragma unroll
    for (int o = 16; o > 0; o >>= 1) {
        s += __shfl_down_sync(0xffffffffu, s, o);
        ss += __shfl_down_sync(0xffffffffu, ss, o);
    }
    __shared__ float red[64];
    int lane = tid & 31, wid = tid >> 5;
    if (lane == 0) { red[wid] = s; red[32 + wid] = ss; }
    __syncthreads();
    if (tid == 0) {
        float S = 0, SS = 0;
#pragma unroll
        for (int w = 0; w < 8; w++) { S += red[w]; SS += red[32 + w]; }
        red[0] = S; red[32] = SS;
    }
    __syncthreads();
    float mean = red[0] * (1.f / CD);
    float var = red[32] * (1.f / CD) - mean * mean;
    float inv = rsqrtf(var + 1e-5f);
    float4 sc = ((const float4*)scale)[tid];
    float4 bi = ((const float4*)bias)[tid];
    __half2* o2 = (__half2*)(lnh + (size_t)bk * CD);
    o2[2 * tid] = __floats2half2_rn((v.x - mean) * inv * sc.x + bi.x,
                                    (v.y - mean) * inv * sc.y + bi.y);
    o2[2 * tid + 1] = __floats2half2_rn((v.z - mean) * inv * sc.z + bi.z,
                                        (v.w - mean) * inv * sc.w + bi.w);
}

// ---------------- layernorm (fp32 in -> fp16 out) ---------------------------
__global__ void layernorm_kernel(const float* __restrict__ in, __half* __restrict__ out,
                                 const float* __restrict__ scale,
                                 const float* __restrict__ bias) {
    int row = blockIdx.x;
    int tid = threadIdx.x;
    const float4* p = (const float4*)(in + (size_t)row * CD);
    float4 v = p[tid];
    float s = v.x + v.y + v.z + v.w;
    float ss = v.x * v.x + v.y * v.y + v.z * v.z + v.w * v.w;
#pragma unroll
    for (int o = 16; o > 0; o >>= 1) {
        s += __shfl_down_sync(0xffffffffu, s, o);
        ss += __shfl_down_sync(0xffffffffu, ss, o);
    }
    __shared__ float red[64];
    int lane = tid & 31, wid = tid >> 5;
    if (lane == 0) { red[wid] = s; red[32 + wid] = ss; }
    __syncthreads();
    if (tid == 0) {
        float S = 0, SS = 0;
#pragma unroll
        for (int w = 0; w < 8; w++) { S += red[w]; SS += red[32 + w]; }
        red[0] = S; red[32] = SS;
    }
    __syncthreads();
    float mean = red[0] * (1.f / CD);
    float var = red[32] * (1.f / CD) - mean * mean;
    float inv = rsqrtf(var + 1e-5f);
    float4 sc = ((const float4*)scale)[tid];
    float4 bi = ((const float4*)bias)[tid];
    __half2* o2 = (__half2*)(out + (size_t)row * CD);
    o2[2 * tid] = __floats2half2_rn((v.x - mean) * inv * sc.x + bi.x,
                                    (v.y - mean) * inv * sc.y + bi.y);
    o2[2 * tid + 1] = __floats2half2_rn((v.z - mean) * inv * sc.z + bi.z,
                                        (v.w - mean) * inv * sc.w + bi.w);
}

// ---------------- merged weight fp16 convert (4x strided float4/thread) ------
constexpr int CVT_THREADS_TOTAL = (int)(WTF_TOTAL / 4 / 4);   // 1,572,864
__global__ void cvtw_all_kernel(const float* __restrict__ wqkv,
                                const float* __restrict__ wo,
                                const float* __restrict__ w1,
                                const float* __restrict__ w2,
                                __half* __restrict__ dst) {
    constexpr size_t Q4 = WQKV_SZ / 4, O4 = WO_SZ / 4, A4 = W1_SZ / 4;
    const size_t stride = (size_t)CVT_THREADS_TOTAL;
    size_t i0 = (size_t)blockIdx.x * blockDim.x + threadIdx.x;
    __half2* d2 = (__half2*)dst;
#pragma unroll
    for (int j = 0; j < 4; j++) {
        size_t i = i0 + (size_t)j * stride;
        float4 v;
        if (i < Q4)                 v = ((const float4*)wqkv)[i];
        else if (i < Q4 + O4)       v = ((const float4*)wo)[i - Q4];
        else if (i < Q4 + O4 + A4)  v = ((const float4*)w1)[i - Q4 - O4];
        else                        v = ((const float4*)w2)[i - Q4 - O4 - A4];
        d2[2 * i]     = __floats2half2_rn(v.x, v.y);
        d2[2 * i + 1] = __floats2half2_rn(v.z, v.w);
    }
}

// ---------------- common GEMM bits -------------------------------------------
__device__ __forceinline__ float gelu_tanh(float x) {
    float x3 = x * x * x;
    float t = tanhf(0.7978845608028654f * (x + 0.044715f * x3));
    return 0.5f * x * (1.f + t);
}

// ============ narrow GEMM: 128x128x64, 3-stage cp.async, fp32 out + residual
constexpr int GBM = 128, GBN = 128, GBK = 64;
constexpr int AST = GBK + 8;
constexpr int BST = GBN + 8;
constexpr int ABUFH = GBM * AST;
constexpr int BBUFH = GBK * BST;
constexpr size_t TGEMM_SMEM = (size_t)(ABUFH + BBUFH) * 3 * sizeof(__half); // 107520

__global__ __launch_bounds__(256) void tgemm_kernel(
    const __half* __restrict__ A, const __half* __restrict__ W,
    const float* __restrict__ bias, const float* __restrict__ R,
    float* __restrict__ C, int M, int N, int Kd) {
    extern __shared__ __half dsm[];
    __half* As = dsm;
    __half* Bs = dsm + 3 * ABUFH;

    const int tid = threadIdx.x;
    const int bx = blockIdx.x, by = blockIdx.y;
    const int wid = tid >> 5, lane = tid & 31;
    const int warp_m = wid & 1;
    const int warp_n = wid >> 1;
    const int g = lane >> 2;
    const int tg = lane & 3;
    const int lm = (lane & 7) + ((lane >> 3) & 1) * 8;
    const int lk = ((lane >> 4) & 1) * 8;
    const int vrow = (lane & 7) + ((lane >> 3) & 1) * 8;
    const int vcol = ((lane >> 4) & 1) * 8;

    float c[4][4][4];
#pragma unroll
    for (int mi = 0; mi < 4; mi++)
#pragma unroll
        for (int ni = 0; ni < 4; ni++)
#pragma unroll
            for (int r = 0; r < 4; r++) c[mi][ni][r] = 0.f;

    const int ntiles = Kd / GBK;

    auto issue_tile = [&](int t, int buf) {
        int k0 = t * GBK;
        uint32_t abase = (uint32_t)__cvta_generic_to_shared(As + buf * ABUFH);
        uint32_t bbase = (uint32_t)__cvta_generic_to_shared(Bs + buf * BBUFH);
#pragma unroll
        for (int i = 0; i < 4; i++) {
            int q = tid + i * 256;
            int row = q >> 3, c8 = (q & 7) * 8;
            cp16(abase + (row * AST + c8) * 2, A + (size_t)(by * GBM + row) * Kd + k0 + c8);
        }
#pragma unroll
        for (int i = 0; i < 4; i++) {
            int q = tid + i * 256;
            int row = q >> 4, n8 = (q & 15) * 8;
            cp16(bbase + (row * BST + n8) * 2, W + (size_t)(k0 + row) * N + bx * GBN + n8);
        }
        asm volatile("cp.async.commit_group;\n");
    };

    issue_tile(0, 0);
    if (ntiles > 1) issue_tile(1, 1);
    for (int t = 0; t < ntiles; t++) {
        if (t + 2 < ntiles) {
            issue_tile(t + 2, (t + 2) % 3);
            asm volatile("cp.async.wait_group 2;\n");
        } else if (t + 1 < ntiles) {
            asm volatile("cp.async.wait_group 1;\n");
        } else {
            asm volatile("cp.async.wait_group 0;\n");
        }
        __syncthreads();
        int buf = t % 3;
        uint32_t Ab = (uint32_t)__cvta_generic_to_shared(As + buf * ABUFH);
        uint32_t Bb = (uint32_t)__cvta_generic_to_shared(Bs + buf * BBUFH);
        uint32_t a_off = Ab + ((warp_m * 64 + lm) * AST + lk) * 2;
#pragma unroll
        for (int ks = 0; ks < GBK / 16; ks++) {
            uint32_t a[4][4], b[4][2];
#pragma unroll
            for (int mi = 0; mi < 4; mi++)
                ldsm_x4(a[mi], a_off + (mi * 16 * AST + ks * 16) * 2);
#pragma unroll
            for (int ni = 0; ni < 4; ni += 2) {
                uint32_t b4[4];
                ldsm_x4t(b4, Bb + ((ks * 16 + vrow) * BST + warp_n * 32 + ni * 8 + vcol) * 2);
                b[ni][0] = b4[0]; b[ni][1] = b4[1];
                b[ni + 1][0] = b4[2]; b[ni + 1][1] = b4[3];
            }
#pragma unroll
            for (int mi = 0; mi < 4; mi++)
#pragma unroll
                for (int ni = 0; ni < 4; ni++)
                    mma_f16(c[mi][ni], a[mi], b[ni][0], b[ni][1]);
        }
        __syncthreads();
    }

#pragma unroll
    for (int mi = 0; mi < 4; mi++) {
        int m0 = by * GBM + warp_m * 64 + mi * 16 + g;
#pragma unroll
        for (int ni = 0; ni < 4; ni++) {
            int n0 = bx * GBN + warp_n * 32 + ni * 8 + 2 * tg;
            float b0 = bias[n0], b1 = bias[n0 + 1];
#pragma unroll
            for (int half = 0; half < 2; half++) {
                int m = m0 + half * 8;
                float v0 = c[mi][ni][half * 2 + 0] + b0;
                float v1 = c[mi][ni][half * 2 + 1] + b1;
                const float2 r2 = *(const float2*)(R + (size_t)m * N + n0);
                v0 += r2.x; v1 += r2.y;
                *(float2*)(C + (size_t)m * N + n0) = make_float2(v0, v1);
            }
        }
    }
}

// ============ wide GEMM: 128x256x64, 4-stage cp.async, fp16 out, opt GELU ===
constexpr int WBN = 256;
constexpr int BSTW = WBN + 8;
constexpr int BBUFW = GBK * BSTW;
constexpr size_t TGEMW_SMEM = (size_t)(ABUFH + BBUFW) * 4 * sizeof(__half); // 208896

template <bool GELU>
__global__ __launch_bounds__(256) void tgemm_wide(
    const __half* __restrict__ A, const __half* __restrict__ W,
    const float* __restrict__ bias, __half* __restrict__ C,
    int M, int N, int Kd) {
    extern __shared__ __half dsm[];
    __half* As = dsm;
    __half* Bs = dsm + 4 * ABUFH;

    const int tid = threadIdx.x;
    const int bx = blockIdx.x, by = blockIdx.y;
    const int wid = tid >> 5, lane = tid & 31;
    const int warp_m = wid & 1;
    const int warp_n = wid >> 1;
    const int g = lane >> 2;
    const int tg = lane & 3;
    const int lm = (lane & 7) + ((lane >> 3) & 1) * 8;
    const int lk = ((lane >> 4) & 1) * 8;
    const int vrow = (lane & 7) + ((lane >> 3) & 1) * 8;
    const int vcol = ((lane >> 4) & 1) * 8;

    float c[4][8][4];
#pragma unroll
    for (int mi = 0; mi < 4; mi++)
#pragma unroll
        for (int ni = 0; ni < 8; ni++)
#pragma unroll
            for (int r = 0; r < 4; r++) c[mi][ni][r] = 0.f;

    const int ntiles = Kd / GBK;

    auto issue_tile = [&](int t, int buf) {
        int k0 = t * GBK;
        uint32_t abase = (uint32_t)__cvta_generic_to_shared(As + buf * ABUFH);
        uint32_t bbase = (uint32_t)__cvta_generic_to_shared(Bs + buf * BBUFW);
#pragma unroll
        for (int i = 0; i < 4; i++) {
            int q = tid + i * 256;
            int row = q >> 3, c8 = (q & 7) * 8;
            cp16(abase + (row * AST + c8) * 2, A + (size_t)(by * GBM + row) * Kd + k0 + c8);
        }
#pragma unroll
        for (int i = 0; i < 8; i++) {
            int q = tid + i * 256;
            int row = q >> 5, n8 = (q & 31) * 8;
            cp16(bbase + (row * BSTW + n8) * 2, W + (size_t)(k0 + row) * N + bx * WBN + n8);
        }
        asm volatile("cp.async.commit_group;\n");
    };

    issue_tile(0, 0);
    if (ntiles > 1) issue_tile(1, 1);
    if (ntiles > 2) issue_tile(2, 2);
    for (int t = 0; t < ntiles; t++) {
        if (t + 3 < ntiles) {
            issue_tile(t + 3, (t + 3) & 3);
            asm volatile("cp.async.wait_group 3;\n");
        } else if (t + 2 < ntiles) {
            asm volatile("cp.async.wait_group 2;\n");
        } else if (t + 1 < ntiles) {
            asm volatile("cp.async.wait_group 1;\n");
        } else {
            asm volatile("cp.async.wait_group 0;\n");
        }
        __syncthreads();
        int buf = t & 3;
        uint32_t Ab = (uint32_t)__cvta_generic_to_shared(As + buf * ABUFH);
        uint32_t Bb = (uint32_t)__cvta_generic_to_shared(Bs + buf * BBUFW);
        uint32_t a_off = Ab + ((warp_m * 64 + lm) * AST + lk) * 2;
#pragma unroll
        for (int ks = 0; ks < GBK / 16; ks++) {
            uint32_t a[4][4], b[8][2];
#pragma unroll
            for (int mi = 0; mi < 4; mi++)
                ldsm_x4(a[mi], a_off + (mi * 16 * AST + ks * 16) * 2);
#pragma unroll
            for (int ni = 0; ni < 8; ni += 2) {
                uint32_t b4[4];
                ldsm_x4t(b4, Bb + ((ks * 16 + vrow) * BSTW + warp_n * 64 + ni * 8 + vcol) * 2);
                b[ni][0] = b4[0]; b[ni][1] = b4[1];
                b[ni + 1][0] = b4[2]; b[ni + 1][1] = b4[3];
            }
#pragma unroll
            for (int mi = 0; mi < 4; mi++)
#pragma unroll
                for (int ni = 0; ni < 8; ni++)
                    mma_f16(c[mi][ni], a[mi], b[ni][0], b[ni][1]);
        }
        __syncthreads();
    }

#pragma unroll
    for (int mi = 0; mi < 4; mi++) {
        int m0 = by * GBM + warp_m * 64 + mi * 16 + g;
#pragma unroll
        for (int ni = 0; ni < 8; ni++) {
            int n0 = bx * WBN + warp_n * 64 + ni * 8 + 2 * tg;
            float b0 = bias[n0], b1 = bias[n0 + 1];
#pragma unroll
            for (int half = 0; half < 2; half++) {
                int m = m0 + half * 8;
                float v0 = c[mi][ni][half * 2 + 0] + b0;
                float v1 = c[mi][ni][half * 2 + 1] + b1;
                if (GELU) { v0 = gelu_tanh(v0); v1 = gelu_tanh(v1); }
                *(__half2*)(C + (size_t)m * N + n0) = __floats2half2_rn(v0, v1);
            }
        }
    }
}

// ---------------- FP16 MMA flash attention v3 (unchanged) --------------------
constexpr int SATT = 72;
constexpr int NQB = CK / 128;   // 16
__global__ __launch_bounds__(256) void attn_kernel(const __half* __restrict__ qkv,
                                                   __half* __restrict__ o) {
    const int pairi = blockIdx.x, h = blockIdx.y, b = blockIdx.z;
    const int tid = threadIdx.x;
    const int w = tid >> 5, lane = tid & 31;
    const int g = lane >> 2, tg = lane & 3;
    const int lm = (lane & 7) + ((lane >> 3) & 1) * 8;
    const int lk = ((lane >> 4) & 1) * 8;

    __shared__ __half KV[4][64 * SATT];
    uint32_t base[4];
#pragma unroll
    for (int i = 0; i < 4; i++) base[i] = (uint32_t)__cvta_generic_to_shared(KV[i]);

    const int srow = (lane & 7) + ((lane >> 4) & 1) * 8;
    const int scol = ((lane >> 3) & 1) * 8;
    const int vrow = (lane & 7) + ((lane >> 3) & 1) * 8;
    const int vcol = ((lane >> 4) & 1) * 8;

    const __half2 sc8 = __float2half2_rn(0.125f);

    for (int s = 0; s < 2; s++) {
        const int qb = (s == 0) ? pairi : (NQB - 1 - pairi);

#pragma unroll
        for (int i = 0; i < 4; i++) {
            int q = tid + i * 256;
            int r = q >> 3, c8 = (q & 7) * 8;
            const __half* src = qkv + ((size_t)(b * CK + qb * 128 + r)) * (3 * CD) + h * 64 + c8;
            uint4 u = *(const uint4*)src;
            __half2* hp = (__half2*)&u;
#pragma unroll
            for (int j = 0; j < 4; j++) hp[j] = __hmul2(hp[j], sc8);
            *(uint4*)&KV[0][r * SATT + c8] = u;
        }
        __syncthreads();
        uint32_t qf[4][4];
#pragma unroll
        for (int ks = 0; ks < 4; ks++)
            ldsm_x4(qf[ks], base[0] + ((w * 16 + lm) * SATT + ks * 16 + lk) * 2);
        __syncthreads();

        float of[8][4];
#pragma unroll
        for (int ni = 0; ni < 8; ni++)
#pragma unroll
            for (int r = 0; r < 4; r++) of[ni][r] = 0.f;
        float mi0 = -1e30f, mi1 = -1e30f, li0 = 0.f, li1 = 0.f;

        const int nt = 2 * qb + 2;
        const int rowg0 = qb * 128 + w * 16 + g;
        const int rowg1 = rowg0 + 8;

        auto issue = [&](int kt, int buf) {
            uint32_t kb = base[buf];
            uint32_t vb = base[2 + buf];
#pragma unroll
            for (int i = 0; i < 2; i++) {
                int q = tid + i * 256;
                int r = q >> 3, c8 = (q & 7) * 8;
                const __half* kbp = qkv + ((size_t)(b * CK + kt * 64 + r)) * (3 * CD) + CD + h * 64 + c8;
                cp16(kb + (r * SATT + c8) * 2, kbp);
                cp16(vb + (r * SATT + c8) * 2, kbp + CD);
            }
            asm volatile("cp.async.commit_group;\n");
        };

        issue(0, 0);
        for (int kt = 0; kt < nt; kt++) {
            if (kt + 1 < nt) {
                issue(kt + 1, (kt + 1) & 1);
                asm volatile("cp.async.wait_group 1;\n");
            } else {
                asm volatile("cp.async.wait_group 0;\n");
            }
            __syncthreads();
            uint32_t ksb = base[kt & 1];
            uint32_t vsb = base[2 + (kt & 1)];

            float sf[8][4];
#pragma unroll
            for (int ni = 0; ni < 8; ni++)
#pragma unroll
                for (int r = 0; r < 4; r++) sf[ni][r] = 0.f;
#pragma unroll
            for (int ks = 0; ks < 4; ks++) {
#pragma unroll
                for (int ni = 0; ni < 8; ni += 2) {
                    uint32_t b4[4];
                    ldsm_x4(b4, ksb + ((ni * 8 + srow) * SATT + ks * 16 + scol) * 2);
                    mma_f16(sf[ni],     qf[ks], b4[0], b4[1]);
                    mma_f16(sf[ni + 1], qf[ks], b4[2], b4[3]);
                }
            }

            if (kt >= 2 * qb) {
                int cbase = kt * 64;
#pragma unroll
                for (int ni = 0; ni < 8; ni++) {
                    int c0 = cbase + ni * 8 + 2 * tg, c1 = c0 + 1;
                    if (c0 > rowg0) sf[ni][0] = -1e30f;
                    if (c1 > rowg0) sf[ni][1] = -1e30f;
                    if (c0 > rowg1) sf[ni][2] = -1e30f;
                    if (c1 > rowg1) sf[ni][3] = -1e30f;
                }
            }

            float m0 = -1e30f, m1 = -1e30f;
#pragma unroll
            for (int ni = 0; ni < 8; ni++) {
                m0 = fmaxf(m0, fmaxf(sf[ni][0], sf[ni][1]));
                m1 = fmaxf(m1, fmaxf(sf[ni][2], sf[ni][3]));
            }
            m0 = fmaxf(m0, __shfl_xor_sync(0xffffffffu, m0, 1));
            m0 = fmaxf(m0, __shfl_xor_sync(0xffffffffu, m0, 2));
            m1 = fmaxf(m1, __shfl_xor_sync(0xffffffffu, m1, 1));
            m1 = fmaxf(m1, __shfl_xor_sync(0xffffffffu, m1, 2));
            float nm0 = fmaxf(mi0, m0), nm1 = fmaxf(mi1, m1);
            float co0 = __expf(mi0 - nm0), co1 = __expf(mi1 - nm1);
            float rs0 = 0.f, rs1 = 0.f;
#pragma unroll
            for (int ni = 0; ni < 8; ni++) {
                sf[ni][0] = __expf(sf[ni][0] - nm0);
                sf[ni][1] = __expf(sf[ni][1] - nm0);
                sf[ni][2] = __expf(sf[ni][2] - nm1);
                sf[ni][3] = __expf(sf[ni][3] - nm1);
                rs0 += sf[ni][0] + sf[ni][1];
                rs1 += sf[ni][2] + sf[ni][3];
            }
            rs0 += __shfl_xor_sync(0xffffffffu, rs0, 1);
            rs0 += __shfl_xor_sync(0xffffffffu, rs0, 2);
            rs1 += __shfl_xor_sync(0xffffffffu, rs1, 1);
            rs1 += __shfl_xor_sync(0xffffffffu, rs1, 2);
            li0 = li0 * co0 + rs0;
            li1 = li1 * co1 + rs1;
            mi0 = nm0; mi1 = nm1;
#pragma unroll
            for (int ni = 0; ni < 8; ni++) {
                of[ni][0] *= co0; of[ni][1] *= co0;
                of[ni][2] *= co1; of[ni][3] *= co1;
            }

#pragma unroll
            for (int js = 0; js < 4; js++) {
                uint32_t a[4];
                a[0] = pack_h2(sf[2 * js][0], sf[2 * js][1]);
                a[1] = pack_h2(sf[2 * js][2], sf[2 * js][3]);
                a[2] = pack_h2(sf[2 * js + 1][0], sf[2 * js + 1][1]);
                a[3] = pack_h2(sf[2 * js + 1][2], sf[2 * js + 1][3]);
#pragma unroll
                for (int ni = 0; ni < 8; ni += 2) {
                    uint32_t b4[4];
                    ldsm_x4t(b4, vsb + ((js * 16 + vrow) * SATT + (ni + (vcol >> 3)) * 8) * 2);
                    mma_f16(of[ni],     a, b4[0], b4[1]);
                    mma_f16(of[ni + 1], a, b4[2], b4[3]);
                }
            }
            __syncthreads();
        }

        float il0 = 1.f / li0, il1 = 1.f / li1;
#pragma unroll
        for (int ni = 0; ni < 8; ni++) {
            int col = h * 64 + ni * 8 + 2 * tg;
            *(__half2*)(o + ((size_t)(b * CK + rowg0)) * CD + col) =
                __floats2half2_rn(of[ni][0] * il0, of[ni][1] * il0);
            *(__half2*)(o + ((size_t)(b * CK + rowg1)) * CD + col) =
                __floats2half2_rn(of[ni][2] * il1, of[ni][3] * il1);
        }
    }
}

// ---------------- output assembly (fused copy + gated scatter) ---------------
__global__ void outfuse_kernel(const float* __restrict__ x,
                               const float* __restrict__ h,
                               const int* __restrict__ inv,
                               const float* __restrict__ gate,
                               float* __restrict__ out) {
    int row = blockIdx.x;
    int b = row >> 12;
    int pos = inv[row];
    const float4* src = (const float4*)(x + (size_t)row * CD);
    float4* dst = (float4*)(out + (size_t)row * CD);
    float4 v = src[threadIdx.x];
    if (pos >= 0) {
        float gval = gate[b * CK + pos];
        const float4* hp = (const float4*)(h + (size_t)(b * CK + pos) * CD);
        float4 hv = hp[threadIdx.x];
        v.x += hv.x * gval; v.y += hv.y * gval;
        v.z += hv.z * gval; v.w += hv.w * gval;
    }
    dst[threadIdx.x] = v;
}

__global__ void tail_kernel(const int* __restrict__ idx, const float* __restrict__ logits,
                            float* __restrict__ out) {
    int i = blockIdx.x * blockDim.x + threadIdx.x;
    if (i < CB * CK) {
        out[BTD + i] = (float)idx[i];
    } else if (i < CB * CK + CB * CT) {
        int j = i - CB * CK;
        out[BTD + CB * CK + j] = logits[j];
    }
}

// ---------------- launch -----------------------------------------------------
extern "C" void kernel_launch(void* const* d_in, const int* in_sizes, int n_in,
                              void* d_out, int out_size) {
    const float* x         = (const float*)d_in[0];
    const float* w_router  = (const float*)d_in[1];
    const float* b_router  = (const float*)d_in[2];
    const float* ln1_scale = (const float*)d_in[3];
    const float* ln1_bias  = (const float*)d_in[4];
    const float* w_qkv     = (const float*)d_in[5];
    const float* b_qkv     = (const float*)d_in[6];
    const float* w_o       = (const float*)d_in[7];
    const float* b_o       = (const float*)d_in[8];
    const float* ln2_scale = (const float*)d_in[9];
    const float* ln2_bias  = (const float*)d_in[10];
    const float* w1        = (const float*)d_in[11];
    const float* b1        = (const float*)d_in[12];
    const float* w2        = (const float*)d_in[13];
    const float* b2        = (const float*)d_in[14];
    float* out = (float*)d_out;

    float *logits, *gate, *h;
    int *sel, *idxp, *invp;
    __half *lnh, *qkvh, *attnh, *midh, *wth;
    cudaGetSymbolAddress((void**)&logits, g_logits);
    cudaGetSymbolAddress((void**)&sel, g_sel);
    cudaGetSymbolAddress((void**)&idxp, g_idx);
    cudaGetSymbolAddress((void**)&invp, g_inv);
    cudaGetSymbolAddress((void**)&gate, g_gate);
    cudaGetSymbolAddress((void**)&h, g_h);
    cudaGetSymbolAddress((void**)&lnh, g_lnh);
    cudaGetSymbolAddress((void**)&qkvh, g_qkvh);
    cudaGetSymbolAddress((void**)&attnh, g_attnh);
    cudaGetSymbolAddress((void**)&midh, g_midh);
    cudaGetSymbolAddress((void**)&wth, g_wth);

    cudaFuncSetAttribute(tgemm_kernel,
                         cudaFuncAttributeMaxDynamicSharedMemorySize, (int)TGEMM_SMEM);
    cudaFuncSetAttribute(tgemm_wide<false>,
                         cudaFuncAttributeMaxDynamicSharedMemorySize, (int)TGEMW_SMEM);
    cudaFuncSetAttribute(tgemm_wide<true>,
                         cudaFuncAttributeMaxDynamicSharedMemorySize, (int)TGEMW_SMEM);

    // 0. pre-convert all weights to fp16 (single kernel, MLP=4/thread)
    cvtw_all_kernel<<<CVT_THREADS_TOTAL / 256, 256>>>(w_qkv, w_o, w1, w2, wth);

    // 1-3. router, top-K, fused gather+LN1(layer0)
    router_kernel<<<(CB * CT) / 8, 256>>>(x, w_router, b_router, logits);
    rank_kernel<<<CB * 64, 256>>>(logits, sel);
    compact_kernel<<<CB, 1024>>>(logits, sel, idxp, invp, gate);
    gather_ln_kernel<<<BK_ROWS, 256>>>(x, idxp, ln1_scale, ln1_bias, h, lnh);

    // 4. transformer blocks
    for (int l = 0; l < CL; l++) {
        if (l > 0)
            layernorm_kernel<<<BK_ROWS, 256>>>(h, lnh, ln1_scale + l * CD, ln1_bias + l * CD);
        tgemm_wide<false><<<dim3(3 * CD / WBN, BK_ROWS / GBM), 256, TGEMW_SMEM>>>(
            lnh, wth + WQKV_OFF + (size_t)l * CD * 3 * CD, b_qkv + l * 3 * CD,
            qkvh, BK_ROWS, 3 * CD, CD);
        attn_kernel<<<dim3(NQB / 2, CH, CB), 256>>>(qkvh, attnh);
        tgemm_kernel<<<dim3(CD / GBN, BK_ROWS / GBM), 256, TGEMM_SMEM>>>(
            attnh, wth + WO_OFF + (size_t)l * CD * CD, b_o + l * CD, h, h,
            BK_ROWS, CD, CD);
        layernorm_kernel<<<BK_ROWS, 256>>>(h, lnh, ln2_scale + l * CD, ln2_bias + l * CD);
        tgemm_wide<true><<<dim3(CF / WBN, BK_ROWS / GBM), 256, TGEMW_SMEM>>>(
            lnh, wth + W1_OFF + (size_t)l * CD * CF, b1 + l * CF,
            midh, BK_ROWS, CF, CD);
        tgemm_kernel<<<dim3(CD / GBN, BK_ROWS / GBM), 256, TGEMM_SMEM>>>(
            midh, wth + W2_OFF + (size_t)l * CF * CD, b2 + l * CD, h, h,
            BK_ROWS, CD, CF);
    }

    // 5. assemble output: total (fused copy+scatter), idx, logits
    outfuse_kernel<<<CB * CT, 256>>>(x, h, invp, gate, out);
    if ((size_t)out_size >= BTD + CB * CK + CB * CT) {
        int ntail = CB * CK + CB * CT;
        tail_kernel<<<(ntail + 255) / 256, 256>>>(idxp, logits, out);
    }
}

// round 12
// speedup vs baseline: 7.3886x; 1.0293x over previous
#include <cuda_runtime.h>
#include <cuda_fp16.h>
#include <math.h>
#include <stdint.h>

// Problem constants
constexpr int CB = 2;      // batch
constexpr int CT = 4096;   // seq len
constexpr int CD = 1024;   // d_model
constexpr int CL = 2;      // layers
constexpr int CH = 16;     // heads
constexpr int CF = 4096;   // d_ff
constexpr int CK = 2048;   // top-k tokens
constexpr int BK_ROWS = CB * CK;
constexpr size_t BTD = (size_t)CB * CT * CD;

// Weight fp16 scratch offsets (elements)
constexpr size_t WQKV_OFF = 0;
constexpr size_t WQKV_SZ  = (size_t)CL * CD * 3 * CD;
constexpr size_t WO_OFF   = WQKV_OFF + WQKV_SZ;
constexpr size_t WO_SZ    = (size_t)CL * CD * CD;
constexpr size_t W1_OFF   = WO_OFF + WO_SZ;
constexpr size_t W1_SZ    = (size_t)CL * CD * CF;
constexpr size_t W2_OFF   = W1_OFF + W1_SZ;
constexpr size_t W2_SZ    = (size_t)CL * CF * CD;
constexpr size_t WTF_TOTAL = W2_OFF + W2_SZ;

// ---------------- scratch (static device globals) ---------------------------
__device__ float  g_logits[CB * CT];
__device__ int    g_sel[CB * CT];
__device__ int    g_idx[CB * CK];
__device__ int    g_inv[CB * CT];
__device__ float  g_gate[CB * CK];
__device__ float  g_h[BK_ROWS * CD];
__device__ __half g_lnh[BK_ROWS * CD];
__device__ __half g_qkvh[(size_t)BK_ROWS * 3 * CD];
__device__ __half g_attnh[BK_ROWS * CD];
__device__ __half g_midh[(size_t)BK_ROWS * CF];
__device__ __half g_wth[WTF_TOTAL];

__device__ __forceinline__ void mma_f16(float c[4], const uint32_t a[4],
                                        uint32_t b0, uint32_t b1) {
    asm volatile(
        "mma.sync.aligned.m16n8k16.row.col.f32.f16.f16.f32 "
        "{%0,%1,%2,%3}, {%4,%5,%6,%7}, {%8,%9}, {%0,%1,%2,%3};\n"
        : "+f"(c[0]), "+f"(c[1]), "+f"(c[2]), "+f"(c[3])
        : "r"(a[0]), "r"(a[1]), "r"(a[2]), "r"(a[3]), "r"(b0), "r"(b1));
}
__device__ __forceinline__ void ldsm_x4(uint32_t r[4], uint32_t saddr) {
    asm volatile("ldmatrix.sync.aligned.m8n8.x4.shared.b16 {%0,%1,%2,%3}, [%4];"
                 : "=r"(r[0]), "=r"(r[1]), "=r"(r[2]), "=r"(r[3]) : "r"(saddr));
}
__device__ __forceinline__ void ldsm_x4t(uint32_t r[4], uint32_t saddr) {
    asm volatile("ldmatrix.sync.aligned.m8n8.x4.trans.shared.b16 {%0,%1,%2,%3}, [%4];"
                 : "=r"(r[0]), "=r"(r[1]), "=r"(r[2]), "=r"(r[3]) : "r"(saddr));
}
__device__ __forceinline__ void cp16(uint32_t dst, const void* src) {
    asm volatile("cp.async.cg.shared.global [%0], [%1], 16;\n" :: "r"(dst), "l"(src));
}
__device__ __forceinline__ uint32_t pack_h2(float a, float b) {
    __half2 h = __floats2half2_rn(a, b);
    return *(uint32_t*)&h;
}

// ---------------- router ----------------------------------------------------
__global__ void router_kernel(const float* __restrict__ x,
                              const float* __restrict__ wr,
                              const float* __restrict__ br,
                              float* __restrict__ logits) {
    int gw = (blockIdx.x * blockDim.x + threadIdx.x) >> 5;
    if (gw >= CB * CT) return;
    int lane = threadIdx.x & 31;
    const float4* p = (const float4*)(x + (size_t)gw * CD);
    const float4* w4 = (const float4*)wr;
    float s = 0.f;
#pragma unroll
    for (int i = 0; i < CD / 128; i++) {
        float4 a = p[lane + i * 32];
        float4 w = w4[lane + i * 32];
        s += a.x * w.x + a.y * w.y + a.z * w.z + a.w * w.w;
    }
#pragma unroll
    for (int o = 16; o > 0; o >>= 1) s += __shfl_down_sync(0xffffffffu, s, o);
    if (lane == 0) logits[gw] = s + br[0];
}

// ---------------- top-K -----------------------------------------------------
__global__ void rank_kernel(const float* __restrict__ logits, int* __restrict__ sel) {
    int blk = blockIdx.x;
    int b = blk >> 6;
    int base = (blk & 63) * 64;
    __shared__ float lv[CT];
    int tid = threadIdx.x;
    for (int t = tid; t < CT; t += 256) lv[t] = logits[b * CT + t];
    __syncthreads();
    int tt = tid >> 2, part = tid & 3;
    int t = base + tt;
    float v = lv[t];
    int cnt = 0;
    int s0 = part * 1024;
#pragma unroll 8
    for (int s = s0; s < s0 + 1024; s++) {
        float u = lv[s];
        cnt += (u > v) || (u == v && s < t);
    }
    __shared__ int rk[64];
    if (part == 0) rk[tt] = 0;
    __syncthreads();
    atomicAdd(&rk[tt], cnt);
    __syncthreads();
    if (part == 0) sel[b * CT + t] = (rk[tt] < CK) ? 1 : 0;
}

__global__ void compact_kernel(const float* __restrict__ logits,
                               const int* __restrict__ sel,
                               int* __restrict__ idx_out,
                               int* __restrict__ inv_out,
                               float* __restrict__ gate_out) {
    int b = blockIdx.x;
    int tid = threadIdx.x;
    int f[4]; int c = 0;
#pragma unroll
    for (int i = 0; i < 4; i++) { f[i] = sel[b * CT + tid * 4 + i]; c += f[i]; }
    int lane = tid & 31, wid = tid >> 5;
    int incl = c;
#pragma unroll
    for (int o = 1; o < 32; o <<= 1) {
        int n = __shfl_up_sync(0xffffffffu, incl, o);
        if (lane >= o) incl += n;
    }
    __shared__ int wsum[32];
    if (lane == 31) wsum[wid] = incl;
    __syncthreads();
    if (wid == 0) {
        int w = wsum[lane];
#pragma unroll
        for (int o = 1; o < 32; o <<= 1) {
            int n = __shfl_up_sync(0xffffffffu, w, o);
            if (lane >= o) w += n;
        }
        wsum[lane] = w;
    }
    __syncthreads();
    int pos = (wid ? wsum[wid - 1] : 0) + incl - c;
#pragma unroll
    for (int i = 0; i < 4; i++) {
        int t = tid * 4 + i;
        if (f[i]) {
            idx_out[b * CK + pos] = t;
            inv_out[b * CT + t] = pos;
            float lg = logits[b * CT + t];
            gate_out[b * CK + pos] = 1.f / (1.f + expf(-lg));
            pos++;
        } else {
            inv_out[b * CT + t] = -1;
        }
    }
}

// ---------------- fused gather + first layernorm ------------------------------
__global__ void gather_ln_kernel(const float* __restrict__ x, const int* __restrict__ idx,
                                 const float* __restrict__ scale,
                                 const float* __restrict__ bias,
                                 float* __restrict__ h, __half* __restrict__ lnh) {
    int bk = blockIdx.x;
    int b = bk >> 11;
    int t = idx[bk];
    int tid = threadIdx.x;
    const float4* src = (const float4*)(x + ((size_t)b * CT + t) * CD);
    float4 v = src[tid];
    ((float4*)(h + (size_t)bk * CD))[tid] = v;
    float s = v.x + v.y + v.z + v.w;
    float ss = v.x * v.x + v.y * v.y + v.z * v.z + v.w * v.w;
#pragma unroll
    for (int o = 16; o > 0; o >>= 1) {
        s += __shfl_down_sync(0xffffffffu, s, o);
        ss += __shfl_down_sync(0xffffffffu, ss, o);
    }
    __shared__ float red[64];
    int lane = tid & 31, wid = tid >> 5;
    if (lane == 0) { red[wid] = s; red[32 + wid] = ss; }
    __syncthreads();
    if (tid == 0) {
        float S = 0, SS = 0;
#pragma unroll
        for (int w = 0; w < 8; w++) { S += red[w]; SS += red[32 + w]; }
        red[0] = S; red[32] = SS;
    }
    __syncthreads();
    float mean = red[0] * (1.f / CD);
    float var = red[32] * (1.f / CD) - mean * mean;
    float inv = rsqrtf(var + 1e-5f);
    float4 sc = ((const float4*)scale)[tid];
    float4 bi = ((const float4*)bias)[tid];
    __half2* o2 = (__half2*)(lnh + (size_t)bk * CD);
    o2[2 * tid] = __floats2half2_rn((v.x - mean) * inv * sc.x + bi.x,
                                    (v.y - mean) * inv * sc.y + bi.y);
    o2[2 * tid + 1] = __floats2half2_rn((v.z - mean) * inv * sc.z + bi.z,
                                        (v.w - mean) * inv * sc.w + bi.w);
}

// ---------------- layernorm (fp32 in -> fp16 out) ---------------------------
__global__ void layernorm_kernel(const float* __restrict__ in, __half* __restrict__ out,
                                 const float* __restrict__ scale,
                                 const float* __restrict__ bias) {
    int row = blockIdx.x;
    int tid = threadIdx.x;
    const float4* p = (const float4*)(in + (size_t)row * CD);
    float4 v = p[tid];
    float s = v.x + v.y + v.z + v.w;
    float ss = v.x * v.x + v.y * v.y + v.z * v.z + v.w * v.w;
#pragma unroll
    for (int o = 16; o > 0; o >>= 1) {
        s += __shfl_down_sync(0xffffffffu, s, o);
        ss += __shfl_down_sync(0xffffffffu, ss, o);
    }
    __shared__ float red[64];
    int lane = tid & 31, wid = tid >> 5;
    if (lane == 0) { red[wid] = s; red[32 + wid] = ss; }
    __syncthreads();
    if (tid == 0) {
        float S = 0, SS = 0;
#pragma unroll
        for (int w = 0; w < 8; w++) { S += red[w]; SS += red[32 + w]; }
        red[0] = S; red[32] = SS;
    }
    __syncthreads();
    float mean = red[0] * (1.f / CD);
    float var = red[32] * (1.f / CD) - mean * mean;
    float inv = rsqrtf(var + 1e-5f);
    float4 sc = ((const float4*)scale)[tid];
    float4 bi = ((const float4*)bias)[tid];
    __half2* o2 = (__half2*)(out + (size_t)row * CD);
    o2[2 * tid] = __floats2half2_rn((v.x - mean) * inv * sc.x + bi.x,
                                    (v.y - mean) * inv * sc.y + bi.y);
    o2[2 * tid + 1] = __floats2half2_rn((v.z - mean) * inv * sc.z + bi.z,
                                        (v.w - mean) * inv * sc.w + bi.w);
}

// ---------------- merged weight fp16 convert (4x strided float4/thread) ------
constexpr int CVT_THREADS_TOTAL = (int)(WTF_TOTAL / 4 / 4);
__global__ void cvtw_all_kernel(const float* __restrict__ wqkv,
                                const float* __restrict__ wo,
                                const float* __restrict__ w1,
                                const float* __restrict__ w2,
                                __half* __restrict__ dst) {
    constexpr size_t Q4 = WQKV_SZ / 4, O4 = WO_SZ / 4, A4 = W1_SZ / 4;
    const size_t stride = (size_t)CVT_THREADS_TOTAL;
    size_t i0 = (size_t)blockIdx.x * blockDim.x + threadIdx.x;
    __half2* d2 = (__half2*)dst;
#pragma unroll
    for (int j = 0; j < 4; j++) {
        size_t i = i0 + (size_t)j * stride;
        float4 v;
        if (i < Q4)                 v = ((const float4*)wqkv)[i];
        else if (i < Q4 + O4)       v = ((const float4*)wo)[i - Q4];
        else if (i < Q4 + O4 + A4)  v = ((const float4*)w1)[i - Q4 - O4];
        else                        v = ((const float4*)w2)[i - Q4 - O4 - A4];
        d2[2 * i]     = __floats2half2_rn(v.x, v.y);
        d2[2 * i + 1] = __floats2half2_rn(v.z, v.w);
    }
}

// ---------------- common GEMM bits -------------------------------------------
__device__ __forceinline__ float gelu_tanh(float x) {
    float x3 = x * x * x;
    float t = tanhf(0.7978845608028654f * (x + 0.044715f * x3));
    return 0.5f * x * (1.f + t);
}

// ============ narrow GEMM: 128x128x64, 3-stage cp.async, fp32 out + residual
constexpr int GBM = 128, GBN = 128, GBK = 64;
constexpr int AST = GBK + 8;
constexpr int BST = GBN + 8;
constexpr int ABUFH = GBM * AST;
constexpr int BBUFH = GBK * BST;
constexpr size_t TGEMM_SMEM = (size_t)(ABUFH + BBUFH) * 3 * sizeof(__half);

__global__ __launch_bounds__(256) void tgemm_kernel(
    const __half* __restrict__ A, const __half* __restrict__ W,
    const float* __restrict__ bias, const float* __restrict__ R,
    float* __restrict__ C, int M, int N, int Kd) {
    extern __shared__ __half dsm[];
    __half* As = dsm;
    __half* Bs = dsm + 3 * ABUFH;

    const int tid = threadIdx.x;
    const int bx = blockIdx.x, by = blockIdx.y;
    const int wid = tid >> 5, lane = tid & 31;
    const int warp_m = wid & 1;
    const int warp_n = wid >> 1;
    const int g = lane >> 2;
    const int tg = lane & 3;
    const int lm = (lane & 7) + ((lane >> 3) & 1) * 8;
    const int lk = ((lane >> 4) & 1) * 8;
    const int vrow = (lane & 7) + ((lane >> 3) & 1) * 8;
    const int vcol = ((lane >> 4) & 1) * 8;

    float c[4][4][4];
#pragma unroll
    for (int mi = 0; mi < 4; mi++)
#pragma unroll
        for (int ni = 0; ni < 4; ni++)
#pragma unroll
            for (int r = 0; r < 4; r++) c[mi][ni][r] = 0.f;

    const int ntiles = Kd / GBK;

    auto issue_tile = [&](int t, int buf) {
        int k0 = t * GBK;
        uint32_t abase = (uint32_t)__cvta_generic_to_shared(As + buf * ABUFH);
        uint32_t bbase = (uint32_t)__cvta_generic_to_shared(Bs + buf * BBUFH);
#pragma unroll
        for (int i = 0; i < 4; i++) {
            int q = tid + i * 256;
            int row = q >> 3, c8 = (q & 7) * 8;
            cp16(abase + (row * AST + c8) * 2, A + (size_t)(by * GBM + row) * Kd + k0 + c8);
        }
#pragma unroll
        for (int i = 0; i < 4; i++) {
            int q = tid + i * 256;
            int row = q >> 4, n8 = (q & 15) * 8;
            cp16(bbase + (row * BST + n8) * 2, W + (size_t)(k0 + row) * N + bx * GBN + n8);
        }
        asm volatile("cp.async.commit_group;\n");
    };

    issue_tile(0, 0);
    if (ntiles > 1) issue_tile(1, 1);
    for (int t = 0; t < ntiles; t++) {
        if (t + 2 < ntiles) {
            issue_tile(t + 2, (t + 2) % 3);
            asm volatile("cp.async.wait_group 2;\n");
        } else if (t + 1 < ntiles) {
            asm volatile("cp.async.wait_group 1;\n");
        } else {
            asm volatile("cp.async.wait_group 0;\n");
        }
        __syncthreads();
        int buf = t % 3;
        uint32_t Ab = (uint32_t)__cvta_generic_to_shared(As + buf * ABUFH);
        uint32_t Bb = (uint32_t)__cvta_generic_to_shared(Bs + buf * BBUFH);
        uint32_t a_off = Ab + ((warp_m * 64 + lm) * AST + lk) * 2;
#pragma unroll
        for (int ks = 0; ks < GBK / 16; ks++) {
            uint32_t a[4][4], b[4][2];
#pragma unroll
            for (int mi = 0; mi < 4; mi++)
                ldsm_x4(a[mi], a_off + (mi * 16 * AST + ks * 16) * 2);
#pragma unroll
            for (int ni = 0; ni < 4; ni += 2) {
                uint32_t b4[4];
                ldsm_x4t(b4, Bb + ((ks * 16 + vrow) * BST + warp_n * 32 + ni * 8 + vcol) * 2);
                b[ni][0] = b4[0]; b[ni][1] = b4[1];
                b[ni + 1][0] = b4[2]; b[ni + 1][1] = b4[3];
            }
#pragma unroll
            for (int mi = 0; mi < 4; mi++)
#pragma unroll
                for (int ni = 0; ni < 4; ni++)
                    mma_f16(c[mi][ni], a[mi], b[ni][0], b[ni][1]);
        }
        __syncthreads();
    }

#pragma unroll
    for (int mi = 0; mi < 4; mi++) {
        int m0 = by * GBM + warp_m * 64 + mi * 16 + g;
#pragma unroll
        for (int ni = 0; ni < 4; ni++) {
            int n0 = bx * GBN + warp_n * 32 + ni * 8 + 2 * tg;
            float b0 = bias[n0], b1 = bias[n0 + 1];
#pragma unroll
            for (int half = 0; half < 2; half++) {
                int m = m0 + half * 8;
                float v0 = c[mi][ni][half * 2 + 0] + b0;
                float v1 = c[mi][ni][half * 2 + 1] + b1;
                const float2 r2 = *(const float2*)(R + (size_t)m * N + n0);
                v0 += r2.x; v1 += r2.y;
                *(float2*)(C + (size_t)m * N + n0) = make_float2(v0, v1);
            }
        }
    }
}

// ============ wide GEMM: 128x256x64, 4-buffer ring p=2, SINGLE sync/iter ====
constexpr int WBN = 256;
constexpr int BSTW = WBN + 8;
constexpr int BBUFW = GBK * BSTW;
constexpr size_t TGEMW_SMEM = (size_t)(ABUFH + BBUFW) * 4 * sizeof(__half); // 208896

template <bool GELU>
__global__ __launch_bounds__(256) void tgemm_wide(
    const __half* __restrict__ A, const __half* __restrict__ W,
    const float* __restrict__ bias, __half* __restrict__ C,
    int M, int N, int Kd) {
    extern __shared__ __half dsm[];
    __half* As = dsm;
    __half* Bs = dsm + 4 * ABUFH;

    const int tid = threadIdx.x;
    const int bx = blockIdx.x, by = blockIdx.y;
    const int wid = tid >> 5, lane = tid & 31;
    const int warp_m = wid & 1;
    const int warp_n = wid >> 1;
    const int g = lane >> 2;
    const int tg = lane & 3;
    const int lm = (lane & 7) + ((lane >> 3) & 1) * 8;
    const int lk = ((lane >> 4) & 1) * 8;
    const int vrow = (lane & 7) + ((lane >> 3) & 1) * 8;
    const int vcol = ((lane >> 4) & 1) * 8;

    float c[4][8][4];
#pragma unroll
    for (int mi = 0; mi < 4; mi++)
#pragma unroll
        for (int ni = 0; ni < 8; ni++)
#pragma unroll
            for (int r = 0; r < 4; r++) c[mi][ni][r] = 0.f;

    const int ntiles = Kd / GBK;

    auto issue_tile = [&](int t, int buf) {
        int k0 = t * GBK;
        uint32_t abase = (uint32_t)__cvta_generic_to_shared(As + buf * ABUFH);
        uint32_t bbase = (uint32_t)__cvta_generic_to_shared(Bs + buf * BBUFW);
#pragma unroll
        for (int i = 0; i < 4; i++) {
            int q = tid + i * 256;
            int row = q >> 3, c8 = (q & 7) * 8;
            cp16(abase + (row * AST + c8) * 2, A + (size_t)(by * GBM + row) * Kd + k0 + c8);
        }
#pragma unroll
        for (int i = 0; i < 8; i++) {
            int q = tid + i * 256;
            int row = q >> 5, n8 = (q & 31) * 8;
            cp16(bbase + (row * BSTW + n8) * 2, W + (size_t)(k0 + row) * N + bx * WBN + n8);
        }
        asm volatile("cp.async.commit_group;\n");
    };

    // prefetch depth p=2, nb=4 buffers: 4∤2 and 4∤3 -> single sync per iter safe
    issue_tile(0, 0);
    if (ntiles > 1) issue_tile(1, 1);
    for (int t = 0; t < ntiles; t++) {
        if (t + 2 < ntiles) {
            issue_tile(t + 2, (t + 2) & 3);
            asm volatile("cp.async.wait_group 2;\n");
        } else if (t + 1 < ntiles) {
            asm volatile("cp.async.wait_group 1;\n");
        } else {
            asm volatile("cp.async.wait_group 0;\n");
        }
        __syncthreads();   // single barrier: read-visibility; overwrite-safety by ring math
        int buf = t & 3;
        uint32_t Ab = (uint32_t)__cvta_generic_to_shared(As + buf * ABUFH);
        uint32_t Bb = (uint32_t)__cvta_generic_to_shared(Bs + buf * BBUFW);
        uint32_t a_off = Ab + ((warp_m * 64 + lm) * AST + lk) * 2;
#pragma unroll
        for (int ks = 0; ks < GBK / 16; ks++) {
            uint32_t a[4][4], b[8][2];
#pragma unroll
            for (int mi = 0; mi < 4; mi++)
                ldsm_x4(a[mi], a_off + (mi * 16 * AST + ks * 16) * 2);
#pragma unroll
            for (int ni = 0; ni < 8; ni += 2) {
                uint32_t b4[4];
                ldsm_x4t(b4, Bb + ((ks * 16 + vrow) * BSTW + warp_n * 64 + ni * 8 + vcol) * 2);
                b[ni][0] = b4[0]; b[ni][1] = b4[1];
                b[ni + 1][0] = b4[2]; b[ni + 1][1] = b4[3];
            }
#pragma unroll
            for (int mi = 0; mi < 4; mi++)
#pragma unroll
                for (int ni = 0; ni < 8; ni++)
                    mma_f16(c[mi][ni], a[mi], b[ni][0], b[ni][1]);
        }
    }

#pragma unroll
    for (int mi = 0; mi < 4; mi++) {
        int m0 = by * GBM + warp_m * 64 + mi * 16 + g;
#pragma unroll
        for (int ni = 0; ni < 8; ni++) {
            int n0 = bx * WBN + warp_n * 64 + ni * 8 + 2 * tg;
            float b0 = bias[n0], b1 = bias[n0 + 1];
#pragma unroll
            for (int half = 0; half < 2; half++) {
                int m = m0 + half * 8;
                float v0 = c[mi][ni][half * 2 + 0] + b0;
                float v1 = c[mi][ni][half * 2 + 1] + b1;
                if (GELU) { v0 = gelu_tanh(v0); v1 = gelu_tanh(v1); }
                *(__half2*)(C + (size_t)m * N + n0) = __floats2half2_rn(v0, v1);
            }
        }
    }
}

// ---------------- FP16 MMA flash attention v4 --------------------------------
// Diagonal-paired Q tiles; 3-buffer K/V ring (p=1, nb=3: single sync per tile).
constexpr int SATT = 72;
constexpr int NQB = CK / 128;   // 16
__global__ __launch_bounds__(256) void attn_kernel(const __half* __restrict__ qkv,
                                                   __half* __restrict__ o) {
    const int pairi = blockIdx.x, h = blockIdx.y, b = blockIdx.z;
    const int tid = threadIdx.x;
    const int w = tid >> 5, lane = tid & 31;
    const int g = lane >> 2, tg = lane & 3;
    const int lm = (lane & 7) + ((lane >> 3) & 1) * 8;
    const int lk = ((lane >> 4) & 1) * 8;

    __shared__ __half KV[6][64 * SATT];   // K ring 0..2, V ring 3..5
    uint32_t base[6];
#pragma unroll
    for (int i = 0; i < 6; i++) base[i] = (uint32_t)__cvta_generic_to_shared(KV[i]);

    const int srow = (lane & 7) + ((lane >> 4) & 1) * 8;
    const int scol = ((lane >> 3) & 1) * 8;
    const int vrow = (lane & 7) + ((lane >> 3) & 1) * 8;
    const int vcol = ((lane >> 4) & 1) * 8;

    const __half2 sc8 = __float2half2_rn(0.125f);

    for (int s = 0; s < 2; s++) {
        const int qb = (s == 0) ? pairi : (NQB - 1 - pairi);

        // segment-entry barrier: K0/K1 may still be read by laggards of prev segment
        __syncthreads();
        // stage Q (128 x 64, scaled) over K0..K1, extract frags
#pragma unroll
        for (int i = 0; i < 4; i++) {
            int q = tid + i * 256;
            int r = q >> 3, c8 = (q & 7) * 8;
            const __half* src = qkv + ((size_t)(b * CK + qb * 128 + r)) * (3 * CD) + h * 64 + c8;
            uint4 u = *(const uint4*)src;
            __half2* hp = (__half2*)&u;
#pragma unroll
            for (int j = 0; j < 4; j++) hp[j] = __hmul2(hp[j], sc8);
            *(uint4*)&KV[0][r * SATT + c8] = u;
        }
        __syncthreads();
        uint32_t qf[4][4];
#pragma unroll
        for (int ks = 0; ks < 4; ks++)
            ldsm_x4(qf[ks], base[0] + ((w * 16 + lm) * SATT + ks * 16 + lk) * 2);
        __syncthreads();   // Q frags extracted; K0/K1 reusable

        float of[8][4];
#pragma unroll
        for (int ni = 0; ni < 8; ni++)
#pragma unroll
            for (int r = 0; r < 4; r++) of[ni][r] = 0.f;
        float mi0 = -1e30f, mi1 = -1e30f, li0 = 0.f, li1 = 0.f;

        const int nt = 2 * qb + 2;
        const int rowg0 = qb * 128 + w * 16 + g;
        const int rowg1 = rowg0 + 8;

        auto issue = [&](int kt, int buf) {
            uint32_t kb = base[buf];
            uint32_t vb = base[3 + buf];
#pragma unroll
            for (int i = 0; i < 2; i++) {
                int q = tid + i * 256;
                int r = q >> 3, c8 = (q & 7) * 8;
                const __half* kbp = qkv + ((size_t)(b * CK + kt * 64 + r)) * (3 * CD) + CD + h * 64 + c8;
                cp16(kb + (r * SATT + c8) * 2, kbp);
                cp16(vb + (r * SATT + c8) * 2, kbp + CD);
            }
            asm volatile("cp.async.commit_group;\n");
        };

        issue(0, 0);
        for (int kt = 0; kt < nt; kt++) {
            if (kt + 1 < nt) {
                issue(kt + 1, (kt + 1) % 3);
                asm volatile("cp.async.wait_group 1;\n");
            } else {
                asm volatile("cp.async.wait_group 0;\n");
            }
            __syncthreads();   // single barrier per tile (p=1, nb=3 ring)
            uint32_t ksb = base[kt % 3];
            uint32_t vsb = base[3 + (kt % 3)];

            float sf[8][4];
#pragma unroll
            for (int ni = 0; ni < 8; ni++)
#pragma unroll
                for (int r = 0; r < 4; r++) sf[ni][r] = 0.f;
#pragma unroll
            for (int ks = 0; ks < 4; ks++) {
#pragma unroll
                for (int ni = 0; ni < 8; ni += 2) {
                    uint32_t b4[4];
                    ldsm_x4(b4, ksb + ((ni * 8 + srow) * SATT + ks * 16 + scol) * 2);
                    mma_f16(sf[ni],     qf[ks], b4[0], b4[1]);
                    mma_f16(sf[ni + 1], qf[ks], b4[2], b4[3]);
                }
            }

            if (kt >= 2 * qb) {
                int cbase = kt * 64;
#pragma unroll
                for (int ni = 0; ni < 8; ni++) {
                    int c0 = cbase + ni * 8 + 2 * tg, c1 = c0 + 1;
                    if (c0 > rowg0) sf[ni][0] = -1e30f;
                    if (c1 > rowg0) sf[ni][1] = -1e30f;
                    if (c0 > rowg1) sf[ni][2] = -1e30f;
                    if (c1 > rowg1) sf[ni][3] = -1e30f;
                }
            }

            float m0 = -1e30f, m1 = -1e30f;
#pragma unroll
            for (int ni = 0; ni < 8; ni++) {
                m0 = fmaxf(m0, fmaxf(sf[ni][0], sf[ni][1]));
                m1 = fmaxf(m1, fmaxf(sf[ni][2], sf[ni][3]));
            }
            m0 = fmaxf(m0, __shfl_xor_sync(0xffffffffu, m0, 1));
            m0 = fmaxf(m0, __shfl_xor_sync(0xffffffffu, m0, 2));
            m1 = fmaxf(m1, __shfl_xor_sync(0xffffffffu, m1, 1));
            m1 = fmaxf(m1, __shfl_xor_sync(0xffffffffu, m1, 2));
            float nm0 = fmaxf(mi0, m0), nm1 = fmaxf(mi1, m1);
            float co0 = __expf(mi0 - nm0), co1 = __expf(mi1 - nm1);
            float rs0 = 0.f, rs1 = 0.f;
#pragma unroll
            for (int ni = 0; ni < 8; ni++) {
                sf[ni][0] = __expf(sf[ni][0] - nm0);
                sf[ni][1] = __expf(sf[ni][1] - nm0);
                sf[ni][2] = __expf(sf[ni][2] - nm1);
                sf[ni][3] = __expf(sf[ni][3] - nm1);
                rs0 += sf[ni][0] + sf[ni][1];
                rs1 += sf[ni][2] + sf[ni][3];
            }
            rs0 += __shfl_xor_sync(0xffffffffu, rs0, 1);
            rs0 += __shfl_xor_sync(0xffffffffu, rs0, 2);
            rs1 += __shfl_xor_sync(0xffffffffu, rs1, 1);
            rs1 += __shfl_xor_sync(0xffffffffu, rs1, 2);
            li0 = li0 * co0 + rs0;
            li1 = li1 * co1 + rs1;
            mi0 = nm0; mi1 = nm1;
#pragma unroll
            for (int ni = 0; ni < 8; ni++) {
                of[ni][0] *= co0; of[ni][1] *= co0;
                of[ni][2] *= co1; of[ni][3] *= co1;
            }

#pragma unroll
            for (int js = 0; js < 4; js++) {
                uint32_t a[4];
                a[0] = pack_h2(sf[2 * js][0], sf[2 * js][1]);
                a[1] = pack_h2(sf[2 * js][2], sf[2 * js][3]);
                a[2] = pack_h2(sf[2 * js + 1][0], sf[2 * js + 1][1]);
                a[3] = pack_h2(sf[2 * js + 1][2], sf[2 * js + 1][3]);
#pragma unroll
                for (int ni = 0; ni < 8; ni += 2) {
                    uint32_t b4[4];
                    ldsm_x4t(b4, vsb + ((js * 16 + vrow) * SATT + (ni + (vcol >> 3)) * 8) * 2);
                    mma_f16(of[ni],     a, b4[0], b4[1]);
                    mma_f16(of[ni + 1], a, b4[2], b4[3]);
                }
            }
            // no tail sync: issue at iter kt+1 targets buf (kt+2)%3, laggards read (kt)%3
        }

        float il0 = 1.f / li0, il1 = 1.f / li1;
#pragma unroll
        for (int ni = 0; ni < 8; ni++) {
            int col = h * 64 + ni * 8 + 2 * tg;
            *(__half2*)(o + ((size_t)(b * CK + rowg0)) * CD + col) =
                __floats2half2_rn(of[ni][0] * il0, of[ni][1] * il0);
            *(__half2*)(o + ((size_t)(b * CK + rowg1)) * CD + col) =
                __floats2half2_rn(of[ni][2] * il1, of[ni][3] * il1);
        }
    }
}

// ---------------- output assembly (copy + gated scatter + idx/logits tail) ---
__global__ void outfuse_kernel(const float* __restrict__ x,
                               const float* __restrict__ h,
                               const int* __restrict__ inv,
                               const float* __restrict__ gate,
                               const int* __restrict__ idx,
                               const float* __restrict__ logits,
                               float* __restrict__ out, int has_tail) {
    int row = blockIdx.x;
    int b = row >> 12;
    int pos = inv[row];
    const float4* src = (const float4*)(x + (size_t)row * CD);
    float4* dst = (float4*)(out + (size_t)row * CD);
    float4 v = src[threadIdx.x];
    if (pos >= 0) {
        float gval = gate[b * CK + pos];
        const float4* hp = (const float4*)(h + (size_t)(b * CK + pos) * CD);
        float4 hv = hp[threadIdx.x];
        v.x += hv.x * gval; v.y += hv.y * gval;
        v.z += hv.z * gval; v.w += hv.w * gval;
    }
    dst[threadIdx.x] = v;
    if (has_tail) {
        if (threadIdx.x == 0 && row < CB * CK)
            out[BTD + row] = (float)idx[row];
        if (threadIdx.x == 1)
            out[BTD + CB * CK + row] = logits[row];
    }
}

// ---------------- launch -----------------------------------------------------
extern "C" void kernel_launch(void* const* d_in, const int* in_sizes, int n_in,
                              void* d_out, int out_size) {
    const float* x         = (const float*)d_in[0];
    const float* w_router  = (const float*)d_in[1];
    const float* b_router  = (const float*)d_in[2];
    const float* ln1_scale = (const float*)d_in[3];
    const float* ln1_bias  = (const float*)d_in[4];
    const float* w_qkv     = (const float*)d_in[5];
    const float* b_qkv     = (const float*)d_in[6];
    const float* w_o       = (const float*)d_in[7];
    const float* b_o       = (const float*)d_in[8];
    const float* ln2_scale = (const float*)d_in[9];
    const float* ln2_bias  = (const float*)d_in[10];
    const float* w1        = (const float*)d_in[11];
    const float* b1        = (const float*)d_in[12];
    const float* w2        = (const float*)d_in[13];
    const float* b2        = (const float*)d_in[14];
    float* out = (float*)d_out;

    float *logits, *gate, *h;
    int *sel, *idxp, *invp;
    __half *lnh, *qkvh, *attnh, *midh, *wth;
    cudaGetSymbolAddress((void**)&logits, g_logits);
    cudaGetSymbolAddress((void**)&sel, g_sel);
    cudaGetSymbolAddress((void**)&idxp, g_idx);
    cudaGetSymbolAddress((void**)&invp, g_inv);
    cudaGetSymbolAddress((void**)&gate, g_gate);
    cudaGetSymbolAddress((void**)&h, g_h);
    cudaGetSymbolAddress((void**)&lnh, g_lnh);
    cudaGetSymbolAddress((void**)&qkvh, g_qkvh);
    cudaGetSymbolAddress((void**)&attnh, g_attnh);
    cudaGetSymbolAddress((void**)&midh, g_midh);
    cudaGetSymbolAddress((void**)&wth, g_wth);

    cudaFuncSetAttribute(tgemm_kernel,
                         cudaFuncAttributeMaxDynamicSharedMemorySize, (int)TGEMM_SMEM);
    cudaFuncSetAttribute(tgemm_wide<false>,
                         cudaFuncAttributeMaxDynamicSharedMemorySize, (int)TGEMW_SMEM);
    cudaFuncSetAttribute(tgemm_wide<true>,
                         cudaFuncAttributeMaxDynamicSharedMemorySize, (int)TGEMW_SMEM);

    // 0. pre-convert all weights to fp16
    cvtw_all_kernel<<<CVT_THREADS_TOTAL / 256, 256>>>(w_qkv, w_o, w1, w2, wth);

    // 1-3. router, top-K, fused gather+LN1(layer0)
    router_kernel<<<(CB * CT) / 8, 256>>>(x, w_router, b_router, logits);
    rank_kernel<<<CB * 64, 256>>>(logits, sel);
    compact_kernel<<<CB, 1024>>>(logits, sel, idxp, invp, gate);
    gather_ln_kernel<<<BK_ROWS, 256>>>(x, idxp, ln1_scale, ln1_bias, h, lnh);

    // 4. transformer blocks
    for (int l = 0; l < CL; l++) {
        if (l > 0)
            layernorm_kernel<<<BK_ROWS, 256>>>(h, lnh, ln1_scale + l * CD, ln1_bias + l * CD);
        tgemm_wide<false><<<dim3(3 * CD / WBN, BK_ROWS / GBM), 256, TGEMW_SMEM>>>(
            lnh, wth + WQKV_OFF + (size_t)l * CD * 3 * CD, b_qkv + l * 3 * CD,
            qkvh, BK_ROWS, 3 * CD, CD);
        attn_kernel<<<dim3(NQB / 2, CH, CB), 256>>>(qkvh, attnh);
        tgemm_kernel<<<dim3(CD / GBN, BK_ROWS / GBM), 256, TGEMM_SMEM>>>(
            attnh, wth + WO_OFF + (size_t)l * CD * CD, b_o + l * CD, h, h,
            BK_ROWS, CD, CD);
        layernorm_kernel<<<BK_ROWS, 256>>>(h, lnh, ln2_scale + l * CD, ln2_bias + l * CD);
        tgemm_wide<true><<<dim3(CF / WBN, BK_ROWS / GBM), 256, TGEMW_SMEM>>>(
            lnh, wth + W1_OFF + (size_t)l * CD * CF, b1 + l * CF,
            midh, BK_ROWS, CF, CD);
        tgemm_kernel<<<dim3(CD / GBN, BK_ROWS / GBM), 256, TGEMM_SMEM>>>(
            midh, wth + W2_OFF + (size_t)l * CF * CD, b2 + l * CD, h, h,
            BK_ROWS, CD, CF);
    }

    // 5. assemble output: total + idx + logits in one kernel
    int has_tail = ((size_t)out_size >= BTD + CB * CK + CB * CT) ? 1 : 0;
    outfuse_kernel<<<CB * CT, 256>>>(x, h, invp, gate, idxp, logits, out, has_tail);
}

// round 14
// speedup vs baseline: 7.4044x; 1.0021x over previous
#include <cuda_runtime.h>
#include <cuda_fp16.h>
#include <math.h>
#include <stdint.h>

// Problem constants
constexpr int CB = 2;      // batch
constexpr int CT = 4096;   // seq len
constexpr int CD = 1024;   // d_model
constexpr int CL = 2;      // layers
constexpr int CH = 16;     // heads
constexpr int CF = 4096;   // d_ff
constexpr int CK = 2048;   // top-k tokens
constexpr int BK_ROWS = CB * CK;
constexpr size_t BTD = (size_t)CB * CT * CD;

// Weight fp16 scratch offsets (elements)
constexpr size_t WQKV_OFF = 0;
constexpr size_t WQKV_SZ  = (size_t)CL * CD * 3 * CD;
constexpr size_t WO_OFF   = WQKV_OFF + WQKV_SZ;
constexpr size_t WO_SZ    = (size_t)CL * CD * CD;
constexpr size_t W1_OFF   = WO_OFF + WO_SZ;
constexpr size_t W1_SZ    = (size_t)CL * CD * CF;
constexpr size_t W2_OFF   = W1_OFF + W1_SZ;
constexpr size_t W2_SZ    = (size_t)CL * CF * CD;
constexpr size_t WTF_TOTAL = W2_OFF + W2_SZ;

// ---------------- scratch (static device globals) ---------------------------
__device__ float  g_logits[CB * CT];
__device__ int    g_sel[CB * CT];
__device__ int    g_idx[CB * CK];
__device__ int    g_inv[CB * CT];
__device__ float  g_gate[CB * CK];
__device__ float  g_h[BK_ROWS * CD];
__device__ __half g_lnh[BK_ROWS * CD];
__device__ __half g_qkvh[(size_t)BK_ROWS * 3 * CD];
__device__ __half g_attnh[BK_ROWS * CD];
__device__ __half g_midh[(size_t)BK_ROWS * CF];
__device__ __half g_wth[WTF_TOTAL];

__device__ __forceinline__ void mma_f16(float c[4], const uint32_t a[4],
                                        uint32_t b0, uint32_t b1) {
    asm volatile(
        "mma.sync.aligned.m16n8k16.row.col.f32.f16.f16.f32 "
        "{%0,%1,%2,%3}, {%4,%5,%6,%7}, {%8,%9}, {%0,%1,%2,%3};\n"
        : "+f"(c[0]), "+f"(c[1]), "+f"(c[2]), "+f"(c[3])
        : "r"(a[0]), "r"(a[1]), "r"(a[2]), "r"(a[3]), "r"(b0), "r"(b1));
}
__device__ __forceinline__ void ldsm_x4(uint32_t r[4], uint32_t saddr) {
    asm volatile("ldmatrix.sync.aligned.m8n8.x4.shared.b16 {%0,%1,%2,%3}, [%4];"
                 : "=r"(r[0]), "=r"(r[1]), "=r"(r[2]), "=r"(r[3]) : "r"(saddr));
}
__device__ __forceinline__ void ldsm_x4t(uint32_t r[4], uint32_t saddr) {
    asm volatile("ldmatrix.sync.aligned.m8n8.x4.trans.shared.b16 {%0,%1,%2,%3}, [%4];"
                 : "=r"(r[0]), "=r"(r[1]), "=r"(r[2]), "=r"(r[3]) : "r"(saddr));
}
__device__ __forceinline__ void cp16(uint32_t dst, const void* src) {
    asm volatile("cp.async.cg.shared.global [%0], [%1], 16;\n" :: "r"(dst), "l"(src));
}
__device__ __forceinline__ uint32_t pack_h2(float a, float b) {
    __half2 h = __floats2half2_rn(a, b);
    return *(uint32_t*)&h;
}

// ---------------- merged weight-convert + router (independent work) ----------
constexpr int CVT_THREADS_TOTAL = (int)(WTF_TOTAL / 4 / 4);
constexpr int CVT_BLOCKS = CVT_THREADS_TOTAL / 256;        // 6144
constexpr int ROUTER_BLOCKS = (CB * CT) / 8;               // 1024

__global__ void cvt_router_kernel(const float* __restrict__ wqkv,
                                  const float* __restrict__ wo,
                                  const float* __restrict__ w1,
                                  const float* __restrict__ w2,
                                  __half* __restrict__ dst,
                                  const float* __restrict__ x,
                                  const float* __restrict__ wr,
                                  const float* __restrict__ br,
                                  float* __restrict__ logits) {
    if (blockIdx.x < CVT_BLOCKS) {
        constexpr size_t Q4 = WQKV_SZ / 4, O4 = WO_SZ / 4, A4 = W1_SZ / 4;
        const size_t stride = (size_t)CVT_THREADS_TOTAL;
        size_t i0 = (size_t)blockIdx.x * 256 + threadIdx.x;
        __half2* d2 = (__half2*)dst;
#pragma unroll
        for (int j = 0; j < 4; j++) {
            size_t i = i0 + (size_t)j * stride;
            float4 v;
            if (i < Q4)                 v = ((const float4*)wqkv)[i];
            else if (i < Q4 + O4)       v = ((const float4*)wo)[i - Q4];
            else if (i < Q4 + O4 + A4)  v = ((const float4*)w1)[i - Q4 - O4];
            else                        v = ((const float4*)w2)[i - Q4 - O4 - A4];
            d2[2 * i]     = __floats2half2_rn(v.x, v.y);
            d2[2 * i + 1] = __floats2half2_rn(v.z, v.w);
        }
    } else {
        int gw = (((int)blockIdx.x - CVT_BLOCKS) * 256 + (int)threadIdx.x) >> 5;
        if (gw >= CB * CT) return;
        int lane = threadIdx.x & 31;
        const float4* p = (const float4*)(x + (size_t)gw * CD);
        const float4* w4 = (const float4*)wr;
        float s = 0.f;
#pragma unroll
        for (int i = 0; i < CD / 128; i++) {
            float4 a = p[lane + i * 32];
            float4 w = w4[lane + i * 32];
            s += a.x * w.x + a.y * w.y + a.z * w.z + a.w * w.w;
        }
#pragma unroll
        for (int o = 16; o > 0; o >>= 1) s += __shfl_down_sync(0xffffffffu, s, o);
        if (lane == 0) logits[gw] = s + br[0];
    }
}

// ---------------- top-K -----------------------------------------------------
__global__ void rank_kernel(const float* __restrict__ logits, int* __restrict__ sel) {
    int blk = blockIdx.x;
    int b = blk >> 6;
    int base = (blk & 63) * 64;
    __shared__ float lv[CT];
    int tid = threadIdx.x;
    for (int t = tid; t < CT; t += 256) lv[t] = logits[b * CT + t];
    __syncthreads();
    int tt = tid >> 2, part = tid & 3;
    int t = base + tt;
    float v = lv[t];
    int cnt = 0;
    int s0 = part * 1024;
#pragma unroll 8
    for (int s = s0; s < s0 + 1024; s++) {
        float u = lv[s];
        cnt += (u > v) || (u == v && s < t);
    }
    __shared__ int rk[64];
    if (part == 0) rk[tt] = 0;
    __syncthreads();
    atomicAdd(&rk[tt], cnt);
    __syncthreads();
    if (part == 0) sel[b * CT + t] = (rk[tt] < CK) ? 1 : 0;
}

__global__ void compact_kernel(const float* __restrict__ logits,
                               const int* __restrict__ sel,
                               int* __restrict__ idx_out,
                               int* __restrict__ inv_out,
                               float* __restrict__ gate_out) {
    int b = blockIdx.x;
    int tid = threadIdx.x;
    int f[4]; int c = 0;
#pragma unroll
    for (int i = 0; i < 4; i++) { f[i] = sel[b * CT + tid * 4 + i]; c += f[i]; }
    int lane = tid & 31, wid = tid >> 5;
    int incl = c;
#pragma unroll
    for (int o = 1; o < 32; o <<= 1) {
        int n = __shfl_up_sync(0xffffffffu, incl, o);
        if (lane >= o) incl += n;
    }
    __shared__ int wsum[32];
    if (lane == 31) wsum[wid] = incl;
    __syncthreads();
    if (wid == 0) {
        int w = wsum[lane];
#pragma unroll
        for (int o = 1; o < 32; o <<= 1) {
            int n = __shfl_up_sync(0xffffffffu, w, o);
            if (lane >= o) w += n;
        }
        wsum[lane] = w;
    }
    __syncthreads();
    int pos = (wid ? wsum[wid - 1] : 0) + incl - c;
#pragma unroll
    for (int i = 0; i < 4; i++) {
        int t = tid * 4 + i;
        if (f[i]) {
            idx_out[b * CK + pos] = t;
            inv_out[b * CT + t] = pos;
            float lg = logits[b * CT + t];
            gate_out[b * CK + pos] = 1.f / (1.f + expf(-lg));
            pos++;
        } else {
            inv_out[b * CT + t] = -1;
        }
    }
}

// ---------------- fused gather + first layernorm ------------------------------
__global__ void gather_ln_kernel(const float* __restrict__ x, const int* __restrict__ idx,
                                 const float* __restrict__ scale,
                                 const float* __restrict__ bias,
                                 float* __restrict__ h, __half* __restrict__ lnh) {
    int bk = blockIdx.x;
    int b = bk >> 11;
    int t = idx[bk];
    int tid = threadIdx.x;
    const float4* src = (const float4*)(x + ((size_t)b * CT + t) * CD);
    float4 v = src[tid];
    ((float4*)(h + (size_t)bk * CD))[tid] = v;
    float s = v.x + v.y + v.z + v.w;
    float ss = v.x * v.x + v.y * v.y + v.z * v.z + v.w * v.w;
#pragma unroll
    for (int o = 16; o > 0; o >>= 1) {
        s += __shfl_down_sync(0xffffffffu, s, o);
        ss += __shfl_down_sync(0xffffffffu, ss, o);
    }
    __shared__ float red[64];
    int lane = tid & 31, wid = tid >> 5;
    if (lane == 0) { red[wid] = s; red[32 + wid] = ss; }
    __syncthreads();
    if (tid == 0) {
        float S = 0, SS = 0;
#pragma unroll
        for (int w = 0; w < 8; w++) { S += red[w]; SS += red[32 + w]; }
        red[0] = S; red[32] = SS;
    }
    __syncthreads();
    float mean = red[0] * (1.f / CD);
    float var = red[32] * (1.f / CD) - mean * mean;
    float inv = rsqrtf(var + 1e-5f);
    float4 sc = ((const float4*)scale)[tid];
    float4 bi = ((const float4*)bias)[tid];
    __half2* o2 = (__half2*)(lnh + (size_t)bk * CD);
    o2[2 * tid] = __floats2half2_rn((v.x - mean) * inv * sc.x + bi.x,
                                    (v.y - mean) * inv * sc.y + bi.y);
    o2[2 * tid + 1] = __floats2half2_rn((v.z - mean) * inv * sc.z + bi.z,
                                        (v.w - mean) * inv * sc.w + bi.w);
}

// ---------------- layernorm (fp32 in -> fp16 out) ---------------------------
__global__ void layernorm_kernel(const float* __restrict__ in, __half* __restrict__ out,
                                 const float* __restrict__ scale,
                                 const float* __restrict__ bias) {
    int row = blockIdx.x;
    int tid = threadIdx.x;
    const float4* p = (const float4*)(in + (size_t)row * CD);
    float4 v = p[tid];
    float s = v.x + v.y + v.z + v.w;
    float ss = v.x * v.x + v.y * v.y + v.z * v.z + v.w * v.w;
#pragma unroll
    for (int o = 16; o > 0; o >>= 1) {
        s += __shfl_down_sync(0xffffffffu, s, o);
        ss += __shfl_down_sync(0xffffffffu, ss, o);
    }
    __shared__ float red[64];
    int lane = tid & 31, wid = tid >> 5;
    if (lane == 0) { red[wid] = s; red[32 + wid] = ss; }
    __syncthreads();
    if (tid == 0) {
        float S = 0, SS = 0;
#pragma unroll
        for (int w = 0; w < 8; w++) { S += red[w]; SS += red[32 + w]; }
        red[0] = S; red[32] = SS;
    }
    __syncthreads();
    float mean = red[0] * (1.f / CD);
    float var = red[32] * (1.f / CD) - mean * mean;
    float inv = rsqrtf(var + 1e-5f);
    float4 sc = ((const float4*)scale)[tid];
    float4 bi = ((const float4*)bias)[tid];
    __half2* o2 = (__half2*)(out + (size_t)row * CD);
    o2[2 * tid] = __floats2half2_rn((v.x - mean) * inv * sc.x + bi.x,
                                    (v.y - mean) * inv * sc.y + bi.y);
    o2[2 * tid + 1] = __floats2half2_rn((v.z - mean) * inv * sc.z + bi.z,
                                        (v.w - mean) * inv * sc.w + bi.w);
}

// ---------------- common GEMM bits -------------------------------------------
__device__ __forceinline__ float gelu_tanh(float x) {
    float x3 = x * x * x;
    float t = tanhf(0.7978845608028654f * (x + 0.044715f * x3));
    return 0.5f * x * (1.f + t);
}

// ============ narrow GEMM: 128x128x64, 3-stage, issue->wait->sync->compute->sync
// (R11 proven form; tail sync REQUIRED for nb=3/p=2 overwrite safety)
constexpr int GBM = 128, GBN = 128, GBK = 64;
constexpr int AST = GBK + 8;
constexpr int BST = GBN + 8;
constexpr int ABUFH = GBM * AST;
constexpr int BBUFH = GBK * BST;
constexpr size_t TGEMM_SMEM = (size_t)(ABUFH + BBUFH) * 3 * sizeof(__half);

__global__ __launch_bounds__(256) void tgemm_kernel(
    const __half* __restrict__ A, const __half* __restrict__ W,
    const float* __restrict__ bias, const float* __restrict__ R,
    float* __restrict__ C, int M, int N, int Kd) {
    extern __shared__ __half dsm[];
    __half* As = dsm;
    __half* Bs = dsm + 3 * ABUFH;

    const int tid = threadIdx.x;
    const int bx = blockIdx.x, by = blockIdx.y;
    const int wid = tid >> 5, lane = tid & 31;
    const int warp_m = wid & 1;
    const int warp_n = wid >> 1;
    const int g = lane >> 2;
    const int tg = lane & 3;
    const int lm = (lane & 7) + ((lane >> 3) & 1) * 8;
    const int lk = ((lane >> 4) & 1) * 8;
    const int vrow = (lane & 7) + ((lane >> 3) & 1) * 8;
    const int vcol = ((lane >> 4) & 1) * 8;

    float c[4][4][4];
#pragma unroll
    for (int mi = 0; mi < 4; mi++)
#pragma unroll
        for (int ni = 0; ni < 4; ni++)
#pragma unroll
            for (int r = 0; r < 4; r++) c[mi][ni][r] = 0.f;

    const int ntiles = Kd / GBK;

    auto issue_tile = [&](int t, int buf) {
        int k0 = t * GBK;
        uint32_t abase = (uint32_t)__cvta_generic_to_shared(As + buf * ABUFH);
        uint32_t bbase = (uint32_t)__cvta_generic_to_shared(Bs + buf * BBUFH);
#pragma unroll
        for (int i = 0; i < 4; i++) {
            int q = tid + i * 256;
            int row = q >> 3, c8 = (q & 7) * 8;
            cp16(abase + (row * AST + c8) * 2, A + (size_t)(by * GBM + row) * Kd + k0 + c8);
        }
#pragma unroll
        for (int i = 0; i < 4; i++) {
            int q = tid + i * 256;
            int row = q >> 4, n8 = (q & 15) * 8;
            cp16(bbase + (row * BST + n8) * 2, W + (size_t)(k0 + row) * N + bx * GBN + n8);
        }
        asm volatile("cp.async.commit_group;\n");
    };

    issue_tile(0, 0);
    if (ntiles > 1) issue_tile(1, 1);
    for (int t = 0; t < ntiles; t++) {
        if (t + 2 < ntiles) {
            issue_tile(t + 2, (t + 2) % 3);
            asm volatile("cp.async.wait_group 2;\n");
        } else if (t + 1 < ntiles) {
            asm volatile("cp.async.wait_group 1;\n");
        } else {
            asm volatile("cp.async.wait_group 0;\n");
        }
        __syncthreads();   // publish all threads' tile-t copies
        int buf = t % 3;
        uint32_t Ab = (uint32_t)__cvta_generic_to_shared(As + buf * ABUFH);
        uint32_t Bb = (uint32_t)__cvta_generic_to_shared(Bs + buf * BBUFH);
        uint32_t a_off = Ab + ((warp_m * 64 + lm) * AST + lk) * 2;
#pragma unroll
        for (int ks = 0; ks < GBK / 16; ks++) {
            uint32_t a[4][4], b[4][2];
#pragma unroll
            for (int mi = 0; mi < 4; mi++)
                ldsm_x4(a[mi], a_off + (mi * 16 * AST + ks * 16) * 2);
#pragma unroll
            for (int ni = 0; ni < 4; ni += 2) {
                uint32_t b4[4];
                ldsm_x4t(b4, Bb + ((ks * 16 + vrow) * BST + warp_n * 32 + ni * 8 + vcol) * 2);
                b[ni][0] = b4[0]; b[ni][1] = b4[1];
                b[ni + 1][0] = b4[2]; b[ni + 1][1] = b4[3];
            }
#pragma unroll
            for (int mi = 0; mi < 4; mi++)
#pragma unroll
                for (int ni = 0; ni < 4; ni++)
                    mma_f16(c[mi][ni], a[mi], b[ni][0], b[ni][1]);
        }
        __syncthreads();   // overwrite safety before next iter's issue
    }

#pragma unroll
    for (int mi = 0; mi < 4; mi++) {
        int m0 = by * GBM + warp_m * 64 + mi * 16 + g;
#pragma unroll
        for (int ni = 0; ni < 4; ni++) {
            int n0 = bx * GBN + warp_n * 32 + ni * 8 + 2 * tg;
            float b0 = bias[n0], b1 = bias[n0 + 1];
#pragma unroll
            for (int half = 0; half < 2; half++) {
                int m = m0 + half * 8;
                float v0 = c[mi][ni][half * 2 + 0] + b0;
                float v1 = c[mi][ni][half * 2 + 1] + b1;
                const float2 r2 = *(const float2*)(R + (size_t)m * N + n0);
                v0 += r2.x; v1 += r2.y;
                *(float2*)(C + (size_t)m * N + n0) = make_float2(v0, v1);
            }
        }
    }
}

// ============ wide GEMM: 128x256x64, 4-buffer ring p=2, SINGLE sync/iter ====
// issue -> wait -> sync -> compute: sync AFTER wait publishes all copies;
// nb=4 ring keeps the issued buffer disjoint from any laggard's read buffer.
constexpr int WBN = 256;
constexpr int BSTW = WBN + 8;
constexpr int BBUFW = GBK * BSTW;
constexpr size_t TGEMW_SMEM = (size_t)(ABUFH + BBUFW) * 4 * sizeof(__half); // 208896

template <bool GELU>
__global__ __launch_bounds__(256) void tgemm_wide(
    const __half* __restrict__ A, const __half* __restrict__ W,
    const float* __restrict__ bias, __half* __restrict__ C,
    int M, int N, int Kd) {
    extern __shared__ __half dsm[];
    __half* As = dsm;
    __half* Bs = dsm + 4 * ABUFH;

    const int tid = threadIdx.x;
    const int bx = blockIdx.x, by = blockIdx.y;
    const int wid = tid >> 5, lane = tid & 31;
    const int warp_m = wid & 1;
    const int warp_n = wid >> 1;
    const int g = lane >> 2;
    const int tg = lane & 3;
    const int lm = (lane & 7) + ((lane >> 3) & 1) * 8;
    const int lk = ((lane >> 4) & 1) * 8;
    const int vrow = (lane & 7) + ((lane >> 3) & 1) * 8;
    const int vcol = ((lane >> 4) & 1) * 8;

    float c[4][8][4];
#pragma unroll
    for (int mi = 0; mi < 4; mi++)
#pragma unroll
        for (int ni = 0; ni < 8; ni++)
#pragma unroll
            for (int r = 0; r < 4; r++) c[mi][ni][r] = 0.f;

    const int ntiles = Kd / GBK;

    auto issue_tile = [&](int t, int buf) {
        int k0 = t * GBK;
        uint32_t abase = (uint32_t)__cvta_generic_to_shared(As + buf * ABUFH);
        uint32_t bbase = (uint32_t)__cvta_generic_to_shared(Bs + buf * BBUFW);
#pragma unroll
        for (int i = 0; i < 4; i++) {
            int q = tid + i * 256;
            int row = q >> 3, c8 = (q & 7) * 8;
            cp16(abase + (row * AST + c8) * 2, A + (size_t)(by * GBM + row) * Kd + k0 + c8);
        }
#pragma unroll
        for (int i = 0; i < 8; i++) {
            int q = tid + i * 256;
            int row = q >> 5, n8 = (q & 31) * 8;
            cp16(bbase + (row * BSTW + n8) * 2, W + (size_t)(k0 + row) * N + bx * WBN + n8);
        }
        asm volatile("cp.async.commit_group;\n");
    };

    issue_tile(0, 0);
    if (ntiles > 1) issue_tile(1, 1);
    for (int t = 0; t < ntiles; t++) {
        if (t + 2 < ntiles) {
            issue_tile(t + 2, (t + 2) & 3);
            asm volatile("cp.async.wait_group 2;\n");
        } else if (t + 1 < ntiles) {
            asm volatile("cp.async.wait_group 1;\n");
        } else {
            asm volatile("cp.async.wait_group 0;\n");
        }
        __syncthreads();
        int buf = t & 3;
        uint32_t Ab = (uint32_t)__cvta_generic_to_shared(As + buf * ABUFH);
        uint32_t Bb = (uint32_t)__cvta_generic_to_shared(Bs + buf * BBUFW);
        uint32_t a_off = Ab + ((warp_m * 64 + lm) * AST + lk) * 2;
#pragma unroll
        for (int ks = 0; ks < GBK / 16; ks++) {
            uint32_t a[4][4], b[8][2];
#pragma unroll
            for (int mi = 0; mi < 4; mi++)
                ldsm_x4(a[mi], a_off + (mi * 16 * AST + ks * 16) * 2);
#pragma unroll
            for (int ni = 0; ni < 8; ni += 2) {
                uint32_t b4[4];
                ldsm_x4t(b4, Bb + ((ks * 16 + vrow) * BSTW + warp_n * 64 + ni * 8 + vcol) * 2);
                b[ni][0] = b4[0]; b[ni][1] = b4[1];
                b[ni + 1][0] = b4[2]; b[ni + 1][1] = b4[3];
            }
#pragma unroll
            for (int mi = 0; mi < 4; mi++)
#pragma unroll
                for (int ni = 0; ni < 8; ni++)
                    mma_f16(c[mi][ni], a[mi], b[ni][0], b[ni][1]);
        }
    }

#pragma unroll
    for (int mi = 0; mi < 4; mi++) {
        int m0 = by * GBM + warp_m * 64 + mi * 16 + g;
#pragma unroll
        for (int ni = 0; ni < 8; ni++) {
            int n0 = bx * WBN + warp_n * 64 + ni * 8 + 2 * tg;
            float b0 = bias[n0], b1 = bias[n0 + 1];
#pragma unroll
            for (int half = 0; half < 2; half++) {
                int m = m0 + half * 8;
                float v0 = c[mi][ni][half * 2 + 0] + b0;
                float v1 = c[mi][ni][half * 2 + 1] + b1;
                if (GELU) { v0 = gelu_tanh(v0); v1 = gelu_tanh(v1); }
                *(__half2*)(C + (size_t)m * N + n0) = __floats2half2_rn(v0, v1);
            }
        }
    }
}

// ---------------- FP16 MMA flash attention v4 (unchanged from R11) -----------
constexpr int SATT = 72;
constexpr int NQB = CK / 128;   // 16
__global__ __launch_bounds__(256) void attn_kernel(const __half* __restrict__ qkv,
                                                   __half* __restrict__ o) {
    const int pairi = blockIdx.x, h = blockIdx.y, b = blockIdx.z;
    const int tid = threadIdx.x;
    const int w = tid >> 5, lane = tid & 31;
    const int g = lane >> 2, tg = lane & 3;
    const int lm = (lane & 7) + ((lane >> 3) & 1) * 8;
    const int lk = ((lane >> 4) & 1) * 8;

    __shared__ __half KV[6][64 * SATT];   // K ring 0..2, V ring 3..5
    uint32_t base[6];
#pragma unroll
    for (int i = 0; i < 6; i++) base[i] = (uint32_t)__cvta_generic_to_shared(KV[i]);

    const int srow = (lane & 7) + ((lane >> 4) & 1) * 8;
    const int scol = ((lane >> 3) & 1) * 8;
    const int vrow = (lane & 7) + ((lane >> 3) & 1) * 8;
    const int vcol = ((lane >> 4) & 1) * 8;

    const __half2 sc8 = __float2half2_rn(0.125f);

    for (int s = 0; s < 2; s++) {
        const int qb = (s == 0) ? pairi : (NQB - 1 - pairi);

        __syncthreads();
#pragma unroll
        for (int i = 0; i < 4; i++) {
            int q = tid + i * 256;
            int r = q >> 3, c8 = (q & 7) * 8;
            const __half* src = qkv + ((size_t)(b * CK + qb * 128 + r)) * (3 * CD) + h * 64 + c8;
            uint4 u = *(const uint4*)src;
            __half2* hp = (__half2*)&u;
#pragma unroll
            for (int j = 0; j < 4; j++) hp[j] = __hmul2(hp[j], sc8);
            *(uint4*)&KV[0][r * SATT + c8] = u;
        }
        __syncthreads();
        uint32_t qf[4][4];
#pragma unroll
        for (int ks = 0; ks < 4; ks++)
            ldsm_x4(qf[ks], base[0] + ((w * 16 + lm) * SATT + ks * 16 + lk) * 2);
        __syncthreads();

        float of[8][4];
#pragma unroll
        for (int ni = 0; ni < 8; ni++)
#pragma unroll
            for (int r = 0; r < 4; r++) of[ni][r] = 0.f;
        float mi0 = -1e30f, mi1 = -1e30f, li0 = 0.f, li1 = 0.f;

        const int nt = 2 * qb + 2;
        const int rowg0 = qb * 128 + w * 16 + g;
        const int rowg1 = rowg0 + 8;

        auto issue = [&](int kt, int buf) {
            uint32_t kb = base[buf];
            uint32_t vb = base[3 + buf];
#pragma unroll
            for (int i = 0; i < 2; i++) {
                int q = tid + i * 256;
                int r = q >> 3, c8 = (q & 7) * 8;
                const __half* kbp = qkv + ((size_t)(b * CK + kt * 64 + r)) * (3 * CD) + CD + h * 64 + c8;
                cp16(kb + (r * SATT + c8) * 2, kbp);
                cp16(vb + (r * SATT + c8) * 2, kbp + CD);
            }
            asm volatile("cp.async.commit_group;\n");
        };

        issue(0, 0);
        for (int kt = 0; kt < nt; kt++) {
            if (kt + 1 < nt) {
                issue(kt + 1, (kt + 1) % 3);
                asm volatile("cp.async.wait_group 1;\n");
            } else {
                asm volatile("cp.async.wait_group 0;\n");
            }
            __syncthreads();
            uint32_t ksb = base[kt % 3];
            uint32_t vsb = base[3 + (kt % 3)];

            float sf[8][4];
#pragma unroll
            for (int ni = 0; ni < 8; ni++)
#pragma unroll
                for (int r = 0; r < 4; r++) sf[ni][r] = 0.f;
#pragma unroll
            for (int ks = 0; ks < 4; ks++) {
#pragma unroll
                for (int ni = 0; ni < 8; ni += 2) {
                    uint32_t b4[4];
                    ldsm_x4(b4, ksb + ((ni * 8 + srow) * SATT + ks * 16 + scol) * 2);
                    mma_f16(sf[ni],     qf[ks], b4[0], b4[1]);
                    mma_f16(sf[ni + 1], qf[ks], b4[2], b4[3]);
                }
            }

            if (kt >= 2 * qb) {
                int cbase = kt * 64;
#pragma unroll
                for (int ni = 0; ni < 8; ni++) {
                    int c0 = cbase + ni * 8 + 2 * tg, c1 = c0 + 1;
                    if (c0 > rowg0) sf[ni][0] = -1e30f;
                    if (c1 > rowg0) sf[ni][1] = -1e30f;
                    if (c0 > rowg1) sf[ni][2] = -1e30f;
                    if (c1 > rowg1) sf[ni][3] = -1e30f;
                }
            }

            float m0 = -1e30f, m1 = -1e30f;
#pragma unroll
            for (int ni = 0; ni < 8; ni++) {
                m0 = fmaxf(m0, fmaxf(sf[ni][0], sf[ni][1]));
                m1 = fmaxf(m1, fmaxf(sf[ni][2], sf[ni][3]));
            }
            m0 = fmaxf(m0, __shfl_xor_sync(0xffffffffu, m0, 1));
            m0 = fmaxf(m0, __shfl_xor_sync(0xffffffffu, m0, 2));
            m1 = fmaxf(m1, __shfl_xor_sync(0xffffffffu, m1, 1));
            m1 = fmaxf(m1, __shfl_xor_sync(0xffffffffu, m1, 2));
            float nm0 = fmaxf(mi0, m0), nm1 = fmaxf(mi1, m1);
            float co0 = __expf(mi0 - nm0), co1 = __expf(mi1 - nm1);
            float rs0 = 0.f, rs1 = 0.f;
#pragma unroll
            for (int ni = 0; ni < 8; ni++) {
                sf[ni][0] = __expf(sf[ni][0] - nm0);
                sf[ni][1] = __expf(sf[ni][1] - nm0);
                sf[ni][2] = __expf(sf[ni][2] - nm1);
                sf[ni][3] = __expf(sf[ni][3] - nm1);
                rs0 += sf[ni][0] + sf[ni][1];
                rs1 += sf[ni][2] + sf[ni][3];
            }
            rs0 += __shfl_xor_sync(0xffffffffu, rs0, 1);
            rs0 += __shfl_xor_sync(0xffffffffu, rs0, 2);
            rs1 += __shfl_xor_sync(0xffffffffu, rs1, 1);
            rs1 += __shfl_xor_sync(0xffffffffu, rs1, 2);
            li0 = li0 * co0 + rs0;
            li1 = li1 * co1 + rs1;
            mi0 = nm0; mi1 = nm1;
#pragma unroll
            for (int ni = 0; ni < 8; ni++) {
                of[ni][0] *= co0; of[ni][1] *= co0;
                of[ni][2] *= co1; of[ni][3] *= co1;
            }

#pragma unroll
            for (int js = 0; js < 4; js++) {
                uint32_t a[4];
                a[0] = pack_h2(sf[2 * js][0], sf[2 * js][1]);
                a[1] = pack_h2(sf[2 * js][2], sf[2 * js][3]);
                a[2] = pack_h2(sf[2 * js + 1][0], sf[2 * js + 1][1]);
                a[3] = pack_h2(sf[2 * js + 1][2], sf[2 * js + 1][3]);
#pragma unroll
                for (int ni = 0; ni < 8; ni += 2) {
                    uint32_t b4[4];
                    ldsm_x4t(b4, vsb + ((js * 16 + vrow) * SATT + (ni + (vcol >> 3)) * 8) * 2);
                    mma_f16(of[ni],     a, b4[0], b4[1]);
                    mma_f16(of[ni + 1], a, b4[2], b4[3]);
                }
            }
        }

        float il0 = 1.f / li0, il1 = 1.f / li1;
#pragma unroll
        for (int ni = 0; ni < 8; ni++) {
            int col = h * 64 + ni * 8 + 2 * tg;
            *(__half2*)(o + ((size_t)(b * CK + rowg0)) * CD + col) =
                __floats2half2_rn(of[ni][0] * il0, of[ni][1] * il0);
            *(__half2*)(o + ((size_t)(b * CK + rowg1)) * CD + col) =
                __floats2half2_rn(of[ni][2] * il1, of[ni][3] * il1);
        }
    }
}

// ---------------- output assembly (copy + gated scatter + idx/logits tail) ---
__global__ void outfuse_kernel(const float* __restrict__ x,
                               const float* __restrict__ h,
                               const int* __restrict__ inv,
                               const float* __restrict__ gate,
                               const int* __restrict__ idx,
                               const float* __restrict__ logits,
                               float* __restrict__ out, int has_tail) {
    int row = blockIdx.x;
    int b = row >> 12;
    int pos = inv[row];
    const float4* src = (const float4*)(x + (size_t)row * CD);
    float4* dst = (float4*)(out + (size_t)row * CD);
    float4 v = src[threadIdx.x];
    if (pos >= 0) {
        float gval = gate[b * CK + pos];
        const float4* hp = (const float4*)(h + (size_t)(b * CK + pos) * CD);
        float4 hv = hp[threadIdx.x];
        v.x += hv.x * gval; v.y += hv.y * gval;
        v.z += hv.z * gval; v.w += hv.w * gval;
    }
    dst[threadIdx.x] = v;
    if (has_tail) {
        if (threadIdx.x == 0 && row < CB * CK)
            out[BTD + row] = (float)idx[row];
        if (threadIdx.x == 1)
            out[BTD + CB * CK + row] = logits[row];
    }
}

// ---------------- launch -----------------------------------------------------
extern "C" void kernel_launch(void* const* d_in, const int* in_sizes, int n_in,
                              void* d_out, int out_size) {
    const float* x         = (const float*)d_in[0];
    const float* w_router  = (const float*)d_in[1];
    const float* b_router  = (const float*)d_in[2];
    const float* ln1_scale = (const float*)d_in[3];
    const float* ln1_bias  = (const float*)d_in[4];
    const float* w_qkv     = (const float*)d_in[5];
    const float* b_qkv     = (const float*)d_in[6];
    const float* w_o       = (const float*)d_in[7];
    const float* b_o       = (const float*)d_in[8];
    const float* ln2_scale = (const float*)d_in[9];
    const float* ln2_bias  = (const float*)d_in[10];
    const float* w1        = (const float*)d_in[11];
    const float* b1        = (const float*)d_in[12];
    const float* w2        = (const float*)d_in[13];
    const float* b2        = (const float*)d_in[14];
    float* out = (float*)d_out;

    float *logits, *gate, *h;
    int *sel, *idxp, *invp;
    __half *lnh, *qkvh, *attnh, *midh, *wth;
    cudaGetSymbolAddress((void**)&logits, g_logits);
    cudaGetSymbolAddress((void**)&sel, g_sel);
    cudaGetSymbolAddress((void**)&idxp, g_idx);
    cudaGetSymbolAddress((void**)&invp, g_inv);
    cudaGetSymbolAddress((void**)&gate, g_gate);
    cudaGetSymbolAddress((void**)&h, g_h);
    cudaGetSymbolAddress((void**)&lnh, g_lnh);
    cudaGetSymbolAddress((void**)&qkvh, g_qkvh);
    cudaGetSymbolAddress((void**)&attnh, g_attnh);
    cudaGetSymbolAddress((void**)&midh, g_midh);
    cudaGetSymbolAddress((void**)&wth, g_wth);

    cudaFuncSetAttribute(tgemm_kernel,
                         cudaFuncAttributeMaxDynamicSharedMemorySize, (int)TGEMM_SMEM);
    cudaFuncSetAttribute(tgemm_wide<false>,
                         cudaFuncAttributeMaxDynamicSharedMemorySize, (int)TGEMW_SMEM);
    cudaFuncSetAttribute(tgemm_wide<true>,
                         cudaFuncAttributeMaxDynamicSharedMemorySize, (int)TGEMW_SMEM);

    // 0+1. weight conversion AND router in one concurrent kernel
    cvt_router_kernel<<<CVT_BLOCKS + ROUTER_BLOCKS, 256>>>(
        w_qkv, w_o, w1, w2, wth, x, w_router, b_router, logits);

    // 2-3. top-K, fused gather+LN1(layer0)
    rank_kernel<<<CB * 64, 256>>>(logits, sel);
    compact_kernel<<<CB, 1024>>>(logits, sel, idxp, invp, gate);
    gather_ln_kernel<<<BK_ROWS, 256>>>(x, idxp, ln1_scale, ln1_bias, h, lnh);

    // 4. transformer blocks
    for (int l = 0; l < CL; l++) {
        if (l > 0)
            layernorm_kernel<<<BK_ROWS, 256>>>(h, lnh, ln1_scale + l * CD, ln1_bias + l * CD);
        tgemm_wide<false><<<dim3(3 * CD / WBN, BK_ROWS / GBM), 256, TGEMW_SMEM>>>(
            lnh, wth + WQKV_OFF + (size_t)l * CD * 3 * CD, b_qkv + l * 3 * CD,
            qkvh, BK_ROWS, 3 * CD, CD);
        attn_kernel<<<dim3(NQB / 2, CH, CB), 256>>>(qkvh, attnh);
        tgemm_kernel<<<dim3(CD / GBN, BK_ROWS / GBM), 256, TGEMM_SMEM>>>(
            attnh, wth + WO_OFF + (size_t)l * CD * CD, b_o + l * CD, h, h,
            BK_ROWS, CD, CD);
        layernorm_kernel<<<BK_ROWS, 256>>>(h, lnh, ln2_scale + l * CD, ln2_bias + l * CD);
        tgemm_wide<true><<<dim3(CF / WBN, BK_ROWS / GBM), 256, TGEMW_SMEM>>>(
            lnh, wth + W1_OFF + (size_t)l * CD * CF, b1 + l * CF,
            midh, BK_ROWS, CF, CD);
        tgemm_kernel<<<dim3(CD / GBN, BK_ROWS / GBM), 256, TGEMM_SMEM>>>(
            midh, wth + W2_OFF + (size_t)l * CF * CD, b2 + l * CD, h, h,
            BK_ROWS, CD, CF);
    }

    // 5. assemble output: total + idx + logits in one kernel
    int has_tail = ((size_t)out_size >= BTD + CB * CK + CB * CT) ? 1 : 0;
    outfuse_kernel<<<CB * CT, 256>>>(x, h, invp, gate, idxp, logits, out, has_tail);
}

// round 15
// speedup vs baseline: 7.4510x; 1.0063x over previous
#include <cuda_runtime.h>
#include <cuda_fp16.h>
#include <math.h>
#include <stdint.h>

// Problem constants
constexpr int CB = 2;      // batch
constexpr int CT = 4096;   // seq len
constexpr int CD = 1024;   // d_model
constexpr int CL = 2;      // layers
constexpr int CH = 16;     // heads
constexpr int CF = 4096;   // d_ff
constexpr int CK = 2048;   // top-k tokens
constexpr int BK_ROWS = CB * CK;
constexpr size_t BTD = (size_t)CB * CT * CD;

// Weight fp16 scratch offsets (elements)
constexpr size_t WQKV_OFF = 0;
constexpr size_t WQKV_SZ  = (size_t)CL * CD * 3 * CD;
constexpr size_t WO_OFF   = WQKV_OFF + WQKV_SZ;
constexpr size_t WO_SZ    = (size_t)CL * CD * CD;
constexpr size_t W1_OFF   = WO_OFF + WO_SZ;
constexpr size_t W1_SZ    = (size_t)CL * CD * CF;
constexpr size_t W2_OFF   = W1_OFF + W1_SZ;
constexpr size_t W2_SZ    = (size_t)CL * CF * CD;
constexpr size_t WTF_TOTAL = W2_OFF + W2_SZ;

// ---------------- scratch (static device globals) ---------------------------
__device__ float  g_logits[CB * CT];
__device__ int    g_sel[CB * CT];
__device__ int    g_idx[CB * CK];
__device__ int    g_inv[CB * CT];
__device__ float  g_gate[CB * CK];
__device__ float  g_h[BK_ROWS * CD];
__device__ __half g_lnh[BK_ROWS * CD];
__device__ __half g_qkvh[(size_t)BK_ROWS * 3 * CD];
__device__ __half g_attnh[BK_ROWS * CD];
__device__ __half g_midh[(size_t)BK_ROWS * CF];
__device__ __half g_wth[WTF_TOTAL];

__device__ __forceinline__ void mma_f16(float c[4], const uint32_t a[4],
                                        uint32_t b0, uint32_t b1) {
    asm volatile(
        "mma.sync.aligned.m16n8k16.row.col.f32.f16.f16.f32 "
        "{%0,%1,%2,%3}, {%4,%5,%6,%7}, {%8,%9}, {%0,%1,%2,%3};\n"
        : "+f"(c[0]), "+f"(c[1]), "+f"(c[2]), "+f"(c[3])
        : "r"(a[0]), "r"(a[1]), "r"(a[2]), "r"(a[3]), "r"(b0), "r"(b1));
}
__device__ __forceinline__ void ldsm_x4(uint32_t r[4], uint32_t saddr) {
    asm volatile("ldmatrix.sync.aligned.m8n8.x4.shared.b16 {%0,%1,%2,%3}, [%4];"
                 : "=r"(r[0]), "=r"(r[1]), "=r"(r[2]), "=r"(r[3]) : "r"(saddr));
}
__device__ __forceinline__ void ldsm_x4t(uint32_t r[4], uint32_t saddr) {
    asm volatile("ldmatrix.sync.aligned.m8n8.x4.trans.shared.b16 {%0,%1,%2,%3}, [%4];"
                 : "=r"(r[0]), "=r"(r[1]), "=r"(r[2]), "=r"(r[3]) : "r"(saddr));
}
__device__ __forceinline__ void cp16(uint32_t dst, const void* src) {
    asm volatile("cp.async.cg.shared.global [%0], [%1], 16;\n" :: "r"(dst), "l"(src));
}
__device__ __forceinline__ uint32_t pack_h2(float a, float b) {
    __half2 h = __floats2half2_rn(a, b);
    return *(uint32_t*)&h;
}

// ---------------- merged weight-convert + router (independent work) ----------
constexpr int CVT_THREADS_TOTAL = (int)(WTF_TOTAL / 4 / 4);
constexpr int CVT_BLOCKS = CVT_THREADS_TOTAL / 256;        // 6144
constexpr int ROUTER_BLOCKS = (CB * CT) / 8;               // 1024

__global__ void cvt_router_kernel(const float* __restrict__ wqkv,
                                  const float* __restrict__ wo,
                                  const float* __restrict__ w1,
                                  const float* __restrict__ w2,
                                  __half* __restrict__ dst,
                                  const float* __restrict__ x,
                                  const float* __restrict__ wr,
                                  const float* __restrict__ br,
                                  float* __restrict__ logits) {
    if (blockIdx.x < CVT_BLOCKS) {
        constexpr size_t Q4 = WQKV_SZ / 4, O4 = WO_SZ / 4, A4 = W1_SZ / 4;
        const size_t stride = (size_t)CVT_THREADS_TOTAL;
        size_t i0 = (size_t)blockIdx.x * 256 + threadIdx.x;
        __half2* d2 = (__half2*)dst;
#pragma unroll
        for (int j = 0; j < 4; j++) {
            size_t i = i0 + (size_t)j * stride;
            float4 v;
            if (i < Q4)                 v = ((const float4*)wqkv)[i];
            else if (i < Q4 + O4)       v = ((const float4*)wo)[i - Q4];
            else if (i < Q4 + O4 + A4)  v = ((const float4*)w1)[i - Q4 - O4];
            else                        v = ((const float4*)w2)[i - Q4 - O4 - A4];
            d2[2 * i]     = __floats2half2_rn(v.x, v.y);
            d2[2 * i + 1] = __floats2half2_rn(v.z, v.w);
        }
    } else {
        int gw = (((int)blockIdx.x - CVT_BLOCKS) * 256 + (int)threadIdx.x) >> 5;
        if (gw >= CB * CT) return;
        int lane = threadIdx.x & 31;
        const float4* p = (const float4*)(x + (size_t)gw * CD);
        const float4* w4 = (const float4*)wr;
        float s = 0.f;
#pragma unroll
        for (int i = 0; i < CD / 128; i++) {
            float4 a = p[lane + i * 32];
            float4 w = w4[lane + i * 32];
            s += a.x * w.x + a.y * w.y + a.z * w.z + a.w * w.w;
        }
#pragma unroll
        for (int o = 16; o > 0; o >>= 1) s += __shfl_down_sync(0xffffffffu, s, o);
        if (lane == 0) logits[gw] = s + br[0];
    }
}

// ---------------- top-K -----------------------------------------------------
__global__ void rank_kernel(const float* __restrict__ logits, int* __restrict__ sel) {
    int blk = blockIdx.x;
    int b = blk >> 6;
    int base = (blk & 63) * 64;
    __shared__ float lv[CT];
    int tid = threadIdx.x;
    for (int t = tid; t < CT; t += 256) lv[t] = logits[b * CT + t];
    __syncthreads();
    int tt = tid >> 2, part = tid & 3;
    int t = base + tt;
    float v = lv[t];
    int cnt = 0;
    int s0 = part * 1024;
#pragma unroll 8
    for (int s = s0; s < s0 + 1024; s++) {
        float u = lv[s];
        cnt += (u > v) || (u == v && s < t);
    }
    __shared__ int rk[64];
    if (part == 0) rk[tt] = 0;
    __syncthreads();
    atomicAdd(&rk[tt], cnt);
    __syncthreads();
    if (part == 0) sel[b * CT + t] = (rk[tt] < CK) ? 1 : 0;
}

__global__ void compact_kernel(const float* __restrict__ logits,
                               const int* __restrict__ sel,
                               int* __restrict__ idx_out,
                               int* __restrict__ inv_out,
                               float* __restrict__ gate_out) {
    int b = blockIdx.x;
    int tid = threadIdx.x;
    int f[4]; int c = 0;
#pragma unroll
    for (int i = 0; i < 4; i++) { f[i] = sel[b * CT + tid * 4 + i]; c += f[i]; }
    int lane = tid & 31, wid = tid >> 5;
    int incl = c;
#pragma unroll
    for (int o = 1; o < 32; o <<= 1) {
        int n = __shfl_up_sync(0xffffffffu, incl, o);
        if (lane >= o) incl += n;
    }
    __shared__ int wsum[32];
    if (lane == 31) wsum[wid] = incl;
    __syncthreads();
    if (wid == 0) {
        int w = wsum[lane];
#pragma unroll
        for (int o = 1; o < 32; o <<= 1) {
            int n = __shfl_up_sync(0xffffffffu, w, o);
            if (lane >= o) w += n;
        }
        wsum[lane] = w;
    }
    __syncthreads();
    int pos = (wid ? wsum[wid - 1] : 0) + incl - c;
#pragma unroll
    for (int i = 0; i < 4; i++) {
        int t = tid * 4 + i;
        if (f[i]) {
            idx_out[b * CK + pos] = t;
            inv_out[b * CT + t] = pos;
            float lg = logits[b * CT + t];
            gate_out[b * CK + pos] = 1.f / (1.f + expf(-lg));
            pos++;
        } else {
            inv_out[b * CT + t] = -1;
        }
    }
}

// ---------------- warp-per-row LN core ---------------------------------------
// One warp owns a full 1024-float row: 8 float4 per lane, shfl-xor reduce,
// no smem, no block barriers.
__device__ __forceinline__ void warp_ln_row(const float4 v[8], int lane,
                                            const float* __restrict__ scale,
                                            const float* __restrict__ bias,
                                            __half* __restrict__ outrow) {
    float s = 0.f, ss = 0.f;
#pragma unroll
    for (int j = 0; j < 8; j++) {
        s  += v[j].x + v[j].y + v[j].z + v[j].w;
        ss += v[j].x * v[j].x + v[j].y * v[j].y + v[j].z * v[j].z + v[j].w * v[j].w;
    }
#pragma unroll
    for (int o = 16; o > 0; o >>= 1) {
        s  += __shfl_xor_sync(0xffffffffu, s, o);
        ss += __shfl_xor_sync(0xffffffffu, ss, o);
    }
    float mean = s * (1.f / CD);
    float var = ss * (1.f / CD) - mean * mean;
    float inv = rsqrtf(var + 1e-5f);
#pragma unroll
    for (int j = 0; j < 8; j++) {
        int c4 = lane + 32 * j;
        float4 sc = ((const float4*)scale)[c4];
        float4 bi = ((const float4*)bias)[c4];
        __half2 h0 = __floats2half2_rn((v[j].x - mean) * inv * sc.x + bi.x,
                                       (v[j].y - mean) * inv * sc.y + bi.y);
        __half2 h1 = __floats2half2_rn((v[j].z - mean) * inv * sc.z + bi.z,
                                       (v[j].w - mean) * inv * sc.w + bi.w);
        __half2* o2 = (__half2*)outrow;
        o2[2 * c4]     = h0;
        o2[2 * c4 + 1] = h1;
    }
}

// ---------------- fused gather + first layernorm (warp-per-row) --------------
__global__ void gather_ln_kernel(const float* __restrict__ x, const int* __restrict__ idx,
                                 const float* __restrict__ scale,
                                 const float* __restrict__ bias,
                                 float* __restrict__ h, __half* __restrict__ lnh) {
    int bk = blockIdx.x * 8 + (threadIdx.x >> 5);   // grid = BK_ROWS/8
    int lane = threadIdx.x & 31;
    int b = bk >> 11;
    int t = idx[bk];
    const float4* src = (const float4*)(x + ((size_t)b * CT + t) * CD);
    float4* hdst = (float4*)(h + (size_t)bk * CD);
    float4 v[8];
#pragma unroll
    for (int j = 0; j < 8; j++) {
        v[j] = src[lane + 32 * j];
        hdst[lane + 32 * j] = v[j];
    }
    warp_ln_row(v, lane, scale, bias, lnh + (size_t)bk * CD);
}

// ---------------- layernorm (warp-per-row, fp32 in -> fp16 out) --------------
__global__ void layernorm_kernel(const float* __restrict__ in, __half* __restrict__ out,
                                 const float* __restrict__ scale,
                                 const float* __restrict__ bias) {
    int row = blockIdx.x * 8 + (threadIdx.x >> 5);
    int lane = threadIdx.x & 31;
    const float4* p = (const float4*)(in + (size_t)row * CD);
    float4 v[8];
#pragma unroll
    for (int j = 0; j < 8; j++) v[j] = p[lane + 32 * j];
    warp_ln_row(v, lane, scale, bias, out + (size_t)row * CD);
}

// ---------------- common GEMM bits -------------------------------------------
__device__ __forceinline__ float gelu_tanh(float x) {
    float x3 = x * x * x;
    float t = tanhf(0.7978845608028654f * (x + 0.044715f * x3));
    return 0.5f * x * (1.f + t);
}

// ============ narrow GEMM: 128x128x64, 3-stage, issue->wait->sync->compute->sync
constexpr int GBM = 128, GBN = 128, GBK = 64;
constexpr int AST = GBK + 8;
constexpr int BST = GBN + 8;
constexpr int ABUFH = GBM * AST;
constexpr int BBUFH = GBK * BST;
constexpr size_t TGEMM_SMEM = (size_t)(ABUFH + BBUFH) * 3 * sizeof(__half);

__global__ __launch_bounds__(256) void tgemm_kernel(
    const __half* __restrict__ A, const __half* __restrict__ W,
    const float* __restrict__ bias, const float* __restrict__ R,
    float* __restrict__ C, int M, int N, int Kd) {
    extern __shared__ __half dsm[];
    __half* As = dsm;
    __half* Bs = dsm + 3 * ABUFH;

    const int tid = threadIdx.x;
    const int bx = blockIdx.x, by = blockIdx.y;
    const int wid = tid >> 5, lane = tid & 31;
    const int warp_m = wid & 1;
    const int warp_n = wid >> 1;
    const int g = lane >> 2;
    const int tg = lane & 3;
    const int lm = (lane & 7) + ((lane >> 3) & 1) * 8;
    const int lk = ((lane >> 4) & 1) * 8;
    const int vrow = (lane & 7) + ((lane >> 3) & 1) * 8;
    const int vcol = ((lane >> 4) & 1) * 8;

    float c[4][4][4];
#pragma unroll
    for (int mi = 0; mi < 4; mi++)
#pragma unroll
        for (int ni = 0; ni < 4; ni++)
#pragma unroll
            for (int r = 0; r < 4; r++) c[mi][ni][r] = 0.f;

    const int ntiles = Kd / GBK;

    auto issue_tile = [&](int t, int buf) {
        int k0 = t * GBK;
        uint32_t abase = (uint32_t)__cvta_generic_to_shared(As + buf * ABUFH);
        uint32_t bbase = (uint32_t)__cvta_generic_to_shared(Bs + buf * BBUFH);
#pragma unroll
        for (int i = 0; i < 4; i++) {
            int q = tid + i * 256;
            int row = q >> 3, c8 = (q & 7) * 8;
            cp16(abase + (row * AST + c8) * 2, A + (size_t)(by * GBM + row) * Kd + k0 + c8);
        }
#pragma unroll
        for (int i = 0; i < 4; i++) {
            int q = tid + i * 256;
            int row = q >> 4, n8 = (q & 15) * 8;
            cp16(bbase + (row * BST + n8) * 2, W + (size_t)(k0 + row) * N + bx * GBN + n8);
        }
        asm volatile("cp.async.commit_group;\n");
    };

    issue_tile(0, 0);
    if (ntiles > 1) issue_tile(1, 1);
    for (int t = 0; t < ntiles; t++) {
        if (t + 2 < ntiles) {
            issue_tile(t + 2, (t + 2) % 3);
            asm volatile("cp.async.wait_group 2;\n");
        } else if (t + 1 < ntiles) {
            asm volatile("cp.async.wait_group 1;\n");
        } else {
            asm volatile("cp.async.wait_group 0;\n");
        }
        __syncthreads();
        int buf = t % 3;
        uint32_t Ab = (uint32_t)__cvta_generic_to_shared(As + buf * ABUFH);
        uint32_t Bb = (uint32_t)__cvta_generic_to_shared(Bs + buf * BBUFH);
        uint32_t a_off = Ab + ((warp_m * 64 + lm) * AST + lk) * 2;
#pragma unroll
        for (int ks = 0; ks < GBK / 16; ks++) {
            uint32_t a[4][4], b[4][2];
#pragma unroll
            for (int mi = 0; mi < 4; mi++)
                ldsm_x4(a[mi], a_off + (mi * 16 * AST + ks * 16) * 2);
#pragma unroll
            for (int ni = 0; ni < 4; ni += 2) {
                uint32_t b4[4];
                ldsm_x4t(b4, Bb + ((ks * 16 + vrow) * BST + warp_n * 32 + ni * 8 + vcol) * 2);
                b[ni][0] = b4[0]; b[ni][1] = b4[1];
                b[ni + 1][0] = b4[2]; b[ni + 1][1] = b4[3];
            }
#pragma unroll
            for (int mi = 0; mi < 4; mi++)
#pragma unroll
                for (int ni = 0; ni < 4; ni++)
                    mma_f16(c[mi][ni], a[mi], b[ni][0], b[ni][1]);
        }
        __syncthreads();
    }

#pragma unroll
    for (int mi = 0; mi < 4; mi++) {
        int m0 = by * GBM + warp_m * 64 + mi * 16 + g;
#pragma unroll
        for (int ni = 0; ni < 4; ni++) {
            int n0 = bx * GBN + warp_n * 32 + ni * 8 + 2 * tg;
            float b0 = bias[n0], b1 = bias[n0 + 1];
#pragma unroll
            for (int half = 0; half < 2; half++) {
                int m = m0 + half * 8;
                float v0 = c[mi][ni][half * 2 + 0] + b0;
                float v1 = c[mi][ni][half * 2 + 1] + b1;
                const float2 r2 = *(const float2*)(R + (size_t)m * N + n0);
                v0 += r2.x; v1 += r2.y;
                *(float2*)(C + (size_t)m * N + n0) = make_float2(v0, v1);
            }
        }
    }
}

// ============ wide GEMM: 128x256x64, 4-buffer ring p=2, SINGLE sync/iter ====
constexpr int WBN = 256;
constexpr int BSTW = WBN + 8;
constexpr int BBUFW = GBK * BSTW;
constexpr size_t TGEMW_SMEM = (size_t)(ABUFH + BBUFW) * 4 * sizeof(__half);

template <bool GELU>
__global__ __launch_bounds__(256) void tgemm_wide(
    const __half* __restrict__ A, const __half* __restrict__ W,
    const float* __restrict__ bias, __half* __restrict__ C,
    int M, int N, int Kd) {
    extern __shared__ __half dsm[];
    __half* As = dsm;
    __half* Bs = dsm + 4 * ABUFH;

    const int tid = threadIdx.x;
    const int bx = blockIdx.x, by = blockIdx.y;
    const int wid = tid >> 5, lane = tid & 31;
    const int warp_m = wid & 1;
    const int warp_n = wid >> 1;
    const int g = lane >> 2;
    const int tg = lane & 3;
    const int lm = (lane & 7) + ((lane >> 3) & 1) * 8;
    const int lk = ((lane >> 4) & 1) * 8;
    const int vrow = (lane & 7) + ((lane >> 3) & 1) * 8;
    const int vcol = ((lane >> 4) & 1) * 8;

    float c[4][8][4];
#pragma unroll
    for (int mi = 0; mi < 4; mi++)
#pragma unroll
        for (int ni = 0; ni < 8; ni++)
#pragma unroll
            for (int r = 0; r < 4; r++) c[mi][ni][r] = 0.f;

    const int ntiles = Kd / GBK;

    auto issue_tile = [&](int t, int buf) {
        int k0 = t * GBK;
        uint32_t abase = (uint32_t)__cvta_generic_to_shared(As + buf * ABUFH);
        uint32_t bbase = (uint32_t)__cvta_generic_to_shared(Bs + buf * BBUFW);
#pragma unroll
        for (int i = 0; i < 4; i++) {
            int q = tid + i * 256;
            int row = q >> 3, c8 = (q & 7) * 8;
            cp16(abase + (row * AST + c8) * 2, A + (size_t)(by * GBM + row) * Kd + k0 + c8);
        }
#pragma unroll
        for (int i = 0; i < 8; i++) {
            int q = tid + i * 256;
            int row = q >> 5, n8 = (q & 31) * 8;
            cp16(bbase + (row * BSTW + n8) * 2, W + (size_t)(k0 + row) * N + bx * WBN + n8);
        }
        asm volatile("cp.async.commit_group;\n");
    };

    issue_tile(0, 0);
    if (ntiles > 1) issue_tile(1, 1);
    for (int t = 0; t < ntiles; t++) {
        if (t + 2 < ntiles) {
            issue_tile(t + 2, (t + 2) & 3);
            asm volatile("cp.async.wait_group 2;\n");
        } else if (t + 1 < ntiles) {
            asm volatile("cp.async.wait_group 1;\n");
        } else {
            asm volatile("cp.async.wait_group 0;\n");
        }
        __syncthreads();
        int buf = t & 3;
        uint32_t Ab = (uint32_t)__cvta_generic_to_shared(As + buf * ABUFH);
        uint32_t Bb = (uint32_t)__cvta_generic_to_shared(Bs + buf * BBUFW);
        uint32_t a_off = Ab + ((warp_m * 64 + lm) * AST + lk) * 2;
#pragma unroll
        for (int ks = 0; ks < GBK / 16; ks++) {
            uint32_t a[4][4], b[8][2];
#pragma unroll
            for (int mi = 0; mi < 4; mi++)
                ldsm_x4(a[mi], a_off + (mi * 16 * AST + ks * 16) * 2);
#pragma unroll
            for (int ni = 0; ni < 8; ni += 2) {
                uint32_t b4[4];
                ldsm_x4t(b4, Bb + ((ks * 16 + vrow) * BSTW + warp_n * 64 + ni * 8 + vcol) * 2);
                b[ni][0] = b4[0]; b[ni][1] = b4[1];
                b[ni + 1][0] = b4[2]; b[ni + 1][1] = b4[3];
            }
#pragma unroll
            for (int mi = 0; mi < 4; mi++)
#pragma unroll
                for (int ni = 0; ni < 8; ni++)
                    mma_f16(c[mi][ni], a[mi], b[ni][0], b[ni][1]);
        }
    }

#pragma unroll
    for (int mi = 0; mi < 4; mi++) {
        int m0 = by * GBM + warp_m * 64 + mi * 16 + g;
#pragma unroll
        for (int ni = 0; ni < 8; ni++) {
            int n0 = bx * WBN + warp_n * 64 + ni * 8 + 2 * tg;
            float b0 = bias[n0], b1 = bias[n0 + 1];
#pragma unroll
            for (int half = 0; half < 2; half++) {
                int m = m0 + half * 8;
                float v0 = c[mi][ni][half * 2 + 0] + b0;
                float v1 = c[mi][ni][half * 2 + 1] + b1;
                if (GELU) { v0 = gelu_tanh(v0); v1 = gelu_tanh(v1); }
                *(__half2*)(C + (size_t)m * N + n0) = __floats2half2_rn(v0, v1);
            }
        }
    }
}

// ---------------- FP16 MMA flash attention v4 (unchanged) --------------------
constexpr int SATT = 72;
constexpr int NQB = CK / 128;   // 16
__global__ __launch_bounds__(256) void attn_kernel(const __half* __restrict__ qkv,
                                                   __half* __restrict__ o) {
    const int pairi = blockIdx.x, h = blockIdx.y, b = blockIdx.z;
    const int tid = threadIdx.x;
    const int w = tid >> 5, lane = tid & 31;
    const int g = lane >> 2, tg = lane & 3;
    const int lm = (lane & 7) + ((lane >> 3) & 1) * 8;
    const int lk = ((lane >> 4) & 1) * 8;

    __shared__ __half KV[6][64 * SATT];
    uint32_t base[6];
#pragma unroll
    for (int i = 0; i < 6; i++) base[i] = (uint32_t)__cvta_generic_to_shared(KV[i]);

    const int srow = (lane & 7) + ((lane >> 4) & 1) * 8;
    const int scol = ((lane >> 3) & 1) * 8;
    const int vrow = (lane & 7) + ((lane >> 3) & 1) * 8;
    const int vcol = ((lane >> 4) & 1) * 8;

    const __half2 sc8 = __float2half2_rn(0.125f);

    for (int s = 0; s < 2; s++) {
        const int qb = (s == 0) ? pairi : (NQB - 1 - pairi);

        __syncthreads();
#pragma unroll
        for (int i = 0; i < 4; i++) {
            int q = tid + i * 256;
            int r = q >> 3, c8 = (q & 7) * 8;
            const __half* src = qkv + ((size_t)(b * CK + qb * 128 + r)) * (3 * CD) + h * 64 + c8;
            uint4 u = *(const uint4*)src;
            __half2* hp = (__half2*)&u;
#pragma unroll
            for (int j = 0; j < 4; j++) hp[j] = __hmul2(hp[j], sc8);
            *(uint4*)&KV[0][r * SATT + c8] = u;
        }
        __syncthreads();
        uint32_t qf[4][4];
#pragma unroll
        for (int ks = 0; ks < 4; ks++)
            ldsm_x4(qf[ks], base[0] + ((w * 16 + lm) * SATT + ks * 16 + lk) * 2);
        __syncthreads();

        float of[8][4];
#pragma unroll
        for (int ni = 0; ni < 8; ni++)
#pragma unroll
            for (int r = 0; r < 4; r++) of[ni][r] = 0.f;
        float mi0 = -1e30f, mi1 = -1e30f, li0 = 0.f, li1 = 0.f;

        const int nt = 2 * qb + 2;
        const int rowg0 = qb * 128 + w * 16 + g;
        const int rowg1 = rowg0 + 8;

        auto issue = [&](int kt, int buf) {
            uint32_t kb = base[buf];
            uint32_t vb = base[3 + buf];
#pragma unroll
            for (int i = 0; i < 2; i++) {
                int q = tid + i * 256;
                int r = q >> 3, c8 = (q & 7) * 8;
                const __half* kbp = qkv + ((size_t)(b * CK + kt * 64 + r)) * (3 * CD) + CD + h * 64 + c8;
                cp16(kb + (r * SATT + c8) * 2, kbp);
                cp16(vb + (r * SATT + c8) * 2, kbp + CD);
            }
            asm volatile("cp.async.commit_group;\n");
        };

        issue(0, 0);
        for (int kt = 0; kt < nt; kt++) {
            if (kt + 1 < nt) {
                issue(kt + 1, (kt + 1) % 3);
                asm volatile("cp.async.wait_group 1;\n");
            } else {
                asm volatile("cp.async.wait_group 0;\n");
            }
            __syncthreads();
            uint32_t ksb = base[kt % 3];
            uint32_t vsb = base[3 + (kt % 3)];

            float sf[8][4];
#pragma unroll
            for (int ni = 0; ni < 8; ni++)
#pragma unroll
                for (int r = 0; r < 4; r++) sf[ni][r] = 0.f;
#pragma unroll
            for (int ks = 0; ks < 4; ks++) {
#pragma unroll
                for (int ni = 0; ni < 8; ni += 2) {
                    uint32_t b4[4];
                    ldsm_x4(b4, ksb + ((ni * 8 + srow) * SATT + ks * 16 + scol) * 2);
                    mma_f16(sf[ni],     qf[ks], b4[0], b4[1]);
                    mma_f16(sf[ni + 1], qf[ks], b4[2], b4[3]);
                }
            }

            if (kt >= 2 * qb) {
                int cbase = kt * 64;
#pragma unroll
                for (int ni = 0; ni < 8; ni++) {
                    int c0 = cbase + ni * 8 + 2 * tg, c1 = c0 + 1;
                    if (c0 > rowg0) sf[ni][0] = -1e30f;
                    if (c1 > rowg0) sf[ni][1] = -1e30f;
                    if (c0 > rowg1) sf[ni][2] = -1e30f;
                    if (c1 > rowg1) sf[ni][3] = -1e30f;
                }
            }

            float m0 = -1e30f, m1 = -1e30f;
#pragma unroll
            for (int ni = 0; ni < 8; ni++) {
                m0 = fmaxf(m0, fmaxf(sf[ni][0], sf[ni][1]));
                m1 = fmaxf(m1, fmaxf(sf[ni][2], sf[ni][3]));
            }
            m0 = fmaxf(m0, __shfl_xor_sync(0xffffffffu, m0, 1));
            m0 = fmaxf(m0, __shfl_xor_sync(0xffffffffu, m0, 2));
            m1 = fmaxf(m1, __shfl_xor_sync(0xffffffffu, m1, 1));
            m1 = fmaxf(m1, __shfl_xor_sync(0xffffffffu, m1, 2));
            float nm0 = fmaxf(mi0, m0), nm1 = fmaxf(mi1, m1);
            float co0 = __expf(mi0 - nm0), co1 = __expf(mi1 - nm1);
            float rs0 = 0.f, rs1 = 0.f;
#pragma unroll
            for (int ni = 0; ni < 8; ni++) {
                sf[ni][0] = __expf(sf[ni][0] - nm0);
                sf[ni][1] = __expf(sf[ni][1] - nm0);
                sf[ni][2] = __expf(sf[ni][2] - nm1);
                sf[ni][3] = __expf(sf[ni][3] - nm1);
                rs0 += sf[ni][0] + sf[ni][1];
                rs1 += sf[ni][2] + sf[ni][3];
            }
            rs0 += __shfl_xor_sync(0xffffffffu, rs0, 1);
            rs0 += __shfl_xor_sync(0xffffffffu, rs0, 2);
            rs1 += __shfl_xor_sync(0xffffffffu, rs1, 1);
            rs1 += __shfl_xor_sync(0xffffffffu, rs1, 2);
            li0 = li0 * co0 + rs0;
            li1 = li1 * co1 + rs1;
            mi0 = nm0; mi1 = nm1;
#pragma unroll
            for (int ni = 0; ni < 8; ni++) {
                of[ni][0] *= co0; of[ni][1] *= co0;
                of[ni][2] *= co1; of[ni][3] *= co1;
            }

#pragma unroll
            for (int js = 0; js < 4; js++) {
                uint32_t a[4];
                a[0] = pack_h2(sf[2 * js][0], sf[2 * js][1]);
                a[1] = pack_h2(sf[2 * js][2], sf[2 * js][3]);
                a[2] = pack_h2(sf[2 * js + 1][0], sf[2 * js + 1][1]);
                a[3] = pack_h2(sf[2 * js + 1][2], sf[2 * js + 1][3]);
#pragma unroll
                for (int ni = 0; ni < 8; ni += 2) {
                    uint32_t b4[4];
                    ldsm_x4t(b4, vsb + ((js * 16 + vrow) * SATT + (ni + (vcol >> 3)) * 8) * 2);
                    mma_f16(of[ni],     a, b4[0], b4[1]);
                    mma_f16(of[ni + 1], a, b4[2], b4[3]);
                }
            }
        }

        float il0 = 1.f / li0, il1 = 1.f / li1;
#pragma unroll
        for (int ni = 0; ni < 8; ni++) {
            int col = h * 64 + ni * 8 + 2 * tg;
            *(__half2*)(o + ((size_t)(b * CK + rowg0)) * CD + col) =
                __floats2half2_rn(of[ni][0] * il0, of[ni][1] * il0);
            *(__half2*)(o + ((size_t)(b * CK + rowg1)) * CD + col) =
                __floats2half2_rn(of[ni][2] * il1, of[ni][3] * il1);
        }
    }
}

// ---------------- output assembly (copy + gated scatter + idx/logits tail) ---
__global__ void outfuse_kernel(const float* __restrict__ x,
                               const float* __restrict__ h,
                               const int* __restrict__ inv,
                               const float* __restrict__ gate,
                               const int* __restrict__ idx,
                               const float* __restrict__ logits,
                               float* __restrict__ out, int has_tail) {
    int row = blockIdx.x;
    int b = row >> 12;
    int pos = inv[row];
    const float4* src = (const float4*)(x + (size_t)row * CD);
    float4* dst = (float4*)(out + (size_t)row * CD);
    float4 v = src[threadIdx.x];
    if (pos >= 0) {
        float gval = gate[b * CK + pos];
        const float4* hp = (const float4*)(h + (size_t)(b * CK + pos) * CD);
        float4 hv = hp[threadIdx.x];
        v.x += hv.x * gval; v.y += hv.y * gval;
        v.z += hv.z * gval; v.w += hv.w * gval;
    }
    dst[threadIdx.x] = v;
    if (has_tail) {
        if (threadIdx.x == 0 && row < CB * CK)
            out[BTD + row] = (float)idx[row];
        if (threadIdx.x == 1)
            out[BTD + CB * CK + row] = logits[row];
    }
}

// ---------------- launch -----------------------------------------------------
extern "C" void kernel_launch(void* const* d_in, const int* in_sizes, int n_in,
                              void* d_out, int out_size) {
    const float* x         = (const float*)d_in[0];
    const float* w_router  = (const float*)d_in[1];
    const float* b_router  = (const float*)d_in[2];
    const float* ln1_scale = (const float*)d_in[3];
    const float* ln1_bias  = (const float*)d_in[4];
    const float* w_qkv     = (const float*)d_in[5];
    const float* b_qkv     = (const float*)d_in[6];
    const float* w_o       = (const float*)d_in[7];
    const float* b_o       = (const float*)d_in[8];
    const float* ln2_scale = (const float*)d_in[9];
    const float* ln2_bias  = (const float*)d_in[10];
    const float* w1        = (const float*)d_in[11];
    const float* b1        = (const float*)d_in[12];
    const float* w2        = (const float*)d_in[13];
    const float* b2        = (const float*)d_in[14];
    float* out = (float*)d_out;

    float *logits, *gate, *h;
    int *sel, *idxp, *invp;
    __half *lnh, *qkvh, *attnh, *midh, *wth;
    cudaGetSymbolAddress((void**)&logits, g_logits);
    cudaGetSymbolAddress((void**)&sel, g_sel);
    cudaGetSymbolAddress((void**)&idxp, g_idx);
    cudaGetSymbolAddress((void**)&invp, g_inv);
    cudaGetSymbolAddress((void**)&gate, g_gate);
    cudaGetSymbolAddress((void**)&h, g_h);
    cudaGetSymbolAddress((void**)&lnh, g_lnh);
    cudaGetSymbolAddress((void**)&qkvh, g_qkvh);
    cudaGetSymbolAddress((void**)&attnh, g_attnh);
    cudaGetSymbolAddress((void**)&midh, g_midh);
    cudaGetSymbolAddress((void**)&wth, g_wth);

    cudaFuncSetAttribute(tgemm_kernel,
                         cudaFuncAttributeMaxDynamicSharedMemorySize, (int)TGEMM_SMEM);
    cudaFuncSetAttribute(tgemm_wide<false>,
                         cudaFuncAttributeMaxDynamicSharedMemorySize, (int)TGEMW_SMEM);
    cudaFuncSetAttribute(tgemm_wide<true>,
                         cudaFuncAttributeMaxDynamicSharedMemorySize, (int)TGEMW_SMEM);

    // 0+1. weight conversion AND router in one concurrent kernel
    cvt_router_kernel<<<CVT_BLOCKS + ROUTER_BLOCKS, 256>>>(
        w_qkv, w_o, w1, w2, wth, x, w_router, b_router, logits);

    // 2-3. top-K, fused gather+LN1(layer0)
    rank_kernel<<<CB * 64, 256>>>(logits, sel);
    compact_kernel<<<CB, 1024>>>(logits, sel, idxp, invp, gate);
    gather_ln_kernel<<<BK_ROWS / 8, 256>>>(x, idxp, ln1_scale, ln1_bias, h, lnh);

    // 4. transformer blocks
    for (int l = 0; l < CL; l++) {
        if (l > 0)
            layernorm_kernel<<<BK_ROWS / 8, 256>>>(h, lnh, ln1_scale + l * CD, ln1_bias + l * CD);
        tgemm_wide<false><<<dim3(3 * CD / WBN, BK_ROWS / GBM), 256, TGEMW_SMEM>>>(
            lnh, wth + WQKV_OFF + (size_t)l * CD * 3 * CD, b_qkv + l * 3 * CD,
            qkvh, BK_ROWS, 3 * CD, CD);
        attn_kernel<<<dim3(NQB / 2, CH, CB), 256>>>(qkvh, attnh);
        tgemm_kernel<<<dim3(CD / GBN, BK_ROWS / GBM), 256, TGEMM_SMEM>>>(
            attnh, wth + WO_OFF + (size_t)l * CD * CD, b_o + l * CD, h, h,
            BK_ROWS, CD, CD);
        layernorm_kernel<<<BK_ROWS / 8, 256>>>(h, lnh, ln2_scale + l * CD, ln2_bias + l * CD);
        tgemm_wide<true><<<dim3(CF / WBN, BK_ROWS / GBM), 256, TGEMW_SMEM>>>(
            lnh, wth + W1_OFF + (size_t)l * CD * CF, b1 + l * CF,
            midh, BK_ROWS, CF, CD);
        tgemm_kernel<<<dim3(CD / GBN, BK_ROWS / GBM), 256, TGEMM_SMEM>>>(
            midh, wth + W2_OFF + (size_t)l * CF * CD, b2 + l * CD, h, h,
            BK_ROWS, CD, CF);
    }

    // 5. assemble output: total + idx + logits in one kernel
    int has_tail = ((size_t)out_size >= BTD + CB * CK + CB * CT) ? 1 : 0;
    outfuse_kernel<<<CB * CT, 256>>>(x, h, invp, gate, idxp, logits, out, has_tail);
}